// round 1
// baseline (speedup 1.0000x reference)
#include <cuda_runtime.h>
#include <cstddef>

#define F      256
#define NH     8
#define HD     32
#define BATCH  2
#define HH     80
#define WW     80
#define NPIX   (BATCH*HH*WW)   // 12800
#define PDIM   1536
#define HIDN   1024

// ---------------- scratch (no allocations allowed) ----------------
__device__ float g_P0[(size_t)NPIX*PDIM];
__device__ float g_P1[(size_t)NPIX*PDIM];
__device__ float g_Asa0[(size_t)NPIX*F];
__device__ float g_Asa1[(size_t)NPIX*F];
__device__ float g_Atd0[(size_t)NPIX*F];
__device__ float g_Abu0[(size_t)NPIX*F];
__device__ float g_T0[(size_t)NPIX*F];
__device__ float g_T1[(size_t)NPIX*F];
__device__ float g_X0[(size_t)NPIX*F];
__device__ float g_X1[(size_t)NPIX*F];
__device__ float g_U0[(size_t)NPIX*HIDN];
__device__ float g_U1[(size_t)NPIX*HIDN];

// ---------------- GEMM: C[m,n] = act( sum_k A[m,k]*W[n,k] + bias[n] + res[m,n] ) ----------------
// M divisible by 128, N divisible by 128, K divisible by 16. All true here.
#define BM 128
#define BN 128
#define BK 16

__global__ __launch_bounds__(256) void gemm_kernel(
    const float* __restrict__ A, int lda,
    const float* __restrict__ W, int ldw,
    const float* __restrict__ bias,
    const float* __restrict__ res,
    float* __restrict__ C,
    int N, int K, int relu)
{
    __shared__ float As[BK][BM + 4];
    __shared__ float Ws[BK][BN + 4];

    const int tid  = threadIdx.x;
    const int brow = blockIdx.y * BM;
    const int bcol = blockIdx.x * BN;
    const int tr   = tid >> 4;     // 0..15
    const int tc   = tid & 15;     // 0..15
    const int m0   = tr * 8;
    const int n0   = tc * 8;

    float acc[8][8];
#pragma unroll
    for (int i = 0; i < 8; i++)
#pragma unroll
        for (int j = 0; j < 8; j++) acc[i][j] = 0.f;

    for (int k0 = 0; k0 < K; k0 += BK) {
#pragma unroll
        for (int l = 0; l < 2; l++) {
            int idx = tid + l * 256;          // float4 index 0..511
            int row = idx >> 2;               // 0..127
            int k4  = (idx & 3) << 2;         // 0,4,8,12
            float4 av = *(const float4*)(A + (size_t)(brow + row) * lda + k0 + k4);
            As[k4 + 0][row] = av.x; As[k4 + 1][row] = av.y;
            As[k4 + 2][row] = av.z; As[k4 + 3][row] = av.w;
            float4 wv = *(const float4*)(W + (size_t)(bcol + row) * ldw + k0 + k4);
            Ws[k4 + 0][row] = wv.x; Ws[k4 + 1][row] = wv.y;
            Ws[k4 + 2][row] = wv.z; Ws[k4 + 3][row] = wv.w;
        }
        __syncthreads();

#pragma unroll
        for (int k = 0; k < BK; k++) {
            float a[8], b[8];
            const float4* ap = (const float4*)&As[k][m0];
            const float4* bp = (const float4*)&Ws[k][n0];
            float4 a0 = ap[0], a1 = ap[1];
            float4 b0 = bp[0], b1 = bp[1];
            a[0]=a0.x; a[1]=a0.y; a[2]=a0.z; a[3]=a0.w;
            a[4]=a1.x; a[5]=a1.y; a[6]=a1.z; a[7]=a1.w;
            b[0]=b0.x; b[1]=b0.y; b[2]=b0.z; b[3]=b0.w;
            b[4]=b1.x; b[5]=b1.y; b[6]=b1.z; b[7]=b1.w;
#pragma unroll
            for (int i = 0; i < 8; i++)
#pragma unroll
                for (int j = 0; j < 8; j++)
                    acc[i][j] = fmaf(a[i], b[j], acc[i][j]);
        }
        __syncthreads();
    }

#pragma unroll
    for (int i = 0; i < 8; i++) {
        int m = brow + m0 + i;
#pragma unroll
        for (int j = 0; j < 8; j++) {
            int n = bcol + n0 + j;
            float v = acc[i][j] + bias[n];
            if (res) v += res[(size_t)m * N + n];
            if (relu) v = fmaxf(v, 0.f);
            C[(size_t)m * N + n] = v;
        }
    }
}

// ---------------- 9-tap windowed multi-head attention ----------------
// One block per pixel; warp w == head w; lane == dim within head (HD==32).
__global__ __launch_bounds__(256) void attend_kernel(
    const float* __restrict__ Q,   // base + q channel offset, row stride PDIM
    const float* __restrict__ Kp,  // base + k channel offset
    const float* __restrict__ Vp,  // base + v channel offset
    float* __restrict__ Out)       // [NPIX, F]
{
    const int pix = blockIdx.x;
    const int b   = pix / (HH * WW);
    const int r   = pix % (HH * WW);
    const int y   = r / WW;
    const int x   = r % WW;
    const int ch  = threadIdx.x;   // head*32 + lane

    const float scale = 0.17677669529663687f; // 32^-0.5
    const float q = scale * Q[(size_t)pix * PDIM + ch];

    float sc[9], vv[9];
#pragma unroll
    for (int n = 0; n < 9; n++) {
        int dy = n / 3 - 1, dx = n % 3 - 1;
        int yy = y + dy, xx = x + dx;
        float s = 0.f, v = 0.f;
        if (yy >= 0 && yy < HH && xx >= 0 && xx < WW) {
            size_t np = ((size_t)(b * HH + yy) * WW + xx) * PDIM + ch;
            s = q * Kp[np];
            v = Vp[np];
        }
#pragma unroll
        for (int o = 16; o > 0; o >>= 1)
            s += __shfl_xor_sync(0xffffffffu, s, o);
        sc[n] = s;   // zero-padded taps contribute score exactly 0 (q . 0)
        vv[n] = v;
    }

    float mx = sc[0];
#pragma unroll
    for (int n = 1; n < 9; n++) mx = fmaxf(mx, sc[n]);
    float den = 0.f, o = 0.f;
#pragma unroll
    for (int n = 0; n < 9; n++) {
        float w = __expf(sc[n] - mx);
        den += w;
        o += w * vv[n];
    }
    Out[(size_t)pix * F + ch] = o / den;
}

// ---------------- LayerNorm over last dim (256) ----------------
__global__ __launch_bounds__(256) void ln_kernel(
    const float* __restrict__ X,
    const float* __restrict__ g,
    const float* __restrict__ bt,
    float* __restrict__ O)
{
    const int row = blockIdx.x;
    const int t   = threadIdx.x;
    const int warp = t >> 5, lane = t & 31;
    __shared__ float red[8];

    float v = X[(size_t)row * F + t];

    float s = v;
#pragma unroll
    for (int o = 16; o > 0; o >>= 1) s += __shfl_xor_sync(0xffffffffu, s, o);
    if (lane == 0) red[warp] = s;
    __syncthreads();
    float tot = 0.f;
#pragma unroll
    for (int i = 0; i < 8; i++) tot += red[i];
    float mean = tot * (1.0f / F);
    float xc = v - mean;
    __syncthreads();

    float s2 = xc * xc;
#pragma unroll
    for (int o = 16; o > 0; o >>= 1) s2 += __shfl_xor_sync(0xffffffffu, s2, o);
    if (lane == 0) red[warp] = s2;
    __syncthreads();
    float tot2 = 0.f;
#pragma unroll
    for (int i = 0; i < 8; i++) tot2 += red[i];
    float var = tot2 * (1.0f / F);

    O[(size_t)row * F + t] = g[t] * xc * rsqrtf(var + 1e-5f) + bt[t];
}

// ---------------- launch ----------------
extern "C" void kernel_launch(void* const* d_in, const int* in_sizes, int n_in,
                              void* d_out, int out_size)
{
    const float* feat0       = (const float*)d_in[0];
    const float* feat1       = (const float*)d_in[1];
    const float* in_w0       = (const float*)d_in[2];
    const float* in_b0       = (const float*)d_in[3];
    const float* in_w1       = (const float*)d_in[4];
    const float* in_b1       = (const float*)d_in[5];
    const float* out_w0      = (const float*)d_in[6];
    const float* out_b0      = (const float*)d_in[7];
    const float* out_w1      = (const float*)d_in[8];
    const float* out_b1      = (const float*)d_in[9];
    const float* ln1_g0      = (const float*)d_in[10];
    const float* ln1_b0      = (const float*)d_in[11];
    const float* ln1_g1      = (const float*)d_in[12];
    const float* ln1_b1      = (const float*)d_in[13];
    const float* ffn_up_w0   = (const float*)d_in[14];
    const float* ffn_up_b0   = (const float*)d_in[15];
    const float* ffn_down_w0 = (const float*)d_in[16];
    const float* ffn_down_b0 = (const float*)d_in[17];
    const float* ffn_up_w1   = (const float*)d_in[18];
    const float* ffn_up_b1   = (const float*)d_in[19];
    const float* ffn_down_w1 = (const float*)d_in[20];
    const float* ffn_down_b1 = (const float*)d_in[21];
    const float* ln2_g0      = (const float*)d_in[22];
    const float* ln2_b0      = (const float*)d_in[23];
    const float* ln2_g1      = (const float*)d_in[24];
    const float* ln2_b1      = (const float*)d_in[25];

    float *P0, *P1, *Asa0, *Asa1, *Atd0, *Abu0, *T0, *T1, *X0, *X1, *U0, *U1;
    cudaGetSymbolAddress((void**)&P0,   g_P0);
    cudaGetSymbolAddress((void**)&P1,   g_P1);
    cudaGetSymbolAddress((void**)&Asa0, g_Asa0);
    cudaGetSymbolAddress((void**)&Asa1, g_Asa1);
    cudaGetSymbolAddress((void**)&Atd0, g_Atd0);
    cudaGetSymbolAddress((void**)&Abu0, g_Abu0);
    cudaGetSymbolAddress((void**)&T0,   g_T0);
    cudaGetSymbolAddress((void**)&T1,   g_T1);
    cudaGetSymbolAddress((void**)&X0,   g_X0);
    cudaGetSymbolAddress((void**)&X1,   g_X1);
    cudaGetSymbolAddress((void**)&U0,   g_U0);
    cudaGetSymbolAddress((void**)&U1,   g_U1);

    float* out = (float*)d_out;
    dim3 blk(256);

    // in-projection: P = feat @ in_w.T + in_b   [12800,1536]
    gemm_kernel<<<dim3(PDIM / BN, NPIX / BM), blk>>>(feat0, F, in_w0, F, in_b0, nullptr, P0, PDIM, F, 0);
    gemm_kernel<<<dim3(PDIM / BN, NPIX / BM), blk>>>(feat1, F, in_w1, F, in_b1, nullptr, P1, PDIM, F, 0);

    // attentions (channel offsets: q=0, k=F, v=2F | q2=3F, k2=4F, v2=5F)
    attend_kernel<<<NPIX, blk>>>(P0,         P0 + F,     P0 + 2 * F, Asa0);
    attend_kernel<<<NPIX, blk>>>(P1,         P1 + F,     P1 + 2 * F, Asa1);
    attend_kernel<<<NPIX, blk>>>(P0 + 3 * F, P1 + 4 * F, P1 + 5 * F, Atd0);
    attend_kernel<<<NPIX, blk>>>(P1 + 3 * F, P0 + 4 * F, P0 + 5 * F, Abu0);

    // out-projections with residual accumulation:
    // T0 = feat0 + sa0@out_w0[:, :F].T + b + td0@out_w0[:, F:2F].T + b2
    gemm_kernel<<<dim3(F / BN, NPIX / BM), blk>>>(Asa0, F, out_w0,     3 * F, out_b0,     feat0, T0, F, F, 0);
    gemm_kernel<<<dim3(F / BN, NPIX / BM), blk>>>(Atd0, F, out_w0 + F, 3 * F, out_b0 + F, T0,    T0, F, F, 0);
    // T1 = feat1 + sa1@out_w1[:, :F].T + b + bu0@out_w0[:, F:2F].T + b2   (bu0 uses map-0 weights!)
    gemm_kernel<<<dim3(F / BN, NPIX / BM), blk>>>(Asa1, F, out_w1,     3 * F, out_b1,     feat1, T1, F, F, 0);
    gemm_kernel<<<dim3(F / BN, NPIX / BM), blk>>>(Abu0, F, out_w0 + F, 3 * F, out_b0 + F, T1,    T1, F, F, 0);

    // LN1
    ln_kernel<<<NPIX, blk>>>(T0, ln1_g0, ln1_b0, X0);
    ln_kernel<<<NPIX, blk>>>(T1, ln1_g1, ln1_b1, X1);

    // FFN
    gemm_kernel<<<dim3(HIDN / BN, NPIX / BM), blk>>>(X0, F,    ffn_up_w0,   F,    ffn_up_b0,   nullptr, U0, HIDN, F,    1);
    gemm_kernel<<<dim3(F / BN,    NPIX / BM), blk>>>(U0, HIDN, ffn_down_w0, HIDN, ffn_down_b0, X0,      T0, F,    HIDN, 0);
    gemm_kernel<<<dim3(HIDN / BN, NPIX / BM), blk>>>(X1, F,    ffn_up_w1,   F,    ffn_up_b1,   nullptr, U1, HIDN, F,    1);
    gemm_kernel<<<dim3(F / BN,    NPIX / BM), blk>>>(U1, HIDN, ffn_down_w1, HIDN, ffn_down_b1, X1,      T1, F,    HIDN, 0);

    // LN2 -> output (x0 then x1)
    ln_kernel<<<NPIX, blk>>>(T0, ln2_g0, ln2_b0, out);
    ln_kernel<<<NPIX, blk>>>(T1, ln2_g1, ln2_b1, out + (size_t)NPIX * F);
}

// round 2
// speedup vs baseline: 1.0878x; 1.0878x over previous
#include <cuda_runtime.h>
#include <cstddef>

#define F      256
#define NH     8
#define HD     32
#define BATCH  2
#define HH     80
#define WW     80
#define NPIX   (BATCH*HH*WW)   // 12800
#define PDIM   1536
#define HIDN   1024

// ---------------- scratch (no allocations allowed) ----------------
__device__ float g_P0[(size_t)NPIX*PDIM];
__device__ float g_P1[(size_t)NPIX*PDIM];
__device__ float g_QQ0[(size_t)NPIX*2*F];   // [sa0 | td0]
__device__ float g_QQ1[(size_t)NPIX*2*F];   // [sa1 | bu0]
__device__ float g_T0[(size_t)NPIX*F];
__device__ float g_T1[(size_t)NPIX*F];
__device__ float g_X0[(size_t)NPIX*F];
__device__ float g_X1[(size_t)NPIX*F];
__device__ float g_U0[(size_t)NPIX*HIDN];
__device__ float g_U1[(size_t)NPIX*HIDN];

// ---------------- GEMM with f32x2 packed FMA ----------------
// C[m,n] = act( sum_k A[m,k]*W[n,k] + bias[n] (+bias2[n]) (+res[m,n]) )
// W is split: k < Ksplit reads Wlo[n*ldw + k], else Whi[n*ldw + (k-Ksplit)].
// M%128==0, N%128==0, K%16==0, Ksplit%16==0.
#define BM 128
#define BN 128
#define BK 16

__global__ __launch_bounds__(256) void gemm_kernel(
    const float* __restrict__ A, int lda,
    const float* __restrict__ Wlo, const float* __restrict__ Whi, int ldw, int Ksplit,
    const float* __restrict__ bias, const float* __restrict__ bias2,
    const float* __restrict__ res,
    float* __restrict__ C, int N, int K, int relu)
{
    __shared__ float As[2][BK][BM + 4];
    __shared__ float Ws[2][BK][BN + 4];

    const int tid  = threadIdx.x;
    const int brow = blockIdx.y * BM;
    const int bcol = blockIdx.x * BN;
    const int tr   = tid >> 4;       // 0..15
    const int tc   = tid & 15;       // 0..15
    const int m0   = tr * 8;
    const int n0   = tc * 8;

    // loader mapping: each thread loads 8 consecutive k of one row (2 float4)
    const int lrow = tid >> 1;       // 0..127
    const int lk8  = (tid & 1) * 8;  // 0 or 8

    unsigned long long acc2[8][4];
#pragma unroll
    for (int i = 0; i < 8; i++)
#pragma unroll
        for (int j = 0; j < 4; j++) acc2[i][j] = 0ULL;

    const int T = K / BK;

    // ---- prologue: load tile 0 into buffer 0 ----
    {
        const float* Wp = (0 < Ksplit) ? Wlo : Whi;
        int kk = (0 < Ksplit) ? 0 : -Ksplit;
        float4 a0 = *(const float4*)(A + (size_t)(brow + lrow) * lda + lk8);
        float4 a1 = *(const float4*)(A + (size_t)(brow + lrow) * lda + lk8 + 4);
        float4 w0 = *(const float4*)(Wp + (size_t)(bcol + lrow) * ldw + kk + lk8);
        float4 w1 = *(const float4*)(Wp + (size_t)(bcol + lrow) * ldw + kk + lk8 + 4);
        As[0][lk8 + 0][lrow] = a0.x; As[0][lk8 + 1][lrow] = a0.y;
        As[0][lk8 + 2][lrow] = a0.z; As[0][lk8 + 3][lrow] = a0.w;
        As[0][lk8 + 4][lrow] = a1.x; As[0][lk8 + 5][lrow] = a1.y;
        As[0][lk8 + 6][lrow] = a1.z; As[0][lk8 + 7][lrow] = a1.w;
        Ws[0][lk8 + 0][lrow] = w0.x; Ws[0][lk8 + 1][lrow] = w0.y;
        Ws[0][lk8 + 2][lrow] = w0.z; Ws[0][lk8 + 3][lrow] = w0.w;
        Ws[0][lk8 + 4][lrow] = w1.x; Ws[0][lk8 + 5][lrow] = w1.y;
        Ws[0][lk8 + 6][lrow] = w1.z; Ws[0][lk8 + 7][lrow] = w1.w;
    }
    __syncthreads();

    for (int t = 0; t < T; t++) {
        const int cur = t & 1;
        float4 pa0, pa1, pw0, pw1;
        if (t + 1 < T) {
            int k0 = (t + 1) * BK;
            const float* Wp = (k0 < Ksplit) ? Wlo : Whi;
            int kk = (k0 < Ksplit) ? k0 : k0 - Ksplit;
            pa0 = *(const float4*)(A + (size_t)(brow + lrow) * lda + k0 + lk8);
            pa1 = *(const float4*)(A + (size_t)(brow + lrow) * lda + k0 + lk8 + 4);
            pw0 = *(const float4*)(Wp + (size_t)(bcol + lrow) * ldw + kk + lk8);
            pw1 = *(const float4*)(Wp + (size_t)(bcol + lrow) * ldw + kk + lk8 + 4);
        }

#pragma unroll
        for (int k = 0; k < BK; k++) {
            // load A fragment (8 floats) and duplicate-pack into f32x2
            float4 a0 = *(const float4*)&As[cur][k][m0];
            float4 a1 = *(const float4*)&As[cur][k][m0 + 4];
            unsigned int au[8];
            au[0] = __float_as_uint(a0.x); au[1] = __float_as_uint(a0.y);
            au[2] = __float_as_uint(a0.z); au[3] = __float_as_uint(a0.w);
            au[4] = __float_as_uint(a1.x); au[5] = __float_as_uint(a1.y);
            au[6] = __float_as_uint(a1.z); au[7] = __float_as_uint(a1.w);
            unsigned long long a2[8];
#pragma unroll
            for (int i = 0; i < 8; i++)
                asm("mov.b64 %0, {%1, %1};" : "=l"(a2[i]) : "r"(au[i]));

            // load B fragment as packed pairs (already adjacent in n)
            ulonglong2 bq0 = *(const ulonglong2*)&Ws[cur][k][n0];
            ulonglong2 bq1 = *(const ulonglong2*)&Ws[cur][k][n0 + 4];
            unsigned long long b2[4] = {bq0.x, bq0.y, bq1.x, bq1.y};

#pragma unroll
            for (int i = 0; i < 8; i++)
#pragma unroll
                for (int j = 0; j < 4; j++)
                    asm("fma.rn.f32x2 %0, %1, %2, %0;"
                        : "+l"(acc2[i][j]) : "l"(a2[i]), "l"(b2[j]));
        }

        if (t + 1 < T) {
            int nb = (t + 1) & 1;
            As[nb][lk8 + 0][lrow] = pa0.x; As[nb][lk8 + 1][lrow] = pa0.y;
            As[nb][lk8 + 2][lrow] = pa0.z; As[nb][lk8 + 3][lrow] = pa0.w;
            As[nb][lk8 + 4][lrow] = pa1.x; As[nb][lk8 + 5][lrow] = pa1.y;
            As[nb][lk8 + 6][lrow] = pa1.z; As[nb][lk8 + 7][lrow] = pa1.w;
            Ws[nb][lk8 + 0][lrow] = pw0.x; Ws[nb][lk8 + 1][lrow] = pw0.y;
            Ws[nb][lk8 + 2][lrow] = pw0.z; Ws[nb][lk8 + 3][lrow] = pw0.w;
            Ws[nb][lk8 + 4][lrow] = pw1.x; Ws[nb][lk8 + 5][lrow] = pw1.y;
            Ws[nb][lk8 + 6][lrow] = pw1.z; Ws[nb][lk8 + 7][lrow] = pw1.w;
            __syncthreads();
        }
    }

    // ---- epilogue ----
    const int nb0 = bcol + n0;
    float4 bv0 = *(const float4*)(bias + nb0);
    float4 bv1 = *(const float4*)(bias + nb0 + 4);
    if (bias2) {
        float4 c0 = *(const float4*)(bias2 + nb0);
        float4 c1 = *(const float4*)(bias2 + nb0 + 4);
        bv0.x += c0.x; bv0.y += c0.y; bv0.z += c0.z; bv0.w += c0.w;
        bv1.x += c1.x; bv1.y += c1.y; bv1.z += c1.z; bv1.w += c1.w;
    }
    float bb[8] = {bv0.x, bv0.y, bv0.z, bv0.w, bv1.x, bv1.y, bv1.z, bv1.w};

#pragma unroll
    for (int i = 0; i < 8; i++) {
        int m = brow + m0 + i;
        float out[8];
#pragma unroll
        for (int j = 0; j < 4; j++) {
            unsigned int lo, hi;
            asm("mov.b64 {%0, %1}, %2;" : "=r"(lo), "=r"(hi) : "l"(acc2[i][j]));
            out[2 * j]     = __uint_as_float(lo) + bb[2 * j];
            out[2 * j + 1] = __uint_as_float(hi) + bb[2 * j + 1];
        }
        if (res) {
            float4 r0 = *(const float4*)(res + (size_t)m * N + nb0);
            float4 r1 = *(const float4*)(res + (size_t)m * N + nb0 + 4);
            out[0] += r0.x; out[1] += r0.y; out[2] += r0.z; out[3] += r0.w;
            out[4] += r1.x; out[5] += r1.y; out[6] += r1.z; out[7] += r1.w;
        }
        if (relu)
#pragma unroll
            for (int j = 0; j < 8; j++) out[j] = fmaxf(out[j], 0.f);
        *(float4*)(C + (size_t)m * N + nb0)     = make_float4(out[0], out[1], out[2], out[3]);
        *(float4*)(C + (size_t)m * N + nb0 + 4) = make_float4(out[4], out[5], out[6], out[7]);
    }
}

// ---------------- 9-tap windowed multi-head attention (float4 lanes) ----------------
// 4 pixels per block; 64 threads per pixel; thread handles 4 channels.
// 8-lane groups = one head; 3-level shfl reduce.
__global__ __launch_bounds__(256) void attend_kernel(
    const float* __restrict__ Q,
    const float* __restrict__ Kp,
    const float* __restrict__ Vp,
    float* __restrict__ Out, int ostride)
{
    const int t   = threadIdx.x & 63;
    const int pix = blockIdx.x * 4 + (threadIdx.x >> 6);
    const int b   = pix / (HH * WW);
    const int r   = pix % (HH * WW);
    const int y   = r / WW;
    const int x   = r % WW;
    const int ch  = t * 4;

    const float scale = 0.17677669529663687f;
    float4 q = *(const float4*)(Q + (size_t)pix * PDIM + ch);
    q.x *= scale; q.y *= scale; q.z *= scale; q.w *= scale;

    float  sc[9];
    float4 vv[9];
#pragma unroll
    for (int n = 0; n < 9; n++) {
        int dy = n / 3 - 1, dx = n % 3 - 1;
        int yy = y + dy, xx = x + dx;
        float s = 0.f;
        float4 v = make_float4(0.f, 0.f, 0.f, 0.f);
        if (yy >= 0 && yy < HH && xx >= 0 && xx < WW) {
            size_t np = ((size_t)(b * HH + yy) * WW + xx) * PDIM + ch;
            float4 k4 = *(const float4*)(Kp + np);
            v = *(const float4*)(Vp + np);
            s = q.x * k4.x + q.y * k4.y + q.z * k4.z + q.w * k4.w;
        }
        s += __shfl_xor_sync(0xffffffffu, s, 4);
        s += __shfl_xor_sync(0xffffffffu, s, 2);
        s += __shfl_xor_sync(0xffffffffu, s, 1);
        sc[n] = s;    // zero-padded taps -> score exactly 0, matching reference
        vv[n] = v;
    }

    float mx = sc[0];
#pragma unroll
    for (int n = 1; n < 9; n++) mx = fmaxf(mx, sc[n]);
    float den = 0.f;
    float4 o = make_float4(0.f, 0.f, 0.f, 0.f);
#pragma unroll
    for (int n = 0; n < 9; n++) {
        float w = __expf(sc[n] - mx);
        den += w;
        o.x += w * vv[n].x; o.y += w * vv[n].y;
        o.z += w * vv[n].z; o.w += w * vv[n].w;
    }
    float inv = 1.f / den;
    *(float4*)(Out + (size_t)pix * ostride + ch) =
        make_float4(o.x * inv, o.y * inv, o.z * inv, o.w * inv);
}

// ---------------- LayerNorm over last dim (256) ----------------
__global__ __launch_bounds__(256) void ln_kernel(
    const float* __restrict__ X,
    const float* __restrict__ g,
    const float* __restrict__ bt,
    float* __restrict__ O)
{
    const int row = blockIdx.x;
    const int t   = threadIdx.x;
    const int warp = t >> 5, lane = t & 31;
    __shared__ float red[8];

    float v = X[(size_t)row * F + t];

    float s = v;
#pragma unroll
    for (int o = 16; o > 0; o >>= 1) s += __shfl_xor_sync(0xffffffffu, s, o);
    if (lane == 0) red[warp] = s;
    __syncthreads();
    float tot = 0.f;
#pragma unroll
    for (int i = 0; i < 8; i++) tot += red[i];
    float mean = tot * (1.0f / F);
    float xc = v - mean;
    __syncthreads();

    float s2 = xc * xc;
#pragma unroll
    for (int o = 16; o > 0; o >>= 1) s2 += __shfl_xor_sync(0xffffffffu, s2, o);
    if (lane == 0) red[warp] = s2;
    __syncthreads();
    float tot2 = 0.f;
#pragma unroll
    for (int i = 0; i < 8; i++) tot2 += red[i];
    float var = tot2 * (1.0f / F);

    O[(size_t)row * F + t] = g[t] * xc * rsqrtf(var + 1e-5f) + bt[t];
}

// ---------------- launch ----------------
extern "C" void kernel_launch(void* const* d_in, const int* in_sizes, int n_in,
                              void* d_out, int out_size)
{
    const float* feat0       = (const float*)d_in[0];
    const float* feat1       = (const float*)d_in[1];
    const float* in_w0       = (const float*)d_in[2];
    const float* in_b0       = (const float*)d_in[3];
    const float* in_w1       = (const float*)d_in[4];
    const float* in_b1       = (const float*)d_in[5];
    const float* out_w0      = (const float*)d_in[6];
    const float* out_b0      = (const float*)d_in[7];
    const float* out_w1      = (const float*)d_in[8];
    const float* out_b1      = (const float*)d_in[9];
    const float* ln1_g0      = (const float*)d_in[10];
    const float* ln1_b0      = (const float*)d_in[11];
    const float* ln1_g1      = (const float*)d_in[12];
    const float* ln1_b1      = (const float*)d_in[13];
    const float* ffn_up_w0   = (const float*)d_in[14];
    const float* ffn_up_b0   = (const float*)d_in[15];
    const float* ffn_down_w0 = (const float*)d_in[16];
    const float* ffn_down_b0 = (const float*)d_in[17];
    const float* ffn_up_w1   = (const float*)d_in[18];
    const float* ffn_up_b1   = (const float*)d_in[19];
    const float* ffn_down_w1 = (const float*)d_in[20];
    const float* ffn_down_b1 = (const float*)d_in[21];
    const float* ln2_g0      = (const float*)d_in[22];
    const float* ln2_b0      = (const float*)d_in[23];
    const float* ln2_g1      = (const float*)d_in[24];
    const float* ln2_b1      = (const float*)d_in[25];

    float *P0, *P1, *QQ0, *QQ1, *T0, *T1, *X0, *X1, *U0, *U1;
    cudaGetSymbolAddress((void**)&P0,  g_P0);
    cudaGetSymbolAddress((void**)&P1,  g_P1);
    cudaGetSymbolAddress((void**)&QQ0, g_QQ0);
    cudaGetSymbolAddress((void**)&QQ1, g_QQ1);
    cudaGetSymbolAddress((void**)&T0,  g_T0);
    cudaGetSymbolAddress((void**)&T1,  g_T1);
    cudaGetSymbolAddress((void**)&X0,  g_X0);
    cudaGetSymbolAddress((void**)&X1,  g_X1);
    cudaGetSymbolAddress((void**)&U0,  g_U0);
    cudaGetSymbolAddress((void**)&U1,  g_U1);

    float* out = (float*)d_out;
    dim3 blk(256);

    // in-projection: P = feat @ in_w.T + in_b   [12800,1536]
    gemm_kernel<<<dim3(PDIM / BN, NPIX / BM), blk>>>(feat0, F, in_w0, in_w0, F, F, in_b0, nullptr, nullptr, P0, PDIM, F, 0);
    gemm_kernel<<<dim3(PDIM / BN, NPIX / BM), blk>>>(feat1, F, in_w1, in_w1, F, F, in_b1, nullptr, nullptr, P1, PDIM, F, 0);

    // attentions -> QQ buffers ([NPIX, 512]: cols 0:256 self, 256:512 cross)
    attend_kernel<<<NPIX / 4, blk>>>(P0,         P0 + F,     P0 + 2 * F, QQ0,     2 * F);
    attend_kernel<<<NPIX / 4, blk>>>(P1,         P1 + F,     P1 + 2 * F, QQ1,     2 * F);
    attend_kernel<<<NPIX / 4, blk>>>(P0 + 3 * F, P1 + 4 * F, P1 + 5 * F, QQ0 + F, 2 * F);
    attend_kernel<<<NPIX / 4, blk>>>(P1 + 3 * F, P0 + 4 * F, P0 + 5 * F, QQ1 + F, 2 * F);

    // fused out-projections (K=512, split weights), residual = feat
    // T0 = feat0 + sa0 @ out_w0[:,:F].T + td0 @ out_w0[:,F:2F].T + out_b0[:F] + out_b0[F:2F]
    gemm_kernel<<<dim3(F / BN, NPIX / BM), blk>>>(QQ0, 2 * F, out_w0, out_w0 + F, 3 * F, F,
                                                  out_b0, out_b0 + F, feat0, T0, F, 2 * F, 0);
    // T1 = feat1 + sa1 @ out_w1[:,:F].T + bu0 @ out_w0[:,F:2F].T + out_b1[:F] + out_b0[F:2F]
    gemm_kernel<<<dim3(F / BN, NPIX / BM), blk>>>(QQ1, 2 * F, out_w1, out_w0 + F, 3 * F, F,
                                                  out_b1, out_b0 + F, feat1, T1, F, 2 * F, 0);

    // LN1
    ln_kernel<<<NPIX, blk>>>(T0, ln1_g0, ln1_b0, X0);
    ln_kernel<<<NPIX, blk>>>(T1, ln1_g1, ln1_b1, X1);

    // FFN
    gemm_kernel<<<dim3(HIDN / BN, NPIX / BM), blk>>>(X0, F, ffn_up_w0, ffn_up_w0, F, F,
                                                     ffn_up_b0, nullptr, nullptr, U0, HIDN, F, 1);
    gemm_kernel<<<dim3(F / BN, NPIX / BM), blk>>>(U0, HIDN, ffn_down_w0, ffn_down_w0, HIDN, HIDN,
                                                  ffn_down_b0, nullptr, X0, T0, F, HIDN, 0);
    gemm_kernel<<<dim3(HIDN / BN, NPIX / BM), blk>>>(X1, F, ffn_up_w1, ffn_up_w1, F, F,
                                                     ffn_up_b1, nullptr, nullptr, U1, HIDN, F, 1);
    gemm_kernel<<<dim3(F / BN, NPIX / BM), blk>>>(U1, HIDN, ffn_down_w1, ffn_down_w1, HIDN, HIDN,
                                                  ffn_down_b1, nullptr, X1, T1, F, HIDN, 0);

    // LN2 -> output (x0 then x1)
    ln_kernel<<<NPIX, blk>>>(T0, ln2_g0, ln2_b0, out);
    ln_kernel<<<NPIX, blk>>>(T1, ln2_g1, ln2_b1, out + (size_t)NPIX * F);
}

// round 4
// speedup vs baseline: 2.0132x; 1.8507x over previous
#include <cuda_runtime.h>
#include <cuda_bf16.h>
#include <cstdint>
#include <cstddef>

#define F      256
#define NH     8
#define BATCH  2
#define HH     80
#define WW     80
#define NPIX   (BATCH*HH*WW)   // 12800
#define PDIM   1536
#define HIDN   1024

typedef __nv_bfloat16 bf16;

// ---------------- scratch (no allocations allowed) ----------------
__device__ float g_P0[(size_t)NPIX*PDIM];
__device__ float g_P1[(size_t)NPIX*PDIM];
__device__ float g_T0[(size_t)NPIX*F];
__device__ float g_T1[(size_t)NPIX*F];
__device__ float g_X0[(size_t)NPIX*F];
__device__ float g_X1[(size_t)NPIX*F];

__device__ bf16 g_fh0[(size_t)NPIX*F],  g_fl0[(size_t)NPIX*F];
__device__ bf16 g_fh1[(size_t)NPIX*F],  g_fl1[(size_t)NPIX*F];
__device__ bf16 g_wih0[(size_t)PDIM*F], g_wil0[(size_t)PDIM*F];
__device__ bf16 g_wih1[(size_t)PDIM*F], g_wil1[(size_t)PDIM*F];
__device__ bf16 g_woh0[(size_t)F*3*F],  g_wol0[(size_t)F*3*F];
__device__ bf16 g_woh1[(size_t)F*3*F],  g_wol1[(size_t)F*3*F];
__device__ bf16 g_wuh0[(size_t)HIDN*F], g_wul0[(size_t)HIDN*F];
__device__ bf16 g_wuh1[(size_t)HIDN*F], g_wul1[(size_t)HIDN*F];
__device__ bf16 g_wdh0[(size_t)F*HIDN], g_wdl0[(size_t)F*HIDN];
__device__ bf16 g_wdh1[(size_t)F*HIDN], g_wdl1[(size_t)F*HIDN];
__device__ bf16 g_QQh0[(size_t)NPIX*2*F], g_QQl0[(size_t)NPIX*2*F];
__device__ bf16 g_QQh1[(size_t)NPIX*2*F], g_QQl1[(size_t)NPIX*2*F];
__device__ bf16 g_Xh0[(size_t)NPIX*F],  g_Xl0[(size_t)NPIX*F];
__device__ bf16 g_Xh1[(size_t)NPIX*F],  g_Xl1[(size_t)NPIX*F];
__device__ bf16 g_Uh0[(size_t)NPIX*HIDN], g_Ul0[(size_t)NPIX*HIDN];
__device__ bf16 g_Uh1[(size_t)NPIX*HIDN], g_Ul1[(size_t)NPIX*HIDN];

// ================= helpers =================
__device__ __forceinline__ uint32_t smem_u32(const void* p) {
    uint32_t a;
    asm("{ .reg .u64 t; cvta.to.shared.u64 t, %1; cvt.u32.u64 %0, t; }" : "=r"(a) : "l"(p));
    return a;
}
__device__ __forceinline__ void cpasync16(uint32_t dst, const void* src) {
    asm volatile("cp.async.cg.shared.global [%0], [%1], 16;" :: "r"(dst), "l"(src) : "memory");
}
__device__ __forceinline__ void ldsm4(uint32_t (&r)[4], uint32_t addr) {
    asm volatile("ldmatrix.sync.aligned.m8n8.x4.shared.b16 {%0,%1,%2,%3}, [%4];"
                 : "=r"(r[0]), "=r"(r[1]), "=r"(r[2]), "=r"(r[3]) : "r"(addr));
}
__device__ __forceinline__ void mma16816(float* d, const uint32_t* a, const uint32_t* b) {
    asm volatile("mma.sync.aligned.m16n8k16.row.col.f32.bf16.bf16.f32 "
                 "{%0,%1,%2,%3}, {%4,%5,%6,%7}, {%8,%9}, {%0,%1,%2,%3};"
                 : "+f"(d[0]), "+f"(d[1]), "+f"(d[2]), "+f"(d[3])
                 : "r"(a[0]), "r"(a[1]), "r"(a[2]), "r"(a[3]), "r"(b[0]), "r"(b[1]));
}
__device__ __forceinline__ void split2(float v, bf16& h, bf16& l) {
    h = __float2bfloat16(v);
    l = __float2bfloat16(v - __bfloat162float(h));
}

// ================= bf16-split tensor GEMM =================
// C[m,n] = act( sum_k A[m,k]*W[n,k] + bias[n] (+bias2[n]) (+res[m,n]) )
// A given as hi/lo bf16 (k-contig, lda), W as hi/lo bf16 (k-contig, ldb),
// W split at Ksplit between (Bh0,Bl0) and (Bh1,Bl1) (latter pre-offset).
// M,N multiples of 128; K multiple of 32.
#define SMEM_STAGE 32768
#define GEMM_SMEM  (2*SMEM_STAGE)

__global__ __launch_bounds__(256, 1) void gemm_bf16(
    const bf16* __restrict__ Ah, const bf16* __restrict__ Al, int lda,
    const bf16* __restrict__ Bh0, const bf16* __restrict__ Bl0,
    const bf16* __restrict__ Bh1, const bf16* __restrict__ Bl1, int ldb, int Ksplit,
    const float* __restrict__ bias, const float* __restrict__ bias2,
    const float* __restrict__ res, int ldres,
    float* __restrict__ C, bf16* __restrict__ Ch, bf16* __restrict__ Cl, int ldc,
    int K, int relu)
{
    extern __shared__ char smem[];
    const uint32_t sb0 = smem_u32(smem);

    const int tid  = threadIdx.x;
    const int wid  = tid >> 5;
    const int lane = tid & 31;
    const int brow = blockIdx.y * 128;
    const int bcol = blockIdx.x * 128;
    const int wm   = (wid >> 2) * 64;   // warp m offset
    const int wn   = (wid & 3) * 32;    // warp n offset

    float acc[4][4][4];
#pragma unroll
    for (int i = 0; i < 4; i++)
#pragma unroll
        for (int j = 0; j < 4; j++)
#pragma unroll
            for (int r = 0; r < 4; r++) acc[i][j][r] = 0.f;

    // ------- async tile loader -------
    const int lrow = tid >> 1;
    const int lc0  = (tid & 1) * 2;
    const uint32_t lsw = ((uint32_t)lrow >> 1) & 3u;

    auto load_stage = [&](int cIdx) {
        const uint32_t sb = sb0 + (uint32_t)(cIdx & 1) * SMEM_STAGE;
        const int k0 = cIdx * 32;
        const bf16 *bh, *bl;
        int kk;
        if (k0 < Ksplit) { bh = Bh0; bl = Bl0; kk = k0; }
        else             { bh = Bh1; bl = Bl1; kk = k0 - Ksplit; }
        const size_t aoff = (size_t)(brow + lrow) * lda + k0;
        const size_t boff = (size_t)(bcol + lrow) * ldb + kk;
        const uint32_t dbase = sb + (uint32_t)lrow * 64u;
#pragma unroll
        for (int i = 0; i < 2; i++) {
            const int cc = lc0 + i;
            const uint32_t d = dbase + (uint32_t)(cc ^ lsw) * 16u;
            cpasync16(d,           Ah + aoff + cc * 8);
            cpasync16(d + 8192u,   Al + aoff + cc * 8);
            cpasync16(d + 16384u,  bh + boff + cc * 8);
            cpasync16(d + 24576u,  bl + boff + cc * 8);
        }
        asm volatile("cp.async.commit_group;" ::: "memory");
    };

    // ------- fragment geometry -------
    const int tile = lane >> 3;
    const int rin  = lane & 7;
    const uint32_t rsw = (uint32_t)(rin >> 1);

    load_stage(0);
    const int NC = K / 32;

    for (int c = 0; c < NC; c++) {
        if (c + 1 < NC) {
            load_stage(c + 1);
            asm volatile("cp.async.wait_group 1;" ::: "memory");
        } else {
            asm volatile("cp.async.wait_group 0;" ::: "memory");
        }
        __syncthreads();

        const uint32_t sb = sb0 + (uint32_t)(c & 1) * SMEM_STAGE;
#pragma unroll
        for (int ks = 0; ks < 2; ks++) {
            uint32_t ah[4][4], al_[4][4], bh_[2][4], bl_[2][4];
            const uint32_t swa = ((uint32_t)(ks * 2 + (tile >> 1)) ^ rsw) * 16u;
            const uint32_t abase = sb + (uint32_t)(wm + (tile & 1) * 8 + rin) * 64u + swa;
#pragma unroll
            for (int i = 0; i < 4; i++) {
                ldsm4(ah[i],  abase + (uint32_t)i * 1024u);
                ldsm4(al_[i], abase + 8192u + (uint32_t)i * 1024u);
            }
            const uint32_t swb = ((uint32_t)(ks * 2 + (tile & 1)) ^ rsw) * 16u;
            const uint32_t bbase = sb + 16384u + (uint32_t)(wn + (tile >> 1) * 8 + rin) * 64u + swb;
#pragma unroll
            for (int jj = 0; jj < 2; jj++) {
                ldsm4(bh_[jj], bbase + (uint32_t)jj * 1024u);
                ldsm4(bl_[jj], bbase + 8192u + (uint32_t)jj * 1024u);
            }
#pragma unroll
            for (int i = 0; i < 4; i++)
#pragma unroll
                for (int j = 0; j < 4; j++) {
                    const uint32_t* ph = &bh_[j >> 1][(j & 1) * 2];
                    const uint32_t* pl = &bl_[j >> 1][(j & 1) * 2];
                    mma16816(acc[i][j], ah[i],  ph);
                    mma16816(acc[i][j], ah[i],  pl);
                    mma16816(acc[i][j], al_[i], ph);
                }
        }
        __syncthreads();
    }

    // ------- epilogue -------
    const int tq = lane >> 2;
    const int tr = (lane & 3) * 2;
    float bj0[4], bj1[4];
#pragma unroll
    for (int j = 0; j < 4; j++) {
        const int n = bcol + wn + 8 * j + tr;
        float b0 = bias[n], b1 = bias[n + 1];
        if (bias2) { b0 += bias2[n]; b1 += bias2[n + 1]; }
        bj0[j] = b0; bj1[j] = b1;
    }
#pragma unroll
    for (int i = 0; i < 4; i++)
#pragma unroll
        for (int half = 0; half < 2; half++) {
            const int m = brow + wm + 16 * i + tq + half * 8;
#pragma unroll
            for (int j = 0; j < 4; j++) {
                const int n = bcol + wn + 8 * j + tr;
                float v0 = acc[i][j][half * 2 + 0] + bj0[j];
                float v1 = acc[i][j][half * 2 + 1] + bj1[j];
                if (res) {
                    float2 r = *(const float2*)(res + (size_t)m * ldres + n);
                    v0 += r.x; v1 += r.y;
                }
                if (relu) { v0 = fmaxf(v0, 0.f); v1 = fmaxf(v1, 0.f); }
                if (C) *(float2*)(C + (size_t)m * ldc + n) = make_float2(v0, v1);
                if (Ch) {
                    bf16 h0, l0, h1, l1;
                    split2(v0, h0, l0);
                    split2(v1, h1, l1);
                    *(__nv_bfloat162*)(Ch + (size_t)m * ldc + n) = __nv_bfloat162(h0, h1);
                    *(__nv_bfloat162*)(Cl + (size_t)m * ldc + n) = __nv_bfloat162(l0, l1);
                }
            }
        }
}

// ---------------- split-convert fp32 -> bf16 hi/lo ----------------
__global__ __launch_bounds__(256) void conv_split(
    const float* __restrict__ x, bf16* __restrict__ h, bf16* __restrict__ l, int n4)
{
    const int i = blockIdx.x * 256 + threadIdx.x;
    if (i >= n4) return;
    float4 v = ((const float4*)x)[i];
    bf16 h0, l0, h1, l1, h2, l2, h3, l3;
    split2(v.x, h0, l0); split2(v.y, h1, l1);
    split2(v.z, h2, l2); split2(v.w, h3, l3);
    ((__nv_bfloat162*)h)[2 * i]     = __nv_bfloat162(h0, h1);
    ((__nv_bfloat162*)h)[2 * i + 1] = __nv_bfloat162(h2, h3);
    ((__nv_bfloat162*)l)[2 * i]     = __nv_bfloat162(l0, l1);
    ((__nv_bfloat162*)l)[2 * i + 1] = __nv_bfloat162(l2, l3);
}

// ---------------- 9-tap windowed multi-head attention ----------------
__global__ __launch_bounds__(256) void attend_kernel(
    const float* __restrict__ Q,
    const float* __restrict__ Kp,
    const float* __restrict__ Vp,
    bf16* __restrict__ Oh, bf16* __restrict__ Ol, int ostride)
{
    const int t   = threadIdx.x & 63;
    const int pix = blockIdx.x * 4 + (threadIdx.x >> 6);
    const int b   = pix / (HH * WW);
    const int r   = pix % (HH * WW);
    const int y   = r / WW;
    const int x   = r % WW;
    const int ch  = t * 4;

    const float scale = 0.17677669529663687f;
    float4 q = *(const float4*)(Q + (size_t)pix * PDIM + ch);
    q.x *= scale; q.y *= scale; q.z *= scale; q.w *= scale;

    float  sc[9];
    float4 vv[9];
#pragma unroll
    for (int n = 0; n < 9; n++) {
        int dy = n / 3 - 1, dx = n % 3 - 1;
        int yy = y + dy, xx = x + dx;
        float s = 0.f;
        float4 v = make_float4(0.f, 0.f, 0.f, 0.f);
        if (yy >= 0 && yy < HH && xx >= 0 && xx < WW) {
            size_t np = ((size_t)(b * HH + yy) * WW + xx) * PDIM + ch;
            float4 k4 = *(const float4*)(Kp + np);
            v = *(const float4*)(Vp + np);
            s = q.x * k4.x + q.y * k4.y + q.z * k4.z + q.w * k4.w;
        }
        s += __shfl_xor_sync(0xffffffffu, s, 4);
        s += __shfl_xor_sync(0xffffffffu, s, 2);
        s += __shfl_xor_sync(0xffffffffu, s, 1);
        sc[n] = s;
        vv[n] = v;
    }

    float mx = sc[0];
#pragma unroll
    for (int n = 1; n < 9; n++) mx = fmaxf(mx, sc[n]);
    float den = 0.f;
    float4 o = make_float4(0.f, 0.f, 0.f, 0.f);
#pragma unroll
    for (int n = 0; n < 9; n++) {
        float w = __expf(sc[n] - mx);
        den += w;
        o.x += w * vv[n].x; o.y += w * vv[n].y;
        o.z += w * vv[n].z; o.w += w * vv[n].w;
    }
    float inv = 1.f / den;
    bf16 h0, l0, h1, l1, h2, l2, h3, l3;
    split2(o.x * inv, h0, l0); split2(o.y * inv, h1, l1);
    split2(o.z * inv, h2, l2); split2(o.w * inv, h3, l3);
    size_t base = (size_t)pix * ostride + ch;
    *(__nv_bfloat162*)(Oh + base)     = __nv_bfloat162(h0, h1);
    *(__nv_bfloat162*)(Oh + base + 2) = __nv_bfloat162(h2, h3);
    *(__nv_bfloat162*)(Ol + base)     = __nv_bfloat162(l0, l1);
    *(__nv_bfloat162*)(Ol + base + 2) = __nv_bfloat162(l2, l3);
}

// ---------------- LayerNorm over last dim (256) ----------------
__global__ __launch_bounds__(256) void ln_kernel(
    const float* __restrict__ X,
    const float* __restrict__ g,
    const float* __restrict__ bt,
    float* __restrict__ O,
    bf16* __restrict__ Oh, bf16* __restrict__ Ol)
{
    const int row = blockIdx.x;
    const int t   = threadIdx.x;
    const int warp = t >> 5, lane = t & 31;
    __shared__ float red[8];

    float v = X[(size_t)row * F + t];

    float s = v;
#pragma unroll
    for (int o = 16; o > 0; o >>= 1) s += __shfl_xor_sync(0xffffffffu, s, o);
    if (lane == 0) red[warp] = s;
    __syncthreads();
    float tot = 0.f;
#pragma unroll
    for (int i = 0; i < 8; i++) tot += red[i];
    float mean = tot * (1.0f / F);
    float xc = v - mean;
    __syncthreads();

    float s2 = xc * xc;
#pragma unroll
    for (int o = 16; o > 0; o >>= 1) s2 += __shfl_xor_sync(0xffffffffu, s2, o);
    if (lane == 0) red[warp] = s2;
    __syncthreads();
    float tot2 = 0.f;
#pragma unroll
    for (int i = 0; i < 8; i++) tot2 += red[i];
    float var = tot2 * (1.0f / F);

    float out = g[t] * xc * rsqrtf(var + 1e-5f) + bt[t];
    if (O) O[(size_t)row * F + t] = out;
    if (Oh) {
        bf16 h, l;
        split2(out, h, l);
        Oh[(size_t)row * F + t] = h;
        Ol[(size_t)row * F + t] = l;
    }
}

// ---------------- launch ----------------
#define SYM(p, s) cudaGetSymbolAddress((void**)&p, s)

extern "C" void kernel_launch(void* const* d_in, const int* in_sizes, int n_in,
                              void* d_out, int out_size)
{
    const float* feat0       = (const float*)d_in[0];
    const float* feat1       = (const float*)d_in[1];
    const float* in_w0       = (const float*)d_in[2];
    const float* in_b0       = (const float*)d_in[3];
    const float* in_w1       = (const float*)d_in[4];
    const float* in_b1       = (const float*)d_in[5];
    const float* out_w0      = (const float*)d_in[6];
    const float* out_b0      = (const float*)d_in[7];
    const float* out_w1      = (const float*)d_in[8];
    const float* out_b1      = (const float*)d_in[9];
    const float* ln1_g0      = (const float*)d_in[10];
    const float* ln1_b0      = (const float*)d_in[11];
    const float* ln1_g1      = (const float*)d_in[12];
    const float* ln1_b1      = (const float*)d_in[13];
    const float* ffn_up_w0   = (const float*)d_in[14];
    const float* ffn_up_b0   = (const float*)d_in[15];
    const float* ffn_down_w0 = (const float*)d_in[16];
    const float* ffn_down_b0 = (const float*)d_in[17];
    const float* ffn_up_w1   = (const float*)d_in[18];
    const float* ffn_up_b1   = (const float*)d_in[19];
    const float* ffn_down_w1 = (const float*)d_in[20];
    const float* ffn_down_b1 = (const float*)d_in[21];
    const float* ln2_g0      = (const float*)d_in[22];
    const float* ln2_b0      = (const float*)d_in[23];
    const float* ln2_g1      = (const float*)d_in[24];
    const float* ln2_b1      = (const float*)d_in[25];

    float *P0, *P1, *T0, *T1, *X0, *X1;
    SYM(P0, g_P0); SYM(P1, g_P1); SYM(T0, g_T0); SYM(T1, g_T1); SYM(X0, g_X0); SYM(X1, g_X1);
    bf16 *fh0, *fl0, *fh1, *fl1, *wih0, *wil0, *wih1, *wil1;
    bf16 *woh0, *wol0, *woh1, *wol1, *wuh0, *wul0, *wuh1, *wul1, *wdh0, *wdl0, *wdh1, *wdl1;
    bf16 *QQh0, *QQl0, *QQh1, *QQl1, *Xh0, *Xl0, *Xh1, *Xl1, *Uh0, *Ul0, *Uh1, *Ul1;
    SYM(fh0, g_fh0); SYM(fl0, g_fl0); SYM(fh1, g_fh1); SYM(fl1, g_fl1);
    SYM(wih0, g_wih0); SYM(wil0, g_wil0); SYM(wih1, g_wih1); SYM(wil1, g_wil1);
    SYM(woh0, g_woh0); SYM(wol0, g_wol0); SYM(woh1, g_woh1); SYM(wol1, g_wol1);
    SYM(wuh0, g_wuh0); SYM(wul0, g_wul0); SYM(wuh1, g_wuh1); SYM(wul1, g_wul1);
    SYM(wdh0, g_wdh0); SYM(wdl0, g_wdl0); SYM(wdh1, g_wdh1); SYM(wdl1, g_wdl1);
    SYM(QQh0, g_QQh0); SYM(QQl0, g_QQl0); SYM(QQh1, g_QQh1); SYM(QQl1, g_QQl1);
    SYM(Xh0, g_Xh0); SYM(Xl0, g_Xl0); SYM(Xh1, g_Xh1); SYM(Xl1, g_Xl1);
    SYM(Uh0, g_Uh0); SYM(Ul0, g_Ul0); SYM(Uh1, g_Ul1 ? g_Uh1 : g_Uh1); SYM(Ul1, g_Ul1);

    cudaFuncSetAttribute(gemm_bf16, cudaFuncAttributeMaxDynamicSharedMemorySize, GEMM_SMEM);

    float* out = (float*)d_out;
    dim3 blk(256);
    const int MT = NPIX / 128;   // 100

    // 0-3: convert feats + in-proj weights
    conv_split<<<(NPIX * F / 4 + 255) / 256, blk>>>(feat0, fh0, fl0, NPIX * F / 4);
    conv_split<<<(NPIX * F / 4 + 255) / 256, blk>>>(feat1, fh1, fl1, NPIX * F / 4);
    conv_split<<<(PDIM * F / 4 + 255) / 256, blk>>>(in_w0, wih0, wil0, PDIM * F / 4);
    conv_split<<<(PDIM * F / 4 + 255) / 256, blk>>>(in_w1, wih1, wil1, PDIM * F / 4);

    // 4-5: in-projection GEMMs -> P fp32 (ncu -s 5 captures launch idx 5)
    gemm_bf16<<<dim3(PDIM / 128, MT), blk, GEMM_SMEM>>>(
        fh0, fl0, F, wih0, wil0, wih0, wil0, F, F,
        in_b0, nullptr, nullptr, 0, P0, nullptr, nullptr, PDIM, F, 0);
    gemm_bf16<<<dim3(PDIM / 128, MT), blk, GEMM_SMEM>>>(
        fh1, fl1, F, wih1, wil1, wih1, wil1, F, F,
        in_b1, nullptr, nullptr, 0, P1, nullptr, nullptr, PDIM, F, 0);

    // 6-11: convert remaining weights
    conv_split<<<(F * 3 * F / 4 + 255) / 256, blk>>>(out_w0, woh0, wol0, F * 3 * F / 4);
    conv_split<<<(F * 3 * F / 4 + 255) / 256, blk>>>(out_w1, woh1, wol1, F * 3 * F / 4);
    conv_split<<<(HIDN * F / 4 + 255) / 256, blk>>>(ffn_up_w0, wuh0, wul0, HIDN * F / 4);
    conv_split<<<(HIDN * F / 4 + 255) / 256, blk>>>(ffn_up_w1, wuh1, wul1, HIDN * F / 4);
    conv_split<<<(F * HIDN / 4 + 255) / 256, blk>>>(ffn_down_w0, wdh0, wdl0, F * HIDN / 4);
    conv_split<<<(F * HIDN / 4 + 255) / 256, blk>>>(ffn_down_w1, wdh1, wdl1, F * HIDN / 4);

    // 12-15: attentions -> QQ hi/lo bf16 ([NPIX, 512]: 0:256 self, 256:512 cross)
    attend_kernel<<<NPIX / 4, blk>>>(P0,         P0 + F,     P0 + 2 * F, QQh0,     QQl0,     2 * F);
    attend_kernel<<<NPIX / 4, blk>>>(P1,         P1 + F,     P1 + 2 * F, QQh1,     QQl1,     2 * F);
    attend_kernel<<<NPIX / 4, blk>>>(P0 + 3 * F, P1 + 4 * F, P1 + 5 * F, QQh0 + F, QQl0 + F, 2 * F);
    attend_kernel<<<NPIX / 4, blk>>>(P1 + 3 * F, P0 + 4 * F, P0 + 5 * F, QQh1 + F, QQl1 + F, 2 * F);

    // 16-17: fused out-projections (K=512, weight split at 256), residual = feat
    gemm_bf16<<<dim3(F / 128, MT), blk, GEMM_SMEM>>>(
        QQh0, QQl0, 2 * F, woh0, wol0, woh0 + F, wol0 + F, 3 * F, F,
        out_b0, out_b0 + F, feat0, F, T0, nullptr, nullptr, F, 2 * F, 0);
    gemm_bf16<<<dim3(F / 128, MT), blk, GEMM_SMEM>>>(
        QQh1, QQl1, 2 * F, woh1, wol1, woh0 + F, wol0 + F, 3 * F, F,
        out_b1, out_b0 + F, feat1, F, T1, nullptr, nullptr, F, 2 * F, 0);

    // 18-19: LN1 -> X fp32 + hi/lo
    ln_kernel<<<NPIX, blk>>>(T0, ln1_g0, ln1_b0, X0, Xh0, Xl0);
    ln_kernel<<<NPIX, blk>>>(T1, ln1_g1, ln1_b1, X1, Xh1, Xl1);

    // 20-23: FFN (up: relu, bf16-split output only; down: residual X, fp32 out)
    gemm_bf16<<<dim3(HIDN / 128, MT), blk, GEMM_SMEM>>>(
        Xh0, Xl0, F, wuh0, wul0, wuh0, wul0, F, F,
        ffn_up_b0, nullptr, nullptr, 0, nullptr, Uh0, Ul0, HIDN, F, 1);
    gemm_bf16<<<dim3(F / 128, MT), blk, GEMM_SMEM>>>(
        Uh0, Ul0, HIDN, wdh0, wdl0, wdh0, wdl0, HIDN, HIDN,
        ffn_down_b0, nullptr, X0, F, T0, nullptr, nullptr, F, HIDN, 0);
    gemm_bf16<<<dim3(HIDN / 128, MT), blk, GEMM_SMEM>>>(
        Xh1, Xl1, F, wuh1, wul1, wuh1, wul1, F, F,
        ffn_up_b1, nullptr, nullptr, 0, nullptr, Uh1, Ul1, HIDN, F, 1);
    gemm_bf16<<<dim3(F / 128, MT), blk, GEMM_SMEM>>>(
        Uh1, Ul1, HIDN, wdh1, wdl1, wdh1, wdl1, HIDN, HIDN,
        ffn_down_b1, nullptr, X1, F, T1, nullptr, nullptr, F, HIDN, 0);

    // 24-25: LN2 -> output (x0 then x1)
    ln_kernel<<<NPIX, blk>>>(T0, ln2_g0, ln2_b0, out, nullptr, nullptr);
    ln_kernel<<<NPIX, blk>>>(T1, ln2_g1, ln2_b1, out + (size_t)NPIX * F, nullptr, nullptr);
}

// round 5
// speedup vs baseline: 2.0193x; 1.0030x over previous
#include <cuda_runtime.h>
#include <cuda_bf16.h>
#include <cstdint>
#include <cstddef>

#define F      256
#define NH     8
#define BATCH  2
#define HH     80
#define WW     80
#define NPIX   (BATCH*HH*WW)   // 12800
#define PDIM   1536
#define HIDN   1024

typedef __nv_bfloat16 bf16;

// ---------------- scratch (no allocations allowed) ----------------
__device__ float g_P0[(size_t)NPIX*PDIM];
__device__ float g_P1[(size_t)NPIX*PDIM];
__device__ float g_T0[(size_t)NPIX*F];
__device__ float g_T1[(size_t)NPIX*F];
__device__ float g_X0[(size_t)NPIX*F];
__device__ float g_X1[(size_t)NPIX*F];

__device__ bf16 g_fh0[(size_t)NPIX*F],  g_fl0[(size_t)NPIX*F];
__device__ bf16 g_fh1[(size_t)NPIX*F],  g_fl1[(size_t)NPIX*F];
__device__ bf16 g_wih0[(size_t)PDIM*F], g_wil0[(size_t)PDIM*F];
__device__ bf16 g_wih1[(size_t)PDIM*F], g_wil1[(size_t)PDIM*F];
__device__ bf16 g_woh0[(size_t)F*3*F],  g_wol0[(size_t)F*3*F];
__device__ bf16 g_woh1[(size_t)F*3*F],  g_wol1[(size_t)F*3*F];
__device__ bf16 g_wuh0[(size_t)HIDN*F], g_wul0[(size_t)HIDN*F];
__device__ bf16 g_wuh1[(size_t)HIDN*F], g_wul1[(size_t)HIDN*F];
__device__ bf16 g_wdh0[(size_t)F*HIDN], g_wdl0[(size_t)F*HIDN];
__device__ bf16 g_wdh1[(size_t)F*HIDN], g_wdl1[(size_t)F*HIDN];
__device__ bf16 g_QQh0[(size_t)NPIX*2*F], g_QQl0[(size_t)NPIX*2*F];
__device__ bf16 g_QQh1[(size_t)NPIX*2*F], g_QQl1[(size_t)NPIX*2*F];
__device__ bf16 g_Xh0[(size_t)NPIX*F],  g_Xl0[(size_t)NPIX*F];
__device__ bf16 g_Xh1[(size_t)NPIX*F],  g_Xl1[(size_t)NPIX*F];
__device__ bf16 g_Uh0[(size_t)NPIX*HIDN], g_Ul0[(size_t)NPIX*HIDN];
__device__ bf16 g_Uh1[(size_t)NPIX*HIDN], g_Ul1[(size_t)NPIX*HIDN];

// ================= helpers =================
__device__ __forceinline__ uint32_t smem_u32(const void* p) {
    uint32_t a;
    asm("{ .reg .u64 t; cvta.to.shared.u64 t, %1; cvt.u32.u64 %0, t; }" : "=r"(a) : "l"(p));
    return a;
}
__device__ __forceinline__ void cpasync16(uint32_t dst, const void* src) {
    asm volatile("cp.async.cg.shared.global [%0], [%1], 16;" :: "r"(dst), "l"(src) : "memory");
}
__device__ __forceinline__ void ldsm4(uint32_t (&r)[4], uint32_t addr) {
    asm volatile("ldmatrix.sync.aligned.m8n8.x4.shared.b16 {%0,%1,%2,%3}, [%4];"
                 : "=r"(r[0]), "=r"(r[1]), "=r"(r[2]), "=r"(r[3]) : "r"(addr));
}
__device__ __forceinline__ void mma16816(float* d, const uint32_t* a, const uint32_t* b) {
    asm volatile("mma.sync.aligned.m16n8k16.row.col.f32.bf16.bf16.f32 "
                 "{%0,%1,%2,%3}, {%4,%5,%6,%7}, {%8,%9}, {%0,%1,%2,%3};"
                 : "+f"(d[0]), "+f"(d[1]), "+f"(d[2]), "+f"(d[3])
                 : "r"(a[0]), "r"(a[1]), "r"(a[2]), "r"(a[3]), "r"(b[0]), "r"(b[1]));
}
__device__ __forceinline__ void split2(float v, bf16& h, bf16& l) {
    h = __float2bfloat16(v);
    l = __float2bfloat16(v - __bfloat162float(h));
}

// ================= bf16-split tensor GEMM (paired over z) =================
// z = blockIdx.z selects one of two independent GEMMs with shared shape.
// C[m,n] = act( sum_k A[m,k]*W[n,k] + bias[n] (+bias2[n]) (+res[m,n]) )
#define STAGES     4
#define SMEM_STAGE 32768
#define GEMM_SMEM  (STAGES*SMEM_STAGE)

struct GemmPair {
    const bf16 *Ah[2], *Al[2];
    const bf16 *Bh0[2], *Bl0[2], *Bh1[2], *Bl1[2];
    const float *bias[2], *bias2[2], *res[2];
    float *C[2];
    bf16 *Ch[2], *Cl[2];
};

__global__ __launch_bounds__(256, 1) void gemm_bf16(
    GemmPair gp, int lda, int ldb, int Ksplit,
    int ldres, int ldc, int K, int relu)
{
    extern __shared__ char smem[];
    const uint32_t sb0 = smem_u32(smem);

    const int z = blockIdx.z;
    const bf16* __restrict__ Ah  = gp.Ah[z];
    const bf16* __restrict__ Al  = gp.Al[z];
    const bf16* __restrict__ Bh0 = gp.Bh0[z];
    const bf16* __restrict__ Bl0 = gp.Bl0[z];
    const bf16* __restrict__ Bh1 = gp.Bh1[z];
    const bf16* __restrict__ Bl1 = gp.Bl1[z];
    const float* __restrict__ bias  = gp.bias[z];
    const float* __restrict__ bias2 = gp.bias2[z];
    const float* __restrict__ res   = gp.res[z];
    float* __restrict__ C  = gp.C[z];
    bf16*  __restrict__ Ch = gp.Ch[z];
    bf16*  __restrict__ Cl = gp.Cl[z];

    const int tid  = threadIdx.x;
    const int wid  = tid >> 5;
    const int lane = tid & 31;
    const int brow = blockIdx.y * 128;
    const int bcol = blockIdx.x * 128;
    const int wm   = (wid >> 2) * 64;
    const int wn   = (wid & 3) * 32;

    float acc[4][4][4];
#pragma unroll
    for (int i = 0; i < 4; i++)
#pragma unroll
        for (int j = 0; j < 4; j++)
#pragma unroll
            for (int r = 0; r < 4; r++) acc[i][j][r] = 0.f;

    const int lrow = tid >> 1;
    const int lc0  = (tid & 1) * 2;
    const uint32_t lsw = ((uint32_t)lrow >> 1) & 3u;

    auto load_stage = [&](int cIdx) {
        const uint32_t sb = sb0 + (uint32_t)(cIdx % STAGES) * SMEM_STAGE;
        const int k0 = cIdx * 32;
        const bf16 *bh, *bl;
        int kk;
        if (k0 < Ksplit) { bh = Bh0; bl = Bl0; kk = k0; }
        else             { bh = Bh1; bl = Bl1; kk = k0 - Ksplit; }
        const size_t aoff = (size_t)(brow + lrow) * lda + k0;
        const size_t boff = (size_t)(bcol + lrow) * ldb + kk;
        const uint32_t dbase = sb + (uint32_t)lrow * 64u;
#pragma unroll
        for (int i = 0; i < 2; i++) {
            const int cc = lc0 + i;
            const uint32_t d = dbase + (uint32_t)(cc ^ lsw) * 16u;
            cpasync16(d,           Ah + aoff + cc * 8);
            cpasync16(d + 8192u,   Al + aoff + cc * 8);
            cpasync16(d + 16384u,  bh + boff + cc * 8);
            cpasync16(d + 24576u,  bl + boff + cc * 8);
        }
        asm volatile("cp.async.commit_group;" ::: "memory");
    };

    const int tile = lane >> 3;
    const int rin  = lane & 7;
    const uint32_t rsw = (uint32_t)(rin >> 1);

    const int NC = K / 32;
    for (int s = 0; s < STAGES - 1 && s < NC; s++) load_stage(s);

    for (int c = 0; c < NC; c++) {
        if (c + 3 <= NC) {
            asm volatile("cp.async.wait_group 2;" ::: "memory");
        } else if (c + 2 == NC) {
            asm volatile("cp.async.wait_group 1;" ::: "memory");
        } else {
            asm volatile("cp.async.wait_group 0;" ::: "memory");
        }
        __syncthreads();
        if (c + 3 < NC) load_stage(c + 3);

        const uint32_t sb = sb0 + (uint32_t)(c % STAGES) * SMEM_STAGE;
#pragma unroll
        for (int ks = 0; ks < 2; ks++) {
            uint32_t ah[4][4], al_[4][4], bh_[2][4], bl_[2][4];
            const uint32_t swa = ((uint32_t)(ks * 2 + (tile >> 1)) ^ rsw) * 16u;
            const uint32_t abase = sb + (uint32_t)(wm + (tile & 1) * 8 + rin) * 64u + swa;
#pragma unroll
            for (int i = 0; i < 4; i++) {
                ldsm4(ah[i],  abase + (uint32_t)i * 1024u);
                ldsm4(al_[i], abase + 8192u + (uint32_t)i * 1024u);
            }
            const uint32_t swb = ((uint32_t)(ks * 2 + (tile & 1)) ^ rsw) * 16u;
            const uint32_t bbase = sb + 16384u + (uint32_t)(wn + (tile >> 1) * 8 + rin) * 64u + swb;
#pragma unroll
            for (int jj = 0; jj < 2; jj++) {
                ldsm4(bh_[jj], bbase + (uint32_t)jj * 1024u);
                ldsm4(bl_[jj], bbase + 8192u + (uint32_t)jj * 1024u);
            }
#pragma unroll
            for (int i = 0; i < 4; i++)
#pragma unroll
                for (int j = 0; j < 4; j++) {
                    const uint32_t* ph = &bh_[j >> 1][(j & 1) * 2];
                    const uint32_t* pl = &bl_[j >> 1][(j & 1) * 2];
                    mma16816(acc[i][j], ah[i],  ph);
                    mma16816(acc[i][j], ah[i],  pl);
                    mma16816(acc[i][j], al_[i], ph);
                }
        }
    }

    // ------- epilogue -------
    const int tq = lane >> 2;
    const int tr = (lane & 3) * 2;
    float bj0[4], bj1[4];
#pragma unroll
    for (int j = 0; j < 4; j++) {
        const int n = bcol + wn + 8 * j + tr;
        float b0 = bias[n], b1 = bias[n + 1];
        if (bias2) { b0 += bias2[n]; b1 += bias2[n + 1]; }
        bj0[j] = b0; bj1[j] = b1;
    }
#pragma unroll
    for (int i = 0; i < 4; i++)
#pragma unroll
        for (int half = 0; half < 2; half++) {
            const int m = brow + wm + 16 * i + tq + half * 8;
#pragma unroll
            for (int j = 0; j < 4; j++) {
                const int n = bcol + wn + 8 * j + tr;
                float v0 = acc[i][j][half * 2 + 0] + bj0[j];
                float v1 = acc[i][j][half * 2 + 1] + bj1[j];
                if (res) {
                    float2 r = *(const float2*)(res + (size_t)m * ldres + n);
                    v0 += r.x; v1 += r.y;
                }
                if (relu) { v0 = fmaxf(v0, 0.f); v1 = fmaxf(v1, 0.f); }
                if (C) *(float2*)(C + (size_t)m * ldc + n) = make_float2(v0, v1);
                if (Ch) {
                    bf16 h0, l0, h1, l1;
                    split2(v0, h0, l0);
                    split2(v1, h1, l1);
                    *(__nv_bfloat162*)(Ch + (size_t)m * ldc + n) = __nv_bfloat162(h0, h1);
                    *(__nv_bfloat162*)(Cl + (size_t)m * ldc + n) = __nv_bfloat162(l0, l1);
                }
            }
        }
}

// ---------------- merged split-convert fp32 -> bf16 hi/lo (10 segments) ----------------
#define NSEG 10
struct ConvArgs {
    const float* s[NSEG];
    bf16* h[NSEG];
    bf16* l[NSEG];
    int end4[NSEG];   // inclusive-exclusive prefix ends in float4 units
};

__global__ __launch_bounds__(256) void conv_all(ConvArgs a, int total4)
{
    int i = blockIdx.x * 256 + threadIdx.x;
    if (i >= total4) return;
    int seg = 0;
#pragma unroll
    for (int s = 0; s < NSEG - 1; s++) seg += (i >= a.end4[s]) ? 1 : 0;
    const int base = seg ? a.end4[seg - 1] : 0;
    const int j = i - base;

    float4 v = ((const float4*)a.s[seg])[j];
    bf16 h0, l0, h1, l1, h2, l2, h3, l3;
    split2(v.x, h0, l0); split2(v.y, h1, l1);
    split2(v.z, h2, l2); split2(v.w, h3, l3);
    ((__nv_bfloat162*)a.h[seg])[2 * j]     = __nv_bfloat162(h0, h1);
    ((__nv_bfloat162*)a.h[seg])[2 * j + 1] = __nv_bfloat162(h2, h3);
    ((__nv_bfloat162*)a.l[seg])[2 * j]     = __nv_bfloat162(l0, l1);
    ((__nv_bfloat162*)a.l[seg])[2 * j + 1] = __nv_bfloat162(l2, l3);
}

// ---------------- 9-tap windowed multi-head attention (4 fused via z) ----------------
struct AttArgs {
    const float* Q[4];
    const float* Kp[4];
    const float* Vp[4];
    bf16* Oh[4];
    bf16* Ol[4];
};

__global__ __launch_bounds__(256) void attend_kernel(AttArgs a, int ostride)
{
    const int z   = blockIdx.y;
    const int t   = threadIdx.x & 63;
    const int pix = blockIdx.x * 4 + (threadIdx.x >> 6);
    const int b   = pix / (HH * WW);
    const int r   = pix % (HH * WW);
    const int y   = r / WW;
    const int x   = r % WW;
    const int ch  = t * 4;

    const float* __restrict__ Q  = a.Q[z];
    const float* __restrict__ Kp = a.Kp[z];
    const float* __restrict__ Vp = a.Vp[z];

    const float scale = 0.17677669529663687f;
    float4 q = *(const float4*)(Q + (size_t)pix * PDIM + ch);
    q.x *= scale; q.y *= scale; q.z *= scale; q.w *= scale;

    float  sc[9];
    float4 vv[9];
#pragma unroll
    for (int n = 0; n < 9; n++) {
        int dy = n / 3 - 1, dx = n % 3 - 1;
        int yy = y + dy, xx = x + dx;
        float s = 0.f;
        float4 v = make_float4(0.f, 0.f, 0.f, 0.f);
        if (yy >= 0 && yy < HH && xx >= 0 && xx < WW) {
            size_t np = ((size_t)(b * HH + yy) * WW + xx) * PDIM + ch;
            float4 k4 = *(const float4*)(Kp + np);
            v = *(const float4*)(Vp + np);
            s = q.x * k4.x + q.y * k4.y + q.z * k4.z + q.w * k4.w;
        }
        s += __shfl_xor_sync(0xffffffffu, s, 4);
        s += __shfl_xor_sync(0xffffffffu, s, 2);
        s += __shfl_xor_sync(0xffffffffu, s, 1);
        sc[n] = s;
        vv[n] = v;
    }

    float mx = sc[0];
#pragma unroll
    for (int n = 1; n < 9; n++) mx = fmaxf(mx, sc[n]);
    float den = 0.f;
    float4 o = make_float4(0.f, 0.f, 0.f, 0.f);
#pragma unroll
    for (int n = 0; n < 9; n++) {
        float w = __expf(sc[n] - mx);
        den += w;
        o.x += w * vv[n].x; o.y += w * vv[n].y;
        o.z += w * vv[n].z; o.w += w * vv[n].w;
    }
    float inv = 1.f / den;
    bf16 h0, l0, h1, l1, h2, l2, h3, l3;
    split2(o.x * inv, h0, l0); split2(o.y * inv, h1, l1);
    split2(o.z * inv, h2, l2); split2(o.w * inv, h3, l3);
    size_t base = (size_t)pix * ostride + ch;
    *(__nv_bfloat162*)(a.Oh[z] + base)     = __nv_bfloat162(h0, h1);
    *(__nv_bfloat162*)(a.Oh[z] + base + 2) = __nv_bfloat162(h2, h3);
    *(__nv_bfloat162*)(a.Ol[z] + base)     = __nv_bfloat162(l0, l1);
    *(__nv_bfloat162*)(a.Ol[z] + base + 2) = __nv_bfloat162(l2, l3);
}

// ---------------- LayerNorm over last dim (256), pair fused via y ----------------
struct LnArgs {
    const float* X[2];
    const float* g[2];
    const float* bt[2];
    float* O[2];
    bf16* Oh[2];
    bf16* Ol[2];
};

__global__ __launch_bounds__(256) void ln_kernel(LnArgs a)
{
    const int z   = blockIdx.y;
    const int row = blockIdx.x;
    const int t   = threadIdx.x;
    const int warp = t >> 5, lane = t & 31;
    __shared__ float red[8];

    float v = a.X[z][(size_t)row * F + t];

    float s = v;
#pragma unroll
    for (int o = 16; o > 0; o >>= 1) s += __shfl_xor_sync(0xffffffffu, s, o);
    if (lane == 0) red[warp] = s;
    __syncthreads();
    float tot = 0.f;
#pragma unroll
    for (int i = 0; i < 8; i++) tot += red[i];
    float mean = tot * (1.0f / F);
    float xc = v - mean;
    __syncthreads();

    float s2 = xc * xc;
#pragma unroll
    for (int o = 16; o > 0; o >>= 1) s2 += __shfl_xor_sync(0xffffffffu, s2, o);
    if (lane == 0) red[warp] = s2;
    __syncthreads();
    float tot2 = 0.f;
#pragma unroll
    for (int i = 0; i < 8; i++) tot2 += red[i];
    float var = tot2 * (1.0f / F);

    float out = a.g[z][t] * xc * rsqrtf(var + 1e-5f) + a.bt[z][t];
    if (a.O[z]) a.O[z][(size_t)row * F + t] = out;
    if (a.Oh[z]) {
        bf16 h, l;
        split2(out, h, l);
        a.Oh[z][(size_t)row * F + t] = h;
        a.Ol[z][(size_t)row * F + t] = l;
    }
}

// ---------------- launch ----------------
#define SYM(p, s) cudaGetSymbolAddress((void**)&p, s)

extern "C" void kernel_launch(void* const* d_in, const int* in_sizes, int n_in,
                              void* d_out, int out_size)
{
    const float* feat0       = (const float*)d_in[0];
    const float* feat1       = (const float*)d_in[1];
    const float* in_w0       = (const float*)d_in[2];
    const float* in_b0       = (const float*)d_in[3];
    const float* in_w1       = (const float*)d_in[4];
    const float* in_b1       = (const float*)d_in[5];
    const float* out_w0      = (const float*)d_in[6];
    const float* out_b0      = (const float*)d_in[7];
    const float* out_w1      = (const float*)d_in[8];
    const float* out_b1      = (const float*)d_in[9];
    const float* ln1_g0      = (const float*)d_in[10];
    const float* ln1_b0      = (const float*)d_in[11];
    const float* ln1_g1      = (const float*)d_in[12];
    const float* ln1_b1      = (const float*)d_in[13];
    const float* ffn_up_w0   = (const float*)d_in[14];
    const float* ffn_up_b0   = (const float*)d_in[15];
    const float* ffn_down_w0 = (const float*)d_in[16];
    const float* ffn_down_b0 = (const float*)d_in[17];
    const float* ffn_up_w1   = (const float*)d_in[18];
    const float* ffn_up_b1   = (const float*)d_in[19];
    const float* ffn_down_w1 = (const float*)d_in[20];
    const float* ffn_down_b1 = (const float*)d_in[21];
    const float* ln2_g0      = (const float*)d_in[22];
    const float* ln2_b0      = (const float*)d_in[23];
    const float* ln2_g1      = (const float*)d_in[24];
    const float* ln2_b1      = (const float*)d_in[25];

    float *P0, *P1, *T0, *T1, *X0, *X1;
    SYM(P0, g_P0); SYM(P1, g_P1); SYM(T0, g_T0); SYM(T1, g_T1); SYM(X0, g_X0); SYM(X1, g_X1);
    bf16 *fh0, *fl0, *fh1, *fl1, *wih0, *wil0, *wih1, *wil1;
    bf16 *woh0, *wol0, *woh1, *wol1, *wuh0, *wul0, *wuh1, *wul1, *wdh0, *wdl0, *wdh1, *wdl1;
    bf16 *QQh0, *QQl0, *QQh1, *QQl1, *Xh0, *Xl0, *Xh1, *Xl1, *Uh0, *Ul0, *Uh1, *Ul1;
    SYM(fh0, g_fh0); SYM(fl0, g_fl0); SYM(fh1, g_fh1); SYM(fl1, g_fl1);
    SYM(wih0, g_wih0); SYM(wil0, g_wil0); SYM(wih1, g_wih1); SYM(wil1, g_wil1);
    SYM(woh0, g_woh0); SYM(wol0, g_wol0); SYM(woh1, g_woh1); SYM(wol1, g_wol1);
    SYM(wuh0, g_wuh0); SYM(wul0, g_wul0); SYM(wuh1, g_wuh1); SYM(wul1, g_wul1);
    SYM(wdh0, g_wdh0); SYM(wdl0, g_wdl0); SYM(wdh1, g_wdh1); SYM(wdl1, g_wdl1);
    SYM(QQh0, g_QQh0); SYM(QQl0, g_QQl0); SYM(QQh1, g_QQh1); SYM(QQl1, g_QQl1);
    SYM(Xh0, g_Xh0); SYM(Xl0, g_Xl0); SYM(Xh1, g_Xh1); SYM(Xl1, g_Xl1);
    SYM(Uh0, g_Uh0); SYM(Ul0, g_Ul0); SYM(Uh1, g_Uh1); SYM(Ul1, g_Ul1);

    cudaFuncSetAttribute(gemm_bf16, cudaFuncAttributeMaxDynamicSharedMemorySize, GEMM_SMEM);

    float* out = (float*)d_out;
    dim3 blk(256);
    const int MT = NPIX / 128;   // 100

    // ---- launch 0: all converts in one kernel ----
    {
        ConvArgs ca;
        const float* srcs[NSEG] = {feat0, feat1, in_w0, in_w1, out_w0, out_w1,
                                   ffn_up_w0, ffn_up_w1, ffn_down_w0, ffn_down_w1};
        bf16* hs[NSEG] = {fh0, fh1, wih0, wih1, woh0, woh1, wuh0, wuh1, wdh0, wdh1};
        bf16* ls[NSEG] = {fl0, fl1, wil0, wil1, wol0, wol1, wul0, wul1, wdl0, wdl1};
        int sizes4[NSEG] = {NPIX*F/4, NPIX*F/4, PDIM*F/4, PDIM*F/4, F*3*F/4, F*3*F/4,
                            HIDN*F/4, HIDN*F/4, F*HIDN/4, F*HIDN/4};
        int acc4 = 0;
        for (int i = 0; i < NSEG; i++) {
            ca.s[i] = srcs[i]; ca.h[i] = hs[i]; ca.l[i] = ls[i];
            acc4 += sizes4[i];
            ca.end4[i] = acc4;
        }
        conv_all<<<(acc4 + 255) / 256, blk>>>(ca, acc4);
    }

    // ---- launch 1: in-projection GEMMs (both maps via z) ----
    {
        GemmPair gp = {};
        gp.Ah[0]=fh0;  gp.Al[0]=fl0;  gp.Ah[1]=fh1;  gp.Al[1]=fl1;
        gp.Bh0[0]=wih0; gp.Bl0[0]=wil0; gp.Bh1[0]=wih0; gp.Bl1[0]=wil0;
        gp.Bh0[1]=wih1; gp.Bl0[1]=wil1; gp.Bh1[1]=wih1; gp.Bl1[1]=wil1;
        gp.bias[0]=in_b0; gp.bias[1]=in_b1;
        gp.C[0]=P0; gp.C[1]=P1;
        gemm_bf16<<<dim3(PDIM/128, MT, 2), blk, GEMM_SMEM>>>(gp, F, F, F, 0, PDIM, F, 0);
    }

    // ---- launch 2: 4 attentions fused via y ----
    {
        AttArgs aa;
        aa.Q[0]=P0;       aa.Kp[0]=P0+F;     aa.Vp[0]=P0+2*F;  aa.Oh[0]=QQh0;   aa.Ol[0]=QQl0;
        aa.Q[1]=P1;       aa.Kp[1]=P1+F;     aa.Vp[1]=P1+2*F;  aa.Oh[1]=QQh1;   aa.Ol[1]=QQl1;
        aa.Q[2]=P0+3*F;   aa.Kp[2]=P1+4*F;   aa.Vp[2]=P1+5*F;  aa.Oh[2]=QQh0+F; aa.Ol[2]=QQl0+F;
        aa.Q[3]=P1+3*F;   aa.Kp[3]=P0+4*F;   aa.Vp[3]=P0+5*F;  aa.Oh[3]=QQh1+F; aa.Ol[3]=QQl1+F;
        attend_kernel<<<dim3(NPIX/4, 4), blk>>>(aa, 2*F);
    }

    // ---- launch 3: fused out-projections (K=512, split at 256), residual = feat ----
    {
        GemmPair gp = {};
        gp.Ah[0]=QQh0; gp.Al[0]=QQl0; gp.Ah[1]=QQh1; gp.Al[1]=QQl1;
        gp.Bh0[0]=woh0; gp.Bl0[0]=wol0; gp.Bh1[0]=woh0+F; gp.Bl1[0]=wol0+F;
        gp.Bh0[1]=woh1; gp.Bl0[1]=wol1; gp.Bh1[1]=woh0+F; gp.Bl1[1]=wol0+F;
        gp.bias[0]=out_b0; gp.bias2[0]=out_b0+F; gp.res[0]=feat0; gp.C[0]=T0;
        gp.bias[1]=out_b1; gp.bias2[1]=out_b0+F; gp.res[1]=feat1; gp.C[1]=T1;
        gemm_bf16<<<dim3(F/128, MT, 2), blk, GEMM_SMEM>>>(gp, 2*F, 3*F, F, F, F, 2*F, 0);
    }

    // ---- launch 4: LN1 pair ----
    {
        LnArgs la;
        la.X[0]=T0; la.g[0]=ln1_g0; la.bt[0]=ln1_b0; la.O[0]=X0; la.Oh[0]=Xh0; la.Ol[0]=Xl0;
        la.X[1]=T1; la.g[1]=ln1_g1; la.bt[1]=ln1_b1; la.O[1]=X1; la.Oh[1]=Xh1; la.Ol[1]=Xl1;
        ln_kernel<<<dim3(NPIX, 2), blk>>>(la);
    }

    // ---- launch 5: FFN up pair (relu, bf16-split out only) ----
    {
        GemmPair gp = {};
        gp.Ah[0]=Xh0; gp.Al[0]=Xl0; gp.Ah[1]=Xh1; gp.Al[1]=Xl1;
        gp.Bh0[0]=wuh0; gp.Bl0[0]=wul0; gp.Bh1[0]=wuh0; gp.Bl1[0]=wul0;
        gp.Bh0[1]=wuh1; gp.Bl0[1]=wul1; gp.Bh1[1]=wuh1; gp.Bl1[1]=wul1;
        gp.bias[0]=ffn_up_b0; gp.bias[1]=ffn_up_b1;
        gp.Ch[0]=Uh0; gp.Cl[0]=Ul0; gp.Ch[1]=Uh1; gp.Cl[1]=Ul1;
        gemm_bf16<<<dim3(HIDN/128, MT, 2), blk, GEMM_SMEM>>>(gp, F, F, F, 0, HIDN, F, 1);
    }

    // ---- launch 6: FFN down pair (residual X, fp32 out) ----
    {
        GemmPair gp = {};
        gp.Ah[0]=Uh0; gp.Al[0]=Ul0; gp.Ah[1]=Uh1; gp.Al[1]=Ul1;
        gp.Bh0[0]=wdh0; gp.Bl0[0]=wdl0; gp.Bh1[0]=wdh0; gp.Bl1[0]=wdl0;
        gp.Bh0[1]=wdh1; gp.Bl0[1]=wdl1; gp.Bh1[1]=wdh1; gp.Bl1[1]=wdl1;
        gp.bias[0]=ffn_down_b0; gp.bias[1]=ffn_down_b1;
        gp.res[0]=X0; gp.res[1]=X1;
        gp.C[0]=T0; gp.C[1]=T1;
        gemm_bf16<<<dim3(F/128, MT, 2), blk, GEMM_SMEM>>>(gp, HIDN, HIDN, HIDN, F, F, HIDN, 0);
    }

    // ---- launch 7: LN2 pair -> output ----
    {
        LnArgs la;
        la.X[0]=T0; la.g[0]=ln2_g0; la.bt[0]=ln2_b0; la.O[0]=out;
        la.Oh[0]=nullptr; la.Ol[0]=nullptr;
        la.X[1]=T1; la.g[1]=ln2_g1; la.bt[1]=ln2_b1; la.O[1]=out + (size_t)NPIX*F;
        la.Oh[1]=nullptr; la.Ol[1]=nullptr;
        ln_kernel<<<dim3(NPIX, 2), blk>>>(la);
    }
}

// round 6
// speedup vs baseline: 2.0211x; 1.0009x over previous
#include <cuda_runtime.h>
#include <cuda_bf16.h>
#include <cstdint>
#include <cstddef>

#define F      256
#define NH     8
#define BATCH  2
#define HH     80
#define WW     80
#define NPIX   (BATCH*HH*WW)   // 12800
#define PDIM   1536
#define HIDN   1024

typedef __nv_bfloat16 bf16;

// ---------------- scratch (no allocations allowed) ----------------
__device__ float g_P0[(size_t)NPIX*PDIM];
__device__ float g_P1[(size_t)NPIX*PDIM];
__device__ float g_T0[(size_t)NPIX*F];
__device__ float g_T1[(size_t)NPIX*F];
__device__ float g_X0[(size_t)NPIX*F];
__device__ float g_X1[(size_t)NPIX*F];

__device__ bf16 g_fh0[(size_t)NPIX*F],  g_fl0[(size_t)NPIX*F];
__device__ bf16 g_fh1[(size_t)NPIX*F],  g_fl1[(size_t)NPIX*F];
__device__ bf16 g_wih0[(size_t)PDIM*F], g_wil0[(size_t)PDIM*F];
__device__ bf16 g_wih1[(size_t)PDIM*F], g_wil1[(size_t)PDIM*F];
__device__ bf16 g_woh0[(size_t)F*3*F],  g_wol0[(size_t)F*3*F];
__device__ bf16 g_woh1[(size_t)F*3*F],  g_wol1[(size_t)F*3*F];
__device__ bf16 g_wuh0[(size_t)HIDN*F], g_wul0[(size_t)HIDN*F];
__device__ bf16 g_wuh1[(size_t)HIDN*F], g_wul1[(size_t)HIDN*F];
__device__ bf16 g_wdh0[(size_t)F*HIDN], g_wdl0[(size_t)F*HIDN];
__device__ bf16 g_wdh1[(size_t)F*HIDN], g_wdl1[(size_t)F*HIDN];
__device__ bf16 g_QQh0[(size_t)NPIX*2*F], g_QQl0[(size_t)NPIX*2*F];
__device__ bf16 g_QQh1[(size_t)NPIX*2*F], g_QQl1[(size_t)NPIX*2*F];
__device__ bf16 g_Xh0[(size_t)NPIX*F],  g_Xl0[(size_t)NPIX*F];
__device__ bf16 g_Xh1[(size_t)NPIX*F],  g_Xl1[(size_t)NPIX*F];
__device__ bf16 g_Uh0[(size_t)NPIX*HIDN], g_Ul0[(size_t)NPIX*HIDN];
__device__ bf16 g_Uh1[(size_t)NPIX*HIDN], g_Ul1[(size_t)NPIX*HIDN];

// ================= helpers =================
__device__ __forceinline__ uint32_t smem_u32(const void* p) {
    uint32_t a;
    asm("{ .reg .u64 t; cvta.to.shared.u64 t, %1; cvt.u32.u64 %0, t; }" : "=r"(a) : "l"(p));
    return a;
}
__device__ __forceinline__ void cpasync16(uint32_t dst, const void* src) {
    asm volatile("cp.async.cg.shared.global [%0], [%1], 16;" :: "r"(dst), "l"(src) : "memory");
}
__device__ __forceinline__ void ldsm4(uint32_t (&r)[4], uint32_t addr) {
    asm volatile("ldmatrix.sync.aligned.m8n8.x4.shared.b16 {%0,%1,%2,%3}, [%4];"
                 : "=r"(r[0]), "=r"(r[1]), "=r"(r[2]), "=r"(r[3]) : "r"(addr));
}
__device__ __forceinline__ void mma16816(float* d, const uint32_t* a, const uint32_t* b) {
    asm volatile("mma.sync.aligned.m16n8k16.row.col.f32.bf16.bf16.f32 "
                 "{%0,%1,%2,%3}, {%4,%5,%6,%7}, {%8,%9}, {%0,%1,%2,%3};"
                 : "+f"(d[0]), "+f"(d[1]), "+f"(d[2]), "+f"(d[3])
                 : "r"(a[0]), "r"(a[1]), "r"(a[2]), "r"(a[3]), "r"(b[0]), "r"(b[1]));
}
__device__ __forceinline__ void split2(float v, bf16& h, bf16& l) {
    h = __float2bfloat16(v);
    l = __float2bfloat16(v - __bfloat162float(h));
}

// ================= bf16-split tensor GEMM (paired over z) =================
// z = blockIdx.z selects one of two independent GEMMs with shared shape.
// C[m,n] = act( sum_k A[m,k]*W[n,k] + bias[n] (+bias2[n]) (+res[m,n]) )
#define STAGES     4
#define SMEM_STAGE 32768
#define GEMM_SMEM  (STAGES*SMEM_STAGE)

struct GemmPair {
    const bf16 *Ah[2], *Al[2];
    const bf16 *Bh0[2], *Bl0[2], *Bh1[2], *Bl1[2];
    const float *bias[2], *bias2[2], *res[2];
    float *C[2];
    bf16 *Ch[2], *Cl[2];
};

__global__ __launch_bounds__(256, 1) void gemm_bf16(
    GemmPair gp, int lda, int ldb, int Ksplit,
    int ldres, int ldc, int K, int relu)
{
    extern __shared__ char smem[];
    const uint32_t sb0 = smem_u32(smem);

    const int z = blockIdx.z;
    const bf16* __restrict__ Ah  = gp.Ah[z];
    const bf16* __restrict__ Al  = gp.Al[z];
    const bf16* __restrict__ Bh0 = gp.Bh0[z];
    const bf16* __restrict__ Bl0 = gp.Bl0[z];
    const bf16* __restrict__ Bh1 = gp.Bh1[z];
    const bf16* __restrict__ Bl1 = gp.Bl1[z];
    const float* __restrict__ bias  = gp.bias[z];
    const float* __restrict__ bias2 = gp.bias2[z];
    const float* __restrict__ res   = gp.res[z];
    float* __restrict__ C  = gp.C[z];
    bf16*  __restrict__ Ch = gp.Ch[z];
    bf16*  __restrict__ Cl = gp.Cl[z];

    const int tid  = threadIdx.x;
    const int wid  = tid >> 5;
    const int lane = tid & 31;
    const int brow = blockIdx.y * 128;
    const int bcol = blockIdx.x * 128;
    const int wm   = (wid >> 2) * 64;
    const int wn   = (wid & 3) * 32;

    float acc[4][4][4];
#pragma unroll
    for (int i = 0; i < 4; i++)
#pragma unroll
        for (int j = 0; j < 4; j++)
#pragma unroll
            for (int r = 0; r < 4; r++) acc[i][j][r] = 0.f;

    const int lrow = tid >> 1;
    const int lc0  = (tid & 1) * 2;
    const uint32_t lsw = ((uint32_t)lrow >> 1) & 3u;

    auto load_stage = [&](int cIdx) {
        const uint32_t sb = sb0 + (uint32_t)(cIdx % STAGES) * SMEM_STAGE;
        const int k0 = cIdx * 32;
        const bf16 *bh, *bl;
        int kk;
        if (k0 < Ksplit) { bh = Bh0; bl = Bl0; kk = k0; }
        else             { bh = Bh1; bl = Bl1; kk = k0 - Ksplit; }
        const size_t aoff = (size_t)(brow + lrow) * lda + k0;
        const size_t boff = (size_t)(bcol + lrow) * ldb + kk;
        const uint32_t dbase = sb + (uint32_t)lrow * 64u;
#pragma unroll
        for (int i = 0; i < 2; i++) {
            const int cc = lc0 + i;
            const uint32_t d = dbase + (uint32_t)(cc ^ lsw) * 16u;
            cpasync16(d,           Ah + aoff + cc * 8);
            cpasync16(d + 8192u,   Al + aoff + cc * 8);
            cpasync16(d + 16384u,  bh + boff + cc * 8);
            cpasync16(d + 24576u,  bl + boff + cc * 8);
        }
        asm volatile("cp.async.commit_group;" ::: "memory");
    };

    const int tile = lane >> 3;
    const int rin  = lane & 7;
    const uint32_t rsw = (uint32_t)(rin >> 1);

    const int NC = K / 32;
    for (int s = 0; s < STAGES - 1 && s < NC; s++) load_stage(s);

    for (int c = 0; c < NC; c++) {
        if (c + 3 <= NC) {
            asm volatile("cp.async.wait_group 2;" ::: "memory");
        } else if (c + 2 == NC) {
            asm volatile("cp.async.wait_group 1;" ::: "memory");
        } else {
            asm volatile("cp.async.wait_group 0;" ::: "memory");
        }
        __syncthreads();
        if (c + 3 < NC) load_stage(c + 3);

        const uint32_t sb = sb0 + (uint32_t)(c % STAGES) * SMEM_STAGE;
#pragma unroll
        for (int ks = 0; ks < 2; ks++) {
            uint32_t ah[4][4], al_[4][4], bh_[2][4], bl_[2][4];
            const uint32_t swa = ((uint32_t)(ks * 2 + (tile >> 1)) ^ rsw) * 16u;
            const uint32_t abase = sb + (uint32_t)(wm + (tile & 1) * 8 + rin) * 64u + swa;
#pragma unroll
            for (int i = 0; i < 4; i++) {
                ldsm4(ah[i],  abase + (uint32_t)i * 1024u);
                ldsm4(al_[i], abase + 8192u + (uint32_t)i * 1024u);
            }
            const uint32_t swb = ((uint32_t)(ks * 2 + (tile & 1)) ^ rsw) * 16u;
            const uint32_t bbase = sb + 16384u + (uint32_t)(wn + (tile >> 1) * 8 + rin) * 64u + swb;
#pragma unroll
            for (int jj = 0; jj < 2; jj++) {
                ldsm4(bh_[jj], bbase + (uint32_t)jj * 1024u);
                ldsm4(bl_[jj], bbase + 8192u + (uint32_t)jj * 1024u);
            }
            // term-major ordering: 16 independent MMAs between accumulator reuses
#pragma unroll
            for (int i = 0; i < 4; i++)
#pragma unroll
                for (int j = 0; j < 4; j++)
                    mma16816(acc[i][j], ah[i], &bh_[j >> 1][(j & 1) * 2]);
#pragma unroll
            for (int i = 0; i < 4; i++)
#pragma unroll
                for (int j = 0; j < 4; j++)
                    mma16816(acc[i][j], ah[i], &bl_[j >> 1][(j & 1) * 2]);
#pragma unroll
            for (int i = 0; i < 4; i++)
#pragma unroll
                for (int j = 0; j < 4; j++)
                    mma16816(acc[i][j], al_[i], &bh_[j >> 1][(j & 1) * 2]);
        }
    }

    // ------- epilogue -------
    const int tq = lane >> 2;
    const int tr = (lane & 3) * 2;
    float bj0[4], bj1[4];
#pragma unroll
    for (int j = 0; j < 4; j++) {
        const int n = bcol + wn + 8 * j + tr;
        float b0 = bias[n], b1 = bias[n + 1];
        if (bias2) { b0 += bias2[n]; b1 += bias2[n + 1]; }
        bj0[j] = b0; bj1[j] = b1;
    }
#pragma unroll
    for (int i = 0; i < 4; i++)
#pragma unroll
        for (int half = 0; half < 2; half++) {
            const int m = brow + wm + 16 * i + tq + half * 8;
#pragma unroll
            for (int j = 0; j < 4; j++) {
                const int n = bcol + wn + 8 * j + tr;
                float v0 = acc[i][j][half * 2 + 0] + bj0[j];
                float v1 = acc[i][j][half * 2 + 1] + bj1[j];
                if (res) {
                    float2 r = *(const float2*)(res + (size_t)m * ldres + n);
                    v0 += r.x; v1 += r.y;
                }
                if (relu) { v0 = fmaxf(v0, 0.f); v1 = fmaxf(v1, 0.f); }
                if (C) *(float2*)(C + (size_t)m * ldc + n) = make_float2(v0, v1);
                if (Ch) {
                    bf16 h0, l0, h1, l1;
                    split2(v0, h0, l0);
                    split2(v1, h1, l1);
                    *(__nv_bfloat162*)(Ch + (size_t)m * ldc + n) = __nv_bfloat162(h0, h1);
                    *(__nv_bfloat162*)(Cl + (size_t)m * ldc + n) = __nv_bfloat162(l0, l1);
                }
            }
        }
}

// ---------------- merged split-convert fp32 -> bf16 hi/lo (10 segments) ----------------
#define NSEG 10
struct ConvArgs {
    const float* s[NSEG];
    bf16* h[NSEG];
    bf16* l[NSEG];
    int end4[NSEG];
};

__global__ __launch_bounds__(256) void conv_all(ConvArgs a, int total4)
{
    int i = blockIdx.x * 256 + threadIdx.x;
    if (i >= total4) return;
    int seg = 0;
#pragma unroll
    for (int s = 0; s < NSEG - 1; s++) seg += (i >= a.end4[s]) ? 1 : 0;
    const int base = seg ? a.end4[seg - 1] : 0;
    const int j = i - base;

    float4 v = ((const float4*)a.s[seg])[j];
    bf16 h0, l0, h1, l1, h2, l2, h3, l3;
    split2(v.x, h0, l0); split2(v.y, h1, l1);
    split2(v.z, h2, l2); split2(v.w, h3, l3);
    ((__nv_bfloat162*)a.h[seg])[2 * j]     = __nv_bfloat162(h0, h1);
    ((__nv_bfloat162*)a.h[seg])[2 * j + 1] = __nv_bfloat162(h2, h3);
    ((__nv_bfloat162*)a.l[seg])[2 * j]     = __nv_bfloat162(l0, l1);
    ((__nv_bfloat162*)a.l[seg])[2 * j + 1] = __nv_bfloat162(l2, l3);
}

// ---------------- 9-tap windowed multi-head attention (4 fused via y) ----------------
struct AttArgs {
    const float* Q[4];
    const float* Kp[4];
    const float* Vp[4];
    bf16* Oh[4];
    bf16* Ol[4];
};

__global__ __launch_bounds__(256) void attend_kernel(AttArgs a, int ostride)
{
    const int z   = blockIdx.y;
    const int t   = threadIdx.x & 63;
    const int pix = blockIdx.x * 4 + (threadIdx.x >> 6);
    const int b   = pix / (HH * WW);
    const int r   = pix % (HH * WW);
    const int y   = r / WW;
    const int x   = r % WW;
    const int ch  = t * 4;

    const float* __restrict__ Q  = a.Q[z];
    const float* __restrict__ Kp = a.Kp[z];
    const float* __restrict__ Vp = a.Vp[z];

    const float scale = 0.17677669529663687f;
    float4 q = *(const float4*)(Q + (size_t)pix * PDIM + ch);
    q.x *= scale; q.y *= scale; q.z *= scale; q.w *= scale;

    float  sc[9];
    float4 vv[9];
#pragma unroll
    for (int n = 0; n < 9; n++) {
        int dy = n / 3 - 1, dx = n % 3 - 1;
        int yy = y + dy, xx = x + dx;
        float s = 0.f;
        float4 v = make_float4(0.f, 0.f, 0.f, 0.f);
        if (yy >= 0 && yy < HH && xx >= 0 && xx < WW) {
            size_t np = ((size_t)(b * HH + yy) * WW + xx) * PDIM + ch;
            float4 k4 = *(const float4*)(Kp + np);
            v = *(const float4*)(Vp + np);
            s = q.x * k4.x + q.y * k4.y + q.z * k4.z + q.w * k4.w;
        }
        s += __shfl_xor_sync(0xffffffffu, s, 4);
        s += __shfl_xor_sync(0xffffffffu, s, 2);
        s += __shfl_xor_sync(0xffffffffu, s, 1);
        sc[n] = s;
        vv[n] = v;
    }

    float mx = sc[0];
#pragma unroll
    for (int n = 1; n < 9; n++) mx = fmaxf(mx, sc[n]);
    float den = 0.f;
    float4 o = make_float4(0.f, 0.f, 0.f, 0.f);
#pragma unroll
    for (int n = 0; n < 9; n++) {
        float w = __expf(sc[n] - mx);
        den += w;
        o.x += w * vv[n].x; o.y += w * vv[n].y;
        o.z += w * vv[n].z; o.w += w * vv[n].w;
    }
    float inv = 1.f / den;
    bf16 h0, l0, h1, l1, h2, l2, h3, l3;
    split2(o.x * inv, h0, l0); split2(o.y * inv, h1, l1);
    split2(o.z * inv, h2, l2); split2(o.w * inv, h3, l3);
    size_t base = (size_t)pix * ostride + ch;
    *(__nv_bfloat162*)(a.Oh[z] + base)     = __nv_bfloat162(h0, h1);
    *(__nv_bfloat162*)(a.Oh[z] + base + 2) = __nv_bfloat162(h2, h3);
    *(__nv_bfloat162*)(a.Ol[z] + base)     = __nv_bfloat162(l0, l1);
    *(__nv_bfloat162*)(a.Ol[z] + base + 2) = __nv_bfloat162(l2, l3);
}

// ---------------- LayerNorm over last dim (256), pair fused via y ----------------
struct LnArgs {
    const float* X[2];
    const float* g[2];
    const float* bt[2];
    float* O[2];
    bf16* Oh[2];
    bf16* Ol[2];
};

__global__ __launch_bounds__(256) void ln_kernel(LnArgs a)
{
    const int z   = blockIdx.y;
    const int row = blockIdx.x;
    const int t   = threadIdx.x;
    const int warp = t >> 5, lane = t & 31;
    __shared__ float red[8];

    float v = a.X[z][(size_t)row * F + t];

    float s = v;
#pragma unroll
    for (int o = 16; o > 0; o >>= 1) s += __shfl_xor_sync(0xffffffffu, s, o);
    if (lane == 0) red[warp] = s;
    __syncthreads();
    float tot = 0.f;
#pragma unroll
    for (int i = 0; i < 8; i++) tot += red[i];
    float mean = tot * (1.0f / F);
    float xc = v - mean;
    __syncthreads();

    float s2 = xc * xc;
#pragma unroll
    for (int o = 16; o > 0; o >>= 1) s2 += __shfl_xor_sync(0xffffffffu, s2, o);
    if (lane == 0) red[warp] = s2;
    __syncthreads();
    float tot2 = 0.f;
#pragma unroll
    for (int i = 0; i < 8; i++) tot2 += red[i];
    float var = tot2 * (1.0f / F);

    float out = a.g[z][t] * xc * rsqrtf(var + 1e-5f) + a.bt[z][t];
    if (a.O[z]) a.O[z][(size_t)row * F + t] = out;
    if (a.Oh[z]) {
        bf16 h, l;
        split2(out, h, l);
        a.Oh[z][(size_t)row * F + t] = h;
        a.Ol[z][(size_t)row * F + t] = l;
    }
}

// ---------------- launch ----------------
#define SYM(p, s) cudaGetSymbolAddress((void**)&p, s)

extern "C" void kernel_launch(void* const* d_in, const int* in_sizes, int n_in,
                              void* d_out, int out_size)
{
    const float* feat0       = (const float*)d_in[0];
    const float* feat1       = (const float*)d_in[1];
    const float* in_w0       = (const float*)d_in[2];
    const float* in_b0       = (const float*)d_in[3];
    const float* in_w1       = (const float*)d_in[4];
    const float* in_b1       = (const float*)d_in[5];
    const float* out_w0      = (const float*)d_in[6];
    const float* out_b0      = (const float*)d_in[7];
    const float* out_w1      = (const float*)d_in[8];
    const float* out_b1      = (const float*)d_in[9];
    const float* ln1_g0      = (const float*)d_in[10];
    const float* ln1_b0      = (const float*)d_in[11];
    const float* ln1_g1      = (const float*)d_in[12];
    const float* ln1_b1      = (const float*)d_in[13];
    const float* ffn_up_w0   = (const float*)d_in[14];
    const float* ffn_up_b0   = (const float*)d_in[15];
    const float* ffn_down_w0 = (const float*)d_in[16];
    const float* ffn_down_b0 = (const float*)d_in[17];
    const float* ffn_up_w1   = (const float*)d_in[18];
    const float* ffn_up_b1   = (const float*)d_in[19];
    const float* ffn_down_w1 = (const float*)d_in[20];
    const float* ffn_down_b1 = (const float*)d_in[21];
    const float* ln2_g0      = (const float*)d_in[22];
    const float* ln2_b0      = (const float*)d_in[23];
    const float* ln2_g1      = (const float*)d_in[24];
    const float* ln2_b1      = (const float*)d_in[25];

    float *P0, *P1, *T0, *T1, *X0, *X1;
    SYM(P0, g_P0); SYM(P1, g_P1); SYM(T0, g_T0); SYM(T1, g_T1); SYM(X0, g_X0); SYM(X1, g_X1);
    bf16 *fh0, *fl0, *fh1, *fl1, *wih0, *wil0, *wih1, *wil1;
    bf16 *woh0, *wol0, *woh1, *wol1, *wuh0, *wul0, *wuh1, *wul1, *wdh0, *wdl0, *wdh1, *wdl1;
    bf16 *QQh0, *QQl0, *QQh1, *QQl1, *Xh0, *Xl0, *Xh1, *Xl1, *Uh0, *Ul0, *Uh1, *Ul1;
    SYM(fh0, g_fh0); SYM(fl0, g_fl0); SYM(fh1, g_fh1); SYM(fl1, g_fl1);
    SYM(wih0, g_wih0); SYM(wil0, g_wil0); SYM(wih1, g_wih1); SYM(wil1, g_wil1);
    SYM(woh0, g_woh0); SYM(wol0, g_wol0); SYM(woh1, g_woh1); SYM(wol1, g_wol1);
    SYM(wuh0, g_wuh0); SYM(wul0, g_wul0); SYM(wuh1, g_wuh1); SYM(wul1, g_wul1);
    SYM(wdh0, g_wdh0); SYM(wdl0, g_wdl0); SYM(wdh1, g_wdh1); SYM(wdl1, g_wdl1);
    SYM(QQh0, g_QQh0); SYM(QQl0, g_QQl0); SYM(QQh1, g_QQh1); SYM(QQl1, g_QQl1);
    SYM(Xh0, g_Xh0); SYM(Xl0, g_Xl0); SYM(Xh1, g_Xh1); SYM(Xl1, g_Xl1);
    SYM(Uh0, g_Uh0); SYM(Ul0, g_Ul0); SYM(Uh1, g_Uh1); SYM(Ul1, g_Ul1);

    cudaFuncSetAttribute(gemm_bf16, cudaFuncAttributeMaxDynamicSharedMemorySize, GEMM_SMEM);

    float* out = (float*)d_out;
    dim3 blk(256);
    const int MT = NPIX / 128;   // 100

    // ---- launch 0: all converts in one kernel ----
    {
        ConvArgs ca;
        const float* srcs[NSEG] = {feat0, feat1, in_w0, in_w1, out_w0, out_w1,
                                   ffn_up_w0, ffn_up_w1, ffn_down_w0, ffn_down_w1};
        bf16* hs[NSEG] = {fh0, fh1, wih0, wih1, woh0, woh1, wuh0, wuh1, wdh0, wdh1};
        bf16* ls[NSEG] = {fl0, fl1, wil0, wil1, wol0, wol1, wul0, wul1, wdl0, wdl1};
        int sizes4[NSEG] = {NPIX*F/4, NPIX*F/4, PDIM*F/4, PDIM*F/4, F*3*F/4, F*3*F/4,
                            HIDN*F/4, HIDN*F/4, F*HIDN/4, F*HIDN/4};
        int acc4 = 0;
        for (int i = 0; i < NSEG; i++) {
            ca.s[i] = srcs[i]; ca.h[i] = hs[i]; ca.l[i] = ls[i];
            acc4 += sizes4[i];
            ca.end4[i] = acc4;
        }
        conv_all<<<(acc4 + 255) / 256, blk>>>(ca, acc4);
    }

    // ---- launch 1: in-projection GEMMs (both maps via z) ----
    {
        GemmPair gp = {};
        gp.Ah[0]=fh0;  gp.Al[0]=fl0;  gp.Ah[1]=fh1;  gp.Al[1]=fl1;
        gp.Bh0[0]=wih0; gp.Bl0[0]=wil0; gp.Bh1[0]=wih0; gp.Bl1[0]=wil0;
        gp.Bh0[1]=wih1; gp.Bl0[1]=wil1; gp.Bh1[1]=wih1; gp.Bl1[1]=wil1;
        gp.bias[0]=in_b0; gp.bias[1]=in_b1;
        gp.C[0]=P0; gp.C[1]=P1;
        gemm_bf16<<<dim3(PDIM/128, MT, 2), blk, GEMM_SMEM>>>(gp, F, F, F, 0, PDIM, F, 0);
    }

    // ---- launch 2: 4 attentions fused via y ----
    {
        AttArgs aa;
        aa.Q[0]=P0;       aa.Kp[0]=P0+F;     aa.Vp[0]=P0+2*F;  aa.Oh[0]=QQh0;   aa.Ol[0]=QQl0;
        aa.Q[1]=P1;       aa.Kp[1]=P1+F;     aa.Vp[1]=P1+2*F;  aa.Oh[1]=QQh1;   aa.Ol[1]=QQl1;
        aa.Q[2]=P0+3*F;   aa.Kp[2]=P1+4*F;   aa.Vp[2]=P1+5*F;  aa.Oh[2]=QQh0+F; aa.Ol[2]=QQl0+F;
        aa.Q[3]=P1+3*F;   aa.Kp[3]=P0+4*F;   aa.Vp[3]=P0+5*F;  aa.Oh[3]=QQh1+F; aa.Ol[3]=QQl1+F;
        attend_kernel<<<dim3(NPIX/4, 4), blk>>>(aa, 2*F);
    }

    // ---- launch 3: fused out-projections (K=512, split at 256), residual = feat ----
    {
        GemmPair gp = {};
        gp.Ah[0]=QQh0; gp.Al[0]=QQl0; gp.Ah[1]=QQh1; gp.Al[1]=QQl1;
        gp.Bh0[0]=woh0; gp.Bl0[0]=wol0; gp.Bh1[0]=woh0+F; gp.Bl1[0]=wol0+F;
        gp.Bh0[1]=woh1; gp.Bl0[1]=wol1; gp.Bh1[1]=woh0+F; gp.Bl1[1]=wol0+F;
        gp.bias[0]=out_b0; gp.bias2[0]=out_b0+F; gp.res[0]=feat0; gp.C[0]=T0;
        gp.bias[1]=out_b1; gp.bias2[1]=out_b0+F; gp.res[1]=feat1; gp.C[1]=T1;
        gemm_bf16<<<dim3(F/128, MT, 2), blk, GEMM_SMEM>>>(gp, 2*F, 3*F, F, F, F, 2*F, 0);
    }

    // ---- launch 4: LN1 pair ----
    {
        LnArgs la;
        la.X[0]=T0; la.g[0]=ln1_g0; la.bt[0]=ln1_b0; la.O[0]=X0; la.Oh[0]=Xh0; la.Ol[0]=Xl0;
        la.X[1]=T1; la.g[1]=ln1_g1; la.bt[1]=ln1_b1; la.O[1]=X1; la.Oh[1]=Xh1; la.Ol[1]=Xl1;
        ln_kernel<<<dim3(NPIX, 2), blk>>>(la);
    }

    // ---- launch 5: FFN up pair (relu, bf16-split out only) ----
    {
        GemmPair gp = {};
        gp.Ah[0]=Xh0; gp.Al[0]=Xl0; gp.Ah[1]=Xh1; gp.Al[1]=Xl1;
        gp.Bh0[0]=wuh0; gp.Bl0[0]=wul0; gp.Bh1[0]=wuh0; gp.Bl1[0]=wul0;
        gp.Bh0[1]=wuh1; gp.Bl0[1]=wul1; gp.Bh1[1]=wuh1; gp.Bl1[1]=wul1;
        gp.bias[0]=ffn_up_b0; gp.bias[1]=ffn_up_b1;
        gp.Ch[0]=Uh0; gp.Cl[0]=Ul0; gp.Ch[1]=Uh1; gp.Cl[1]=Ul1;
        gemm_bf16<<<dim3(HIDN/128, MT, 2), blk, GEMM_SMEM>>>(gp, F, F, F, 0, HIDN, F, 1);
    }

    // ---- launch 6: FFN down pair (residual X, fp32 out) ----
    {
        GemmPair gp = {};
        gp.Ah[0]=Uh0; gp.Al[0]=Ul0; gp.Ah[1]=Uh1; gp.Al[1]=Ul1;
        gp.Bh0[0]=wdh0; gp.Bl0[0]=wdl0; gp.Bh1[0]=wdh0; gp.Bl1[0]=wdl0;
        gp.Bh0[1]=wdh1; gp.Bl0[1]=wdl1; gp.Bh1[1]=wdh1; gp.Bl1[1]=wdl1;
        gp.bias[0]=ffn_down_b0; gp.bias[1]=ffn_down_b1;
        gp.res[0]=X0; gp.res[1]=X1;
        gp.C[0]=T0; gp.C[1]=T1;
        gemm_bf16<<<dim3(F/128, MT, 2), blk, GEMM_SMEM>>>(gp, HIDN, HIDN, HIDN, F, F, HIDN, 0);
    }

    // ---- launch 7: LN2 pair -> output ----
    {
        LnArgs la;
        la.X[0]=T0; la.g[0]=ln2_g0; la.bt[0]=ln2_b0; la.O[0]=out;
        la.Oh[0]=nullptr; la.Ol[0]=nullptr;
        la.X[1]=T1; la.g[1]=ln2_g1; la.bt[1]=ln2_b1; la.O[1]=out + (size_t)NPIX*F;
        la.Oh[1]=nullptr; la.Ol[1]=nullptr;
        ln_kernel<<<dim3(NPIX, 2), blk>>>(la);
    }
}

// round 7
// speedup vs baseline: 2.0943x; 1.0363x over previous
#include <cuda_runtime.h>
#include <cuda_bf16.h>
#include <cstdint>
#include <cstddef>

#define F      256
#define NH     8
#define BATCH  2
#define HH     80
#define WW     80
#define NPIX   (BATCH*HH*WW)   // 12800
#define PDIM   1536
#define HIDN   1024

typedef __nv_bfloat16 bf16;

// ---------------- scratch (no allocations allowed) ----------------
__device__ float g_P0[(size_t)NPIX*PDIM];
__device__ float g_P1[(size_t)NPIX*PDIM];
__device__ float g_T0[(size_t)NPIX*F];
__device__ float g_T1[(size_t)NPIX*F];
__device__ float g_X0[(size_t)NPIX*F];
__device__ float g_X1[(size_t)NPIX*F];

__device__ bf16 g_fh0[(size_t)NPIX*F],  g_fl0[(size_t)NPIX*F];
__device__ bf16 g_fh1[(size_t)NPIX*F],  g_fl1[(size_t)NPIX*F];
__device__ bf16 g_wih0[(size_t)PDIM*F], g_wil0[(size_t)PDIM*F];
__device__ bf16 g_wih1[(size_t)PDIM*F], g_wil1[(size_t)PDIM*F];
__device__ bf16 g_woh0[(size_t)F*3*F],  g_wol0[(size_t)F*3*F];
__device__ bf16 g_woh1[(size_t)F*3*F],  g_wol1[(size_t)F*3*F];
__device__ bf16 g_wuh0[(size_t)HIDN*F], g_wul0[(size_t)HIDN*F];
__device__ bf16 g_wuh1[(size_t)HIDN*F], g_wul1[(size_t)HIDN*F];
__device__ bf16 g_wdh0[(size_t)F*HIDN], g_wdl0[(size_t)F*HIDN];
__device__ bf16 g_wdh1[(size_t)F*HIDN], g_wdl1[(size_t)F*HIDN];
__device__ bf16 g_QQh0[(size_t)NPIX*2*F], g_QQl0[(size_t)NPIX*2*F];
__device__ bf16 g_QQh1[(size_t)NPIX*2*F], g_QQl1[(size_t)NPIX*2*F];
__device__ bf16 g_Xh0[(size_t)NPIX*F],  g_Xl0[(size_t)NPIX*F];
__device__ bf16 g_Xh1[(size_t)NPIX*F],  g_Xl1[(size_t)NPIX*F];
__device__ bf16 g_Uh0[(size_t)NPIX*HIDN], g_Ul0[(size_t)NPIX*HIDN];
__device__ bf16 g_Uh1[(size_t)NPIX*HIDN], g_Ul1[(size_t)NPIX*HIDN];

// ================= helpers =================
__device__ __forceinline__ uint32_t smem_u32(const void* p) {
    uint32_t a;
    asm("{ .reg .u64 t; cvta.to.shared.u64 t, %1; cvt.u32.u64 %0, t; }" : "=r"(a) : "l"(p));
    return a;
}
__device__ __forceinline__ void cpasync16(uint32_t dst, const void* src) {
    asm volatile("cp.async.cg.shared.global [%0], [%1], 16;" :: "r"(dst), "l"(src) : "memory");
}
__device__ __forceinline__ void ldsm4(uint32_t (&r)[4], uint32_t addr) {
    asm volatile("ldmatrix.sync.aligned.m8n8.x4.shared.b16 {%0,%1,%2,%3}, [%4];"
                 : "=r"(r[0]), "=r"(r[1]), "=r"(r[2]), "=r"(r[3]) : "r"(addr));
}
__device__ __forceinline__ void mma16816(float* d, const uint32_t* a, const uint32_t* b) {
    asm volatile("mma.sync.aligned.m16n8k16.row.col.f32.bf16.bf16.f32 "
                 "{%0,%1,%2,%3}, {%4,%5,%6,%7}, {%8,%9}, {%0,%1,%2,%3};"
                 : "+f"(d[0]), "+f"(d[1]), "+f"(d[2]), "+f"(d[3])
                 : "r"(a[0]), "r"(a[1]), "r"(a[2]), "r"(a[3]), "r"(b[0]), "r"(b[1]));
}
__device__ __forceinline__ void split2(float v, bf16& h, bf16& l) {
    h = __float2bfloat16(v);
    l = __float2bfloat16(v - __bfloat162float(h));
}

// ================= bf16-split tensor GEMM =================
// CTA tile 128(M) x 256(N), 8 warps of 64x64. K chunks of 32.
// C[m,n] = act( sum_k A[m,k]*W[n,k] + bias[n] (+bias2[n]) (+res[m,n]) )
// Stage layout: [Ahi 8K][Alo 8K][Bhi 16K][Blo 16K] = 48KB.
#define STAGES     4
#define SMEM_STAGE 49152
#define OFF_ALO    8192u
#define OFF_BHI    16384u
#define OFF_BLO    32768u
#define GEMM_SMEM  (STAGES*SMEM_STAGE)

struct GemmPair {
    const bf16 *Ah[2], *Al[2];
    const bf16 *Bh0[2], *Bl0[2], *Bh1[2], *Bl1[2];
    const float *bias[2], *bias2[2], *res[2];
    float *C[2];
    bf16 *Ch[2], *Cl[2];
};

__global__ __launch_bounds__(256, 1) void gemm_bf16(
    GemmPair gp, int lda, int ldb, int Ksplit,
    int ldres, int ldc, int K, int relu)
{
    extern __shared__ char smem[];
    const uint32_t sb0 = smem_u32(smem);

    const int z = blockIdx.z;
    const bf16* __restrict__ Ah  = gp.Ah[z];
    const bf16* __restrict__ Al  = gp.Al[z];
    const bf16* __restrict__ Bh0 = gp.Bh0[z];
    const bf16* __restrict__ Bl0 = gp.Bl0[z];
    const bf16* __restrict__ Bh1 = gp.Bh1[z];
    const bf16* __restrict__ Bl1 = gp.Bl1[z];
    const float* __restrict__ bias  = gp.bias[z];
    const float* __restrict__ bias2 = gp.bias2[z];
    const float* __restrict__ res   = gp.res[z];
    float* __restrict__ C  = gp.C[z];
    bf16*  __restrict__ Ch = gp.Ch[z];
    bf16*  __restrict__ Cl = gp.Cl[z];

    const int tid  = threadIdx.x;
    const int wid  = tid >> 5;
    const int lane = tid & 31;
    const int brow = blockIdx.y * 128;
    const int bcol = blockIdx.x * 256;
    const int wm   = (wid >> 2) * 64;   // 0 or 64
    const int wn   = (wid & 3) * 64;    // 0,64,128,192

    float acc[4][8][4];
#pragma unroll
    for (int i = 0; i < 4; i++)
#pragma unroll
        for (int j = 0; j < 8; j++)
#pragma unroll
            for (int r = 0; r < 4; r++) acc[i][j][r] = 0.f;

    // ------- async tile loader: 12 quads (16B) per thread -------
    auto load_stage = [&](int cIdx) {
        const uint32_t sb = sb0 + (uint32_t)(cIdx % STAGES) * SMEM_STAGE;
        const int k0 = cIdx * 32;
        const bf16 *bh, *bl;
        int kk;
        if (k0 < Ksplit) { bh = Bh0; bl = Bl0; kk = k0; }
        else             { bh = Bh1; bl = Bl1; kk = k0 - Ksplit; }
#pragma unroll
        for (int s = 0; s < 12; s++) {
            const int qid = tid + s * 256;
            const bf16* src;
            uint32_t dstbase;
            int row, c;
            if (qid < 1024) {                 // A region (hi then lo)
                const int q = qid & 511;
                row = q >> 2; c = q & 3;
                src = (qid < 512 ? Ah : Al) + (size_t)(brow + row) * lda + k0 + c * 8;
                dstbase = sb + (qid < 512 ? 0u : OFF_ALO);
            } else {                          // B region (hi then lo)
                const int q2 = qid - 1024;
                const int q = q2 & 1023;
                row = q >> 2; c = q & 3;
                src = (q2 < 1024 ? bh : bl) + (size_t)(bcol + row) * ldb + kk + c * 8;
                dstbase = sb + (q2 < 1024 ? OFF_BHI : OFF_BLO);
            }
            cpasync16(dstbase + (uint32_t)row * 64u +
                      (uint32_t)((c ^ ((row >> 1) & 3)) * 16), src);
        }
        asm volatile("cp.async.commit_group;" ::: "memory");
    };

    const int tile = lane >> 3;          // 0..3
    const int rin  = lane & 7;           // 0..7
    const uint32_t rsw = (uint32_t)(rin >> 1);

    const int NC = K / 32;
    for (int s = 0; s < STAGES - 1 && s < NC; s++) load_stage(s);

    for (int c = 0; c < NC; c++) {
        if (c + 3 <= NC) {
            asm volatile("cp.async.wait_group 2;" ::: "memory");
        } else if (c + 2 == NC) {
            asm volatile("cp.async.wait_group 1;" ::: "memory");
        } else {
            asm volatile("cp.async.wait_group 0;" ::: "memory");
        }
        __syncthreads();
        if (c + 3 < NC) load_stage(c + 3);

        const uint32_t sb = sb0 + (uint32_t)(c % STAGES) * SMEM_STAGE;
#pragma unroll
        for (int ks = 0; ks < 2; ks++) {
            uint32_t ah[4][4], al_[4][4], bh_[4][4], bl_[4][4];
            const uint32_t swa = ((uint32_t)(ks * 2 + (tile >> 1)) ^ rsw) * 16u;
#pragma unroll
            for (int i = 0; i < 4; i++) {
                const uint32_t abase = sb +
                    (uint32_t)(wm + i * 16 + (tile & 1) * 8 + rin) * 64u + swa;
                ldsm4(ah[i],  abase);
                ldsm4(al_[i], abase + OFF_ALO);
            }
            const uint32_t swb = ((uint32_t)(ks * 2 + (tile & 1)) ^ rsw) * 16u;
#pragma unroll
            for (int jj = 0; jj < 4; jj++) {
                const uint32_t bbase = sb + OFF_BHI +
                    (uint32_t)(wn + jj * 16 + (tile >> 1) * 8 + rin) * 64u + swb;
                ldsm4(bh_[jj], bbase);
                ldsm4(bl_[jj], bbase + (OFF_BLO - OFF_BHI));
            }
#pragma unroll
            for (int i = 0; i < 4; i++)
#pragma unroll
                for (int j = 0; j < 8; j++) {
                    const uint32_t* ph = &bh_[j >> 1][(j & 1) * 2];
                    const uint32_t* pl = &bl_[j >> 1][(j & 1) * 2];
                    mma16816(acc[i][j], ah[i],  ph);
                    mma16816(acc[i][j], ah[i],  pl);
                    mma16816(acc[i][j], al_[i], ph);
                }
        }
    }

    // ------- epilogue -------
    const int tq = lane >> 2;
    const int tr = (lane & 3) * 2;
    float bj0[8], bj1[8];
#pragma unroll
    for (int j = 0; j < 8; j++) {
        const int n = bcol + wn + 8 * j + tr;
        float b0 = bias[n], b1 = bias[n + 1];
        if (bias2) { b0 += bias2[n]; b1 += bias2[n + 1]; }
        bj0[j] = b0; bj1[j] = b1;
    }
#pragma unroll
    for (int i = 0; i < 4; i++)
#pragma unroll
        for (int half = 0; half < 2; half++) {
            const int m = brow + wm + 16 * i + tq + half * 8;
#pragma unroll
            for (int j = 0; j < 8; j++) {
                const int n = bcol + wn + 8 * j + tr;
                float v0 = acc[i][j][half * 2 + 0] + bj0[j];
                float v1 = acc[i][j][half * 2 + 1] + bj1[j];
                if (res) {
                    float2 r = *(const float2*)(res + (size_t)m * ldres + n);
                    v0 += r.x; v1 += r.y;
                }
                if (relu) { v0 = fmaxf(v0, 0.f); v1 = fmaxf(v1, 0.f); }
                if (C) *(float2*)(C + (size_t)m * ldc + n) = make_float2(v0, v1);
                if (Ch) {
                    bf16 h0, l0, h1, l1;
                    split2(v0, h0, l0);
                    split2(v1, h1, l1);
                    *(__nv_bfloat162*)(Ch + (size_t)m * ldc + n) = __nv_bfloat162(h0, h1);
                    *(__nv_bfloat162*)(Cl + (size_t)m * ldc + n) = __nv_bfloat162(l0, l1);
                }
            }
        }
}

// ---------------- merged split-convert fp32 -> bf16 hi/lo (10 segments) ----------------
#define NSEG 10
struct ConvArgs {
    const float* s[NSEG];
    bf16* h[NSEG];
    bf16* l[NSEG];
    int end4[NSEG];
};

__global__ __launch_bounds__(256) void conv_all(ConvArgs a, int total4)
{
    int i = blockIdx.x * 256 + threadIdx.x;
    if (i >= total4) return;
    int seg = 0;
#pragma unroll
    for (int s = 0; s < NSEG - 1; s++) seg += (i >= a.end4[s]) ? 1 : 0;
    const int base = seg ? a.end4[seg - 1] : 0;
    const int j = i - base;

    float4 v = ((const float4*)a.s[seg])[j];
    bf16 h0, l0, h1, l1, h2, l2, h3, l3;
    split2(v.x, h0, l0); split2(v.y, h1, l1);
    split2(v.z, h2, l2); split2(v.w, h3, l3);
    ((__nv_bfloat162*)a.h[seg])[2 * j]     = __nv_bfloat162(h0, h1);
    ((__nv_bfloat162*)a.h[seg])[2 * j + 1] = __nv_bfloat162(h2, h3);
    ((__nv_bfloat162*)a.l[seg])[2 * j]     = __nv_bfloat162(l0, l1);
    ((__nv_bfloat162*)a.l[seg])[2 * j + 1] = __nv_bfloat162(l2, l3);
}

// ---------------- 9-tap windowed multi-head attention (4 fused via y) ----------------
struct AttArgs {
    const float* Q[4];
    const float* Kp[4];
    const float* Vp[4];
    bf16* Oh[4];
    bf16* Ol[4];
};

__global__ __launch_bounds__(256) void attend_kernel(AttArgs a, int ostride)
{
    const int z   = blockIdx.y;
    const int t   = threadIdx.x & 63;
    const int pix = blockIdx.x * 4 + (threadIdx.x >> 6);
    const int b   = pix / (HH * WW);
    const int r   = pix % (HH * WW);
    const int y   = r / WW;
    const int x   = r % WW;
    const int ch  = t * 4;

    const float* __restrict__ Q  = a.Q[z];
    const float* __restrict__ Kp = a.Kp[z];
    const float* __restrict__ Vp = a.Vp[z];

    const float scale = 0.17677669529663687f;
    float4 q = *(const float4*)(Q + (size_t)pix * PDIM + ch);
    q.x *= scale; q.y *= scale; q.z *= scale; q.w *= scale;

    float  sc[9];
    float4 vv[9];
#pragma unroll
    for (int n = 0; n < 9; n++) {
        int dy = n / 3 - 1, dx = n % 3 - 1;
        int yy = y + dy, xx = x + dx;
        float s = 0.f;
        float4 v = make_float4(0.f, 0.f, 0.f, 0.f);
        if (yy >= 0 && yy < HH && xx >= 0 && xx < WW) {
            size_t np = ((size_t)(b * HH + yy) * WW + xx) * PDIM + ch;
            float4 k4 = *(const float4*)(Kp + np);
            v = *(const float4*)(Vp + np);
            s = q.x * k4.x + q.y * k4.y + q.z * k4.z + q.w * k4.w;
        }
        s += __shfl_xor_sync(0xffffffffu, s, 4);
        s += __shfl_xor_sync(0xffffffffu, s, 2);
        s += __shfl_xor_sync(0xffffffffu, s, 1);
        sc[n] = s;
        vv[n] = v;
    }

    float mx = sc[0];
#pragma unroll
    for (int n = 1; n < 9; n++) mx = fmaxf(mx, sc[n]);
    float den = 0.f;
    float4 o = make_float4(0.f, 0.f, 0.f, 0.f);
#pragma unroll
    for (int n = 0; n < 9; n++) {
        float w = __expf(sc[n] - mx);
        den += w;
        o.x += w * vv[n].x; o.y += w * vv[n].y;
        o.z += w * vv[n].z; o.w += w * vv[n].w;
    }
    float inv = 1.f / den;
    bf16 h0, l0, h1, l1, h2, l2, h3, l3;
    split2(o.x * inv, h0, l0); split2(o.y * inv, h1, l1);
    split2(o.z * inv, h2, l2); split2(o.w * inv, h3, l3);
    size_t base = (size_t)pix * ostride + ch;
    *(__nv_bfloat162*)(a.Oh[z] + base)     = __nv_bfloat162(h0, h1);
    *(__nv_bfloat162*)(a.Oh[z] + base + 2) = __nv_bfloat162(h2, h3);
    *(__nv_bfloat162*)(a.Ol[z] + base)     = __nv_bfloat162(l0, l1);
    *(__nv_bfloat162*)(a.Ol[z] + base + 2) = __nv_bfloat162(l2, l3);
}

// ---------------- LayerNorm over last dim (256), pair fused via y ----------------
struct LnArgs {
    const float* X[2];
    const float* g[2];
    const float* bt[2];
    float* O[2];
    bf16* Oh[2];
    bf16* Ol[2];
};

__global__ __launch_bounds__(256) void ln_kernel(LnArgs a)
{
    const int z   = blockIdx.y;
    const int row = blockIdx.x;
    const int t   = threadIdx.x;
    const int warp = t >> 5, lane = t & 31;
    __shared__ float red[8];

    float v = a.X[z][(size_t)row * F + t];

    float s = v;
#pragma unroll
    for (int o = 16; o > 0; o >>= 1) s += __shfl_xor_sync(0xffffffffu, s, o);
    if (lane == 0) red[warp] = s;
    __syncthreads();
    float tot = 0.f;
#pragma unroll
    for (int i = 0; i < 8; i++) tot += red[i];
    float mean = tot * (1.0f / F);
    float xc = v - mean;
    __syncthreads();

    float s2 = xc * xc;
#pragma unroll
    for (int o = 16; o > 0; o >>= 1) s2 += __shfl_xor_sync(0xffffffffu, s2, o);
    if (lane == 0) red[warp] = s2;
    __syncthreads();
    float tot2 = 0.f;
#pragma unroll
    for (int i = 0; i < 8; i++) tot2 += red[i];
    float var = tot2 * (1.0f / F);

    float out = a.g[z][t] * xc * rsqrtf(var + 1e-5f) + a.bt[z][t];
    if (a.O[z]) a.O[z][(size_t)row * F + t] = out;
    if (a.Oh[z]) {
        bf16 h, l;
        split2(out, h, l);
        a.Oh[z][(size_t)row * F + t] = h;
        a.Ol[z][(size_t)row * F + t] = l;
    }
}

// ---------------- launch ----------------
#define SYM(p, s) cudaGetSymbolAddress((void**)&p, s)

extern "C" void kernel_launch(void* const* d_in, const int* in_sizes, int n_in,
                              void* d_out, int out_size)
{
    const float* feat0       = (const float*)d_in[0];
    const float* feat1       = (const float*)d_in[1];
    const float* in_w0       = (const float*)d_in[2];
    const float* in_b0       = (const float*)d_in[3];
    const float* in_w1       = (const float*)d_in[4];
    const float* in_b1       = (const float*)d_in[5];
    const float* out_w0      = (const float*)d_in[6];
    const float* out_b0      = (const float*)d_in[7];
    const float* out_w1      = (const float*)d_in[8];
    const float* out_b1      = (const float*)d_in[9];
    const float* ln1_g0      = (const float*)d_in[10];
    const float* ln1_b0      = (const float*)d_in[11];
    const float* ln1_g1      = (const float*)d_in[12];
    const float* ln1_b1      = (const float*)d_in[13];
    const float* ffn_up_w0   = (const float*)d_in[14];
    const float* ffn_up_b0   = (const float*)d_in[15];
    const float* ffn_down_w0 = (const float*)d_in[16];
    const float* ffn_down_b0 = (const float*)d_in[17];
    const float* ffn_up_w1   = (const float*)d_in[18];
    const float* ffn_up_b1   = (const float*)d_in[19];
    const float* ffn_down_w1 = (const float*)d_in[20];
    const float* ffn_down_b1 = (const float*)d_in[21];
    const float* ln2_g0      = (const float*)d_in[22];
    const float* ln2_b0      = (const float*)d_in[23];
    const float* ln2_g1      = (const float*)d_in[24];
    const float* ln2_b1      = (const float*)d_in[25];

    float *P0, *P1, *T0, *T1, *X0, *X1;
    SYM(P0, g_P0); SYM(P1, g_P1); SYM(T0, g_T0); SYM(T1, g_T1); SYM(X0, g_X0); SYM(X1, g_X1);
    bf16 *fh0, *fl0, *fh1, *fl1, *wih0, *wil0, *wih1, *wil1;
    bf16 *woh0, *wol0, *woh1, *wol1, *wuh0, *wul0, *wuh1, *wul1, *wdh0, *wdl0, *wdh1, *wdl1;
    bf16 *QQh0, *QQl0, *QQh1, *QQl1, *Xh0, *Xl0, *Xh1, *Xl1, *Uh0, *Ul0, *Uh1, *Ul1;
    SYM(fh0, g_fh0); SYM(fl0, g_fl0); SYM(fh1, g_fh1); SYM(fl1, g_fl1);
    SYM(wih0, g_wih0); SYM(wil0, g_wil0); SYM(wih1, g_wih1); SYM(wil1, g_wil1);
    SYM(woh0, g_woh0); SYM(wol0, g_wol0); SYM(woh1, g_woh1); SYM(wol1, g_wol1);
    SYM(wuh0, g_wuh0); SYM(wul0, g_wul0); SYM(wuh1, g_wuh1); SYM(wul1, g_wul1);
    SYM(wdh0, g_wdh0); SYM(wdl0, g_wdl0); SYM(wdh1, g_wdh1); SYM(wdl1, g_wdl1);
    SYM(QQh0, g_QQh0); SYM(QQl0, g_QQl0); SYM(QQh1, g_QQh1); SYM(QQl1, g_QQl1);
    SYM(Xh0, g_Xh0); SYM(Xl0, g_Xl0); SYM(Xh1, g_Xh1); SYM(Xl1, g_Xl1);
    SYM(Uh0, g_Uh0); SYM(Ul0, g_Ul0); SYM(Uh1, g_Uh1); SYM(Ul1, g_Ul1);

    cudaFuncSetAttribute(gemm_bf16, cudaFuncAttributeMaxDynamicSharedMemorySize, GEMM_SMEM);

    float* out = (float*)d_out;
    dim3 blk(256);
    const int MT = NPIX / 128;   // 100

    // ---- launch 0: all converts in one kernel ----
    {
        ConvArgs ca;
        const float* srcs[NSEG] = {feat0, feat1, in_w0, in_w1, out_w0, out_w1,
                                   ffn_up_w0, ffn_up_w1, ffn_down_w0, ffn_down_w1};
        bf16* hs[NSEG] = {fh0, fh1, wih0, wih1, woh0, woh1, wuh0, wuh1, wdh0, wdh1};
        bf16* ls[NSEG] = {fl0, fl1, wil0, wil1, wol0, wol1, wul0, wul1, wdl0, wdl1};
        int sizes4[NSEG] = {NPIX*F/4, NPIX*F/4, PDIM*F/4, PDIM*F/4, F*3*F/4, F*3*F/4,
                            HIDN*F/4, HIDN*F/4, F*HIDN/4, F*HIDN/4};
        int acc4 = 0;
        for (int i = 0; i < NSEG; i++) {
            ca.s[i] = srcs[i]; ca.h[i] = hs[i]; ca.l[i] = ls[i];
            acc4 += sizes4[i];
            ca.end4[i] = acc4;
        }
        conv_all<<<(acc4 + 255) / 256, blk>>>(ca, acc4);
    }

    // ---- launch 1: in-projection GEMMs (both maps via z) ----
    {
        GemmPair gp = {};
        gp.Ah[0]=fh0;  gp.Al[0]=fl0;  gp.Ah[1]=fh1;  gp.Al[1]=fl1;
        gp.Bh0[0]=wih0; gp.Bl0[0]=wil0; gp.Bh1[0]=wih0; gp.Bl1[0]=wil0;
        gp.Bh0[1]=wih1; gp.Bl0[1]=wil1; gp.Bh1[1]=wih1; gp.Bl1[1]=wil1;
        gp.bias[0]=in_b0; gp.bias[1]=in_b1;
        gp.C[0]=P0; gp.C[1]=P1;
        gemm_bf16<<<dim3(PDIM/256, MT, 2), blk, GEMM_SMEM>>>(gp, F, F, F, 0, PDIM, F, 0);
    }

    // ---- launch 2: 4 attentions fused via y ----
    {
        AttArgs aa;
        aa.Q[0]=P0;       aa.Kp[0]=P0+F;     aa.Vp[0]=P0+2*F;  aa.Oh[0]=QQh0;   aa.Ol[0]=QQl0;
        aa.Q[1]=P1;       aa.Kp[1]=P1+F;     aa.Vp[1]=P1+2*F;  aa.Oh[1]=QQh1;   aa.Ol[1]=QQl1;
        aa.Q[2]=P0+3*F;   aa.Kp[2]=P1+4*F;   aa.Vp[2]=P1+5*F;  aa.Oh[2]=QQh0+F; aa.Ol[2]=QQl0+F;
        aa.Q[3]=P1+3*F;   aa.Kp[3]=P0+4*F;   aa.Vp[3]=P0+5*F;  aa.Oh[3]=QQh1+F; aa.Ol[3]=QQl1+F;
        attend_kernel<<<dim3(NPIX/4, 4), blk>>>(aa, 2*F);
    }

    // ---- launch 3: fused out-projections (K=512, split at 256), residual = feat ----
    {
        GemmPair gp = {};
        gp.Ah[0]=QQh0; gp.Al[0]=QQl0; gp.Ah[1]=QQh1; gp.Al[1]=QQl1;
        gp.Bh0[0]=woh0; gp.Bl0[0]=wol0; gp.Bh1[0]=woh0+F; gp.Bl1[0]=wol0+F;
        gp.Bh0[1]=woh1; gp.Bl0[1]=wol1; gp.Bh1[1]=woh0+F; gp.Bl1[1]=wol0+F;
        gp.bias[0]=out_b0; gp.bias2[0]=out_b0+F; gp.res[0]=feat0; gp.C[0]=T0;
        gp.bias[1]=out_b1; gp.bias2[1]=out_b0+F; gp.res[1]=feat1; gp.C[1]=T1;
        gemm_bf16<<<dim3(F/256, MT, 2), blk, GEMM_SMEM>>>(gp, 2*F, 3*F, F, F, F, 2*F, 0);
    }

    // ---- launch 4: LN1 pair ----
    {
        LnArgs la;
        la.X[0]=T0; la.g[0]=ln1_g0; la.bt[0]=ln1_b0; la.O[0]=X0; la.Oh[0]=Xh0; la.Ol[0]=Xl0;
        la.X[1]=T1; la.g[1]=ln1_g1; la.bt[1]=ln1_b1; la.O[1]=X1; la.Oh[1]=Xh1; la.Ol[1]=Xl1;
        ln_kernel<<<dim3(NPIX, 2), blk>>>(la);
    }

    // ---- launch 5: FFN up pair (relu, bf16-split out only) ----
    {
        GemmPair gp = {};
        gp.Ah[0]=Xh0; gp.Al[0]=Xl0; gp.Ah[1]=Xh1; gp.Al[1]=Xl1;
        gp.Bh0[0]=wuh0; gp.Bl0[0]=wul0; gp.Bh1[0]=wuh0; gp.Bl1[0]=wul0;
        gp.Bh0[1]=wuh1; gp.Bl0[1]=wul1; gp.Bh1[1]=wuh1; gp.Bl1[1]=wul1;
        gp.bias[0]=ffn_up_b0; gp.bias[1]=ffn_up_b1;
        gp.Ch[0]=Uh0; gp.Cl[0]=Ul0; gp.Ch[1]=Uh1; gp.Cl[1]=Ul1;
        gemm_bf16<<<dim3(HIDN/256, MT, 2), blk, GEMM_SMEM>>>(gp, F, F, F, 0, HIDN, F, 1);
    }

    // ---- launch 6: FFN down pair (residual X, fp32 out) ----
    {
        GemmPair gp = {};
        gp.Ah[0]=Uh0; gp.Al[0]=Ul0; gp.Ah[1]=Uh1; gp.Al[1]=Ul1;
        gp.Bh0[0]=wdh0; gp.Bl0[0]=wdl0; gp.Bh1[0]=wdh0; gp.Bl1[0]=wdl0;
        gp.Bh0[1]=wdh1; gp.Bl0[1]=wdl1; gp.Bh1[1]=wdh1; gp.Bl1[1]=wdl1;
        gp.bias[0]=ffn_down_b0; gp.bias[1]=ffn_down_b1;
        gp.res[0]=X0; gp.res[1]=X1;
        gp.C[0]=T0; gp.C[1]=T1;
        gemm_bf16<<<dim3(F/256, MT, 2), blk, GEMM_SMEM>>>(gp, HIDN, HIDN, HIDN, F, F, HIDN, 0);
    }

    // ---- launch 7: LN2 pair -> output ----
    {
        LnArgs la;
        la.X[0]=T0; la.g[0]=ln2_g0; la.bt[0]=ln2_b0; la.O[0]=out;
        la.Oh[0]=nullptr; la.Ol[0]=nullptr;
        la.X[1]=T1; la.g[1]=ln2_g1; la.bt[1]=ln2_b1; la.O[1]=out + (size_t)NPIX*F;
        la.Oh[1]=nullptr; la.Ol[1]=nullptr;
        ln_kernel<<<dim3(NPIX, 2), blk>>>(la);
    }
}

// round 8
// speedup vs baseline: 3.0766x; 1.4690x over previous
#include <cuda_runtime.h>
#include <cuda_fp16.h>
#include <cstdint>
#include <cstddef>

#define F      256
#define NH     8
#define BATCH  2
#define HH     80
#define WW     80
#define NPIX   (BATCH*HH*WW)   // 12800
#define PDIM   1536
#define HIDN   1024

typedef __half h16;

// ---------------- scratch (no allocations allowed) ----------------
__device__ float g_P0[(size_t)NPIX*PDIM];
__device__ float g_P1[(size_t)NPIX*PDIM];
__device__ float g_T0[(size_t)NPIX*F];
__device__ float g_T1[(size_t)NPIX*F];
__device__ float g_X0[(size_t)NPIX*F];
__device__ float g_X1[(size_t)NPIX*F];

__device__ h16 g_f0[(size_t)NPIX*F];
__device__ h16 g_f1[(size_t)NPIX*F];
__device__ h16 g_wih0[(size_t)PDIM*F], g_wil0[(size_t)PDIM*F];
__device__ h16 g_wih1[(size_t)PDIM*F], g_wil1[(size_t)PDIM*F];
__device__ h16 g_woh0[(size_t)F*3*F],  g_wol0[(size_t)F*3*F];
__device__ h16 g_woh1[(size_t)F*3*F],  g_wol1[(size_t)F*3*F];
__device__ h16 g_wuh0[(size_t)HIDN*F], g_wul0[(size_t)HIDN*F];
__device__ h16 g_wuh1[(size_t)HIDN*F], g_wul1[(size_t)HIDN*F];
__device__ h16 g_wdh0[(size_t)F*HIDN], g_wdl0[(size_t)F*HIDN];
__device__ h16 g_wdh1[(size_t)F*HIDN], g_wdl1[(size_t)F*HIDN];
__device__ h16 g_QQ0[(size_t)NPIX*2*F];
__device__ h16 g_QQ1[(size_t)NPIX*2*F];
__device__ h16 g_Xq0[(size_t)NPIX*F];
__device__ h16 g_Xq1[(size_t)NPIX*F];
__device__ h16 g_U0[(size_t)NPIX*HIDN];
__device__ h16 g_U1[(size_t)NPIX*HIDN];

// ================= helpers =================
__device__ __forceinline__ uint32_t smem_u32(const void* p) {
    uint32_t a;
    asm("{ .reg .u64 t; cvta.to.shared.u64 t, %1; cvt.u32.u64 %0, t; }" : "=r"(a) : "l"(p));
    return a;
}
__device__ __forceinline__ void cpasync16(uint32_t dst, const void* src) {
    asm volatile("cp.async.cg.shared.global [%0], [%1], 16;" :: "r"(dst), "l"(src) : "memory");
}
__device__ __forceinline__ void ldsm4(uint32_t (&r)[4], uint32_t addr) {
    asm volatile("ldmatrix.sync.aligned.m8n8.x4.shared.b16 {%0,%1,%2,%3}, [%4];"
                 : "=r"(r[0]), "=r"(r[1]), "=r"(r[2]), "=r"(r[3]) : "r"(addr));
}
__device__ __forceinline__ void mma16816(float* d, const uint32_t* a, const uint32_t* b) {
    asm volatile("mma.sync.aligned.m16n8k16.row.col.f32.f16.f16.f32 "
                 "{%0,%1,%2,%3}, {%4,%5,%6,%7}, {%8,%9}, {%0,%1,%2,%3};"
                 : "+f"(d[0]), "+f"(d[1]), "+f"(d[2]), "+f"(d[3])
                 : "r"(a[0]), "r"(a[1]), "r"(a[2]), "r"(a[3]), "r"(b[0]), "r"(b[1]));
}
__device__ __forceinline__ void hsplit(float v, h16& h, h16& l) {
    h = __float2half_rn(v);
    l = __float2half_rn(v - __half2float(h));
}

// ================= fp16 2-term tensor GEMM (paired over z) =================
// C[m,n] = act( sum_k A[m,k]*W[n,k] + bias[n] (+bias2[n]) (+res[m,n]) )
// A: single fp16. W: hi/lo fp16 split (exact to 2^-22), split at Ksplit between
// (Bh0,Bl0) and (Bh1,Bl1). Tile 128x128, warps 64x32, K chunks of 32.
// Stage: [A 8K][Bh 8K][Bl 8K] = 24KB; 4 stages = 96KB; 2 CTAs/SM.
#define STAGES     4
#define SMEM_STAGE 24576
#define OFF_BH     8192u
#define OFF_BL     16384u
#define GEMM_SMEM  (STAGES*SMEM_STAGE)

struct GemmPair {
    const h16 *A[2];
    const h16 *Bh0[2], *Bl0[2], *Bh1[2], *Bl1[2];
    const float *bias[2], *bias2[2], *res[2];
    float *C[2];
    h16 *Ch[2];
};

__global__ __launch_bounds__(256, 2) void gemm_h16(
    GemmPair gp, int lda, int ldb, int Ksplit,
    int ldres, int ldc, int K, int relu)
{
    extern __shared__ char smem[];
    const uint32_t sb0 = smem_u32(smem);

    const int z = blockIdx.z;
    const h16* __restrict__ A   = gp.A[z];
    const h16* __restrict__ Bh0 = gp.Bh0[z];
    const h16* __restrict__ Bl0 = gp.Bl0[z];
    const h16* __restrict__ Bh1 = gp.Bh1[z];
    const h16* __restrict__ Bl1 = gp.Bl1[z];
    const float* __restrict__ bias  = gp.bias[z];
    const float* __restrict__ bias2 = gp.bias2[z];
    const float* __restrict__ res   = gp.res[z];
    float* __restrict__ C  = gp.C[z];
    h16*   __restrict__ Ch = gp.Ch[z];

    const int tid  = threadIdx.x;
    const int wid  = tid >> 5;
    const int lane = tid & 31;
    const int brow = blockIdx.y * 128;
    const int bcol = blockIdx.x * 128;
    const int wm   = (wid >> 2) * 64;   // 0 or 64
    const int wn   = (wid & 3) * 32;    // 0..96

    float acc[4][4][4];
#pragma unroll
    for (int i = 0; i < 4; i++)
#pragma unroll
        for (int j = 0; j < 4; j++)
#pragma unroll
            for (int r = 0; r < 4; r++) acc[i][j][r] = 0.f;

    // loader: 1536 quads(16B)/stage, 6 per thread
    auto load_stage = [&](int cIdx) {
        const uint32_t sb = sb0 + (uint32_t)(cIdx % STAGES) * SMEM_STAGE;
        const int k0 = cIdx * 32;
        const h16 *bh, *bl;
        int kk;
        if (k0 < Ksplit) { bh = Bh0; bl = Bl0; kk = k0; }
        else             { bh = Bh1; bl = Bl1; kk = k0 - Ksplit; }
#pragma unroll
        for (int s = 0; s < 6; s++) {
            const int qid = tid + s * 256;
            const int q   = qid & 511;
            const int row = q >> 2;
            const int c   = q & 3;
            const h16* src;
            uint32_t dstbase;
            if (qid < 512) {
                src = A + (size_t)(brow + row) * lda + k0 + c * 8;
                dstbase = sb;
            } else if (qid < 1024) {
                src = bh + (size_t)(bcol + row) * ldb + kk + c * 8;
                dstbase = sb + OFF_BH;
            } else {
                src = bl + (size_t)(bcol + row) * ldb + kk + c * 8;
                dstbase = sb + OFF_BL;
            }
            cpasync16(dstbase + (uint32_t)row * 64u +
                      (uint32_t)((c ^ ((row >> 1) & 3)) * 16), src);
        }
        asm volatile("cp.async.commit_group;" ::: "memory");
    };

    const int tile = lane >> 3;
    const int rin  = lane & 7;
    const uint32_t rsw = (uint32_t)(rin >> 1);

    const int NC = K / 32;
    for (int s = 0; s < STAGES - 1 && s < NC; s++) load_stage(s);

    for (int c = 0; c < NC; c++) {
        if (c + 3 <= NC) {
            asm volatile("cp.async.wait_group 2;" ::: "memory");
        } else if (c + 2 == NC) {
            asm volatile("cp.async.wait_group 1;" ::: "memory");
        } else {
            asm volatile("cp.async.wait_group 0;" ::: "memory");
        }
        __syncthreads();
        if (c + 3 < NC) load_stage(c + 3);

        const uint32_t sb = sb0 + (uint32_t)(c % STAGES) * SMEM_STAGE;
#pragma unroll
        for (int ks = 0; ks < 2; ks++) {
            uint32_t ah[4][4], bh_[2][4], bl_[2][4];
            const uint32_t swa = ((uint32_t)(ks * 2 + (tile >> 1)) ^ rsw) * 16u;
#pragma unroll
            for (int i = 0; i < 4; i++)
                ldsm4(ah[i], sb + (uint32_t)(wm + i * 16 + (tile & 1) * 8 + rin) * 64u + swa);
            const uint32_t swb = ((uint32_t)(ks * 2 + (tile & 1)) ^ rsw) * 16u;
#pragma unroll
            for (int jj = 0; jj < 2; jj++) {
                const uint32_t bbase = sb + OFF_BH +
                    (uint32_t)(wn + jj * 16 + (tile >> 1) * 8 + rin) * 64u + swb;
                ldsm4(bh_[jj], bbase);
                ldsm4(bl_[jj], bbase + (OFF_BL - OFF_BH));
            }
#pragma unroll
            for (int i = 0; i < 4; i++)
#pragma unroll
                for (int j = 0; j < 4; j++)
                    mma16816(acc[i][j], ah[i], &bh_[j >> 1][(j & 1) * 2]);
#pragma unroll
            for (int i = 0; i < 4; i++)
#pragma unroll
                for (int j = 0; j < 4; j++)
                    mma16816(acc[i][j], ah[i], &bl_[j >> 1][(j & 1) * 2]);
        }
    }

    // ------- epilogue -------
    const int tq = lane >> 2;
    const int tr = (lane & 3) * 2;
    float bj0[4], bj1[4];
#pragma unroll
    for (int j = 0; j < 4; j++) {
        const int n = bcol + wn + 8 * j + tr;
        float b0 = bias[n], b1 = bias[n + 1];
        if (bias2) { b0 += bias2[n]; b1 += bias2[n + 1]; }
        bj0[j] = b0; bj1[j] = b1;
    }
#pragma unroll
    for (int i = 0; i < 4; i++)
#pragma unroll
        for (int half = 0; half < 2; half++) {
            const int m = brow + wm + 16 * i + tq + half * 8;
#pragma unroll
            for (int j = 0; j < 4; j++) {
                const int n = bcol + wn + 8 * j + tr;
                float v0 = acc[i][j][half * 2 + 0] + bj0[j];
                float v1 = acc[i][j][half * 2 + 1] + bj1[j];
                if (res) {
                    float2 r = *(const float2*)(res + (size_t)m * ldres + n);
                    v0 += r.x; v1 += r.y;
                }
                if (relu) { v0 = fmaxf(v0, 0.f); v1 = fmaxf(v1, 0.f); }
                if (C) *(float2*)(C + (size_t)m * ldc + n) = make_float2(v0, v1);
                if (Ch)
                    *(__half2*)(Ch + (size_t)m * ldc + n) =
                        __halves2half2(__float2half_rn(v0), __float2half_rn(v1));
            }
        }
}

// ---------------- merged convert fp32 -> fp16 (single or hi/lo split) ----------------
#define NSEG 10
struct ConvArgs {
    const float* s[NSEG];
    h16* h[NSEG];
    h16* l[NSEG];       // null -> single-precision-quantize only
    int end4[NSEG];
};

__global__ __launch_bounds__(256) void conv_all(ConvArgs a, int total4)
{
    int i = blockIdx.x * 256 + threadIdx.x;
    if (i >= total4) return;
    int seg = 0;
#pragma unroll
    for (int s = 0; s < NSEG - 1; s++) seg += (i >= a.end4[s]) ? 1 : 0;
    const int base = seg ? a.end4[seg - 1] : 0;
    const int j = i - base;

    float4 v = ((const float4*)a.s[seg])[j];
    h16* hp = a.h[seg];
    h16* lp = a.l[seg];
    if (lp) {
        h16 h0, l0, h1, l1, h2, l2, h3, l3;
        hsplit(v.x, h0, l0); hsplit(v.y, h1, l1);
        hsplit(v.z, h2, l2); hsplit(v.w, h3, l3);
        ((__half2*)hp)[2 * j]     = __halves2half2(h0, h1);
        ((__half2*)hp)[2 * j + 1] = __halves2half2(h2, h3);
        ((__half2*)lp)[2 * j]     = __halves2half2(l0, l1);
        ((__half2*)lp)[2 * j + 1] = __halves2half2(l2, l3);
    } else {
        ((__half2*)hp)[2 * j]     = __halves2half2(__float2half_rn(v.x), __float2half_rn(v.y));
        ((__half2*)hp)[2 * j + 1] = __halves2half2(__float2half_rn(v.z), __float2half_rn(v.w));
    }
}

// ---------------- 9-tap windowed multi-head attention (4 fused via y) ----------------
struct AttArgs {
    const float* Q[4];
    const float* Kp[4];
    const float* Vp[4];
    h16* O[4];
};

__global__ __launch_bounds__(256) void attend_kernel(AttArgs a, int ostride)
{
    const int z   = blockIdx.y;
    const int t   = threadIdx.x & 63;
    const int pix = blockIdx.x * 4 + (threadIdx.x >> 6);
    const int b   = pix / (HH * WW);
    const int r   = pix % (HH * WW);
    const int y   = r / WW;
    const int x   = r % WW;
    const int ch  = t * 4;

    const float* __restrict__ Q  = a.Q[z];
    const float* __restrict__ Kp = a.Kp[z];
    const float* __restrict__ Vp = a.Vp[z];

    const float scale = 0.17677669529663687f;
    float4 q = *(const float4*)(Q + (size_t)pix * PDIM + ch);
    q.x *= scale; q.y *= scale; q.z *= scale; q.w *= scale;

    float  sc[9];
    float4 vv[9];
#pragma unroll
    for (int n = 0; n < 9; n++) {
        int dy = n / 3 - 1, dx = n % 3 - 1;
        int yy = y + dy, xx = x + dx;
        float s = 0.f;
        float4 v = make_float4(0.f, 0.f, 0.f, 0.f);
        if (yy >= 0 && yy < HH && xx >= 0 && xx < WW) {
            size_t np = ((size_t)(b * HH + yy) * WW + xx) * PDIM + ch;
            float4 k4 = *(const float4*)(Kp + np);
            v = *(const float4*)(Vp + np);
            s = q.x * k4.x + q.y * k4.y + q.z * k4.z + q.w * k4.w;
        }
        s += __shfl_xor_sync(0xffffffffu, s, 4);
        s += __shfl_xor_sync(0xffffffffu, s, 2);
        s += __shfl_xor_sync(0xffffffffu, s, 1);
        sc[n] = s;
        vv[n] = v;
    }

    float mx = sc[0];
#pragma unroll
    for (int n = 1; n < 9; n++) mx = fmaxf(mx, sc[n]);
    float den = 0.f;
    float4 o = make_float4(0.f, 0.f, 0.f, 0.f);
#pragma unroll
    for (int n = 0; n < 9; n++) {
        float w = __expf(sc[n] - mx);
        den += w;
        o.x += w * vv[n].x; o.y += w * vv[n].y;
        o.z += w * vv[n].z; o.w += w * vv[n].w;
    }
    float inv = 1.f / den;
    size_t base = (size_t)pix * ostride + ch;
    *(__half2*)(a.O[z] + base) =
        __halves2half2(__float2half_rn(o.x * inv), __float2half_rn(o.y * inv));
    *(__half2*)(a.O[z] + base + 2) =
        __halves2half2(__float2half_rn(o.z * inv), __float2half_rn(o.w * inv));
}

// ---------------- LayerNorm over last dim (256), pair fused via y ----------------
struct LnArgs {
    const float* X[2];
    const float* g[2];
    const float* bt[2];
    float* O[2];
    h16* Oh[2];
};

__global__ __launch_bounds__(256) void ln_kernel(LnArgs a)
{
    const int z   = blockIdx.y;
    const int row = blockIdx.x;
    const int t   = threadIdx.x;
    const int warp = t >> 5, lane = t & 31;
    __shared__ float red[8];

    float v = a.X[z][(size_t)row * F + t];

    float s = v;
#pragma unroll
    for (int o = 16; o > 0; o >>= 1) s += __shfl_xor_sync(0xffffffffu, s, o);
    if (lane == 0) red[warp] = s;
    __syncthreads();
    float tot = 0.f;
#pragma unroll
    for (int i = 0; i < 8; i++) tot += red[i];
    float mean = tot * (1.0f / F);
    float xc = v - mean;
    __syncthreads();

    float s2 = xc * xc;
#pragma unroll
    for (int o = 16; o > 0; o >>= 1) s2 += __shfl_xor_sync(0xffffffffu, s2, o);
    if (lane == 0) red[warp] = s2;
    __syncthreads();
    float tot2 = 0.f;
#pragma unroll
    for (int i = 0; i < 8; i++) tot2 += red[i];
    float var = tot2 * (1.0f / F);

    float out = a.g[z][t] * xc * rsqrtf(var + 1e-5f) + a.bt[z][t];
    if (a.O[z])  a.O[z][(size_t)row * F + t] = out;
    if (a.Oh[z]) a.Oh[z][(size_t)row * F + t] = __float2half_rn(out);
}

// ---------------- launch ----------------
#define SYM(p, s) cudaGetSymbolAddress((void**)&p, s)

extern "C" void kernel_launch(void* const* d_in, const int* in_sizes, int n_in,
                              void* d_out, int out_size)
{
    const float* feat0       = (const float*)d_in[0];
    const float* feat1       = (const float*)d_in[1];
    const float* in_w0       = (const float*)d_in[2];
    const float* in_b0       = (const float*)d_in[3];
    const float* in_w1       = (const float*)d_in[4];
    const float* in_b1       = (const float*)d_in[5];
    const float* out_w0      = (const float*)d_in[6];
    const float* out_b0      = (const float*)d_in[7];
    const float* out_w1      = (const float*)d_in[8];
    const float* out_b1      = (const float*)d_in[9];
    const float* ln1_g0      = (const float*)d_in[10];
    const float* ln1_b0      = (const float*)d_in[11];
    const float* ln1_g1      = (const float*)d_in[12];
    const float* ln1_b1      = (const float*)d_in[13];
    const float* ffn_up_w0   = (const float*)d_in[14];
    const float* ffn_up_b0   = (const float*)d_in[15];
    const float* ffn_down_w0 = (const float*)d_in[16];
    const float* ffn_down_b0 = (const float*)d_in[17];
    const float* ffn_up_w1   = (const float*)d_in[18];
    const float* ffn_up_b1   = (const float*)d_in[19];
    const float* ffn_down_w1 = (const float*)d_in[20];
    const float* ffn_down_b1 = (const float*)d_in[21];
    const float* ln2_g0      = (const float*)d_in[22];
    const float* ln2_b0      = (const float*)d_in[23];
    const float* ln2_g1      = (const float*)d_in[24];
    const float* ln2_b1      = (const float*)d_in[25];

    float *P0, *P1, *T0, *T1, *X0, *X1;
    SYM(P0, g_P0); SYM(P1, g_P1); SYM(T0, g_T0); SYM(T1, g_T1); SYM(X0, g_X0); SYM(X1, g_X1);
    h16 *f0, *f1, *wih0, *wil0, *wih1, *wil1;
    h16 *woh0, *wol0, *woh1, *wol1, *wuh0, *wul0, *wuh1, *wul1, *wdh0, *wdl0, *wdh1, *wdl1;
    h16 *QQ0, *QQ1, *Xq0, *Xq1, *U0, *U1;
    SYM(f0, g_f0); SYM(f1, g_f1);
    SYM(wih0, g_wih0); SYM(wil0, g_wil0); SYM(wih1, g_wih1); SYM(wil1, g_wil1);
    SYM(woh0, g_woh0); SYM(wol0, g_wol0); SYM(woh1, g_woh1); SYM(wol1, g_wol1);
    SYM(wuh0, g_wuh0); SYM(wul0, g_wul0); SYM(wuh1, g_wuh1); SYM(wul1, g_wul1);
    SYM(wdh0, g_wdh0); SYM(wdl0, g_wdl0); SYM(wdh1, g_wdh1); SYM(wdl1, g_wdl1);
    SYM(QQ0, g_QQ0); SYM(QQ1, g_QQ1); SYM(Xq0, g_Xq0); SYM(Xq1, g_Xq1);
    SYM(U0, g_U0); SYM(U1, g_U1);

    cudaFuncSetAttribute(gemm_h16, cudaFuncAttributeMaxDynamicSharedMemorySize, GEMM_SMEM);

    float* out = (float*)d_out;
    dim3 blk(256);
    const int MT = NPIX / 128;   // 100

    // ---- launch 0: all converts ----
    {
        ConvArgs ca;
        const float* srcs[NSEG] = {feat0, feat1, in_w0, in_w1, out_w0, out_w1,
                                   ffn_up_w0, ffn_up_w1, ffn_down_w0, ffn_down_w1};
        h16* hs[NSEG] = {f0, f1, wih0, wih1, woh0, woh1, wuh0, wuh1, wdh0, wdh1};
        h16* ls[NSEG] = {nullptr, nullptr, wil0, wil1, wol0, wol1, wul0, wul1, wdl0, wdl1};
        int sizes4[NSEG] = {NPIX*F/4, NPIX*F/4, PDIM*F/4, PDIM*F/4, F*3*F/4, F*3*F/4,
                            HIDN*F/4, HIDN*F/4, F*HIDN/4, F*HIDN/4};
        int acc4 = 0;
        for (int i = 0; i < NSEG; i++) {
            ca.s[i] = srcs[i]; ca.h[i] = hs[i]; ca.l[i] = ls[i];
            acc4 += sizes4[i];
            ca.end4[i] = acc4;
        }
        conv_all<<<(acc4 + 255) / 256, blk>>>(ca, acc4);
    }

    // ---- launch 1: in-projection GEMMs ----
    {
        GemmPair gp = {};
        gp.A[0]=f0; gp.A[1]=f1;
        gp.Bh0[0]=wih0; gp.Bl0[0]=wil0; gp.Bh1[0]=wih0; gp.Bl1[0]=wil0;
        gp.Bh0[1]=wih1; gp.Bl0[1]=wil1; gp.Bh1[1]=wih1; gp.Bl1[1]=wil1;
        gp.bias[0]=in_b0; gp.bias[1]=in_b1;
        gp.C[0]=P0; gp.C[1]=P1;
        gemm_h16<<<dim3(PDIM/128, MT, 2), blk, GEMM_SMEM>>>(gp, F, F, F, 0, PDIM, F, 0);
    }

    // ---- launch 2: 4 attentions -> QQ fp16 ----
    {
        AttArgs aa;
        aa.Q[0]=P0;     aa.Kp[0]=P0+F;   aa.Vp[0]=P0+2*F; aa.O[0]=QQ0;
        aa.Q[1]=P1;     aa.Kp[1]=P1+F;   aa.Vp[1]=P1+2*F; aa.O[1]=QQ1;
        aa.Q[2]=P0+3*F; aa.Kp[2]=P1+4*F; aa.Vp[2]=P1+5*F; aa.O[2]=QQ0+F;
        aa.Q[3]=P1+3*F; aa.Kp[3]=P0+4*F; aa.Vp[3]=P0+5*F; aa.O[3]=QQ1+F;
        attend_kernel<<<dim3(NPIX/4, 4), blk>>>(aa, 2*F);
    }

    // ---- launch 3: fused out-projections (K=512, split at 256), residual = feat ----
    {
        GemmPair gp = {};
        gp.A[0]=QQ0; gp.A[1]=QQ1;
        gp.Bh0[0]=woh0; gp.Bl0[0]=wol0; gp.Bh1[0]=woh0+F; gp.Bl1[0]=wol0+F;
        gp.Bh0[1]=woh1; gp.Bl0[1]=wol1; gp.Bh1[1]=woh0+F; gp.Bl1[1]=wol0+F;
        gp.bias[0]=out_b0; gp.bias2[0]=out_b0+F; gp.res[0]=feat0; gp.C[0]=T0;
        gp.bias[1]=out_b1; gp.bias2[1]=out_b0+F; gp.res[1]=feat1; gp.C[1]=T1;
        gemm_h16<<<dim3(F/128, MT, 2), blk, GEMM_SMEM>>>(gp, 2*F, 3*F, F, F, F, 2*F, 0);
    }

    // ---- launch 4: LN1 pair ----
    {
        LnArgs la;
        la.X[0]=T0; la.g[0]=ln1_g0; la.bt[0]=ln1_b0; la.O[0]=X0; la.Oh[0]=Xq0;
        la.X[1]=T1; la.g[1]=ln1_g1; la.bt[1]=ln1_b1; la.O[1]=X1; la.Oh[1]=Xq1;
        ln_kernel<<<dim3(NPIX, 2), blk>>>(la);
    }

    // ---- launch 5: FFN up pair (relu, fp16 out) ----
    {
        GemmPair gp = {};
        gp.A[0]=Xq0; gp.A[1]=Xq1;
        gp.Bh0[0]=wuh0; gp.Bl0[0]=wul0; gp.Bh1[0]=wuh0; gp.Bl1[0]=wul0;
        gp.Bh0[1]=wuh1; gp.Bl0[1]=wul1; gp.Bh1[1]=wuh1; gp.Bl1[1]=wul1;
        gp.bias[0]=ffn_up_b0; gp.bias[1]=ffn_up_b1;
        gp.Ch[0]=U0; gp.Ch[1]=U1;
        gemm_h16<<<dim3(HIDN/128, MT, 2), blk, GEMM_SMEM>>>(gp, F, F, F, 0, HIDN, F, 1);
    }

    // ---- launch 6: FFN down pair (residual X, fp32 out) ----
    {
        GemmPair gp = {};
        gp.A[0]=U0; gp.A[1]=U1;
        gp.Bh0[0]=wdh0; gp.Bl0[0]=wdl0; gp.Bh1[0]=wdh0; gp.Bl1[0]=wdl0;
        gp.Bh0[1]=wdh1; gp.Bl0[1]=wdl1; gp.Bh1[1]=wdh1; gp.Bl1[1]=wdl1;
        gp.bias[0]=ffn_down_b0; gp.bias[1]=ffn_down_b1;
        gp.res[0]=X0; gp.res[1]=X1;
        gp.C[0]=T0; gp.C[1]=T1;
        gemm_h16<<<dim3(F/128, MT, 2), blk, GEMM_SMEM>>>(gp, HIDN, HIDN, HIDN, F, F, HIDN, 0);
    }

    // ---- launch 7: LN2 pair -> output ----
    {
        LnArgs la;
        la.X[0]=T0; la.g[0]=ln2_g0; la.bt[0]=ln2_b0; la.O[0]=out; la.Oh[0]=nullptr;
        la.X[1]=T1; la.g[1]=ln2_g1; la.bt[1]=ln2_b1; la.O[1]=out + (size_t)NPIX*F; la.Oh[1]=nullptr;
        ln_kernel<<<dim3(NPIX, 2), blk>>>(la);
    }
}

// round 9
// speedup vs baseline: 3.5057x; 1.1395x over previous
#include <cuda_runtime.h>
#include <cuda_fp16.h>
#include <cstdint>
#include <cstddef>

#define F      256
#define NH     8
#define BATCH  2
#define HH     80
#define WW     80
#define NPIX   (BATCH*HH*WW)   // 12800
#define PDIM   1536
#define HIDN   1024

typedef __half h16;

// ---------------- scratch (no allocations allowed) ----------------
__device__ float g_P0[(size_t)NPIX*PDIM];
__device__ float g_P1[(size_t)NPIX*PDIM];
__device__ float g_T0[(size_t)NPIX*F];
__device__ float g_T1[(size_t)NPIX*F];
__device__ float g_X0[(size_t)NPIX*F];
__device__ float g_X1[(size_t)NPIX*F];

__device__ h16 g_f0[(size_t)NPIX*F];
__device__ h16 g_f1[(size_t)NPIX*F];
__device__ h16 g_wi0[(size_t)PDIM*F];
__device__ h16 g_wi1[(size_t)PDIM*F];
__device__ h16 g_wo0[(size_t)F*3*F];
__device__ h16 g_wo1[(size_t)F*3*F];
__device__ h16 g_wu0[(size_t)HIDN*F];
__device__ h16 g_wu1[(size_t)HIDN*F];
__device__ h16 g_wd0[(size_t)F*HIDN];
__device__ h16 g_wd1[(size_t)F*HIDN];
__device__ h16 g_QQ0[(size_t)NPIX*2*F];
__device__ h16 g_QQ1[(size_t)NPIX*2*F];
__device__ h16 g_Xq0[(size_t)NPIX*F];
__device__ h16 g_Xq1[(size_t)NPIX*F];
__device__ h16 g_U0[(size_t)NPIX*HIDN];
__device__ h16 g_U1[(size_t)NPIX*HIDN];

// ================= helpers =================
__device__ __forceinline__ uint32_t smem_u32(const void* p) {
    uint32_t a;
    asm("{ .reg .u64 t; cvta.to.shared.u64 t, %1; cvt.u32.u64 %0, t; }" : "=r"(a) : "l"(p));
    return a;
}
__device__ __forceinline__ void cpasync16(uint32_t dst, const void* src) {
    asm volatile("cp.async.cg.shared.global [%0], [%1], 16;" :: "r"(dst), "l"(src) : "memory");
}
__device__ __forceinline__ void ldsm4(uint32_t (&r)[4], uint32_t addr) {
    asm volatile("ldmatrix.sync.aligned.m8n8.x4.shared.b16 {%0,%1,%2,%3}, [%4];"
                 : "=r"(r[0]), "=r"(r[1]), "=r"(r[2]), "=r"(r[3]) : "r"(addr));
}
__device__ __forceinline__ void mma16816(float* d, const uint32_t* a, const uint32_t* b) {
    asm volatile("mma.sync.aligned.m16n8k16.row.col.f32.f16.f16.f32 "
                 "{%0,%1,%2,%3}, {%4,%5,%6,%7}, {%8,%9}, {%0,%1,%2,%3};"
                 : "+f"(d[0]), "+f"(d[1]), "+f"(d[2]), "+f"(d[3])
                 : "r"(a[0]), "r"(a[1]), "r"(a[2]), "r"(a[3]), "r"(b[0]), "r"(b[1]));
}

// ================= fp16 tensor GEMM (paired over z) =================
// C[m,n] = act( sum_k A[m,k]*W[n,k] + bias[n] (+bias2[n]) (+res[m,n]) )
// A, W single fp16. W split at Ksplit between B0 and B1 (pre-offset).
// Tile 128x128, warps 64x32, K chunks of 32.
// Stage: [A 8K][B 8K] = 16KB; 4 stages = 64KB; 2 CTAs/SM.
#define STAGES     4
#define SMEM_STAGE 16384
#define OFF_B      8192u
#define GEMM_SMEM  (STAGES*SMEM_STAGE)

struct GemmPair {
    const h16 *A[2];
    const h16 *B0[2], *B1[2];
    const float *bias[2], *bias2[2], *res[2];
    float *C[2];
    h16 *Ch[2];
};

__global__ __launch_bounds__(256, 2) void gemm_h16(
    GemmPair gp, int lda, int ldb, int Ksplit,
    int ldres, int ldc, int K, int relu)
{
    extern __shared__ char smem[];
    const uint32_t sb0 = smem_u32(smem);

    const int z = blockIdx.z;
    const h16* __restrict__ A  = gp.A[z];
    const h16* __restrict__ B0 = gp.B0[z];
    const h16* __restrict__ B1 = gp.B1[z];
    const float* __restrict__ bias  = gp.bias[z];
    const float* __restrict__ bias2 = gp.bias2[z];
    const float* __restrict__ res   = gp.res[z];
    float* __restrict__ C  = gp.C[z];
    h16*   __restrict__ Ch = gp.Ch[z];

    const int tid  = threadIdx.x;
    const int wid  = tid >> 5;
    const int lane = tid & 31;
    const int brow = blockIdx.y * 128;
    const int bcol = blockIdx.x * 128;
    const int wm   = (wid >> 2) * 64;   // 0 or 64
    const int wn   = (wid & 3) * 32;    // 0..96

    float acc[4][4][4];
#pragma unroll
    for (int i = 0; i < 4; i++)
#pragma unroll
        for (int j = 0; j < 4; j++)
#pragma unroll
            for (int r = 0; r < 4; r++) acc[i][j][r] = 0.f;

    // loader: 1024 quads(16B)/stage, 4 per thread
    auto load_stage = [&](int cIdx) {
        const uint32_t sb = sb0 + (uint32_t)(cIdx % STAGES) * SMEM_STAGE;
        const int k0 = cIdx * 32;
        const h16* bp;
        int kk;
        if (k0 < Ksplit) { bp = B0; kk = k0; }
        else             { bp = B1; kk = k0 - Ksplit; }
#pragma unroll
        for (int s = 0; s < 4; s++) {
            const int qid = tid + s * 256;
            const int q   = qid & 511;
            const int row = q >> 2;
            const int c   = q & 3;
            const h16* src;
            uint32_t dstbase;
            if (qid < 512) {
                src = A + (size_t)(brow + row) * lda + k0 + c * 8;
                dstbase = sb;
            } else {
                src = bp + (size_t)(bcol + row) * ldb + kk + c * 8;
                dstbase = sb + OFF_B;
            }
            cpasync16(dstbase + (uint32_t)row * 64u +
                      (uint32_t)((c ^ ((row >> 1) & 3)) * 16), src);
        }
        asm volatile("cp.async.commit_group;" ::: "memory");
    };

    const int tile = lane >> 3;
    const int rin  = lane & 7;
    const uint32_t rsw = (uint32_t)(rin >> 1);

    const int NC = K / 32;
    for (int s = 0; s < STAGES - 1 && s < NC; s++) load_stage(s);

    for (int c = 0; c < NC; c++) {
        if (c + 3 <= NC) {
            asm volatile("cp.async.wait_group 2;" ::: "memory");
        } else if (c + 2 == NC) {
            asm volatile("cp.async.wait_group 1;" ::: "memory");
        } else {
            asm volatile("cp.async.wait_group 0;" ::: "memory");
        }
        __syncthreads();
        if (c + 3 < NC) load_stage(c + 3);

        const uint32_t sb = sb0 + (uint32_t)(c % STAGES) * SMEM_STAGE;
#pragma unroll
        for (int ks = 0; ks < 2; ks++) {
            uint32_t ah[4][4], bh_[2][4];
            const uint32_t swa = ((uint32_t)(ks * 2 + (tile >> 1)) ^ rsw) * 16u;
#pragma unroll
            for (int i = 0; i < 4; i++)
                ldsm4(ah[i], sb + (uint32_t)(wm + i * 16 + (tile & 1) * 8 + rin) * 64u + swa);
            const uint32_t swb = ((uint32_t)(ks * 2 + (tile & 1)) ^ rsw) * 16u;
#pragma unroll
            for (int jj = 0; jj < 2; jj++)
                ldsm4(bh_[jj], sb + OFF_B +
                      (uint32_t)(wn + jj * 16 + (tile >> 1) * 8 + rin) * 64u + swb);
#pragma unroll
            for (int i = 0; i < 4; i++)
#pragma unroll
                for (int j = 0; j < 4; j++)
                    mma16816(acc[i][j], ah[i], &bh_[j >> 1][(j & 1) * 2]);
        }
    }

    // ------- epilogue -------
    const int tq = lane >> 2;
    const int tr = (lane & 3) * 2;
    float bj0[4], bj1[4];
#pragma unroll
    for (int j = 0; j < 4; j++) {
        const int n = bcol + wn + 8 * j + tr;
        float b0 = bias[n], b1 = bias[n + 1];
        if (bias2) { b0 += bias2[n]; b1 += bias2[n + 1]; }
        bj0[j] = b0; bj1[j] = b1;
    }
#pragma unroll
    for (int i = 0; i < 4; i++)
#pragma unroll
        for (int half = 0; half < 2; half++) {
            const int m = brow + wm + 16 * i + tq + half * 8;
#pragma unroll
            for (int j = 0; j < 4; j++) {
                const int n = bcol + wn + 8 * j + tr;
                float v0 = acc[i][j][half * 2 + 0] + bj0[j];
                float v1 = acc[i][j][half * 2 + 1] + bj1[j];
                if (res) {
                    float2 r = *(const float2*)(res + (size_t)m * ldres + n);
                    v0 += r.x; v1 += r.y;
                }
                if (relu) { v0 = fmaxf(v0, 0.f); v1 = fmaxf(v1, 0.f); }
                if (C) *(float2*)(C + (size_t)m * ldc + n) = make_float2(v0, v1);
                if (Ch)
                    *(__half2*)(Ch + (size_t)m * ldc + n) =
                        __halves2half2(__float2half_rn(v0), __float2half_rn(v1));
            }
        }
}

// ---------------- merged convert fp32 -> fp16 ----------------
#define NSEG 10
struct ConvArgs {
    const float* s[NSEG];
    h16* h[NSEG];
    int end4[NSEG];
};

__global__ __launch_bounds__(256) void conv_all(ConvArgs a, int total4)
{
    int i = blockIdx.x * 256 + threadIdx.x;
    if (i >= total4) return;
    int seg = 0;
#pragma unroll
    for (int s = 0; s < NSEG - 1; s++) seg += (i >= a.end4[s]) ? 1 : 0;
    const int base = seg ? a.end4[seg - 1] : 0;
    const int j = i - base;

    float4 v = ((const float4*)a.s[seg])[j];
    h16* hp = a.h[seg];
    ((__half2*)hp)[2 * j]     = __halves2half2(__float2half_rn(v.x), __float2half_rn(v.y));
    ((__half2*)hp)[2 * j + 1] = __halves2half2(__float2half_rn(v.z), __float2half_rn(v.w));
}

// ---------------- 9-tap windowed multi-head attention (4 fused via y) ----------------
struct AttArgs {
    const float* Q[4];
    const float* Kp[4];
    const float* Vp[4];
    h16* O[4];
};

__global__ __launch_bounds__(256) void attend_kernel(AttArgs a, int ostride)
{
    const int z   = blockIdx.y;
    const int t   = threadIdx.x & 63;
    const int pix = blockIdx.x * 4 + (threadIdx.x >> 6);
    const int b   = pix / (HH * WW);
    const int r   = pix % (HH * WW);
    const int y   = r / WW;
    const int x   = r % WW;
    const int ch  = t * 4;

    const float* __restrict__ Q  = a.Q[z];
    const float* __restrict__ Kp = a.Kp[z];
    const float* __restrict__ Vp = a.Vp[z];

    const float scale = 0.17677669529663687f;
    float4 q = *(const float4*)(Q + (size_t)pix * PDIM + ch);
    q.x *= scale; q.y *= scale; q.z *= scale; q.w *= scale;

    float  sc[9];
    float4 vv[9];
#pragma unroll
    for (int n = 0; n < 9; n++) {
        int dy = n / 3 - 1, dx = n % 3 - 1;
        int yy = y + dy, xx = x + dx;
        float s = 0.f;
        float4 v = make_float4(0.f, 0.f, 0.f, 0.f);
        if (yy >= 0 && yy < HH && xx >= 0 && xx < WW) {
            size_t np = ((size_t)(b * HH + yy) * WW + xx) * PDIM + ch;
            float4 k4 = *(const float4*)(Kp + np);
            v = *(const float4*)(Vp + np);
            s = q.x * k4.x + q.y * k4.y + q.z * k4.z + q.w * k4.w;
        }
        s += __shfl_xor_sync(0xffffffffu, s, 4);
        s += __shfl_xor_sync(0xffffffffu, s, 2);
        s += __shfl_xor_sync(0xffffffffu, s, 1);
        sc[n] = s;
        vv[n] = v;
    }

    float mx = sc[0];
#pragma unroll
    for (int n = 1; n < 9; n++) mx = fmaxf(mx, sc[n]);
    float den = 0.f;
    float4 o = make_float4(0.f, 0.f, 0.f, 0.f);
#pragma unroll
    for (int n = 0; n < 9; n++) {
        float w = __expf(sc[n] - mx);
        den += w;
        o.x += w * vv[n].x; o.y += w * vv[n].y;
        o.z += w * vv[n].z; o.w += w * vv[n].w;
    }
    float inv = 1.f / den;
    size_t base = (size_t)pix * ostride + ch;
    *(__half2*)(a.O[z] + base) =
        __halves2half2(__float2half_rn(o.x * inv), __float2half_rn(o.y * inv));
    *(__half2*)(a.O[z] + base + 2) =
        __halves2half2(__float2half_rn(o.z * inv), __float2half_rn(o.w * inv));
}

// ---------------- LayerNorm over last dim (256), pair fused via y ----------------
struct LnArgs {
    const float* X[2];
    const float* g[2];
    const float* bt[2];
    float* O[2];
    h16* Oh[2];
};

__global__ __launch_bounds__(256) void ln_kernel(LnArgs a)
{
    const int z   = blockIdx.y;
    const int row = blockIdx.x;
    const int t   = threadIdx.x;
    const int warp = t >> 5, lane = t & 31;
    __shared__ float red[8];

    float v = a.X[z][(size_t)row * F + t];

    float s = v;
#pragma unroll
    for (int o = 16; o > 0; o >>= 1) s += __shfl_xor_sync(0xffffffffu, s, o);
    if (lane == 0) red[warp] = s;
    __syncthreads();
    float tot = 0.f;
#pragma unroll
    for (int i = 0; i < 8; i++) tot += red[i];
    float mean = tot * (1.0f / F);
    float xc = v - mean;
    __syncthreads();

    float s2 = xc * xc;
#pragma unroll
    for (int o = 16; o > 0; o >>= 1) s2 += __shfl_xor_sync(0xffffffffu, s2, o);
    if (lane == 0) red[warp] = s2;
    __syncthreads();
    float tot2 = 0.f;
#pragma unroll
    for (int i = 0; i < 8; i++) tot2 += red[i];
    float var = tot2 * (1.0f / F);

    float out = a.g[z][t] * xc * rsqrtf(var + 1e-5f) + a.bt[z][t];
    if (a.O[z])  a.O[z][(size_t)row * F + t] = out;
    if (a.Oh[z]) a.Oh[z][(size_t)row * F + t] = __float2half_rn(out);
}

// ---------------- launch ----------------
#define SYM(p, s) cudaGetSymbolAddress((void**)&p, s)

extern "C" void kernel_launch(void* const* d_in, const int* in_sizes, int n_in,
                              void* d_out, int out_size)
{
    const float* feat0       = (const float*)d_in[0];
    const float* feat1       = (const float*)d_in[1];
    const float* in_w0       = (const float*)d_in[2];
    const float* in_b0       = (const float*)d_in[3];
    const float* in_w1       = (const float*)d_in[4];
    const float* in_b1       = (const float*)d_in[5];
    const float* out_w0      = (const float*)d_in[6];
    const float* out_b0      = (const float*)d_in[7];
    const float* out_w1      = (const float*)d_in[8];
    const float* out_b1      = (const float*)d_in[9];
    const float* ln1_g0      = (const float*)d_in[10];
    const float* ln1_b0      = (const float*)d_in[11];
    const float* ln1_g1      = (const float*)d_in[12];
    const float* ln1_b1      = (const float*)d_in[13];
    const float* ffn_up_w0   = (const float*)d_in[14];
    const float* ffn_up_b0   = (const float*)d_in[15];
    const float* ffn_down_w0 = (const float*)d_in[16];
    const float* ffn_down_b0 = (const float*)d_in[17];
    const float* ffn_up_w1   = (const float*)d_in[18];
    const float* ffn_up_b1   = (const float*)d_in[19];
    const float* ffn_down_w1 = (const float*)d_in[20];
    const float* ffn_down_b1 = (const float*)d_in[21];
    const float* ln2_g0      = (const float*)d_in[22];
    const float* ln2_b0      = (const float*)d_in[23];
    const float* ln2_g1      = (const float*)d_in[24];
    const float* ln2_b1      = (const float*)d_in[25];

    float *P0, *P1, *T0, *T1, *X0, *X1;
    SYM(P0, g_P0); SYM(P1, g_P1); SYM(T0, g_T0); SYM(T1, g_T1); SYM(X0, g_X0); SYM(X1, g_X1);
    h16 *f0, *f1, *wi0, *wi1, *wo0, *wo1, *wu0, *wu1, *wd0, *wd1;
    h16 *QQ0, *QQ1, *Xq0, *Xq1, *U0, *U1;
    SYM(f0, g_f0); SYM(f1, g_f1);
    SYM(wi0, g_wi0); SYM(wi1, g_wi1);
    SYM(wo0, g_wo0); SYM(wo1, g_wo1);
    SYM(wu0, g_wu0); SYM(wu1, g_wu1);
    SYM(wd0, g_wd0); SYM(wd1, g_wd1);
    SYM(QQ0, g_QQ0); SYM(QQ1, g_QQ1); SYM(Xq0, g_Xq0); SYM(Xq1, g_Xq1);
    SYM(U0, g_U0); SYM(U1, g_U1);

    cudaFuncSetAttribute(gemm_h16, cudaFuncAttributeMaxDynamicSharedMemorySize, GEMM_SMEM);

    float* out = (float*)d_out;
    dim3 blk(256);
    const int MT = NPIX / 128;   // 100

    // ---- launch 0: all converts ----
    {
        ConvArgs ca;
        const float* srcs[NSEG] = {feat0, feat1, in_w0, in_w1, out_w0, out_w1,
                                   ffn_up_w0, ffn_up_w1, ffn_down_w0, ffn_down_w1};
        h16* hs[NSEG] = {f0, f1, wi0, wi1, wo0, wo1, wu0, wu1, wd0, wd1};
        int sizes4[NSEG] = {NPIX*F/4, NPIX*F/4, PDIM*F/4, PDIM*F/4, F*3*F/4, F*3*F/4,
                            HIDN*F/4, HIDN*F/4, F*HIDN/4, F*HIDN/4};
        int acc4 = 0;
        for (int i = 0; i < NSEG; i++) {
            ca.s[i] = srcs[i]; ca.h[i] = hs[i];
            acc4 += sizes4[i];
            ca.end4[i] = acc4;
        }
        conv_all<<<(acc4 + 255) / 256, blk>>>(ca, acc4);
    }

    // ---- launch 1: in-projection GEMMs ----
    {
        GemmPair gp = {};
        gp.A[0]=f0; gp.A[1]=f1;
        gp.B0[0]=wi0; gp.B1[0]=wi0;
        gp.B0[1]=wi1; gp.B1[1]=wi1;
        gp.bias[0]=in_b0; gp.bias[1]=in_b1;
        gp.C[0]=P0; gp.C[1]=P1;
        gemm_h16<<<dim3(PDIM/128, MT, 2), blk, GEMM_SMEM>>>(gp, F, F, F, 0, PDIM, F, 0);
    }

    // ---- launch 2: 4 attentions -> QQ fp16 ----
    {
        AttArgs aa;
        aa.Q[0]=P0;     aa.Kp[0]=P0+F;   aa.Vp[0]=P0+2*F; aa.O[0]=QQ0;
        aa.Q[1]=P1;     aa.Kp[1]=P1+F;   aa.Vp[1]=P1+2*F; aa.O[1]=QQ1;
        aa.Q[2]=P0+3*F; aa.Kp[2]=P1+4*F; aa.Vp[2]=P1+5*F; aa.O[2]=QQ0+F;
        aa.Q[3]=P1+3*F; aa.Kp[3]=P0+4*F; aa.Vp[3]=P0+5*F; aa.O[3]=QQ1+F;
        attend_kernel<<<dim3(NPIX/4, 4), blk>>>(aa, 2*F);
    }

    // ---- launch 3: fused out-projections (K=512, split at 256), residual = feat ----
    {
        GemmPair gp = {};
        gp.A[0]=QQ0; gp.A[1]=QQ1;
        gp.B0[0]=wo0; gp.B1[0]=wo0+F;
        gp.B0[1]=wo1; gp.B1[1]=wo0+F;
        gp.bias[0]=out_b0; gp.bias2[0]=out_b0+F; gp.res[0]=feat0; gp.C[0]=T0;
        gp.bias[1]=out_b1; gp.bias2[1]=out_b0+F; gp.res[1]=feat1; gp.C[1]=T1;
        gemm_h16<<<dim3(F/128, MT, 2), blk, GEMM_SMEM>>>(gp, 2*F, 3*F, F, F, F, 2*F, 0);
    }

    // ---- launch 4: LN1 pair ----
    {
        LnArgs la;
        la.X[0]=T0; la.g[0]=ln1_g0; la.bt[0]=ln1_b0; la.O[0]=X0; la.Oh[0]=Xq0;
        la.X[1]=T1; la.g[1]=ln1_g1; la.bt[1]=ln1_b1; la.O[1]=X1; la.Oh[1]=Xq1;
        ln_kernel<<<dim3(NPIX, 2), blk>>>(la);
    }

    // ---- launch 5: FFN up pair (relu, fp16 out) ----
    {
        GemmPair gp = {};
        gp.A[0]=Xq0; gp.A[1]=Xq1;
        gp.B0[0]=wu0; gp.B1[0]=wu0;
        gp.B0[1]=wu1; gp.B1[1]=wu1;
        gp.bias[0]=ffn_up_b0; gp.bias[1]=ffn_up_b1;
        gp.Ch[0]=U0; gp.Ch[1]=U1;
        gemm_h16<<<dim3(HIDN/128, MT, 2), blk, GEMM_SMEM>>>(gp, F, F, F, 0, HIDN, F, 1);
    }

    // ---- launch 6: FFN down pair (residual X, fp32 out) ----
    {
        GemmPair gp = {};
        gp.A[0]=U0; gp.A[1]=U1;
        gp.B0[0]=wd0; gp.B1[0]=wd0;
        gp.B0[1]=wd1; gp.B1[1]=wd1;
        gp.bias[0]=ffn_down_b0; gp.bias[1]=ffn_down_b1;
        gp.res[0]=X0; gp.res[1]=X1;
        gp.C[0]=T0; gp.C[1]=T1;
        gemm_h16<<<dim3(F/128, MT, 2), blk, GEMM_SMEM>>>(gp, HIDN, HIDN, HIDN, F, F, HIDN, 0);
    }

    // ---- launch 7: LN2 pair -> output ----
    {
        LnArgs la;
        la.X[0]=T0; la.g[0]=ln2_g0; la.bt[0]=ln2_b0; la.O[0]=out; la.Oh[0]=nullptr;
        la.X[1]=T1; la.g[1]=ln2_g1; la.bt[1]=ln2_b1; la.O[1]=out + (size_t)NPIX*F; la.Oh[1]=nullptr;
        ln_kernel<<<dim3(NPIX, 2), blk>>>(la);
    }
}

// round 10
// speedup vs baseline: 3.5481x; 1.0121x over previous
#include <cuda_runtime.h>
#include <cuda_fp16.h>
#include <cstdint>
#include <cstddef>

#define F      256
#define NH     8
#define BATCH  2
#define HH     80
#define WW     80
#define NPIX   (BATCH*HH*WW)   // 12800
#define PDIM   1536
#define HIDN   1024

typedef __half h16;

// ---------------- scratch (no allocations allowed) ----------------
__device__ float g_T0[(size_t)NPIX*F];
__device__ float g_T1[(size_t)NPIX*F];
__device__ float g_X0[(size_t)NPIX*F];
__device__ float g_X1[(size_t)NPIX*F];

__device__ h16 g_P0[(size_t)NPIX*PDIM];   // fp16 in-proj output
__device__ h16 g_P1[(size_t)NPIX*PDIM];
__device__ h16 g_f0[(size_t)NPIX*F];
__device__ h16 g_f1[(size_t)NPIX*F];
__device__ h16 g_wi0[(size_t)PDIM*F];
__device__ h16 g_wi1[(size_t)PDIM*F];
__device__ h16 g_wo0[(size_t)F*3*F];
__device__ h16 g_wo1[(size_t)F*3*F];
__device__ h16 g_wu0[(size_t)HIDN*F];
__device__ h16 g_wu1[(size_t)HIDN*F];
__device__ h16 g_wd0[(size_t)F*HIDN];
__device__ h16 g_wd1[(size_t)F*HIDN];
__device__ h16 g_QQ0[(size_t)NPIX*2*F];
__device__ h16 g_QQ1[(size_t)NPIX*2*F];
__device__ h16 g_Xq0[(size_t)NPIX*F];
__device__ h16 g_Xq1[(size_t)NPIX*F];
__device__ h16 g_U0[(size_t)NPIX*HIDN];
__device__ h16 g_U1[(size_t)NPIX*HIDN];

// ================= helpers =================
__device__ __forceinline__ uint32_t smem_u32(const void* p) {
    uint32_t a;
    asm("{ .reg .u64 t; cvta.to.shared.u64 t, %1; cvt.u32.u64 %0, t; }" : "=r"(a) : "l"(p));
    return a;
}
__device__ __forceinline__ void cpasync16(uint32_t dst, const void* src) {
    asm volatile("cp.async.cg.shared.global [%0], [%1], 16;" :: "r"(dst), "l"(src) : "memory");
}
__device__ __forceinline__ void ldsm4(uint32_t (&r)[4], uint32_t addr) {
    asm volatile("ldmatrix.sync.aligned.m8n8.x4.shared.b16 {%0,%1,%2,%3}, [%4];"
                 : "=r"(r[0]), "=r"(r[1]), "=r"(r[2]), "=r"(r[3]) : "r"(addr));
}
__device__ __forceinline__ void mma16816(float* d, const uint32_t* a, const uint32_t* b) {
    asm volatile("mma.sync.aligned.m16n8k16.row.col.f32.f16.f16.f32 "
                 "{%0,%1,%2,%3}, {%4,%5,%6,%7}, {%8,%9}, {%0,%1,%2,%3};"
                 : "+f"(d[0]), "+f"(d[1]), "+f"(d[2]), "+f"(d[3])
                 : "r"(a[0]), "r"(a[1]), "r"(a[2]), "r"(a[3]), "r"(b[0]), "r"(b[1]));
}

// ================= fp16 tensor GEMM (paired over z) =================
// Tile 128x128, warps 64x32, K chunks of 32.
// Stage: [A 8K][B 8K] = 16KB; 4 stages = 64KB; 2 CTAs/SM.
#define STAGES     4
#define SMEM_STAGE 16384
#define OFF_B      8192u
#define GEMM_SMEM  (STAGES*SMEM_STAGE)

struct GemmPair {
    const h16 *A[2];
    const h16 *B0[2], *B1[2];
    const float *bias[2], *bias2[2], *res[2];
    float *C[2];
    h16 *Ch[2];
};

__global__ __launch_bounds__(256, 2) void gemm_h16(
    GemmPair gp, int lda, int ldb, int Ksplit,
    int ldres, int ldc, int K, int relu)
{
    extern __shared__ char smem[];
    const uint32_t sb0 = smem_u32(smem);

    const int z = blockIdx.z;
    const h16* __restrict__ A  = gp.A[z];
    const h16* __restrict__ B0 = gp.B0[z];
    const h16* __restrict__ B1 = gp.B1[z];
    const float* __restrict__ bias  = gp.bias[z];
    const float* __restrict__ bias2 = gp.bias2[z];
    const float* __restrict__ res   = gp.res[z];
    float* __restrict__ C  = gp.C[z];
    h16*   __restrict__ Ch = gp.Ch[z];

    const int tid  = threadIdx.x;
    const int wid  = tid >> 5;
    const int lane = tid & 31;
    const int brow = blockIdx.y * 128;
    const int bcol = blockIdx.x * 128;
    const int wm   = (wid >> 2) * 64;
    const int wn   = (wid & 3) * 32;

    float acc[4][4][4];
#pragma unroll
    for (int i = 0; i < 4; i++)
#pragma unroll
        for (int j = 0; j < 4; j++)
#pragma unroll
            for (int r = 0; r < 4; r++) acc[i][j][r] = 0.f;

    auto load_stage = [&](int cIdx) {
        const uint32_t sb = sb0 + (uint32_t)(cIdx % STAGES) * SMEM_STAGE;
        const int k0 = cIdx * 32;
        const h16* bp;
        int kk;
        if (k0 < Ksplit) { bp = B0; kk = k0; }
        else             { bp = B1; kk = k0 - Ksplit; }
#pragma unroll
        for (int s = 0; s < 4; s++) {
            const int qid = tid + s * 256;
            const int q   = qid & 511;
            const int row = q >> 2;
            const int c   = q & 3;
            const h16* src;
            uint32_t dstbase;
            if (qid < 512) {
                src = A + (size_t)(brow + row) * lda + k0 + c * 8;
                dstbase = sb;
            } else {
                src = bp + (size_t)(bcol + row) * ldb + kk + c * 8;
                dstbase = sb + OFF_B;
            }
            cpasync16(dstbase + (uint32_t)row * 64u +
                      (uint32_t)((c ^ ((row >> 1) & 3)) * 16), src);
        }
        asm volatile("cp.async.commit_group;" ::: "memory");
    };

    const int tile = lane >> 3;
    const int rin  = lane & 7;
    const uint32_t rsw = (uint32_t)(rin >> 1);

    const int NC = K / 32;
    for (int s = 0; s < STAGES - 1 && s < NC; s++) load_stage(s);

    for (int c = 0; c < NC; c++) {
        if (c + 3 <= NC) {
            asm volatile("cp.async.wait_group 2;" ::: "memory");
        } else if (c + 2 == NC) {
            asm volatile("cp.async.wait_group 1;" ::: "memory");
        } else {
            asm volatile("cp.async.wait_group 0;" ::: "memory");
        }
        __syncthreads();
        if (c + 3 < NC) load_stage(c + 3);

        const uint32_t sb = sb0 + (uint32_t)(c % STAGES) * SMEM_STAGE;
#pragma unroll
        for (int ks = 0; ks < 2; ks++) {
            uint32_t ah[4][4], bh_[2][4];
            const uint32_t swa = ((uint32_t)(ks * 2 + (tile >> 1)) ^ rsw) * 16u;
#pragma unroll
            for (int i = 0; i < 4; i++)
                ldsm4(ah[i], sb + (uint32_t)(wm + i * 16 + (tile & 1) * 8 + rin) * 64u + swa);
            const uint32_t swb = ((uint32_t)(ks * 2 + (tile & 1)) ^ rsw) * 16u;
#pragma unroll
            for (int jj = 0; jj < 2; jj++)
                ldsm4(bh_[jj], sb + OFF_B +
                      (uint32_t)(wn + jj * 16 + (tile >> 1) * 8 + rin) * 64u + swb);
#pragma unroll
            for (int i = 0; i < 4; i++)
#pragma unroll
                for (int j = 0; j < 4; j++)
                    mma16816(acc[i][j], ah[i], &bh_[j >> 1][(j & 1) * 2]);
        }
    }

    // ------- epilogue -------
    const int tq = lane >> 2;
    const int tr = (lane & 3) * 2;
    float bj0[4], bj1[4];
#pragma unroll
    for (int j = 0; j < 4; j++) {
        const int n = bcol + wn + 8 * j + tr;
        float b0 = bias[n], b1 = bias[n + 1];
        if (bias2) { b0 += bias2[n]; b1 += bias2[n + 1]; }
        bj0[j] = b0; bj1[j] = b1;
    }
#pragma unroll
    for (int i = 0; i < 4; i++)
#pragma unroll
        for (int half = 0; half < 2; half++) {
            const int m = brow + wm + 16 * i + tq + half * 8;
#pragma unroll
            for (int j = 0; j < 4; j++) {
                const int n = bcol + wn + 8 * j + tr;
                float v0 = acc[i][j][half * 2 + 0] + bj0[j];
                float v1 = acc[i][j][half * 2 + 1] + bj1[j];
                if (res) {
                    float2 r = *(const float2*)(res + (size_t)m * ldres + n);
                    v0 += r.x; v1 += r.y;
                }
                if (relu) { v0 = fmaxf(v0, 0.f); v1 = fmaxf(v1, 0.f); }
                if (C) *(float2*)(C + (size_t)m * ldc + n) = make_float2(v0, v1);
                if (Ch)
                    *(__half2*)(Ch + (size_t)m * ldc + n) =
                        __halves2half2(__float2half_rn(v0), __float2half_rn(v1));
            }
        }
}

// ---------------- merged convert fp32 -> fp16 ----------------
#define NSEG 10
struct ConvArgs {
    const float* s[NSEG];
    h16* h[NSEG];
    int end4[NSEG];
};

__global__ __launch_bounds__(256) void conv_all(ConvArgs a, int total4)
{
    int i = blockIdx.x * 256 + threadIdx.x;
    if (i >= total4) return;
    int seg = 0;
#pragma unroll
    for (int s = 0; s < NSEG - 1; s++) seg += (i >= a.end4[s]) ? 1 : 0;
    const int base = seg ? a.end4[seg - 1] : 0;
    const int j = i - base;

    float4 v = ((const float4*)a.s[seg])[j];
    h16* hp = a.h[seg];
    ((__half2*)hp)[2 * j]     = __halves2half2(__float2half_rn(v.x), __float2half_rn(v.y));
    ((__half2*)hp)[2 * j + 1] = __halves2half2(__float2half_rn(v.z), __float2half_rn(v.w));
}

// ---------------- 9-tap windowed multi-head attention (fp16 inputs, 4 fused via y) ----------------
struct AttArgs {
    const h16* Q[4];
    const h16* Kp[4];
    const h16* Vp[4];
    h16* O[4];
};

__global__ __launch_bounds__(256) void attend_kernel(AttArgs a, int ostride)
{
    const int z   = blockIdx.y;
    const int t   = threadIdx.x & 63;
    const int pix = blockIdx.x * 4 + (threadIdx.x >> 6);
    const int b   = pix / (HH * WW);
    const int r   = pix % (HH * WW);
    const int y   = r / WW;
    const int x   = r % WW;
    const int ch  = t * 4;

    const h16* __restrict__ Q  = a.Q[z];
    const h16* __restrict__ Kp = a.Kp[z];
    const h16* __restrict__ Vp = a.Vp[z];

    const float scale = 0.17677669529663687f;
    float qf[4];
    {
        uint2 qr = *(const uint2*)(Q + (size_t)pix * PDIM + ch);
        float2 a0 = __half22float2(*(__half2*)&qr.x);
        float2 a1 = __half22float2(*(__half2*)&qr.y);
        qf[0] = a0.x * scale; qf[1] = a0.y * scale;
        qf[2] = a1.x * scale; qf[3] = a1.y * scale;
    }

    float  sc[9];
    float4 vv[9];
#pragma unroll
    for (int n = 0; n < 9; n++) {
        int dy = n / 3 - 1, dx = n % 3 - 1;
        int yy = y + dy, xx = x + dx;
        float s = 0.f;
        float4 v = make_float4(0.f, 0.f, 0.f, 0.f);
        if (yy >= 0 && yy < HH && xx >= 0 && xx < WW) {
            size_t np = ((size_t)(b * HH + yy) * WW + xx) * PDIM + ch;
            uint2 kr = *(const uint2*)(Kp + np);
            uint2 vr = *(const uint2*)(Vp + np);
            float2 k0 = __half22float2(*(__half2*)&kr.x);
            float2 k1 = __half22float2(*(__half2*)&kr.y);
            float2 v0 = __half22float2(*(__half2*)&vr.x);
            float2 v1 = __half22float2(*(__half2*)&vr.y);
            s = qf[0] * k0.x + qf[1] * k0.y + qf[2] * k1.x + qf[3] * k1.y;
            v = make_float4(v0.x, v0.y, v1.x, v1.y);
        }
        s += __shfl_xor_sync(0xffffffffu, s, 4);
        s += __shfl_xor_sync(0xffffffffu, s, 2);
        s += __shfl_xor_sync(0xffffffffu, s, 1);
        sc[n] = s;
        vv[n] = v;
    }

    float mx = sc[0];
#pragma unroll
    for (int n = 1; n < 9; n++) mx = fmaxf(mx, sc[n]);
    float den = 0.f;
    float4 o = make_float4(0.f, 0.f, 0.f, 0.f);
#pragma unroll
    for (int n = 0; n < 9; n++) {
        float w = __expf(sc[n] - mx);
        den += w;
        o.x += w * vv[n].x; o.y += w * vv[n].y;
        o.z += w * vv[n].z; o.w += w * vv[n].w;
    }
    float inv = 1.f / den;
    size_t base = (size_t)pix * ostride + ch;
    *(__half2*)(a.O[z] + base) =
        __halves2half2(__float2half_rn(o.x * inv), __float2half_rn(o.y * inv));
    *(__half2*)(a.O[z] + base + 2) =
        __halves2half2(__float2half_rn(o.z * inv), __float2half_rn(o.w * inv));
}

// ---------------- LayerNorm over last dim (256), pair fused via y ----------------
struct LnArgs {
    const float* X[2];
    const float* g[2];
    const float* bt[2];
    float* O[2];
    h16* Oh[2];
};

__global__ __launch_bounds__(256) void ln_kernel(LnArgs a)
{
    const int z   = blockIdx.y;
    const int row = blockIdx.x;
    const int t   = threadIdx.x;
    const int warp = t >> 5, lane = t & 31;
    __shared__ float red[8];

    float v = a.X[z][(size_t)row * F + t];

    float s = v;
#pragma unroll
    for (int o = 16; o > 0; o >>= 1) s += __shfl_xor_sync(0xffffffffu, s, o);
    if (lane == 0) red[warp] = s;
    __syncthreads();
    float tot = 0.f;
#pragma unroll
    for (int i = 0; i < 8; i++) tot += red[i];
    float mean = tot * (1.0f / F);
    float xc = v - mean;
    __syncthreads();

    float s2 = xc * xc;
#pragma unroll
    for (int o = 16; o > 0; o >>= 1) s2 += __shfl_xor_sync(0xffffffffu, s2, o);
    if (lane == 0) red[warp] = s2;
    __syncthreads();
    float tot2 = 0.f;
#pragma unroll
    for (int i = 0; i < 8; i++) tot2 += red[i];
    float var = tot2 * (1.0f / F);

    float out = a.g[z][t] * xc * rsqrtf(var + 1e-5f) + a.bt[z][t];
    if (a.O[z])  a.O[z][(size_t)row * F + t] = out;
    if (a.Oh[z]) a.Oh[z][(size_t)row * F + t] = __float2half_rn(out);
}

// ---------------- launch ----------------
#define SYM(p, s) cudaGetSymbolAddress((void**)&p, s)

extern "C" void kernel_launch(void* const* d_in, const int* in_sizes, int n_in,
                              void* d_out, int out_size)
{
    const float* feat0       = (const float*)d_in[0];
    const float* feat1       = (const float*)d_in[1];
    const float* in_w0       = (const float*)d_in[2];
    const float* in_b0       = (const float*)d_in[3];
    const float* in_w1       = (const float*)d_in[4];
    const float* in_b1       = (const float*)d_in[5];
    const float* out_w0      = (const float*)d_in[6];
    const float* out_b0      = (const float*)d_in[7];
    const float* out_w1      = (const float*)d_in[8];
    const float* out_b1      = (const float*)d_in[9];
    const float* ln1_g0      = (const float*)d_in[10];
    const float* ln1_b0      = (const float*)d_in[11];
    const float* ln1_g1      = (const float*)d_in[12];
    const float* ln1_b1      = (const float*)d_in[13];
    const float* ffn_up_w0   = (const float*)d_in[14];
    const float* ffn_up_b0   = (const float*)d_in[15];
    const float* ffn_down_w0 = (const float*)d_in[16];
    const float* ffn_down_b0 = (const float*)d_in[17];
    const float* ffn_up_w1   = (const float*)d_in[18];
    const float* ffn_up_b1   = (const float*)d_in[19];
    const float* ffn_down_w1 = (const float*)d_in[20];
    const float* ffn_down_b1 = (const float*)d_in[21];
    const float* ln2_g0      = (const float*)d_in[22];
    const float* ln2_b0      = (const float*)d_in[23];
    const float* ln2_g1      = (const float*)d_in[24];
    const float* ln2_b1      = (const float*)d_in[25];

    float *T0, *T1, *X0, *X1;
    SYM(T0, g_T0); SYM(T1, g_T1); SYM(X0, g_X0); SYM(X1, g_X1);
    h16 *P0, *P1, *f0, *f1, *wi0, *wi1, *wo0, *wo1, *wu0, *wu1, *wd0, *wd1;
    h16 *QQ0, *QQ1, *Xq0, *Xq1, *U0, *U1;
    SYM(P0, g_P0); SYM(P1, g_P1);
    SYM(f0, g_f0); SYM(f1, g_f1);
    SYM(wi0, g_wi0); SYM(wi1, g_wi1);
    SYM(wo0, g_wo0); SYM(wo1, g_wo1);
    SYM(wu0, g_wu0); SYM(wu1, g_wu1);
    SYM(wd0, g_wd0); SYM(wd1, g_wd1);
    SYM(QQ0, g_QQ0); SYM(QQ1, g_QQ1); SYM(Xq0, g_Xq0); SYM(Xq1, g_Xq1);
    SYM(U0, g_U0); SYM(U1, g_U1);

    cudaFuncSetAttribute(gemm_h16, cudaFuncAttributeMaxDynamicSharedMemorySize, GEMM_SMEM);

    float* out = (float*)d_out;
    dim3 blk(256);
    const int MT = NPIX / 128;   // 100

    // ---- launch 0: all converts ----
    {
        ConvArgs ca;
        const float* srcs[NSEG] = {feat0, feat1, in_w0, in_w1, out_w0, out_w1,
                                   ffn_up_w0, ffn_up_w1, ffn_down_w0, ffn_down_w1};
        h16* hs[NSEG] = {f0, f1, wi0, wi1, wo0, wo1, wu0, wu1, wd0, wd1};
        int sizes4[NSEG] = {NPIX*F/4, NPIX*F/4, PDIM*F/4, PDIM*F/4, F*3*F/4, F*3*F/4,
                            HIDN*F/4, HIDN*F/4, F*HIDN/4, F*HIDN/4};
        int acc4 = 0;
        for (int i = 0; i < NSEG; i++) {
            ca.s[i] = srcs[i]; ca.h[i] = hs[i];
            acc4 += sizes4[i];
            ca.end4[i] = acc4;
        }
        conv_all<<<(acc4 + 255) / 256, blk>>>(ca, acc4);
    }

    // ---- launch 1: in-projection GEMMs -> P fp16 ----
    {
        GemmPair gp = {};
        gp.A[0]=f0; gp.A[1]=f1;
        gp.B0[0]=wi0; gp.B1[0]=wi0;
        gp.B0[1]=wi1; gp.B1[1]=wi1;
        gp.bias[0]=in_b0; gp.bias[1]=in_b1;
        gp.Ch[0]=P0; gp.Ch[1]=P1;
        gemm_h16<<<dim3(PDIM/128, MT, 2), blk, GEMM_SMEM>>>(gp, F, F, F, 0, PDIM, F, 0);
    }

    // ---- launch 2: 4 attentions (fp16 in) -> QQ fp16 ----
    {
        AttArgs aa;
        aa.Q[0]=P0;     aa.Kp[0]=P0+F;   aa.Vp[0]=P0+2*F; aa.O[0]=QQ0;
        aa.Q[1]=P1;     aa.Kp[1]=P1+F;   aa.Vp[1]=P1+2*F; aa.O[1]=QQ1;
        aa.Q[2]=P0+3*F; aa.Kp[2]=P1+4*F; aa.Vp[2]=P1+5*F; aa.O[2]=QQ0+F;
        aa.Q[3]=P1+3*F; aa.Kp[3]=P0+4*F; aa.Vp[3]=P0+5*F; aa.O[3]=QQ1+F;
        attend_kernel<<<dim3(NPIX/4, 4), blk>>>(aa, 2*F);
    }

    // ---- launch 3: fused out-projections (K=512, split at 256), residual = feat ----
    {
        GemmPair gp = {};
        gp.A[0]=QQ0; gp.A[1]=QQ1;
        gp.B0[0]=wo0; gp.B1[0]=wo0+F;
        gp.B0[1]=wo1; gp.B1[1]=wo0+F;
        gp.bias[0]=out_b0; gp.bias2[0]=out_b0+F; gp.res[0]=feat0; gp.C[0]=T0;
        gp.bias[1]=out_b1; gp.bias2[1]=out_b0+F; gp.res[1]=feat1; gp.C[1]=T1;
        gemm_h16<<<dim3(F/128, MT, 2), blk, GEMM_SMEM>>>(gp, 2*F, 3*F, F, F, F, 2*F, 0);
    }

    // ---- launch 4: LN1 pair ----
    {
        LnArgs la;
        la.X[0]=T0; la.g[0]=ln1_g0; la.bt[0]=ln1_b0; la.O[0]=X0; la.Oh[0]=Xq0;
        la.X[1]=T1; la.g[1]=ln1_g1; la.bt[1]=ln1_b1; la.O[1]=X1; la.Oh[1]=Xq1;
        ln_kernel<<<dim3(NPIX, 2), blk>>>(la);
    }

    // ---- launch 5: FFN up pair (relu, fp16 out) ----
    {
        GemmPair gp = {};
        gp.A[0]=Xq0; gp.A[1]=Xq1;
        gp.B0[0]=wu0; gp.B1[0]=wu0;
        gp.B0[1]=wu1; gp.B1[1]=wu1;
        gp.bias[0]=ffn_up_b0; gp.bias[1]=ffn_up_b1;
        gp.Ch[0]=U0; gp.Ch[1]=U1;
        gemm_h16<<<dim3(HIDN/128, MT, 2), blk, GEMM_SMEM>>>(gp, F, F, F, 0, HIDN, F, 1);
    }

    // ---- launch 6: FFN down pair (residual X, fp32 out) ----
    {
        GemmPair gp = {};
        gp.A[0]=U0; gp.A[1]=U1;
        gp.B0[0]=wd0; gp.B1[0]=wd0;
        gp.B0[1]=wd1; gp.B1[1]=wd1;
        gp.bias[0]=ffn_down_b0; gp.bias[1]=ffn_down_b1;
        gp.res[0]=X0; gp.res[1]=X1;
        gp.C[0]=T0; gp.C[1]=T1;
        gemm_h16<<<dim3(F/128, MT, 2), blk, GEMM_SMEM>>>(gp, HIDN, HIDN, HIDN, F, F, HIDN, 0);
    }

    // ---- launch 7: LN2 pair -> output ----
    {
        LnArgs la;
        la.X[0]=T0; la.g[0]=ln2_g0; la.bt[0]=ln2_b0; la.O[0]=out; la.Oh[0]=nullptr;
        la.X[1]=T1; la.g[1]=ln2_g1; la.bt[1]=ln2_b1; la.O[1]=out + (size_t)NPIX*F; la.Oh[1]=nullptr;
        ln_kernel<<<dim3(NPIX, 2), blk>>>(la);
    }
}

// round 11
// speedup vs baseline: 4.7454x; 1.3374x over previous
#include <cuda_runtime.h>
#include <cuda_fp16.h>
#include <cstdint>
#include <cstddef>

#define F      256
#define NH     8
#define BATCH  2
#define HH     80
#define WW     80
#define NPIX   (BATCH*HH*WW)   // 12800
#define PDIM   1536
#define HIDN   1024

typedef __half h16;

// ---------------- scratch (no allocations allowed) ----------------
__device__ float g_X0[(size_t)NPIX*F];
__device__ float g_X1[(size_t)NPIX*F];

__device__ h16 g_P0[(size_t)NPIX*PDIM];
__device__ h16 g_P1[(size_t)NPIX*PDIM];
__device__ h16 g_f0[(size_t)NPIX*F];
__device__ h16 g_f1[(size_t)NPIX*F];
__device__ h16 g_wi0[(size_t)PDIM*F];
__device__ h16 g_wi1[(size_t)PDIM*F];
__device__ h16 g_wo0[(size_t)F*3*F];
__device__ h16 g_wo1[(size_t)F*3*F];
__device__ h16 g_wu0[(size_t)HIDN*F];
__device__ h16 g_wu1[(size_t)HIDN*F];
__device__ h16 g_wd0[(size_t)F*HIDN];
__device__ h16 g_wd1[(size_t)F*HIDN];
__device__ h16 g_QQ0[(size_t)NPIX*2*F];
__device__ h16 g_QQ1[(size_t)NPIX*2*F];
__device__ h16 g_Xq0[(size_t)NPIX*F];
__device__ h16 g_Xq1[(size_t)NPIX*F];
__device__ h16 g_U0[(size_t)NPIX*HIDN];
__device__ h16 g_U1[(size_t)NPIX*HIDN];

// ================= helpers =================
__device__ __forceinline__ uint32_t smem_u32(const void* p) {
    uint32_t a;
    asm("{ .reg .u64 t; cvta.to.shared.u64 t, %1; cvt.u32.u64 %0, t; }" : "=r"(a) : "l"(p));
    return a;
}
__device__ __forceinline__ void cpasync16(uint32_t dst, const void* src) {
    asm volatile("cp.async.cg.shared.global [%0], [%1], 16;" :: "r"(dst), "l"(src) : "memory");
}
__device__ __forceinline__ void ldsm4(uint32_t (&r)[4], uint32_t addr) {
    asm volatile("ldmatrix.sync.aligned.m8n8.x4.shared.b16 {%0,%1,%2,%3}, [%4];"
                 : "=r"(r[0]), "=r"(r[1]), "=r"(r[2]), "=r"(r[3]) : "r"(addr));
}
__device__ __forceinline__ void mma16816(float* d, const uint32_t* a, const uint32_t* b) {
    asm volatile("mma.sync.aligned.m16n8k16.row.col.f32.f16.f16.f32 "
                 "{%0,%1,%2,%3}, {%4,%5,%6,%7}, {%8,%9}, {%0,%1,%2,%3};"
                 : "+f"(d[0]), "+f"(d[1]), "+f"(d[2]), "+f"(d[3])
                 : "r"(a[0]), "r"(a[1]), "r"(a[2]), "r"(a[3]), "r"(b[0]), "r"(b[1]));
}

// ================= fp16 tensor GEMM 128x128 (paired over z) =================
#define STAGES     4
#define SMEM_STAGE 16384
#define OFF_B      8192u
#define GEMM_SMEM  (STAGES*SMEM_STAGE)

struct GemmPair {
    const h16 *A[2];
    const h16 *B0[2], *B1[2];
    const float *bias[2], *bias2[2], *res[2];
    float *C[2];
    h16 *Ch[2];
};

__global__ __launch_bounds__(256, 2) void gemm_h16(
    GemmPair gp, int lda, int ldb, int Ksplit,
    int ldres, int ldc, int K, int relu)
{
    extern __shared__ char smem[];
    const uint32_t sb0 = smem_u32(smem);

    const int z = blockIdx.z;
    const h16* __restrict__ A  = gp.A[z];
    const h16* __restrict__ B0 = gp.B0[z];
    const h16* __restrict__ B1 = gp.B1[z];
    const float* __restrict__ bias  = gp.bias[z];
    const float* __restrict__ bias2 = gp.bias2[z];
    const float* __restrict__ res   = gp.res[z];
    float* __restrict__ C  = gp.C[z];
    h16*   __restrict__ Ch = gp.Ch[z];

    const int tid  = threadIdx.x;
    const int wid  = tid >> 5;
    const int lane = tid & 31;
    const int brow = blockIdx.y * 128;
    const int bcol = blockIdx.x * 128;
    const int wm   = (wid >> 2) * 64;
    const int wn   = (wid & 3) * 32;

    float acc[4][4][4];
#pragma unroll
    for (int i = 0; i < 4; i++)
#pragma unroll
        for (int j = 0; j < 4; j++)
#pragma unroll
            for (int r = 0; r < 4; r++) acc[i][j][r] = 0.f;

    auto load_stage = [&](int cIdx) {
        const uint32_t sb = sb0 + (uint32_t)(cIdx % STAGES) * SMEM_STAGE;
        const int k0 = cIdx * 32;
        const h16* bp;
        int kk;
        if (k0 < Ksplit) { bp = B0; kk = k0; }
        else             { bp = B1; kk = k0 - Ksplit; }
#pragma unroll
        for (int s = 0; s < 4; s++) {
            const int qid = tid + s * 256;
            const int q   = qid & 511;
            const int row = q >> 2;
            const int c   = q & 3;
            const h16* src;
            uint32_t dstbase;
            if (qid < 512) {
                src = A + (size_t)(brow + row) * lda + k0 + c * 8;
                dstbase = sb;
            } else {
                src = bp + (size_t)(bcol + row) * ldb + kk + c * 8;
                dstbase = sb + OFF_B;
            }
            cpasync16(dstbase + (uint32_t)row * 64u +
                      (uint32_t)((c ^ ((row >> 1) & 3)) * 16), src);
        }
        asm volatile("cp.async.commit_group;" ::: "memory");
    };

    const int tile = lane >> 3;
    const int rin  = lane & 7;
    const uint32_t rsw = (uint32_t)(rin >> 1);

    const int NC = K / 32;
    for (int s = 0; s < STAGES - 1 && s < NC; s++) load_stage(s);

    for (int c = 0; c < NC; c++) {
        if (c + 3 <= NC) {
            asm volatile("cp.async.wait_group 2;" ::: "memory");
        } else if (c + 2 == NC) {
            asm volatile("cp.async.wait_group 1;" ::: "memory");
        } else {
            asm volatile("cp.async.wait_group 0;" ::: "memory");
        }
        __syncthreads();
        if (c + 3 < NC) load_stage(c + 3);

        const uint32_t sb = sb0 + (uint32_t)(c % STAGES) * SMEM_STAGE;
#pragma unroll
        for (int ks = 0; ks < 2; ks++) {
            uint32_t ah[4][4], bh_[2][4];
            const uint32_t swa = ((uint32_t)(ks * 2 + (tile >> 1)) ^ rsw) * 16u;
#pragma unroll
            for (int i = 0; i < 4; i++)
                ldsm4(ah[i], sb + (uint32_t)(wm + i * 16 + (tile & 1) * 8 + rin) * 64u + swa);
            const uint32_t swb = ((uint32_t)(ks * 2 + (tile & 1)) ^ rsw) * 16u;
#pragma unroll
            for (int jj = 0; jj < 2; jj++)
                ldsm4(bh_[jj], sb + OFF_B +
                      (uint32_t)(wn + jj * 16 + (tile >> 1) * 8 + rin) * 64u + swb);
#pragma unroll
            for (int i = 0; i < 4; i++)
#pragma unroll
                for (int j = 0; j < 4; j++)
                    mma16816(acc[i][j], ah[i], &bh_[j >> 1][(j & 1) * 2]);
        }
    }

    const int tq = lane >> 2;
    const int tr = (lane & 3) * 2;
    float bj0[4], bj1[4];
#pragma unroll
    for (int j = 0; j < 4; j++) {
        const int n = bcol + wn + 8 * j + tr;
        float b0 = bias[n], b1 = bias[n + 1];
        if (bias2) { b0 += bias2[n]; b1 += bias2[n + 1]; }
        bj0[j] = b0; bj1[j] = b1;
    }
#pragma unroll
    for (int i = 0; i < 4; i++)
#pragma unroll
        for (int half = 0; half < 2; half++) {
            const int m = brow + wm + 16 * i + tq + half * 8;
#pragma unroll
            for (int j = 0; j < 4; j++) {
                const int n = bcol + wn + 8 * j + tr;
                float v0 = acc[i][j][half * 2 + 0] + bj0[j];
                float v1 = acc[i][j][half * 2 + 1] + bj1[j];
                if (res) {
                    float2 r = *(const float2*)(res + (size_t)m * ldres + n);
                    v0 += r.x; v1 += r.y;
                }
                if (relu) { v0 = fmaxf(v0, 0.f); v1 = fmaxf(v1, 0.f); }
                if (C) *(float2*)(C + (size_t)m * ldc + n) = make_float2(v0, v1);
                if (Ch)
                    *(__half2*)(Ch + (size_t)m * ldc + n) =
                        __halves2half2(__float2half_rn(v0), __float2half_rn(v1));
            }
        }
}

// ================= fp16 GEMM 128x256 + fused LayerNorm (paired over z) =================
// N = 256 = full LN row per CTA. 8 warps of 64x64.
// out = g * (v - mean)/sqrt(var+eps) + bt, v = A@W^T + bias (+bias2) + res
#define LSTAGES    4
#define LSTAGE_SZ  24576
#define LOFF_B     8192u
#define GEMMLN_SMEM (LSTAGES*LSTAGE_SZ)

struct GemmLnPair {
    const h16 *A[2];
    const h16 *B0[2], *B1[2];
    const float *bias[2], *bias2[2], *res[2];
    const float *g[2], *bt[2];
    float *O[2];
    h16 *Oh[2];
};

__global__ __launch_bounds__(256, 1) void gemm_ln(
    GemmLnPair gp, int lda, int ldb, int Ksplit, int ldres, int K)
{
    extern __shared__ char smem[];
    const uint32_t sb0 = smem_u32(smem);

    const int z = blockIdx.z;
    const h16* __restrict__ A  = gp.A[z];
    const h16* __restrict__ B0 = gp.B0[z];
    const h16* __restrict__ B1 = gp.B1[z];
    const float* __restrict__ bias  = gp.bias[z];
    const float* __restrict__ bias2 = gp.bias2[z];
    const float* __restrict__ res   = gp.res[z];
    const float* __restrict__ gam   = gp.g[z];
    const float* __restrict__ bet   = gp.bt[z];
    float* __restrict__ O  = gp.O[z];
    h16*   __restrict__ Oh = gp.Oh[z];

    const int tid  = threadIdx.x;
    const int wid  = tid >> 5;
    const int lane = tid & 31;
    const int brow = blockIdx.y * 128;
    const int wm   = (wid >> 2) * 64;   // 0 or 64
    const int wn   = (wid & 3) * 64;    // 0,64,128,192

    float acc[4][8][4];
#pragma unroll
    for (int i = 0; i < 4; i++)
#pragma unroll
        for (int j = 0; j < 8; j++)
#pragma unroll
            for (int r = 0; r < 4; r++) acc[i][j][r] = 0.f;

    // loader: A 512 quads + B 1024 quads = 1536, 6/thread
    auto load_stage = [&](int cIdx) {
        const uint32_t sb = sb0 + (uint32_t)(cIdx % LSTAGES) * LSTAGE_SZ;
        const int k0 = cIdx * 32;
        const h16* bp;
        int kk;
        if (k0 < Ksplit) { bp = B0; kk = k0; }
        else             { bp = B1; kk = k0 - Ksplit; }
#pragma unroll
        for (int s = 0; s < 6; s++) {
            const int qid = tid + s * 256;
            const h16* src;
            uint32_t dstbase;
            int row, c;
            if (qid < 512) {
                row = qid >> 2; c = qid & 3;
                src = A + (size_t)(brow + row) * lda + k0 + c * 8;
                dstbase = sb;
            } else {
                const int q2 = qid - 512;
                row = q2 >> 2; c = q2 & 3;
                src = bp + (size_t)row * ldb + kk + c * 8;
                dstbase = sb + LOFF_B;
            }
            cpasync16(dstbase + (uint32_t)row * 64u +
                      (uint32_t)((c ^ ((row >> 1) & 3)) * 16), src);
        }
        asm volatile("cp.async.commit_group;" ::: "memory");
    };

    const int tile = lane >> 3;
    const int rin  = lane & 7;
    const uint32_t rsw = (uint32_t)(rin >> 1);

    const int NC = K / 32;
    for (int s = 0; s < LSTAGES - 1 && s < NC; s++) load_stage(s);

    for (int c = 0; c < NC; c++) {
        if (c + 3 <= NC) {
            asm volatile("cp.async.wait_group 2;" ::: "memory");
        } else if (c + 2 == NC) {
            asm volatile("cp.async.wait_group 1;" ::: "memory");
        } else {
            asm volatile("cp.async.wait_group 0;" ::: "memory");
        }
        __syncthreads();
        if (c + 3 < NC) load_stage(c + 3);

        const uint32_t sb = sb0 + (uint32_t)(c % LSTAGES) * LSTAGE_SZ;
#pragma unroll
        for (int ks = 0; ks < 2; ks++) {
            uint32_t ah[4][4], bh_[4][4];
            const uint32_t swa = ((uint32_t)(ks * 2 + (tile >> 1)) ^ rsw) * 16u;
#pragma unroll
            for (int i = 0; i < 4; i++)
                ldsm4(ah[i], sb + (uint32_t)(wm + i * 16 + (tile & 1) * 8 + rin) * 64u + swa);
            const uint32_t swb = ((uint32_t)(ks * 2 + (tile & 1)) ^ rsw) * 16u;
#pragma unroll
            for (int jj = 0; jj < 4; jj++)
                ldsm4(bh_[jj], sb + LOFF_B +
                      (uint32_t)(wn + jj * 16 + (tile >> 1) * 8 + rin) * 64u + swb);
#pragma unroll
            for (int i = 0; i < 4; i++)
#pragma unroll
                for (int j = 0; j < 8; j++)
                    mma16816(acc[i][j], ah[i], &bh_[j >> 1][(j & 1) * 2]);
        }
    }

    // ---------- fused LayerNorm epilogue ----------
    __syncthreads();   // smem stages done; reuse for reductions
    float* redS = (float*)smem;          // [128][4]
    float* redQ = (float*)smem + 512;    // [128][4]

    const int tq = lane >> 2;
    const int tr = (lane & 3) * 2;
    const int wslot = wn >> 6;

    float bj0[8], bj1[8];
#pragma unroll
    for (int j = 0; j < 8; j++) {
        const int n = wn + 8 * j + tr;
        float b0 = bias[n], b1 = bias[n + 1];
        if (bias2) { b0 += bias2[n]; b1 += bias2[n + 1]; }
        bj0[j] = b0; bj1[j] = b1;
    }

#pragma unroll
    for (int i = 0; i < 4; i++)
#pragma unroll
        for (int half = 0; half < 2; half++) {
            const int mrow = wm + 16 * i + 8 * half + tq;
            const int m = brow + mrow;
            float s1 = 0.f, s2 = 0.f;
#pragma unroll
            for (int j = 0; j < 8; j++) {
                float v0 = acc[i][j][half * 2 + 0] + bj0[j];
                float v1 = acc[i][j][half * 2 + 1] + bj1[j];
                if (res) {
                    float2 rr = *(const float2*)(res + (size_t)m * ldres + wn + 8 * j + tr);
                    v0 += rr.x; v1 += rr.y;
                }
                acc[i][j][half * 2 + 0] = v0;
                acc[i][j][half * 2 + 1] = v1;
                s1 += v0 + v1;
                s2 += v0 * v0 + v1 * v1;
            }
            s1 += __shfl_xor_sync(0xffffffffu, s1, 1);
            s2 += __shfl_xor_sync(0xffffffffu, s2, 1);
            s1 += __shfl_xor_sync(0xffffffffu, s1, 2);
            s2 += __shfl_xor_sync(0xffffffffu, s2, 2);
            if ((lane & 3) == 0) {
                redS[mrow * 4 + wslot] = s1;
                redQ[mrow * 4 + wslot] = s2;
            }
        }
    __syncthreads();

    float gj0[8], gj1[8], tj0[8], tj1[8];
#pragma unroll
    for (int j = 0; j < 8; j++) {
        const int n = wn + 8 * j + tr;
        float2 gg = *(const float2*)(gam + n);
        float2 bb = *(const float2*)(bet + n);
        gj0[j] = gg.x; gj1[j] = gg.y;
        tj0[j] = bb.x; tj1[j] = bb.y;
    }

#pragma unroll
    for (int i = 0; i < 4; i++)
#pragma unroll
        for (int half = 0; half < 2; half++) {
            const int mrow = wm + 16 * i + 8 * half + tq;
            const int m = brow + mrow;
            float tS = redS[mrow * 4 + 0] + redS[mrow * 4 + 1]
                     + redS[mrow * 4 + 2] + redS[mrow * 4 + 3];
            float tQ = redQ[mrow * 4 + 0] + redQ[mrow * 4 + 1]
                     + redQ[mrow * 4 + 2] + redQ[mrow * 4 + 3];
            float mean = tS * (1.0f / F);
            float var  = tQ * (1.0f / F) - mean * mean;
            float rstd = rsqrtf(var + 1e-5f);
#pragma unroll
            for (int j = 0; j < 8; j++) {
                const int n = wn + 8 * j + tr;
                float o0 = gj0[j] * (acc[i][j][half * 2 + 0] - mean) * rstd + tj0[j];
                float o1 = gj1[j] * (acc[i][j][half * 2 + 1] - mean) * rstd + tj1[j];
                if (O) *(float2*)(O + (size_t)m * F + n) = make_float2(o0, o1);
                if (Oh)
                    *(__half2*)(Oh + (size_t)m * F + n) =
                        __halves2half2(__float2half_rn(o0), __float2half_rn(o1));
            }
        }
}

// ---------------- merged convert fp32 -> fp16 ----------------
#define NSEG 10
struct ConvArgs {
    const float* s[NSEG];
    h16* h[NSEG];
    int end4[NSEG];
};

__global__ __launch_bounds__(256) void conv_all(ConvArgs a, int total4)
{
    int i = blockIdx.x * 256 + threadIdx.x;
    if (i >= total4) return;
    int seg = 0;
#pragma unroll
    for (int s = 0; s < NSEG - 1; s++) seg += (i >= a.end4[s]) ? 1 : 0;
    const int base = seg ? a.end4[seg - 1] : 0;
    const int j = i - base;

    float4 v = ((const float4*)a.s[seg])[j];
    h16* hp = a.h[seg];
    ((__half2*)hp)[2 * j]     = __halves2half2(__float2half_rn(v.x), __float2half_rn(v.y));
    ((__half2*)hp)[2 * j + 1] = __halves2half2(__float2half_rn(v.z), __float2half_rn(v.w));
}

// ---------------- 9-tap windowed multi-head attention (fp16 in, 4 fused via y) ----------------
struct AttArgs {
    const h16* Q[4];
    const h16* Kp[4];
    const h16* Vp[4];
    h16* O[4];
};

__global__ __launch_bounds__(256) void attend_kernel(AttArgs a, int ostride)
{
    const int z   = blockIdx.y;
    const int t   = threadIdx.x & 63;
    const int pix = blockIdx.x * 4 + (threadIdx.x >> 6);
    const int b   = pix / (HH * WW);
    const int r   = pix % (HH * WW);
    const int y   = r / WW;
    const int x   = r % WW;
    const int ch  = t * 4;

    const h16* __restrict__ Q  = a.Q[z];
    const h16* __restrict__ Kp = a.Kp[z];
    const h16* __restrict__ Vp = a.Vp[z];

    const float scale = 0.17677669529663687f;
    float qf[4];
    {
        uint2 qr = *(const uint2*)(Q + (size_t)pix * PDIM + ch);
        float2 a0 = __half22float2(*(__half2*)&qr.x);
        float2 a1 = __half22float2(*(__half2*)&qr.y);
        qf[0] = a0.x * scale; qf[1] = a0.y * scale;
        qf[2] = a1.x * scale; qf[3] = a1.y * scale;
    }

    float  sc[9];
    float4 vv[9];
#pragma unroll
    for (int n = 0; n < 9; n++) {
        int dy = n / 3 - 1, dx = n % 3 - 1;
        int yy = y + dy, xx = x + dx;
        float s = 0.f;
        float4 v = make_float4(0.f, 0.f, 0.f, 0.f);
        if (yy >= 0 && yy < HH && xx >= 0 && xx < WW) {
            size_t np = ((size_t)(b * HH + yy) * WW + xx) * PDIM + ch;
            uint2 kr = *(const uint2*)(Kp + np);
            uint2 vr = *(const uint2*)(Vp + np);
            float2 k0 = __half22float2(*(__half2*)&kr.x);
            float2 k1 = __half22float2(*(__half2*)&kr.y);
            float2 v0 = __half22float2(*(__half2*)&vr.x);
            float2 v1 = __half22float2(*(__half2*)&vr.y);
            s = qf[0] * k0.x + qf[1] * k0.y + qf[2] * k1.x + qf[3] * k1.y;
            v = make_float4(v0.x, v0.y, v1.x, v1.y);
        }
        s += __shfl_xor_sync(0xffffffffu, s, 4);
        s += __shfl_xor_sync(0xffffffffu, s, 2);
        s += __shfl_xor_sync(0xffffffffu, s, 1);
        sc[n] = s;
        vv[n] = v;
    }

    float mx = sc[0];
#pragma unroll
    for (int n = 1; n < 9; n++) mx = fmaxf(mx, sc[n]);
    float den = 0.f;
    float4 o = make_float4(0.f, 0.f, 0.f, 0.f);
#pragma unroll
    for (int n = 0; n < 9; n++) {
        float w = __expf(sc[n] - mx);
        den += w;
        o.x += w * vv[n].x; o.y += w * vv[n].y;
        o.z += w * vv[n].z; o.w += w * vv[n].w;
    }
    float inv = 1.f / den;
    size_t base = (size_t)pix * ostride + ch;
    *(__half2*)(a.O[z] + base) =
        __halves2half2(__float2half_rn(o.x * inv), __float2half_rn(o.y * inv));
    *(__half2*)(a.O[z] + base + 2) =
        __halves2half2(__float2half_rn(o.z * inv), __float2half_rn(o.w * inv));
}

// ---------------- launch ----------------
#define SYM(p, s) cudaGetSymbolAddress((void**)&p, s)

extern "C" void kernel_launch(void* const* d_in, const int* in_sizes, int n_in,
                              void* d_out, int out_size)
{
    const float* feat0       = (const float*)d_in[0];
    const float* feat1       = (const float*)d_in[1];
    const float* in_w0       = (const float*)d_in[2];
    const float* in_b0       = (const float*)d_in[3];
    const float* in_w1       = (const float*)d_in[4];
    const float* in_b1       = (const float*)d_in[5];
    const float* out_w0      = (const float*)d_in[6];
    const float* out_b0      = (const float*)d_in[7];
    const float* out_w1      = (const float*)d_in[8];
    const float* out_b1      = (const float*)d_in[9];
    const float* ln1_g0      = (const float*)d_in[10];
    const float* ln1_b0      = (const float*)d_in[11];
    const float* ln1_g1      = (const float*)d_in[12];
    const float* ln1_b1      = (const float*)d_in[13];
    const float* ffn_up_w0   = (const float*)d_in[14];
    const float* ffn_up_b0   = (const float*)d_in[15];
    const float* ffn_down_w0 = (const float*)d_in[16];
    const float* ffn_down_b0 = (const float*)d_in[17];
    const float* ffn_up_w1   = (const float*)d_in[18];
    const float* ffn_up_b1   = (const float*)d_in[19];
    const float* ffn_down_w1 = (const float*)d_in[20];
    const float* ffn_down_b1 = (const float*)d_in[21];
    const float* ln2_g0      = (const float*)d_in[22];
    const float* ln2_b0      = (const float*)d_in[23];
    const float* ln2_g1      = (const float*)d_in[24];
    const float* ln2_b1      = (const float*)d_in[25];

    float *X0, *X1;
    SYM(X0, g_X0); SYM(X1, g_X1);
    h16 *P0, *P1, *f0, *f1, *wi0, *wi1, *wo0, *wo1, *wu0, *wu1, *wd0, *wd1;
    h16 *QQ0, *QQ1, *Xq0, *Xq1, *U0, *U1;
    SYM(P0, g_P0); SYM(P1, g_P1);
    SYM(f0, g_f0); SYM(f1, g_f1);
    SYM(wi0, g_wi0); SYM(wi1, g_wi1);
    SYM(wo0, g_wo0); SYM(wo1, g_wo1);
    SYM(wu0, g_wu0); SYM(wu1, g_wu1);
    SYM(wd0, g_wd0); SYM(wd1, g_wd1);
    SYM(QQ0, g_QQ0); SYM(QQ1, g_QQ1); SYM(Xq0, g_Xq0); SYM(Xq1, g_Xq1);
    SYM(U0, g_U0); SYM(U1, g_U1);

    cudaFuncSetAttribute(gemm_h16, cudaFuncAttributeMaxDynamicSharedMemorySize, GEMM_SMEM);
    cudaFuncSetAttribute(gemm_ln,  cudaFuncAttributeMaxDynamicSharedMemorySize, GEMMLN_SMEM);

    float* out = (float*)d_out;
    dim3 blk(256);
    const int MT = NPIX / 128;   // 100

    // ---- launch 0: all converts ----
    {
        ConvArgs ca;
        const float* srcs[NSEG] = {feat0, feat1, in_w0, in_w1, out_w0, out_w1,
                                   ffn_up_w0, ffn_up_w1, ffn_down_w0, ffn_down_w1};
        h16* hs[NSEG] = {f0, f1, wi0, wi1, wo0, wo1, wu0, wu1, wd0, wd1};
        int sizes4[NSEG] = {NPIX*F/4, NPIX*F/4, PDIM*F/4, PDIM*F/4, F*3*F/4, F*3*F/4,
                            HIDN*F/4, HIDN*F/4, F*HIDN/4, F*HIDN/4};
        int acc4 = 0;
        for (int i = 0; i < NSEG; i++) {
            ca.s[i] = srcs[i]; ca.h[i] = hs[i];
            acc4 += sizes4[i];
            ca.end4[i] = acc4;
        }
        conv_all<<<(acc4 + 255) / 256, blk>>>(ca, acc4);
    }

    // ---- launch 1: in-projection GEMMs -> P fp16 ----
    {
        GemmPair gp = {};
        gp.A[0]=f0; gp.A[1]=f1;
        gp.B0[0]=wi0; gp.B1[0]=wi0;
        gp.B0[1]=wi1; gp.B1[1]=wi1;
        gp.bias[0]=in_b0; gp.bias[1]=in_b1;
        gp.Ch[0]=P0; gp.Ch[1]=P1;
        gemm_h16<<<dim3(PDIM/128, MT, 2), blk, GEMM_SMEM>>>(gp, F, F, F, 0, PDIM, F, 0);
    }

    // ---- launch 2: 4 attentions (fp16 in) -> QQ fp16 ----
    {
        AttArgs aa;
        aa.Q[0]=P0;     aa.Kp[0]=P0+F;   aa.Vp[0]=P0+2*F; aa.O[0]=QQ0;
        aa.Q[1]=P1;     aa.Kp[1]=P1+F;   aa.Vp[1]=P1+2*F; aa.O[1]=QQ1;
        aa.Q[2]=P0+3*F; aa.Kp[2]=P1+4*F; aa.Vp[2]=P1+5*F; aa.O[2]=QQ0+F;
        aa.Q[3]=P1+3*F; aa.Kp[3]=P0+4*F; aa.Vp[3]=P0+5*F; aa.O[3]=QQ1+F;
        attend_kernel<<<dim3(NPIX/4, 4), blk>>>(aa, 2*F);
    }

    // ---- launch 3: out-projection (K=512, split at 256) + residual + LN1 fused ----
    {
        GemmLnPair gp = {};
        gp.A[0]=QQ0; gp.A[1]=QQ1;
        gp.B0[0]=wo0; gp.B1[0]=wo0+F;
        gp.B0[1]=wo1; gp.B1[1]=wo0+F;
        gp.bias[0]=out_b0; gp.bias2[0]=out_b0+F; gp.res[0]=feat0;
        gp.bias[1]=out_b1; gp.bias2[1]=out_b0+F; gp.res[1]=feat1;
        gp.g[0]=ln1_g0; gp.bt[0]=ln1_b0; gp.O[0]=X0; gp.Oh[0]=Xq0;
        gp.g[1]=ln1_g1; gp.bt[1]=ln1_b1; gp.O[1]=X1; gp.Oh[1]=Xq1;
        gemm_ln<<<dim3(1, MT, 2), blk, GEMMLN_SMEM>>>(gp, 2*F, 3*F, F, F, 2*F);
    }

    // ---- launch 4: FFN up pair (relu, fp16 out) ----
    {
        GemmPair gp = {};
        gp.A[0]=Xq0; gp.A[1]=Xq1;
        gp.B0[0]=wu0; gp.B1[0]=wu0;
        gp.B0[1]=wu1; gp.B1[1]=wu1;
        gp.bias[0]=ffn_up_b0; gp.bias[1]=ffn_up_b1;
        gp.Ch[0]=U0; gp.Ch[1]=U1;
        gemm_h16<<<dim3(HIDN/128, MT, 2), blk, GEMM_SMEM>>>(gp, F, F, F, 0, HIDN, F, 1);
    }

    // ---- launch 5: FFN down (K=1024) + residual X + LN2 fused -> output ----
    {
        GemmLnPair gp = {};
        gp.A[0]=U0; gp.A[1]=U1;
        gp.B0[0]=wd0; gp.B1[0]=wd0;
        gp.B0[1]=wd1; gp.B1[1]=wd1;
        gp.bias[0]=ffn_down_b0; gp.res[0]=X0;
        gp.bias[1]=ffn_down_b1; gp.res[1]=X1;
        gp.g[0]=ln2_g0; gp.bt[0]=ln2_b0; gp.O[0]=out;
        gp.g[1]=ln2_g1; gp.bt[1]=ln2_b1; gp.O[1]=out + (size_t)NPIX*F;
        gemm_ln<<<dim3(1, MT, 2), blk, GEMMLN_SMEM>>>(gp, HIDN, HIDN, HIDN, F, HIDN);
    }
}

// round 12
// speedup vs baseline: 5.1152x; 1.0779x over previous
#include <cuda_runtime.h>
#include <cuda_fp16.h>
#include <cstdint>
#include <cstddef>

#define F      256
#define NH     8
#define BATCH  2
#define HH     80
#define WW     80
#define NPIX   (BATCH*HH*WW)   // 12800
#define PDIM   1536
#define HIDN   1024

typedef __half h16;

// ---------------- scratch (no allocations allowed) ----------------
__device__ float g_X0[(size_t)NPIX*F];
__device__ float g_X1[(size_t)NPIX*F];

__device__ h16 g_P0[(size_t)NPIX*PDIM];
__device__ h16 g_P1[(size_t)NPIX*PDIM];
__device__ h16 g_f0[(size_t)NPIX*F];
__device__ h16 g_f1[(size_t)NPIX*F];
__device__ h16 g_wi0[(size_t)PDIM*F];
__device__ h16 g_wi1[(size_t)PDIM*F];
__device__ h16 g_wo0[(size_t)F*3*F];
__device__ h16 g_wo1[(size_t)F*3*F];
__device__ h16 g_wu0[(size_t)HIDN*F];
__device__ h16 g_wu1[(size_t)HIDN*F];
__device__ h16 g_wd0[(size_t)F*HIDN];
__device__ h16 g_wd1[(size_t)F*HIDN];
__device__ h16 g_QQ0[(size_t)NPIX*2*F];
__device__ h16 g_QQ1[(size_t)NPIX*2*F];
__device__ h16 g_Xq0[(size_t)NPIX*F];
__device__ h16 g_Xq1[(size_t)NPIX*F];

// ================= helpers =================
__device__ __forceinline__ uint32_t smem_u32(const void* p) {
    uint32_t a;
    asm("{ .reg .u64 t; cvta.to.shared.u64 t, %1; cvt.u32.u64 %0, t; }" : "=r"(a) : "l"(p));
    return a;
}
__device__ __forceinline__ void cpasync16(uint32_t dst, const void* src) {
    asm volatile("cp.async.cg.shared.global [%0], [%1], 16;" :: "r"(dst), "l"(src) : "memory");
}
__device__ __forceinline__ void ldsm4(uint32_t (&r)[4], uint32_t addr) {
    asm volatile("ldmatrix.sync.aligned.m8n8.x4.shared.b16 {%0,%1,%2,%3}, [%4];"
                 : "=r"(r[0]), "=r"(r[1]), "=r"(r[2]), "=r"(r[3]) : "r"(addr));
}
__device__ __forceinline__ void mma16816(float* d, const uint32_t* a, const uint32_t* b) {
    asm volatile("mma.sync.aligned.m16n8k16.row.col.f32.f16.f16.f32 "
                 "{%0,%1,%2,%3}, {%4,%5,%6,%7}, {%8,%9}, {%0,%1,%2,%3};"
                 : "+f"(d[0]), "+f"(d[1]), "+f"(d[2]), "+f"(d[3])
                 : "r"(a[0]), "r"(a[1]), "r"(a[2]), "r"(a[3]), "r"(b[0]), "r"(b[1]));
}

// ================= fp16 tensor GEMM 128x128 (paired over z) =================
#define STAGES     4
#define SMEM_STAGE 16384
#define OFF_B      8192u
#define GEMM_SMEM  (STAGES*SMEM_STAGE)

struct GemmPair {
    const h16 *A[2];
    const h16 *B0[2], *B1[2];
    const float *bias[2], *bias2[2], *res[2];
    float *C[2];
    h16 *Ch[2];
};

__global__ __launch_bounds__(256, 2) void gemm_h16(
    GemmPair gp, int lda, int ldb, int Ksplit,
    int ldres, int ldc, int K, int relu)
{
    extern __shared__ char smem[];
    const uint32_t sb0 = smem_u32(smem);

    const int z = blockIdx.z;
    const h16* __restrict__ A  = gp.A[z];
    const h16* __restrict__ B0 = gp.B0[z];
    const h16* __restrict__ B1 = gp.B1[z];
    const float* __restrict__ bias  = gp.bias[z];
    const float* __restrict__ bias2 = gp.bias2[z];
    const float* __restrict__ res   = gp.res[z];
    float* __restrict__ C  = gp.C[z];
    h16*   __restrict__ Ch = gp.Ch[z];

    const int tid  = threadIdx.x;
    const int wid  = tid >> 5;
    const int lane = tid & 31;
    const int brow = blockIdx.y * 128;
    const int bcol = blockIdx.x * 128;
    const int wm   = (wid >> 2) * 64;
    const int wn   = (wid & 3) * 32;

    float acc[4][4][4];
#pragma unroll
    for (int i = 0; i < 4; i++)
#pragma unroll
        for (int j = 0; j < 4; j++)
#pragma unroll
            for (int r = 0; r < 4; r++) acc[i][j][r] = 0.f;

    auto load_stage = [&](int cIdx) {
        const uint32_t sb = sb0 + (uint32_t)(cIdx % STAGES) * SMEM_STAGE;
        const int k0 = cIdx * 32;
        const h16* bp;
        int kk;
        if (k0 < Ksplit) { bp = B0; kk = k0; }
        else             { bp = B1; kk = k0 - Ksplit; }
#pragma unroll
        for (int s = 0; s < 4; s++) {
            const int qid = tid + s * 256;
            const int q   = qid & 511;
            const int row = q >> 2;
            const int c   = q & 3;
            const h16* src;
            uint32_t dstbase;
            if (qid < 512) {
                src = A + (size_t)(brow + row) * lda + k0 + c * 8;
                dstbase = sb;
            } else {
                src = bp + (size_t)(bcol + row) * ldb + kk + c * 8;
                dstbase = sb + OFF_B;
            }
            cpasync16(dstbase + (uint32_t)row * 64u +
                      (uint32_t)((c ^ ((row >> 1) & 3)) * 16), src);
        }
        asm volatile("cp.async.commit_group;" ::: "memory");
    };

    const int tile = lane >> 3;
    const int rin  = lane & 7;
    const uint32_t rsw = (uint32_t)(rin >> 1);

    const int NC = K / 32;
    for (int s = 0; s < STAGES - 1 && s < NC; s++) load_stage(s);

    for (int c = 0; c < NC; c++) {
        if (c + 3 <= NC) {
            asm volatile("cp.async.wait_group 2;" ::: "memory");
        } else if (c + 2 == NC) {
            asm volatile("cp.async.wait_group 1;" ::: "memory");
        } else {
            asm volatile("cp.async.wait_group 0;" ::: "memory");
        }
        __syncthreads();
        if (c + 3 < NC) load_stage(c + 3);

        const uint32_t sb = sb0 + (uint32_t)(c % STAGES) * SMEM_STAGE;
#pragma unroll
        for (int ks = 0; ks < 2; ks++) {
            uint32_t ah[4][4], bh_[2][4];
            const uint32_t swa = ((uint32_t)(ks * 2 + (tile >> 1)) ^ rsw) * 16u;
#pragma unroll
            for (int i = 0; i < 4; i++)
                ldsm4(ah[i], sb + (uint32_t)(wm + i * 16 + (tile & 1) * 8 + rin) * 64u + swa);
            const uint32_t swb = ((uint32_t)(ks * 2 + (tile & 1)) ^ rsw) * 16u;
#pragma unroll
            for (int jj = 0; jj < 2; jj++)
                ldsm4(bh_[jj], sb + OFF_B +
                      (uint32_t)(wn + jj * 16 + (tile >> 1) * 8 + rin) * 64u + swb);
#pragma unroll
            for (int i = 0; i < 4; i++)
#pragma unroll
                for (int j = 0; j < 4; j++)
                    mma16816(acc[i][j], ah[i], &bh_[j >> 1][(j & 1) * 2]);
        }
    }

    const int tq = lane >> 2;
    const int tr = (lane & 3) * 2;
    float bj0[4], bj1[4];
#pragma unroll
    for (int j = 0; j < 4; j++) {
        const int n = bcol + wn + 8 * j + tr;
        float b0 = bias[n], b1 = bias[n + 1];
        if (bias2) { b0 += bias2[n]; b1 += bias2[n + 1]; }
        bj0[j] = b0; bj1[j] = b1;
    }
#pragma unroll
    for (int i = 0; i < 4; i++)
#pragma unroll
        for (int half = 0; half < 2; half++) {
            const int m = brow + wm + 16 * i + tq + half * 8;
#pragma unroll
            for (int j = 0; j < 4; j++) {
                const int n = bcol + wn + 8 * j + tr;
                float v0 = acc[i][j][half * 2 + 0] + bj0[j];
                float v1 = acc[i][j][half * 2 + 1] + bj1[j];
                if (res) {
                    float2 r = *(const float2*)(res + (size_t)m * ldres + n);
                    v0 += r.x; v1 += r.y;
                }
                if (relu) { v0 = fmaxf(v0, 0.f); v1 = fmaxf(v1, 0.f); }
                if (C) *(float2*)(C + (size_t)m * ldc + n) = make_float2(v0, v1);
                if (Ch)
                    *(__half2*)(Ch + (size_t)m * ldc + n) =
                        __halves2half2(__float2half_rn(v0), __float2half_rn(v1));
            }
        }
}

// ================= fp16 GEMM 128x256 + fused LayerNorm (paired over z) =================
#define LSTAGES    4
#define LSTAGE_SZ  24576
#define LOFF_B     8192u
#define GEMMLN_SMEM (LSTAGES*LSTAGE_SZ)

struct GemmLnPair {
    const h16 *A[2];
    const h16 *B0[2], *B1[2];
    const float *bias[2], *bias2[2], *res[2];
    const float *g[2], *bt[2];
    float *O[2];
    h16 *Oh[2];
};

__global__ __launch_bounds__(256, 1) void gemm_ln(
    GemmLnPair gp, int lda, int ldb, int Ksplit, int ldres, int K)
{
    extern __shared__ char smem[];
    const uint32_t sb0 = smem_u32(smem);

    const int z = blockIdx.z;
    const h16* __restrict__ A  = gp.A[z];
    const h16* __restrict__ B0 = gp.B0[z];
    const h16* __restrict__ B1 = gp.B1[z];
    const float* __restrict__ bias  = gp.bias[z];
    const float* __restrict__ bias2 = gp.bias2[z];
    const float* __restrict__ res   = gp.res[z];
    const float* __restrict__ gam   = gp.g[z];
    const float* __restrict__ bet   = gp.bt[z];
    float* __restrict__ O  = gp.O[z];
    h16*   __restrict__ Oh = gp.Oh[z];

    const int tid  = threadIdx.x;
    const int wid  = tid >> 5;
    const int lane = tid & 31;
    const int brow = blockIdx.y * 128;
    const int wm   = (wid >> 2) * 64;
    const int wn   = (wid & 3) * 64;

    float acc[4][8][4];
#pragma unroll
    for (int i = 0; i < 4; i++)
#pragma unroll
        for (int j = 0; j < 8; j++)
#pragma unroll
            for (int r = 0; r < 4; r++) acc[i][j][r] = 0.f;

    auto load_stage = [&](int cIdx) {
        const uint32_t sb = sb0 + (uint32_t)(cIdx % LSTAGES) * LSTAGE_SZ;
        const int k0 = cIdx * 32;
        const h16* bp;
        int kk;
        if (k0 < Ksplit) { bp = B0; kk = k0; }
        else             { bp = B1; kk = k0 - Ksplit; }
#pragma unroll
        for (int s = 0; s < 6; s++) {
            const int qid = tid + s * 256;
            const h16* src;
            uint32_t dstbase;
            int row, c;
            if (qid < 512) {
                row = qid >> 2; c = qid & 3;
                src = A + (size_t)(brow + row) * lda + k0 + c * 8;
                dstbase = sb;
            } else {
                const int q2 = qid - 512;
                row = q2 >> 2; c = q2 & 3;
                src = bp + (size_t)row * ldb + kk + c * 8;
                dstbase = sb + LOFF_B;
            }
            cpasync16(dstbase + (uint32_t)row * 64u +
                      (uint32_t)((c ^ ((row >> 1) & 3)) * 16), src);
        }
        asm volatile("cp.async.commit_group;" ::: "memory");
    };

    const int tile = lane >> 3;
    const int rin  = lane & 7;
    const uint32_t rsw = (uint32_t)(rin >> 1);

    const int NC = K / 32;
    for (int s = 0; s < LSTAGES - 1 && s < NC; s++) load_stage(s);

    for (int c = 0; c < NC; c++) {
        if (c + 3 <= NC) {
            asm volatile("cp.async.wait_group 2;" ::: "memory");
        } else if (c + 2 == NC) {
            asm volatile("cp.async.wait_group 1;" ::: "memory");
        } else {
            asm volatile("cp.async.wait_group 0;" ::: "memory");
        }
        __syncthreads();
        if (c + 3 < NC) load_stage(c + 3);

        const uint32_t sb = sb0 + (uint32_t)(c % LSTAGES) * LSTAGE_SZ;
#pragma unroll
        for (int ks = 0; ks < 2; ks++) {
            uint32_t ah[4][4], bh_[4][4];
            const uint32_t swa = ((uint32_t)(ks * 2 + (tile >> 1)) ^ rsw) * 16u;
#pragma unroll
            for (int i = 0; i < 4; i++)
                ldsm4(ah[i], sb + (uint32_t)(wm + i * 16 + (tile & 1) * 8 + rin) * 64u + swa);
            const uint32_t swb = ((uint32_t)(ks * 2 + (tile & 1)) ^ rsw) * 16u;
#pragma unroll
            for (int jj = 0; jj < 4; jj++)
                ldsm4(bh_[jj], sb + LOFF_B +
                      (uint32_t)(wn + jj * 16 + (tile >> 1) * 8 + rin) * 64u + swb);
#pragma unroll
            for (int i = 0; i < 4; i++)
#pragma unroll
                for (int j = 0; j < 8; j++)
                    mma16816(acc[i][j], ah[i], &bh_[j >> 1][(j & 1) * 2]);
        }
    }

    __syncthreads();
    float* redS = (float*)smem;
    float* redQ = (float*)smem + 512;

    const int tq = lane >> 2;
    const int tr = (lane & 3) * 2;
    const int wslot = wn >> 6;

    float bj0[8], bj1[8];
#pragma unroll
    for (int j = 0; j < 8; j++) {
        const int n = wn + 8 * j + tr;
        float b0 = bias[n], b1 = bias[n + 1];
        if (bias2) { b0 += bias2[n]; b1 += bias2[n + 1]; }
        bj0[j] = b0; bj1[j] = b1;
    }

#pragma unroll
    for (int i = 0; i < 4; i++)
#pragma unroll
        for (int half = 0; half < 2; half++) {
            const int mrow = wm + 16 * i + 8 * half + tq;
            const int m = brow + mrow;
            float s1 = 0.f, s2 = 0.f;
#pragma unroll
            for (int j = 0; j < 8; j++) {
                float v0 = acc[i][j][half * 2 + 0] + bj0[j];
                float v1 = acc[i][j][half * 2 + 1] + bj1[j];
                if (res) {
                    float2 rr = *(const float2*)(res + (size_t)m * ldres + wn + 8 * j + tr);
                    v0 += rr.x; v1 += rr.y;
                }
                acc[i][j][half * 2 + 0] = v0;
                acc[i][j][half * 2 + 1] = v1;
                s1 += v0 + v1;
                s2 += v0 * v0 + v1 * v1;
            }
            s1 += __shfl_xor_sync(0xffffffffu, s1, 1);
            s2 += __shfl_xor_sync(0xffffffffu, s2, 1);
            s1 += __shfl_xor_sync(0xffffffffu, s1, 2);
            s2 += __shfl_xor_sync(0xffffffffu, s2, 2);
            if ((lane & 3) == 0) {
                redS[mrow * 4 + wslot] = s1;
                redQ[mrow * 4 + wslot] = s2;
            }
        }
    __syncthreads();

    float gj0[8], gj1[8], tj0[8], tj1[8];
#pragma unroll
    for (int j = 0; j < 8; j++) {
        const int n = wn + 8 * j + tr;
        float2 gg = *(const float2*)(gam + n);
        float2 bb = *(const float2*)(bet + n);
        gj0[j] = gg.x; gj1[j] = gg.y;
        tj0[j] = bb.x; tj1[j] = bb.y;
    }

#pragma unroll
    for (int i = 0; i < 4; i++)
#pragma unroll
        for (int half = 0; half < 2; half++) {
            const int mrow = wm + 16 * i + 8 * half + tq;
            const int m = brow + mrow;
            float tS = redS[mrow * 4 + 0] + redS[mrow * 4 + 1]
                     + redS[mrow * 4 + 2] + redS[mrow * 4 + 3];
            float tQ = redQ[mrow * 4 + 0] + redQ[mrow * 4 + 1]
                     + redQ[mrow * 4 + 2] + redQ[mrow * 4 + 3];
            float mean = tS * (1.0f / F);
            float var  = tQ * (1.0f / F) - mean * mean;
            float rstd = rsqrtf(var + 1e-5f);
#pragma unroll
            for (int j = 0; j < 8; j++) {
                const int n = wn + 8 * j + tr;
                float o0 = gj0[j] * (acc[i][j][half * 2 + 0] - mean) * rstd + tj0[j];
                float o1 = gj1[j] * (acc[i][j][half * 2 + 1] - mean) * rstd + tj1[j];
                if (O) *(float2*)(O + (size_t)m * F + n) = make_float2(o0, o1);
                if (Oh)
                    *(__half2*)(Oh + (size_t)m * F + n) =
                        __halves2half2(__float2half_rn(o0), __float2half_rn(o1));
            }
        }
}

// ================= fused FFN: up(relu) + down + residual + LN2 =================
// CTA: 64 rows. Xq staged once; 8 hidden chunks of 128.
// smem: XQ 8x4KB | WU 8x8KB | WD 4x16KB | UC 4x4KB  (176KB)
#define XQ_OFF 0u
#define WU_OFF 32768u
#define WD_OFF 98304u
#define UC_OFF 163840u
#define FFN_SMEM 180224

struct FfnPair {
    const h16 *Xq[2];
    const h16 *Wu[2], *Wd[2];
    const float *bu[2], *bd[2], *res[2];
    const float *g[2], *bt[2];
    float *O[2];
};

__global__ __launch_bounds__(256, 1) void ffn_fused(FfnPair fp)
{
    extern __shared__ char smem[];
    const uint32_t sb = smem_u32(smem);

    const int z = blockIdx.z;
    const h16* __restrict__ Xq = fp.Xq[z];
    const h16* __restrict__ Wu = fp.Wu[z];
    const h16* __restrict__ Wd = fp.Wd[z];
    const float* __restrict__ bu  = fp.bu[z];
    const float* __restrict__ bd  = fp.bd[z];
    const float* __restrict__ res = fp.res[z];
    const float* __restrict__ gam = fp.g[z];
    const float* __restrict__ bet = fp.bt[z];
    float* __restrict__ O = fp.O[z];

    const int tid  = threadIdx.x;
    const int wid  = tid >> 5;
    const int lane = tid & 31;
    const int brow = blockIdx.y * 64;

    const int tile = lane >> 3;
    const int rin  = lane & 7;
    const uint32_t rsw = (uint32_t)(rin >> 1);
    const int tq = lane >> 2;
    const int tr = (lane & 3) * 2;

    // phase-1 warp layout: wm1 in {0,32}, wh in {0,32,64,96}
    const int wm1 = (wid & 1) * 32;
    const int wh  = (wid >> 1) * 32;
    // phase-2 warp layout: wm2 in {0,32}, wn2 in {0,64,128,192}
    const int wm2 = (wid >> 2) * 32;
    const int wn2 = (wid & 3) * 64;

    // main accumulator: out[64,256] -> per-thread acc[2][8][4]
    float acc[2][8][4];
#pragma unroll
    for (int i = 0; i < 2; i++)
#pragma unroll
        for (int j = 0; j < 8; j++)
#pragma unroll
            for (int r = 0; r < 4; r++) acc[i][j][r] = 0.f;

    auto load_xq = [&]() {
#pragma unroll
        for (int t = 0; t < 8; t++) {
            const int qid = tid + t * 256;
            const int s = qid >> 8, q = qid & 255;
            const int r = q >> 2, c = q & 3;
            cpasync16(sb + XQ_OFF + (uint32_t)s * 4096u + (uint32_t)r * 64u +
                      (uint32_t)((c ^ ((r >> 1) & 3)) * 16),
                      Xq + (size_t)(brow + r) * F + s * 32 + c * 8);
        }
    };
    auto load_wu = [&](int hc) {
#pragma unroll
        for (int t = 0; t < 16; t++) {
            const int qid = tid + t * 256;
            const int s = qid >> 9, q = qid & 511;
            const int r = q >> 2, c = q & 3;
            cpasync16(sb + WU_OFF + (uint32_t)s * 8192u + (uint32_t)r * 64u +
                      (uint32_t)((c ^ ((r >> 1) & 3)) * 16),
                      Wu + (size_t)(hc * 128 + r) * F + s * 32 + c * 8);
        }
        asm volatile("cp.async.commit_group;" ::: "memory");
    };
    auto load_wd = [&](int hc) {
#pragma unroll
        for (int t = 0; t < 16; t++) {
            const int qid = tid + t * 256;
            const int s = qid >> 10, q = qid & 1023;
            const int r = q >> 2, c = q & 3;
            cpasync16(sb + WD_OFF + (uint32_t)s * 16384u + (uint32_t)r * 64u +
                      (uint32_t)((c ^ ((r >> 1) & 3)) * 16),
                      Wd + (size_t)r * HIDN + hc * 128 + s * 32 + c * 8);
        }
        asm volatile("cp.async.commit_group;" ::: "memory");
    };

    // prologue: Xq + Wu0
    load_xq();
    load_wu(0);
    asm volatile("cp.async.wait_group 0;" ::: "memory");
    __syncthreads();

    for (int hc = 0; hc < 8; hc++) {
        load_wd(hc);   // overlaps phase 1

        // ---- phase 1: Uc = relu(Xq @ Wu_hc^T + bu) ----
        float acc1[2][4][4];
#pragma unroll
        for (int i = 0; i < 2; i++)
#pragma unroll
            for (int j = 0; j < 4; j++)
#pragma unroll
                for (int r = 0; r < 4; r++) acc1[i][j][r] = 0.f;

#pragma unroll
        for (int kc = 0; kc < 8; kc++) {
            const uint32_t sx = sb + XQ_OFF + (uint32_t)kc * 4096u;
            const uint32_t sw = sb + WU_OFF + (uint32_t)kc * 8192u;
#pragma unroll
            for (int ks = 0; ks < 2; ks++) {
                uint32_t ah[2][4], bh_[2][4];
                const uint32_t swa = ((uint32_t)(ks * 2 + (tile >> 1)) ^ rsw) * 16u;
#pragma unroll
                for (int i = 0; i < 2; i++)
                    ldsm4(ah[i], sx + (uint32_t)(wm1 + i * 16 + (tile & 1) * 8 + rin) * 64u + swa);
                const uint32_t swb = ((uint32_t)(ks * 2 + (tile & 1)) ^ rsw) * 16u;
#pragma unroll
                for (int jj = 0; jj < 2; jj++)
                    ldsm4(bh_[jj], sw + (uint32_t)(wh + jj * 16 + (tile >> 1) * 8 + rin) * 64u + swb);
#pragma unroll
                for (int i = 0; i < 2; i++)
#pragma unroll
                    for (int j = 0; j < 4; j++)
                        mma16816(acc1[i][j], ah[i], &bh_[j >> 1][(j & 1) * 2]);
            }
        }

        // bias + relu + store Uc to smem (standard swizzled layout)
        {
            const int sub = wh >> 5;            // Uc sub-chunk (32-h)
            const uint32_t ucb = sb + UC_OFF + (uint32_t)sub * 4096u;
#pragma unroll
            for (int i = 0; i < 2; i++)
#pragma unroll
                for (int j = 0; j < 4; j++) {
                    const int nh = hc * 128 + wh + j * 8 + tr;
                    float b0 = bu[nh], b1 = bu[nh + 1];
                    float v0 = fmaxf(acc1[i][j][0] + b0, 0.f);
                    float v1 = fmaxf(acc1[i][j][1] + b1, 0.f);
                    float v2 = fmaxf(acc1[i][j][2] + b0, 0.f);
                    float v3 = fmaxf(acc1[i][j][3] + b1, 0.f);
                    const int row0 = wm1 + i * 16 + tq;
                    const int row1 = row0 + 8;
                    uint32_t a0 = ucb + (uint32_t)row0 * 64u +
                                  (uint32_t)((j ^ ((row0 >> 1) & 3)) * 16) + (uint32_t)tr * 2u;
                    uint32_t a1 = ucb + (uint32_t)row1 * 64u +
                                  (uint32_t)((j ^ ((row1 >> 1) & 3)) * 16) + (uint32_t)tr * 2u;
                    __half2 h01 = __halves2half2(__float2half_rn(v0), __float2half_rn(v1));
                    __half2 h23 = __halves2half2(__float2half_rn(v2), __float2half_rn(v3));
                    asm volatile("st.shared.b32 [%0], %1;" :: "r"(a0), "r"(*(uint32_t*)&h01) : "memory");
                    asm volatile("st.shared.b32 [%0], %1;" :: "r"(a1), "r"(*(uint32_t*)&h23) : "memory");
                }
        }

        asm volatile("cp.async.wait_group 0;" ::: "memory");  // Wd_hc ready
        __syncthreads();                                       // Uc visible

        if (hc < 7) load_wu(hc + 1);   // overlaps phase 2

        // ---- phase 2: acc += Uc @ Wd_hc^T ----
#pragma unroll
        for (int s = 0; s < 4; s++) {
            const uint32_t su = sb + UC_OFF + (uint32_t)s * 4096u;
            const uint32_t sd = sb + WD_OFF + (uint32_t)s * 16384u;
#pragma unroll
            for (int ks = 0; ks < 2; ks++) {
                uint32_t ah[2][4], bh_[4][4];
                const uint32_t swa = ((uint32_t)(ks * 2 + (tile >> 1)) ^ rsw) * 16u;
#pragma unroll
                for (int i = 0; i < 2; i++)
                    ldsm4(ah[i], su + (uint32_t)(wm2 + i * 16 + (tile & 1) * 8 + rin) * 64u + swa);
                const uint32_t swb = ((uint32_t)(ks * 2 + (tile & 1)) ^ rsw) * 16u;
#pragma unroll
                for (int jj = 0; jj < 4; jj++)
                    ldsm4(bh_[jj], sd + (uint32_t)(wn2 + jj * 16 + (tile >> 1) * 8 + rin) * 64u + swb);
#pragma unroll
                for (int i = 0; i < 2; i++)
#pragma unroll
                    for (int j = 0; j < 8; j++)
                        mma16816(acc[i][j], ah[i], &bh_[j >> 1][(j & 1) * 2]);
            }
        }

        asm volatile("cp.async.wait_group 0;" ::: "memory");  // Wu_{hc+1} ready
        __syncthreads();                                       // Uc consumed
    }

    // ---- epilogue: bias + residual + LN2 -> O fp32 ----
    float* redS = (float*)(smem + UC_OFF);
    float* redQ = (float*)(smem + UC_OFF) + 256;
    const int wslot = wn2 >> 6;

    float bj0[8], bj1[8];
#pragma unroll
    for (int j = 0; j < 8; j++) {
        const int n = wn2 + 8 * j + tr;
        bj0[j] = bd[n]; bj1[j] = bd[n + 1];
    }

#pragma unroll
    for (int i = 0; i < 2; i++)
#pragma unroll
        for (int half = 0; half < 2; half++) {
            const int mrow = wm2 + 16 * i + 8 * half + tq;
            const int m = brow + mrow;
            float s1 = 0.f, s2 = 0.f;
#pragma unroll
            for (int j = 0; j < 8; j++) {
                float v0 = acc[i][j][half * 2 + 0] + bj0[j];
                float v1 = acc[i][j][half * 2 + 1] + bj1[j];
                float2 rr = *(const float2*)(res + (size_t)m * F + wn2 + 8 * j + tr);
                v0 += rr.x; v1 += rr.y;
                acc[i][j][half * 2 + 0] = v0;
                acc[i][j][half * 2 + 1] = v1;
                s1 += v0 + v1;
                s2 += v0 * v0 + v1 * v1;
            }
            s1 += __shfl_xor_sync(0xffffffffu, s1, 1);
            s2 += __shfl_xor_sync(0xffffffffu, s2, 1);
            s1 += __shfl_xor_sync(0xffffffffu, s1, 2);
            s2 += __shfl_xor_sync(0xffffffffu, s2, 2);
            if ((lane & 3) == 0) {
                redS[mrow * 4 + wslot] = s1;
                redQ[mrow * 4 + wslot] = s2;
            }
        }
    __syncthreads();

    float gj0[8], gj1[8], tj0[8], tj1[8];
#pragma unroll
    for (int j = 0; j < 8; j++) {
        const int n = wn2 + 8 * j + tr;
        float2 gg = *(const float2*)(gam + n);
        float2 bb = *(const float2*)(bet + n);
        gj0[j] = gg.x; gj1[j] = gg.y;
        tj0[j] = bb.x; tj1[j] = bb.y;
    }

#pragma unroll
    for (int i = 0; i < 2; i++)
#pragma unroll
        for (int half = 0; half < 2; half++) {
            const int mrow = wm2 + 16 * i + 8 * half + tq;
            const int m = brow + mrow;
            float tS = redS[mrow * 4 + 0] + redS[mrow * 4 + 1]
                     + redS[mrow * 4 + 2] + redS[mrow * 4 + 3];
            float tQ = redQ[mrow * 4 + 0] + redQ[mrow * 4 + 1]
                     + redQ[mrow * 4 + 2] + redQ[mrow * 4 + 3];
            float mean = tS * (1.0f / F);
            float var  = tQ * (1.0f / F) - mean * mean;
            float rstd = rsqrtf(var + 1e-5f);
#pragma unroll
            for (int j = 0; j < 8; j++) {
                const int n = wn2 + 8 * j + tr;
                float o0 = gj0[j] * (acc[i][j][half * 2 + 0] - mean) * rstd + tj0[j];
                float o1 = gj1[j] * (acc[i][j][half * 2 + 1] - mean) * rstd + tj1[j];
                *(float2*)(O + (size_t)m * F + n) = make_float2(o0, o1);
            }
        }
}

// ---------------- merged convert fp32 -> fp16 ----------------
#define NSEG 10
struct ConvArgs {
    const float* s[NSEG];
    h16* h[NSEG];
    int end4[NSEG];
};

__global__ __launch_bounds__(256) void conv_all(ConvArgs a, int total4)
{
    int i = blockIdx.x * 256 + threadIdx.x;
    if (i >= total4) return;
    int seg = 0;
#pragma unroll
    for (int s = 0; s < NSEG - 1; s++) seg += (i >= a.end4[s]) ? 1 : 0;
    const int base = seg ? a.end4[seg - 1] : 0;
    const int j = i - base;

    float4 v = ((const float4*)a.s[seg])[j];
    h16* hp = a.h[seg];
    ((__half2*)hp)[2 * j]     = __halves2half2(__float2half_rn(v.x), __float2half_rn(v.y));
    ((__half2*)hp)[2 * j + 1] = __halves2half2(__float2half_rn(v.z), __float2half_rn(v.w));
}

// ---------------- 9-tap windowed multi-head attention (fp16 in, 4 fused via y) ----------------
struct AttArgs {
    const h16* Q[4];
    const h16* Kp[4];
    const h16* Vp[4];
    h16* O[4];
};

__global__ __launch_bounds__(256) void attend_kernel(AttArgs a, int ostride)
{
    const int z   = blockIdx.y;
    const int t   = threadIdx.x & 63;
    const int pix = blockIdx.x * 4 + (threadIdx.x >> 6);
    const int b   = pix / (HH * WW);
    const int r   = pix % (HH * WW);
    const int y   = r / WW;
    const int x   = r % WW;
    const int ch  = t * 4;

    const h16* __restrict__ Q  = a.Q[z];
    const h16* __restrict__ Kp = a.Kp[z];
    const h16* __restrict__ Vp = a.Vp[z];

    const float scale = 0.17677669529663687f;
    float qf[4];
    {
        uint2 qr = *(const uint2*)(Q + (size_t)pix * PDIM + ch);
        float2 a0 = __half22float2(*(__half2*)&qr.x);
        float2 a1 = __half22float2(*(__half2*)&qr.y);
        qf[0] = a0.x * scale; qf[1] = a0.y * scale;
        qf[2] = a1.x * scale; qf[3] = a1.y * scale;
    }

    float  sc[9];
    float4 vv[9];
#pragma unroll
    for (int n = 0; n < 9; n++) {
        int dy = n / 3 - 1, dx = n % 3 - 1;
        int yy = y + dy, xx = x + dx;
        float s = 0.f;
        float4 v = make_float4(0.f, 0.f, 0.f, 0.f);
        if (yy >= 0 && yy < HH && xx >= 0 && xx < WW) {
            size_t np = ((size_t)(b * HH + yy) * WW + xx) * PDIM + ch;
            uint2 kr = *(const uint2*)(Kp + np);
            uint2 vr = *(const uint2*)(Vp + np);
            float2 k0 = __half22float2(*(__half2*)&kr.x);
            float2 k1 = __half22float2(*(__half2*)&kr.y);
            float2 v0 = __half22float2(*(__half2*)&vr.x);
            float2 v1 = __half22float2(*(__half2*)&vr.y);
            s = qf[0] * k0.x + qf[1] * k0.y + qf[2] * k1.x + qf[3] * k1.y;
            v = make_float4(v0.x, v0.y, v1.x, v1.y);
        }
        s += __shfl_xor_sync(0xffffffffu, s, 4);
        s += __shfl_xor_sync(0xffffffffu, s, 2);
        s += __shfl_xor_sync(0xffffffffu, s, 1);
        sc[n] = s;
        vv[n] = v;
    }

    float mx = sc[0];
#pragma unroll
    for (int n = 1; n < 9; n++) mx = fmaxf(mx, sc[n]);
    float den = 0.f;
    float4 o = make_float4(0.f, 0.f, 0.f, 0.f);
#pragma unroll
    for (int n = 0; n < 9; n++) {
        float w = __expf(sc[n] - mx);
        den += w;
        o.x += w * vv[n].x; o.y += w * vv[n].y;
        o.z += w * vv[n].z; o.w += w * vv[n].w;
    }
    float inv = 1.f / den;
    size_t base = (size_t)pix * ostride + ch;
    *(__half2*)(a.O[z] + base) =
        __halves2half2(__float2half_rn(o.x * inv), __float2half_rn(o.y * inv));
    *(__half2*)(a.O[z] + base + 2) =
        __halves2half2(__float2half_rn(o.z * inv), __float2half_rn(o.w * inv));
}

// ---------------- launch ----------------
#define SYM(p, s) cudaGetSymbolAddress((void**)&p, s)

extern "C" void kernel_launch(void* const* d_in, const int* in_sizes, int n_in,
                              void* d_out, int out_size)
{
    const float* feat0       = (const float*)d_in[0];
    const float* feat1       = (const float*)d_in[1];
    const float* in_w0       = (const float*)d_in[2];
    const float* in_b0       = (const float*)d_in[3];
    const float* in_w1       = (const float*)d_in[4];
    const float* in_b1       = (const float*)d_in[5];
    const float* out_w0      = (const float*)d_in[6];
    const float* out_b0      = (const float*)d_in[7];
    const float* out_w1      = (const float*)d_in[8];
    const float* out_b1      = (const float*)d_in[9];
    const float* ln1_g0      = (const float*)d_in[10];
    const float* ln1_b0      = (const float*)d_in[11];
    const float* ln1_g1      = (const float*)d_in[12];
    const float* ln1_b1      = (const float*)d_in[13];
    const float* ffn_up_w0   = (const float*)d_in[14];
    const float* ffn_up_b0   = (const float*)d_in[15];
    const float* ffn_down_w0 = (const float*)d_in[16];
    const float* ffn_down_b0 = (const float*)d_in[17];
    const float* ffn_up_w1   = (const float*)d_in[18];
    const float* ffn_up_b1   = (const float*)d_in[19];
    const float* ffn_down_w1 = (const float*)d_in[20];
    const float* ffn_down_b1 = (const float*)d_in[21];
    const float* ln2_g0      = (const float*)d_in[22];
    const float* ln2_b0      = (const float*)d_in[23];
    const float* ln2_g1      = (const float*)d_in[24];
    const float* ln2_b1      = (const float*)d_in[25];

    float *X0, *X1;
    SYM(X0, g_X0); SYM(X1, g_X1);
    h16 *P0, *P1, *f0, *f1, *wi0, *wi1, *wo0, *wo1, *wu0, *wu1, *wd0, *wd1;
    h16 *QQ0, *QQ1, *Xq0, *Xq1;
    SYM(P0, g_P0); SYM(P1, g_P1);
    SYM(f0, g_f0); SYM(f1, g_f1);
    SYM(wi0, g_wi0); SYM(wi1, g_wi1);
    SYM(wo0, g_wo0); SYM(wo1, g_wo1);
    SYM(wu0, g_wu0); SYM(wu1, g_wu1);
    SYM(wd0, g_wd0); SYM(wd1, g_wd1);
    SYM(QQ0, g_QQ0); SYM(QQ1, g_QQ1); SYM(Xq0, g_Xq0); SYM(Xq1, g_Xq1);

    cudaFuncSetAttribute(gemm_h16, cudaFuncAttributeMaxDynamicSharedMemorySize, GEMM_SMEM);
    cudaFuncSetAttribute(gemm_ln,  cudaFuncAttributeMaxDynamicSharedMemorySize, GEMMLN_SMEM);
    cudaFuncSetAttribute(ffn_fused, cudaFuncAttributeMaxDynamicSharedMemorySize, FFN_SMEM);

    float* out = (float*)d_out;
    dim3 blk(256);
    const int MT = NPIX / 128;   // 100

    // ---- launch 0: all converts ----
    {
        ConvArgs ca;
        const float* srcs[NSEG] = {feat0, feat1, in_w0, in_w1, out_w0, out_w1,
                                   ffn_up_w0, ffn_up_w1, ffn_down_w0, ffn_down_w1};
        h16* hs[NSEG] = {f0, f1, wi0, wi1, wo0, wo1, wu0, wu1, wd0, wd1};
        int sizes4[NSEG] = {NPIX*F/4, NPIX*F/4, PDIM*F/4, PDIM*F/4, F*3*F/4, F*3*F/4,
                            HIDN*F/4, HIDN*F/4, F*HIDN/4, F*HIDN/4};
        int acc4 = 0;
        for (int i = 0; i < NSEG; i++) {
            ca.s[i] = srcs[i]; ca.h[i] = hs[i];
            acc4 += sizes4[i];
            ca.end4[i] = acc4;
        }
        conv_all<<<(acc4 + 255) / 256, blk>>>(ca, acc4);
    }

    // ---- launch 1: in-projection GEMMs -> P fp16 ----
    {
        GemmPair gp = {};
        gp.A[0]=f0; gp.A[1]=f1;
        gp.B0[0]=wi0; gp.B1[0]=wi0;
        gp.B0[1]=wi1; gp.B1[1]=wi1;
        gp.bias[0]=in_b0; gp.bias[1]=in_b1;
        gp.Ch[0]=P0; gp.Ch[1]=P1;
        gemm_h16<<<dim3(PDIM/128, MT, 2), blk, GEMM_SMEM>>>(gp, F, F, F, 0, PDIM, F, 0);
    }

    // ---- launch 2: 4 attentions (fp16 in) -> QQ fp16 ----
    {
        AttArgs aa;
        aa.Q[0]=P0;     aa.Kp[0]=P0+F;   aa.Vp[0]=P0+2*F; aa.O[0]=QQ0;
        aa.Q[1]=P1;     aa.Kp[1]=P1+F;   aa.Vp[1]=P1+2*F; aa.O[1]=QQ1;
        aa.Q[2]=P0+3*F; aa.Kp[2]=P1+4*F; aa.Vp[2]=P1+5*F; aa.O[2]=QQ0+F;
        aa.Q[3]=P1+3*F; aa.Kp[3]=P0+4*F; aa.Vp[3]=P0+5*F; aa.O[3]=QQ1+F;
        attend_kernel<<<dim3(NPIX/4, 4), blk>>>(aa, 2*F);
    }

    // ---- launch 3: out-projection (K=512) + residual + LN1 fused ----
    {
        GemmLnPair gp = {};
        gp.A[0]=QQ0; gp.A[1]=QQ1;
        gp.B0[0]=wo0; gp.B1[0]=wo0+F;
        gp.B0[1]=wo1; gp.B1[1]=wo0+F;
        gp.bias[0]=out_b0; gp.bias2[0]=out_b0+F; gp.res[0]=feat0;
        gp.bias[1]=out_b1; gp.bias2[1]=out_b0+F; gp.res[1]=feat1;
        gp.g[0]=ln1_g0; gp.bt[0]=ln1_b0; gp.O[0]=X0; gp.Oh[0]=Xq0;
        gp.g[1]=ln1_g1; gp.bt[1]=ln1_b1; gp.O[1]=X1; gp.Oh[1]=Xq1;
        gemm_ln<<<dim3(1, MT, 2), blk, GEMMLN_SMEM>>>(gp, 2*F, 3*F, F, F, 2*F);
    }

    // ---- launch 4: fused FFN (up + relu + down + residual + LN2) -> output ----
    {
        FfnPair fp = {};
        fp.Xq[0]=Xq0; fp.Xq[1]=Xq1;
        fp.Wu[0]=wu0; fp.Wu[1]=wu1;
        fp.Wd[0]=wd0; fp.Wd[1]=wd1;
        fp.bu[0]=ffn_up_b0;   fp.bu[1]=ffn_up_b1;
        fp.bd[0]=ffn_down_b0; fp.bd[1]=ffn_down_b1;
        fp.res[0]=X0; fp.res[1]=X1;
        fp.g[0]=ln2_g0; fp.bt[0]=ln2_b0; fp.O[0]=out;
        fp.g[1]=ln2_g1; fp.bt[1]=ln2_b1; fp.O[1]=out + (size_t)NPIX*F;
        ffn_fused<<<dim3(1, NPIX/64, 2), blk, FFN_SMEM>>>(fp);
    }
}

// round 13
// speedup vs baseline: 6.3757x; 1.2464x over previous
#include <cuda_runtime.h>
#include <cuda_fp16.h>
#include <cstdint>
#include <cstddef>

#define F      256
#define NH     8
#define BATCH  2
#define HH     80
#define WW     80
#define NPIX   (BATCH*HH*WW)   // 12800
#define PDIM   1536
#define HIDN   1024

typedef __half h16;

// ---------------- scratch (no allocations allowed) ----------------
__device__ float g_X0[(size_t)NPIX*F];
__device__ float g_X1[(size_t)NPIX*F];

__device__ h16 g_P0[(size_t)NPIX*PDIM];
__device__ h16 g_P1[(size_t)NPIX*PDIM];
__device__ h16 g_f0[(size_t)NPIX*F];
__device__ h16 g_f1[(size_t)NPIX*F];
__device__ h16 g_wi0[(size_t)PDIM*F];
__device__ h16 g_wi1[(size_t)PDIM*F];
__device__ h16 g_wo0[(size_t)F*3*F];
__device__ h16 g_wo1[(size_t)F*3*F];
__device__ h16 g_wu0[(size_t)HIDN*F];
__device__ h16 g_wu1[(size_t)HIDN*F];
__device__ h16 g_wd0[(size_t)F*HIDN];
__device__ h16 g_wd1[(size_t)F*HIDN];
__device__ h16 g_QQ0[(size_t)NPIX*2*F];
__device__ h16 g_QQ1[(size_t)NPIX*2*F];
__device__ h16 g_Xq0[(size_t)NPIX*F];
__device__ h16 g_Xq1[(size_t)NPIX*F];

// ================= helpers =================
__device__ __forceinline__ uint32_t smem_u32(const void* p) {
    uint32_t a;
    asm("{ .reg .u64 t; cvta.to.shared.u64 t, %1; cvt.u32.u64 %0, t; }" : "=r"(a) : "l"(p));
    return a;
}
__device__ __forceinline__ void cpasync16(uint32_t dst, const void* src) {
    asm volatile("cp.async.cg.shared.global [%0], [%1], 16;" :: "r"(dst), "l"(src) : "memory");
}
__device__ __forceinline__ void cpasync16z(uint32_t dst, const void* src, int srcsz) {
    asm volatile("cp.async.cg.shared.global [%0], [%1], 16, %2;"
                 :: "r"(dst), "l"(src), "r"(srcsz) : "memory");
}
__device__ __forceinline__ void ldsm4(uint32_t (&r)[4], uint32_t addr) {
    asm volatile("ldmatrix.sync.aligned.m8n8.x4.shared.b16 {%0,%1,%2,%3}, [%4];"
                 : "=r"(r[0]), "=r"(r[1]), "=r"(r[2]), "=r"(r[3]) : "r"(addr));
}
__device__ __forceinline__ void mma16816(float* d, const uint32_t* a, const uint32_t* b) {
    asm volatile("mma.sync.aligned.m16n8k16.row.col.f32.f16.f16.f32 "
                 "{%0,%1,%2,%3}, {%4,%5,%6,%7}, {%8,%9}, {%0,%1,%2,%3};"
                 : "+f"(d[0]), "+f"(d[1]), "+f"(d[2]), "+f"(d[3])
                 : "r"(a[0]), "r"(a[1]), "r"(a[2]), "r"(a[3]), "r"(b[0]), "r"(b[1]));
}

// ================= fp16 tensor GEMM 128x128 (paired over z) =================
#define STAGES     4
#define SMEM_STAGE 16384
#define OFF_B      8192u
#define GEMM_SMEM  (STAGES*SMEM_STAGE)

struct GemmPair {
    const h16 *A[2];
    const h16 *B0[2], *B1[2];
    const float *bias[2], *bias2[2], *res[2];
    float *C[2];
    h16 *Ch[2];
};

__global__ __launch_bounds__(256, 2) void gemm_h16(
    GemmPair gp, int lda, int ldb, int Ksplit,
    int ldres, int ldc, int K, int relu)
{
    extern __shared__ char smem[];
    const uint32_t sb0 = smem_u32(smem);

    const int z = blockIdx.z;
    const h16* __restrict__ A  = gp.A[z];
    const h16* __restrict__ B0 = gp.B0[z];
    const h16* __restrict__ B1 = gp.B1[z];
    const float* __restrict__ bias  = gp.bias[z];
    const float* __restrict__ bias2 = gp.bias2[z];
    const float* __restrict__ res   = gp.res[z];
    float* __restrict__ C  = gp.C[z];
    h16*   __restrict__ Ch = gp.Ch[z];

    const int tid  = threadIdx.x;
    const int wid  = tid >> 5;
    const int lane = tid & 31;
    const int brow = blockIdx.y * 128;
    const int bcol = blockIdx.x * 128;
    const int wm   = (wid >> 2) * 64;
    const int wn   = (wid & 3) * 32;

    float acc[4][4][4];
#pragma unroll
    for (int i = 0; i < 4; i++)
#pragma unroll
        for (int j = 0; j < 4; j++)
#pragma unroll
            for (int r = 0; r < 4; r++) acc[i][j][r] = 0.f;

    auto load_stage = [&](int cIdx) {
        const uint32_t sb = sb0 + (uint32_t)(cIdx % STAGES) * SMEM_STAGE;
        const int k0 = cIdx * 32;
        const h16* bp;
        int kk;
        if (k0 < Ksplit) { bp = B0; kk = k0; }
        else             { bp = B1; kk = k0 - Ksplit; }
#pragma unroll
        for (int s = 0; s < 4; s++) {
            const int qid = tid + s * 256;
            const int q   = qid & 511;
            const int row = q >> 2;
            const int c   = q & 3;
            const h16* src;
            uint32_t dstbase;
            if (qid < 512) {
                src = A + (size_t)(brow + row) * lda + k0 + c * 8;
                dstbase = sb;
            } else {
                src = bp + (size_t)(bcol + row) * ldb + kk + c * 8;
                dstbase = sb + OFF_B;
            }
            cpasync16(dstbase + (uint32_t)row * 64u +
                      (uint32_t)((c ^ ((row >> 1) & 3)) * 16), src);
        }
        asm volatile("cp.async.commit_group;" ::: "memory");
    };

    const int tile = lane >> 3;
    const int rin  = lane & 7;
    const uint32_t rsw = (uint32_t)(rin >> 1);

    const int NC = K / 32;
    for (int s = 0; s < STAGES - 1 && s < NC; s++) load_stage(s);

    for (int c = 0; c < NC; c++) {
        if (c + 3 <= NC) {
            asm volatile("cp.async.wait_group 2;" ::: "memory");
        } else if (c + 2 == NC) {
            asm volatile("cp.async.wait_group 1;" ::: "memory");
        } else {
            asm volatile("cp.async.wait_group 0;" ::: "memory");
        }
        __syncthreads();
        if (c + 3 < NC) load_stage(c + 3);

        const uint32_t sb = sb0 + (uint32_t)(c % STAGES) * SMEM_STAGE;
#pragma unroll
        for (int ks = 0; ks < 2; ks++) {
            uint32_t ah[4][4], bh_[2][4];
            const uint32_t swa = ((uint32_t)(ks * 2 + (tile >> 1)) ^ rsw) * 16u;
#pragma unroll
            for (int i = 0; i < 4; i++)
                ldsm4(ah[i], sb + (uint32_t)(wm + i * 16 + (tile & 1) * 8 + rin) * 64u + swa);
            const uint32_t swb = ((uint32_t)(ks * 2 + (tile & 1)) ^ rsw) * 16u;
#pragma unroll
            for (int jj = 0; jj < 2; jj++)
                ldsm4(bh_[jj], sb + OFF_B +
                      (uint32_t)(wn + jj * 16 + (tile >> 1) * 8 + rin) * 64u + swb);
#pragma unroll
            for (int i = 0; i < 4; i++)
#pragma unroll
                for (int j = 0; j < 4; j++)
                    mma16816(acc[i][j], ah[i], &bh_[j >> 1][(j & 1) * 2]);
        }
    }

    const int tq = lane >> 2;
    const int tr = (lane & 3) * 2;
    float bj0[4], bj1[4];
#pragma unroll
    for (int j = 0; j < 4; j++) {
        const int n = bcol + wn + 8 * j + tr;
        float b0 = bias[n], b1 = bias[n + 1];
        if (bias2) { b0 += bias2[n]; b1 += bias2[n + 1]; }
        bj0[j] = b0; bj1[j] = b1;
    }
#pragma unroll
    for (int i = 0; i < 4; i++)
#pragma unroll
        for (int half = 0; half < 2; half++) {
            const int m = brow + wm + 16 * i + tq + half * 8;
#pragma unroll
            for (int j = 0; j < 4; j++) {
                const int n = bcol + wn + 8 * j + tr;
                float v0 = acc[i][j][half * 2 + 0] + bj0[j];
                float v1 = acc[i][j][half * 2 + 1] + bj1[j];
                if (res) {
                    float2 r = *(const float2*)(res + (size_t)m * ldres + n);
                    v0 += r.x; v1 += r.y;
                }
                if (relu) { v0 = fmaxf(v0, 0.f); v1 = fmaxf(v1, 0.f); }
                if (C) *(float2*)(C + (size_t)m * ldc + n) = make_float2(v0, v1);
                if (Ch)
                    *(__half2*)(Ch + (size_t)m * ldc + n) =
                        __halves2half2(__float2half_rn(v0), __float2half_rn(v1));
            }
        }
}

// ================= fp16 GEMM 64x256 + fused LayerNorm (paired over z), 2 CTA/SM =================
#define LSTAGES    4
#define LSTAGE_SZ  20480
#define LOFF_B     4096u
#define GEMMLN_SMEM (LSTAGES*LSTAGE_SZ)

struct GemmLnPair {
    const h16 *A[2];
    const h16 *B0[2], *B1[2];
    const float *bias[2], *bias2[2], *res[2];
    const float *g[2], *bt[2];
    float *O[2];
    h16 *Oh[2];
};

__global__ __launch_bounds__(256, 2) void gemm_ln(
    GemmLnPair gp, int lda, int ldb, int Ksplit, int ldres, int K)
{
    extern __shared__ char smem[];
    const uint32_t sb0 = smem_u32(smem);

    const int z = blockIdx.z;
    const h16* __restrict__ A  = gp.A[z];
    const h16* __restrict__ B0 = gp.B0[z];
    const h16* __restrict__ B1 = gp.B1[z];
    const float* __restrict__ bias  = gp.bias[z];
    const float* __restrict__ bias2 = gp.bias2[z];
    const float* __restrict__ res   = gp.res[z];
    const float* __restrict__ gam   = gp.g[z];
    const float* __restrict__ bet   = gp.bt[z];
    float* __restrict__ O  = gp.O[z];
    h16*   __restrict__ Oh = gp.Oh[z];

    const int tid  = threadIdx.x;
    const int wid  = tid >> 5;
    const int lane = tid & 31;
    const int brow = blockIdx.y * 64;
    const int wm   = (wid >> 2) * 32;   // 0 or 32
    const int wn   = (wid & 3) * 64;    // 0,64,128,192

    float acc[2][8][4];
#pragma unroll
    for (int i = 0; i < 2; i++)
#pragma unroll
        for (int j = 0; j < 8; j++)
#pragma unroll
            for (int r = 0; r < 4; r++) acc[i][j][r] = 0.f;

    // loader: A 256 quads + B 1024 quads = 1280, 5/thread
    auto load_stage = [&](int cIdx) {
        const uint32_t sb = sb0 + (uint32_t)(cIdx % LSTAGES) * LSTAGE_SZ;
        const int k0 = cIdx * 32;
        const h16* bp;
        int kk;
        if (k0 < Ksplit) { bp = B0; kk = k0; }
        else             { bp = B1; kk = k0 - Ksplit; }
#pragma unroll
        for (int s = 0; s < 5; s++) {
            const int qid = tid + s * 256;
            const h16* src;
            uint32_t dstbase;
            int row, c;
            if (qid < 256) {
                row = qid >> 2; c = qid & 3;
                src = A + (size_t)(brow + row) * lda + k0 + c * 8;
                dstbase = sb;
            } else {
                const int q2 = qid - 256;
                row = q2 >> 2; c = q2 & 3;
                src = bp + (size_t)row * ldb + kk + c * 8;
                dstbase = sb + LOFF_B;
            }
            cpasync16(dstbase + (uint32_t)row * 64u +
                      (uint32_t)((c ^ ((row >> 1) & 3)) * 16), src);
        }
        asm volatile("cp.async.commit_group;" ::: "memory");
    };

    const int tile = lane >> 3;
    const int rin  = lane & 7;
    const uint32_t rsw = (uint32_t)(rin >> 1);

    const int NC = K / 32;
    for (int s = 0; s < LSTAGES - 1 && s < NC; s++) load_stage(s);

    for (int c = 0; c < NC; c++) {
        if (c + 3 <= NC) {
            asm volatile("cp.async.wait_group 2;" ::: "memory");
        } else if (c + 2 == NC) {
            asm volatile("cp.async.wait_group 1;" ::: "memory");
        } else {
            asm volatile("cp.async.wait_group 0;" ::: "memory");
        }
        __syncthreads();
        if (c + 3 < NC) load_stage(c + 3);

        const uint32_t sb = sb0 + (uint32_t)(c % LSTAGES) * LSTAGE_SZ;
#pragma unroll
        for (int ks = 0; ks < 2; ks++) {
            uint32_t ah[2][4], bh_[4][4];
            const uint32_t swa = ((uint32_t)(ks * 2 + (tile >> 1)) ^ rsw) * 16u;
#pragma unroll
            for (int i = 0; i < 2; i++)
                ldsm4(ah[i], sb + (uint32_t)(wm + i * 16 + (tile & 1) * 8 + rin) * 64u + swa);
            const uint32_t swb = ((uint32_t)(ks * 2 + (tile & 1)) ^ rsw) * 16u;
#pragma unroll
            for (int jj = 0; jj < 4; jj++)
                ldsm4(bh_[jj], sb + LOFF_B +
                      (uint32_t)(wn + jj * 16 + (tile >> 1) * 8 + rin) * 64u + swb);
#pragma unroll
            for (int i = 0; i < 2; i++)
#pragma unroll
                for (int j = 0; j < 8; j++)
                    mma16816(acc[i][j], ah[i], &bh_[j >> 1][(j & 1) * 2]);
        }
    }

    __syncthreads();
    float* redS = (float*)smem;          // [64][4]
    float* redQ = (float*)smem + 256;

    const int tq = lane >> 2;
    const int tr = (lane & 3) * 2;
    const int wslot = wn >> 6;

    float bj0[8], bj1[8];
#pragma unroll
    for (int j = 0; j < 8; j++) {
        const int n = wn + 8 * j + tr;
        float b0 = bias[n], b1 = bias[n + 1];
        if (bias2) { b0 += bias2[n]; b1 += bias2[n + 1]; }
        bj0[j] = b0; bj1[j] = b1;
    }

#pragma unroll
    for (int i = 0; i < 2; i++)
#pragma unroll
        for (int half = 0; half < 2; half++) {
            const int mrow = wm + 16 * i + 8 * half + tq;
            const int m = brow + mrow;
            float s1 = 0.f, s2 = 0.f;
#pragma unroll
            for (int j = 0; j < 8; j++) {
                float v0 = acc[i][j][half * 2 + 0] + bj0[j];
                float v1 = acc[i][j][half * 2 + 1] + bj1[j];
                if (res) {
                    float2 rr = *(const float2*)(res + (size_t)m * ldres + wn + 8 * j + tr);
                    v0 += rr.x; v1 += rr.y;
                }
                acc[i][j][half * 2 + 0] = v0;
                acc[i][j][half * 2 + 1] = v1;
                s1 += v0 + v1;
                s2 += v0 * v0 + v1 * v1;
            }
            s1 += __shfl_xor_sync(0xffffffffu, s1, 1);
            s2 += __shfl_xor_sync(0xffffffffu, s2, 1);
            s1 += __shfl_xor_sync(0xffffffffu, s1, 2);
            s2 += __shfl_xor_sync(0xffffffffu, s2, 2);
            if ((lane & 3) == 0) {
                redS[mrow * 4 + wslot] = s1;
                redQ[mrow * 4 + wslot] = s2;
            }
        }
    __syncthreads();

#pragma unroll
    for (int i = 0; i < 2; i++)
#pragma unroll
        for (int half = 0; half < 2; half++) {
            const int mrow = wm + 16 * i + 8 * half + tq;
            const int m = brow + mrow;
            float tS = redS[mrow * 4 + 0] + redS[mrow * 4 + 1]
                     + redS[mrow * 4 + 2] + redS[mrow * 4 + 3];
            float tQ = redQ[mrow * 4 + 0] + redQ[mrow * 4 + 1]
                     + redQ[mrow * 4 + 2] + redQ[mrow * 4 + 3];
            float mean = tS * (1.0f / F);
            float var  = tQ * (1.0f / F) - mean * mean;
            float rstd = rsqrtf(var + 1e-5f);
#pragma unroll
            for (int j = 0; j < 8; j++) {
                const int n = wn + 8 * j + tr;
                float2 gg = *(const float2*)(gam + n);
                float2 bb = *(const float2*)(bet + n);
                float o0 = gg.x * (acc[i][j][half * 2 + 0] - mean) * rstd + bb.x;
                float o1 = gg.y * (acc[i][j][half * 2 + 1] - mean) * rstd + bb.y;
                if (O) *(float2*)(O + (size_t)m * F + n) = make_float2(o0, o1);
                if (Oh)
                    *(__half2*)(Oh + (size_t)m * F + n) =
                        __halves2half2(__float2half_rn(o0), __float2half_rn(o1));
            }
        }
}

// ================= fused FFN: up(relu) + down + residual + LN2 =================
#define XQ_OFF 0u
#define WU_OFF 32768u
#define WD_OFF 98304u
#define UC_OFF 163840u
#define FFN_SMEM 180224

struct FfnPair {
    const h16 *Xq[2];
    const h16 *Wu[2], *Wd[2];
    const float *bu[2], *bd[2], *res[2];
    const float *g[2], *bt[2];
    float *O[2];
};

__global__ __launch_bounds__(256, 1) void ffn_fused(FfnPair fp)
{
    extern __shared__ char smem[];
    const uint32_t sb = smem_u32(smem);

    const int z = blockIdx.z;
    const h16* __restrict__ Xq = fp.Xq[z];
    const h16* __restrict__ Wu = fp.Wu[z];
    const h16* __restrict__ Wd = fp.Wd[z];
    const float* __restrict__ bu  = fp.bu[z];
    const float* __restrict__ bd  = fp.bd[z];
    const float* __restrict__ res = fp.res[z];
    const float* __restrict__ gam = fp.g[z];
    const float* __restrict__ bet = fp.bt[z];
    float* __restrict__ O = fp.O[z];

    const int tid  = threadIdx.x;
    const int wid  = tid >> 5;
    const int lane = tid & 31;
    const int brow = blockIdx.y * 64;

    const int tile = lane >> 3;
    const int rin  = lane & 7;
    const uint32_t rsw = (uint32_t)(rin >> 1);
    const int tq = lane >> 2;
    const int tr = (lane & 3) * 2;

    const int wm1 = (wid & 1) * 32;
    const int wh  = (wid >> 1) * 32;
    const int wm2 = (wid >> 2) * 32;
    const int wn2 = (wid & 3) * 64;

    float acc[2][8][4];
#pragma unroll
    for (int i = 0; i < 2; i++)
#pragma unroll
        for (int j = 0; j < 8; j++)
#pragma unroll
            for (int r = 0; r < 4; r++) acc[i][j][r] = 0.f;

    auto load_xq = [&]() {
#pragma unroll
        for (int t = 0; t < 8; t++) {
            const int qid = tid + t * 256;
            const int s = qid >> 8, q = qid & 255;
            const int r = q >> 2, c = q & 3;
            cpasync16(sb + XQ_OFF + (uint32_t)s * 4096u + (uint32_t)r * 64u +
                      (uint32_t)((c ^ ((r >> 1) & 3)) * 16),
                      Xq + (size_t)(brow + r) * F + s * 32 + c * 8);
        }
    };
    auto load_wu = [&](int hc) {
#pragma unroll
        for (int t = 0; t < 16; t++) {
            const int qid = tid + t * 256;
            const int s = qid >> 9, q = qid & 511;
            const int r = q >> 2, c = q & 3;
            cpasync16(sb + WU_OFF + (uint32_t)s * 8192u + (uint32_t)r * 64u +
                      (uint32_t)((c ^ ((r >> 1) & 3)) * 16),
                      Wu + (size_t)(hc * 128 + r) * F + s * 32 + c * 8);
        }
        asm volatile("cp.async.commit_group;" ::: "memory");
    };
    auto load_wd = [&](int hc) {
#pragma unroll
        for (int t = 0; t < 16; t++) {
            const int qid = tid + t * 256;
            const int s = qid >> 10, q = qid & 1023;
            const int r = q >> 2, c = q & 3;
            cpasync16(sb + WD_OFF + (uint32_t)s * 16384u + (uint32_t)r * 64u +
                      (uint32_t)((c ^ ((r >> 1) & 3)) * 16),
                      Wd + (size_t)r * HIDN + hc * 128 + s * 32 + c * 8);
        }
        asm volatile("cp.async.commit_group;" ::: "memory");
    };

    load_xq();
    load_wu(0);
    asm volatile("cp.async.wait_group 0;" ::: "memory");
    __syncthreads();

    for (int hc = 0; hc < 8; hc++) {
        load_wd(hc);

        float acc1[2][4][4];
#pragma unroll
        for (int i = 0; i < 2; i++)
#pragma unroll
            for (int j = 0; j < 4; j++)
#pragma unroll
                for (int r = 0; r < 4; r++) acc1[i][j][r] = 0.f;

#pragma unroll
        for (int kc = 0; kc < 8; kc++) {
            const uint32_t sx = sb + XQ_OFF + (uint32_t)kc * 4096u;
            const uint32_t sw = sb + WU_OFF + (uint32_t)kc * 8192u;
#pragma unroll
            for (int ks = 0; ks < 2; ks++) {
                uint32_t ah[2][4], bh_[2][4];
                const uint32_t swa = ((uint32_t)(ks * 2 + (tile >> 1)) ^ rsw) * 16u;
#pragma unroll
                for (int i = 0; i < 2; i++)
                    ldsm4(ah[i], sx + (uint32_t)(wm1 + i * 16 + (tile & 1) * 8 + rin) * 64u + swa);
                const uint32_t swb = ((uint32_t)(ks * 2 + (tile & 1)) ^ rsw) * 16u;
#pragma unroll
                for (int jj = 0; jj < 2; jj++)
                    ldsm4(bh_[jj], sw + (uint32_t)(wh + jj * 16 + (tile >> 1) * 8 + rin) * 64u + swb);
#pragma unroll
                for (int i = 0; i < 2; i++)
#pragma unroll
                    for (int j = 0; j < 4; j++)
                        mma16816(acc1[i][j], ah[i], &bh_[j >> 1][(j & 1) * 2]);
            }
        }

        {
            const int sub = wh >> 5;
            const uint32_t ucb = sb + UC_OFF + (uint32_t)sub * 4096u;
#pragma unroll
            for (int i = 0; i < 2; i++)
#pragma unroll
                for (int j = 0; j < 4; j++) {
                    const int nh = hc * 128 + wh + j * 8 + tr;
                    float b0 = bu[nh], b1 = bu[nh + 1];
                    float v0 = fmaxf(acc1[i][j][0] + b0, 0.f);
                    float v1 = fmaxf(acc1[i][j][1] + b1, 0.f);
                    float v2 = fmaxf(acc1[i][j][2] + b0, 0.f);
                    float v3 = fmaxf(acc1[i][j][3] + b1, 0.f);
                    const int row0 = wm1 + i * 16 + tq;
                    const int row1 = row0 + 8;
                    uint32_t a0 = ucb + (uint32_t)row0 * 64u +
                                  (uint32_t)((j ^ ((row0 >> 1) & 3)) * 16) + (uint32_t)tr * 2u;
                    uint32_t a1 = ucb + (uint32_t)row1 * 64u +
                                  (uint32_t)((j ^ ((row1 >> 1) & 3)) * 16) + (uint32_t)tr * 2u;
                    __half2 h01 = __halves2half2(__float2half_rn(v0), __float2half_rn(v1));
                    __half2 h23 = __halves2half2(__float2half_rn(v2), __float2half_rn(v3));
                    asm volatile("st.shared.b32 [%0], %1;" :: "r"(a0), "r"(*(uint32_t*)&h01) : "memory");
                    asm volatile("st.shared.b32 [%0], %1;" :: "r"(a1), "r"(*(uint32_t*)&h23) : "memory");
                }
        }

        asm volatile("cp.async.wait_group 0;" ::: "memory");
        __syncthreads();

        if (hc < 7) load_wu(hc + 1);

#pragma unroll
        for (int s = 0; s < 4; s++) {
            const uint32_t su = sb + UC_OFF + (uint32_t)s * 4096u;
            const uint32_t sd = sb + WD_OFF + (uint32_t)s * 16384u;
#pragma unroll
            for (int ks = 0; ks < 2; ks++) {
                uint32_t ah[2][4], bh_[4][4];
                const uint32_t swa = ((uint32_t)(ks * 2 + (tile >> 1)) ^ rsw) * 16u;
#pragma unroll
                for (int i = 0; i < 2; i++)
                    ldsm4(ah[i], su + (uint32_t)(wm2 + i * 16 + (tile & 1) * 8 + rin) * 64u + swa);
                const uint32_t swb = ((uint32_t)(ks * 2 + (tile & 1)) ^ rsw) * 16u;
#pragma unroll
                for (int jj = 0; jj < 4; jj++)
                    ldsm4(bh_[jj], sd + (uint32_t)(wn2 + jj * 16 + (tile >> 1) * 8 + rin) * 64u + swb);
#pragma unroll
                for (int i = 0; i < 2; i++)
#pragma unroll
                    for (int j = 0; j < 8; j++)
                        mma16816(acc[i][j], ah[i], &bh_[j >> 1][(j & 1) * 2]);
            }
        }

        asm volatile("cp.async.wait_group 0;" ::: "memory");
        __syncthreads();
    }

    float* redS = (float*)(smem + UC_OFF);
    float* redQ = (float*)(smem + UC_OFF) + 256;
    const int wslot = wn2 >> 6;

    float bj0[8], bj1[8];
#pragma unroll
    for (int j = 0; j < 8; j++) {
        const int n = wn2 + 8 * j + tr;
        bj0[j] = bd[n]; bj1[j] = bd[n + 1];
    }

#pragma unroll
    for (int i = 0; i < 2; i++)
#pragma unroll
        for (int half = 0; half < 2; half++) {
            const int mrow = wm2 + 16 * i + 8 * half + tq;
            const int m = brow + mrow;
            float s1 = 0.f, s2 = 0.f;
#pragma unroll
            for (int j = 0; j < 8; j++) {
                float v0 = acc[i][j][half * 2 + 0] + bj0[j];
                float v1 = acc[i][j][half * 2 + 1] + bj1[j];
                float2 rr = *(const float2*)(res + (size_t)m * F + wn2 + 8 * j + tr);
                v0 += rr.x; v1 += rr.y;
                acc[i][j][half * 2 + 0] = v0;
                acc[i][j][half * 2 + 1] = v1;
                s1 += v0 + v1;
                s2 += v0 * v0 + v1 * v1;
            }
            s1 += __shfl_xor_sync(0xffffffffu, s1, 1);
            s2 += __shfl_xor_sync(0xffffffffu, s2, 1);
            s1 += __shfl_xor_sync(0xffffffffu, s1, 2);
            s2 += __shfl_xor_sync(0xffffffffu, s2, 2);
            if ((lane & 3) == 0) {
                redS[mrow * 4 + wslot] = s1;
                redQ[mrow * 4 + wslot] = s2;
            }
        }
    __syncthreads();

    float gj0[8], gj1[8], tj0[8], tj1[8];
#pragma unroll
    for (int j = 0; j < 8; j++) {
        const int n = wn2 + 8 * j + tr;
        float2 gg = *(const float2*)(gam + n);
        float2 bb = *(const float2*)(bet + n);
        gj0[j] = gg.x; gj1[j] = gg.y;
        tj0[j] = bb.x; tj1[j] = bb.y;
    }

#pragma unroll
    for (int i = 0; i < 2; i++)
#pragma unroll
        for (int half = 0; half < 2; half++) {
            const int mrow = wm2 + 16 * i + 8 * half + tq;
            const int m = brow + mrow;
            float tS = redS[mrow * 4 + 0] + redS[mrow * 4 + 1]
                     + redS[mrow * 4 + 2] + redS[mrow * 4 + 3];
            float tQ = redQ[mrow * 4 + 0] + redQ[mrow * 4 + 1]
                     + redQ[mrow * 4 + 2] + redQ[mrow * 4 + 3];
            float mean = tS * (1.0f / F);
            float var  = tQ * (1.0f / F) - mean * mean;
            float rstd = rsqrtf(var + 1e-5f);
#pragma unroll
            for (int j = 0; j < 8; j++) {
                const int n = wn2 + 8 * j + tr;
                float o0 = gj0[j] * (acc[i][j][half * 2 + 0] - mean) * rstd + tj0[j];
                float o1 = gj1[j] * (acc[i][j][half * 2 + 1] - mean) * rstd + tj1[j];
                *(float2*)(O + (size_t)m * F + n) = make_float2(o0, o1);
            }
        }
}

// ---------------- merged convert fp32 -> fp16 ----------------
#define NSEG 10
struct ConvArgs {
    const float* s[NSEG];
    h16* h[NSEG];
    int end4[NSEG];
};

__global__ __launch_bounds__(256) void conv_all(ConvArgs a, int total4)
{
    int i = blockIdx.x * 256 + threadIdx.x;
    if (i >= total4) return;
    int seg = 0;
#pragma unroll
    for (int s = 0; s < NSEG - 1; s++) seg += (i >= a.end4[s]) ? 1 : 0;
    const int base = seg ? a.end4[seg - 1] : 0;
    const int j = i - base;

    float4 v = ((const float4*)a.s[seg])[j];
    h16* hp = a.h[seg];
    ((__half2*)hp)[2 * j]     = __halves2half2(__float2half_rn(v.x), __float2half_rn(v.y));
    ((__half2*)hp)[2 * j + 1] = __halves2half2(__float2half_rn(v.z), __float2half_rn(v.w));
}

// ---------------- 9-tap attention, smem halo staging (4 slices via y) ----------------
// Block: 16 pixels in one image row; 16 threads/pixel (16 ch each).
// Halo: 3 rows x 18 cols staged in smem (K 512B + V 512B per pixel, stride 1088).
#define APX 16
#define PXSTRIDE 1088u
#define ATT_SMEM (54*1088)

struct AttArgs {
    const h16* Q[4];
    const h16* Kp[4];
    const h16* Vp[4];
    h16* O[4];
};

__global__ __launch_bounds__(256) void attend_kernel(AttArgs a, int ostride)
{
    extern __shared__ char attsm[];
    const uint32_t sb = smem_u32(attsm);

    const int z    = blockIdx.y;
    const int tid  = threadIdx.x;
    const int pix0 = blockIdx.x * APX;
    const int b    = pix0 / (HH * WW);
    const int rr   = pix0 % (HH * WW);
    const int y    = rr / WW;
    const int x0   = rr % WW;

    const h16* __restrict__ Q  = a.Q[z];
    const h16* __restrict__ Kp = a.Kp[z];
    const h16* __restrict__ Vp = a.Vp[z];

    // ---- stage halo K/V (zero-fill out-of-image) ----
#pragma unroll
    for (int t = 0; t < 14; t++) {
        const int qid = tid + t * 256;
        if (qid < 3456) {
            const int e   = qid >> 6;
            const int qq  = qid & 63;
            const int isV = qq >> 5;
            const int q   = qq & 31;
            const int yy  = y + (e / 18) - 1;
            const int xx  = x0 + (e % 18) - 1;
            const bool ok = (yy >= 0 && yy < HH && xx >= 0 && xx < WW);
            const int ys  = ok ? yy : 0;
            const int xs  = ok ? xx : 0;
            const h16* src = (isV ? Vp : Kp) +
                ((size_t)(b * HH + ys) * WW + xs) * PDIM + q * 8;
            cpasync16z(sb + (uint32_t)e * PXSTRIDE + (uint32_t)isV * 512u + (uint32_t)q * 16u,
                       src, ok ? 16 : 0);
        }
    }
    asm volatile("cp.async.commit_group;" ::: "memory");
    asm volatile("cp.async.wait_group 0;" ::: "memory");
    __syncthreads();

    const int px  = tid >> 4;
    const int t16 = tid & 15;
    const int ch  = t16 * 16;
    const int pix = pix0 + px;

    const float scale = 0.17677669529663687f;
    float qf[16];
    {
        const uint4* qp = (const uint4*)(Q + (size_t)pix * PDIM + ch);
        uint4 q0 = qp[0], q1 = qp[1];
        const uint32_t* qu = (const uint32_t*)&q0;
#pragma unroll
        for (int i = 0; i < 4; i++) {
            float2 f = __half22float2(*(__half2*)&qu[i]);
            qf[2 * i] = f.x * scale; qf[2 * i + 1] = f.y * scale;
        }
        const uint32_t* qu2 = (const uint32_t*)&q1;
#pragma unroll
        for (int i = 0; i < 4; i++) {
            float2 f = __half22float2(*(__half2*)&qu2[i]);
            qf[8 + 2 * i] = f.x * scale; qf[8 + 2 * i + 1] = f.y * scale;
        }
    }

    // ---- scores ----
    float sc[9];
#pragma unroll
    for (int n = 0; n < 9; n++) {
        const int hal = (n / 3) * 18 + px + (n % 3);
        const char* kb = attsm + hal * PXSTRIDE + ch * 2;
        uint4 k0 = *(const uint4*)kb;
        uint4 k1 = *(const uint4*)(kb + 16);
        float s = 0.f;
        const uint32_t* ku = (const uint32_t*)&k0;
#pragma unroll
        for (int i = 0; i < 4; i++) {
            float2 f = __half22float2(*(__half2*)&ku[i]);
            s = fmaf(qf[2 * i], f.x, s);
            s = fmaf(qf[2 * i + 1], f.y, s);
        }
        const uint32_t* ku2 = (const uint32_t*)&k1;
#pragma unroll
        for (int i = 0; i < 4; i++) {
            float2 f = __half22float2(*(__half2*)&ku2[i]);
            s = fmaf(qf[8 + 2 * i], f.x, s);
            s = fmaf(qf[8 + 2 * i + 1], f.y, s);
        }
        s += __shfl_xor_sync(0xffffffffu, s, 1);   // head = 32ch = 2 threads
        sc[n] = s;
    }

    float mx = sc[0];
#pragma unroll
    for (int n = 1; n < 9; n++) mx = fmaxf(mx, sc[n]);
    float w[9], den = 0.f;
#pragma unroll
    for (int n = 0; n < 9; n++) { w[n] = __expf(sc[n] - mx); den += w[n]; }

    // ---- weighted V ----
    float o[16];
#pragma unroll
    for (int i = 0; i < 16; i++) o[i] = 0.f;
#pragma unroll
    for (int n = 0; n < 9; n++) {
        const int hal = (n / 3) * 18 + px + (n % 3);
        const char* vb = attsm + hal * PXSTRIDE + 512 + ch * 2;
        uint4 v0 = *(const uint4*)vb;
        uint4 v1 = *(const uint4*)(vb + 16);
        const uint32_t* vu = (const uint32_t*)&v0;
#pragma unroll
        for (int i = 0; i < 4; i++) {
            float2 f = __half22float2(*(__half2*)&vu[i]);
            o[2 * i]     = fmaf(w[n], f.x, o[2 * i]);
            o[2 * i + 1] = fmaf(w[n], f.y, o[2 * i + 1]);
        }
        const uint32_t* vu2 = (const uint32_t*)&v1;
#pragma unroll
        for (int i = 0; i < 4; i++) {
            float2 f = __half22float2(*(__half2*)&vu2[i]);
            o[8 + 2 * i]     = fmaf(w[n], f.x, o[8 + 2 * i]);
            o[8 + 2 * i + 1] = fmaf(w[n], f.y, o[8 + 2 * i + 1]);
        }
    }

    const float inv = 1.f / den;
    uint32_t pk[8];
#pragma unroll
    for (int i = 0; i < 8; i++) {
        __half2 h = __halves2half2(__float2half_rn(o[2 * i] * inv),
                                   __float2half_rn(o[2 * i + 1] * inv));
        pk[i] = *(uint32_t*)&h;
    }
    h16* op = a.O[z] + (size_t)pix * ostride + ch;
    *(uint4*)op        = make_uint4(pk[0], pk[1], pk[2], pk[3]);
    *(uint4*)(op + 8)  = make_uint4(pk[4], pk[5], pk[6], pk[7]);
}

// ---------------- launch ----------------
#define SYM(p, s) cudaGetSymbolAddress((void**)&p, s)

extern "C" void kernel_launch(void* const* d_in, const int* in_sizes, int n_in,
                              void* d_out, int out_size)
{
    const float* feat0       = (const float*)d_in[0];
    const float* feat1       = (const float*)d_in[1];
    const float* in_w0       = (const float*)d_in[2];
    const float* in_b0       = (const float*)d_in[3];
    const float* in_w1       = (const float*)d_in[4];
    const float* in_b1       = (const float*)d_in[5];
    const float* out_w0      = (const float*)d_in[6];
    const float* out_b0      = (const float*)d_in[7];
    const float* out_w1      = (const float*)d_in[8];
    const float* out_b1      = (const float*)d_in[9];
    const float* ln1_g0      = (const float*)d_in[10];
    const float* ln1_b0      = (const float*)d_in[11];
    const float* ln1_g1      = (const float*)d_in[12];
    const float* ln1_b1      = (const float*)d_in[13];
    const float* ffn_up_w0   = (const float*)d_in[14];
    const float* ffn_up_b0   = (const float*)d_in[15];
    const float* ffn_down_w0 = (const float*)d_in[16];
    const float* ffn_down_b0 = (const float*)d_in[17];
    const float* ffn_up_w1   = (const float*)d_in[18];
    const float* ffn_up_b1   = (const float*)d_in[19];
    const float* ffn_down_w1 = (const float*)d_in[20];
    const float* ffn_down_b1 = (const float*)d_in[21];
    const float* ln2_g0      = (const float*)d_in[22];
    const float* ln2_b0      = (const float*)d_in[23];
    const float* ln2_g1      = (const float*)d_in[24];
    const float* ln2_b1      = (const float*)d_in[25];

    float *X0, *X1;
    SYM(X0, g_X0); SYM(X1, g_X1);
    h16 *P0, *P1, *f0, *f1, *wi0, *wi1, *wo0, *wo1, *wu0, *wu1, *wd0, *wd1;
    h16 *QQ0, *QQ1, *Xq0, *Xq1;
    SYM(P0, g_P0); SYM(P1, g_P1);
    SYM(f0, g_f0); SYM(f1, g_f1);
    SYM(wi0, g_wi0); SYM(wi1, g_wi1);
    SYM(wo0, g_wo0); SYM(wo1, g_wo1);
    SYM(wu0, g_wu0); SYM(wu1, g_wu1);
    SYM(wd0, g_wd0); SYM(wd1, g_wd1);
    SYM(QQ0, g_QQ0); SYM(QQ1, g_QQ1); SYM(Xq0, g_Xq0); SYM(Xq1, g_Xq1);

    cudaFuncSetAttribute(gemm_h16, cudaFuncAttributeMaxDynamicSharedMemorySize, GEMM_SMEM);
    cudaFuncSetAttribute(gemm_ln,  cudaFuncAttributeMaxDynamicSharedMemorySize, GEMMLN_SMEM);
    cudaFuncSetAttribute(ffn_fused, cudaFuncAttributeMaxDynamicSharedMemorySize, FFN_SMEM);
    cudaFuncSetAttribute(attend_kernel, cudaFuncAttributeMaxDynamicSharedMemorySize, ATT_SMEM);

    float* out = (float*)d_out;
    dim3 blk(256);
    const int MT = NPIX / 128;   // 100

    // ---- launch 0: all converts ----
    {
        ConvArgs ca;
        const float* srcs[NSEG] = {feat0, feat1, in_w0, in_w1, out_w0, out_w1,
                                   ffn_up_w0, ffn_up_w1, ffn_down_w0, ffn_down_w1};
        h16* hs[NSEG] = {f0, f1, wi0, wi1, wo0, wo1, wu0, wu1, wd0, wd1};
        int sizes4[NSEG] = {NPIX*F/4, NPIX*F/4, PDIM*F/4, PDIM*F/4, F*3*F/4, F*3*F/4,
                            HIDN*F/4, HIDN*F/4, F*HIDN/4, F*HIDN/4};
        int acc4 = 0;
        for (int i = 0; i < NSEG; i++) {
            ca.s[i] = srcs[i]; ca.h[i] = hs[i];
            acc4 += sizes4[i];
            ca.end4[i] = acc4;
        }
        conv_all<<<(acc4 + 255) / 256, blk>>>(ca, acc4);
    }

    // ---- launch 1: in-projection GEMMs -> P fp16 ----
    {
        GemmPair gp = {};
        gp.A[0]=f0; gp.A[1]=f1;
        gp.B0[0]=wi0; gp.B1[0]=wi0;
        gp.B0[1]=wi1; gp.B1[1]=wi1;
        gp.bias[0]=in_b0; gp.bias[1]=in_b1;
        gp.Ch[0]=P0; gp.Ch[1]=P1;
        gemm_h16<<<dim3(PDIM/128, MT, 2), blk, GEMM_SMEM>>>(gp, F, F, F, 0, PDIM, F, 0);
    }

    // ---- launch 2: 4 attentions (smem-tiled) -> QQ fp16 ----
    {
        AttArgs aa;
        aa.Q[0]=P0;     aa.Kp[0]=P0+F;   aa.Vp[0]=P0+2*F; aa.O[0]=QQ0;
        aa.Q[1]=P1;     aa.Kp[1]=P1+F;   aa.Vp[1]=P1+2*F; aa.O[1]=QQ1;
        aa.Q[2]=P0+3*F; aa.Kp[2]=P1+4*F; aa.Vp[2]=P1+5*F; aa.O[2]=QQ0+F;
        aa.Q[3]=P1+3*F; aa.Kp[3]=P0+4*F; aa.Vp[3]=P0+5*F; aa.O[3]=QQ1+F;
        attend_kernel<<<dim3(NPIX/APX, 4), blk, ATT_SMEM>>>(aa, 2*F);
    }

    // ---- launch 3: out-projection (K=512) + residual + LN1 fused (64-row tiles) ----
    {
        GemmLnPair gp = {};
        gp.A[0]=QQ0; gp.A[1]=QQ1;
        gp.B0[0]=wo0; gp.B1[0]=wo0+F;
        gp.B0[1]=wo1; gp.B1[1]=wo0+F;
        gp.bias[0]=out_b0; gp.bias2[0]=out_b0+F; gp.res[0]=feat0;
        gp.bias[1]=out_b1; gp.bias2[1]=out_b0+F; gp.res[1]=feat1;
        gp.g[0]=ln1_g0; gp.bt[0]=ln1_b0; gp.O[0]=X0; gp.Oh[0]=Xq0;
        gp.g[1]=ln1_g1; gp.bt[1]=ln1_b1; gp.O[1]=X1; gp.Oh[1]=Xq1;
        gemm_ln<<<dim3(1, NPIX/64, 2), blk, GEMMLN_SMEM>>>(gp, 2*F, 3*F, F, F, 2*F);
    }

    // ---- launch 4: fused FFN -> output ----
    {
        FfnPair fp = {};
        fp.Xq[0]=Xq0; fp.Xq[1]=Xq1;
        fp.Wu[0]=wu0; fp.Wu[1]=wu1;
        fp.Wd[0]=wd0; fp.Wd[1]=wd1;
        fp.bu[0]=ffn_up_b0;   fp.bu[1]=ffn_up_b1;
        fp.bd[0]=ffn_down_b0; fp.bd[1]=ffn_down_b1;
        fp.res[0]=X0; fp.res[1]=X1;
        fp.g[0]=ln2_g0; fp.bt[0]=ln2_b0; fp.O[0]=out;
        fp.g[1]=ln2_g1; fp.bt[1]=ln2_b1; fp.O[1]=out + (size_t)NPIX*F;
        ffn_fused<<<dim3(1, NPIX/64, 2), blk, FFN_SMEM>>>(fp);
    }
}

// round 14
// speedup vs baseline: 6.4605x; 1.0133x over previous
#include <cuda_runtime.h>
#include <cuda_fp16.h>
#include <cstdint>
#include <cstddef>

#define F      256
#define NH     8
#define BATCH  2
#define HH     80
#define WW     80
#define NPIX   (BATCH*HH*WW)   // 12800
#define PDIM   1536
#define HIDN   1024

typedef __half h16;

// ---------------- scratch (no allocations allowed) ----------------
__device__ float g_X0[(size_t)NPIX*F];
__device__ float g_X1[(size_t)NPIX*F];

__device__ h16 g_P0[(size_t)NPIX*PDIM];
__device__ h16 g_P1[(size_t)NPIX*PDIM];
__device__ h16 g_f0[(size_t)NPIX*F];
__device__ h16 g_f1[(size_t)NPIX*F];
__device__ h16 g_wi0[(size_t)PDIM*F];
__device__ h16 g_wi1[(size_t)PDIM*F];
__device__ h16 g_wo0[(size_t)F*3*F];
__device__ h16 g_wo1[(size_t)F*3*F];
__device__ h16 g_wu0[(size_t)HIDN*F];
__device__ h16 g_wu1[(size_t)HIDN*F];
__device__ h16 g_wd0[(size_t)F*HIDN];
__device__ h16 g_wd1[(size_t)F*HIDN];
__device__ h16 g_QQ0[(size_t)NPIX*2*F];
__device__ h16 g_QQ1[(size_t)NPIX*2*F];
__device__ h16 g_Xq0[(size_t)NPIX*F];
__device__ h16 g_Xq1[(size_t)NPIX*F];

// ================= helpers =================
__device__ __forceinline__ uint32_t smem_u32(const void* p) {
    uint32_t a;
    asm("{ .reg .u64 t; cvta.to.shared.u64 t, %1; cvt.u32.u64 %0, t; }" : "=r"(a) : "l"(p));
    return a;
}
__device__ __forceinline__ void cpasync16(uint32_t dst, const void* src) {
    asm volatile("cp.async.cg.shared.global [%0], [%1], 16;" :: "r"(dst), "l"(src) : "memory");
}
__device__ __forceinline__ void cpasync16z(uint32_t dst, const void* src, int srcsz) {
    asm volatile("cp.async.cg.shared.global [%0], [%1], 16, %2;"
                 :: "r"(dst), "l"(src), "r"(srcsz) : "memory");
}
__device__ __forceinline__ void ldsm4(uint32_t (&r)[4], uint32_t addr) {
    asm volatile("ldmatrix.sync.aligned.m8n8.x4.shared.b16 {%0,%1,%2,%3}, [%4];"
                 : "=r"(r[0]), "=r"(r[1]), "=r"(r[2]), "=r"(r[3]) : "r"(addr));
}
__device__ __forceinline__ void mma16816(float* d, const uint32_t* a, const uint32_t* b) {
    asm volatile("mma.sync.aligned.m16n8k16.row.col.f32.f16.f16.f32 "
                 "{%0,%1,%2,%3}, {%4,%5,%6,%7}, {%8,%9}, {%0,%1,%2,%3};"
                 : "+f"(d[0]), "+f"(d[1]), "+f"(d[2]), "+f"(d[3])
                 : "r"(a[0]), "r"(a[1]), "r"(a[2]), "r"(a[3]), "r"(b[0]), "r"(b[1]));
}

// ================= fp16 tensor GEMM 128x128, k-chunk 64 (paired over z) =================
// Stage: [A 16K][B 16K] = 32KB; 3 stages = 96KB; 2 CTAs/SM.
// 64 MMAs per warp between barriers (4 k16-steps per chunk).
#define STAGES     3
#define SMEM_STAGE 32768
#define OFF_B      16384u
#define GEMM_SMEM  (STAGES*SMEM_STAGE)

struct GemmPair {
    const h16 *A[2];
    const h16 *B0[2], *B1[2];
    const float *bias[2], *bias2[2], *res[2];
    float *C[2];
    h16 *Ch[2];
};

__global__ __launch_bounds__(256, 2) void gemm_h16(
    GemmPair gp, int lda, int ldb, int Ksplit,
    int ldres, int ldc, int K, int relu)
{
    extern __shared__ char smem[];
    const uint32_t sb0 = smem_u32(smem);

    const int z = blockIdx.z;
    const h16* __restrict__ A  = gp.A[z];
    const h16* __restrict__ B0 = gp.B0[z];
    const h16* __restrict__ B1 = gp.B1[z];
    const float* __restrict__ bias  = gp.bias[z];
    const float* __restrict__ bias2 = gp.bias2[z];
    const float* __restrict__ res   = gp.res[z];
    float* __restrict__ C  = gp.C[z];
    h16*   __restrict__ Ch = gp.Ch[z];

    const int tid  = threadIdx.x;
    const int wid  = tid >> 5;
    const int lane = tid & 31;
    const int brow = blockIdx.y * 128;
    const int bcol = blockIdx.x * 128;
    const int wm   = (wid >> 2) * 64;
    const int wn   = (wid & 3) * 32;

    float acc[4][4][4];
#pragma unroll
    for (int i = 0; i < 4; i++)
#pragma unroll
        for (int j = 0; j < 4; j++)
#pragma unroll
            for (int r = 0; r < 4; r++) acc[i][j][r] = 0.f;

    // loader: 2048 quads(16B)/stage (A 1024 + B 1024), 8/thread; rows of 128B, 8-slot swizzle
    auto load_stage = [&](int cIdx) {
        const uint32_t sb = sb0 + (uint32_t)(cIdx % STAGES) * SMEM_STAGE;
        const int k0 = cIdx * 64;
        const h16* bp;
        int kk;
        if (k0 < Ksplit) { bp = B0; kk = k0; }
        else             { bp = B1; kk = k0 - Ksplit; }
#pragma unroll
        for (int s = 0; s < 8; s++) {
            const int qid = tid + s * 256;
            const int q   = qid & 1023;
            const int row = q >> 3;
            const int c   = q & 7;
            const h16* src;
            uint32_t dstbase;
            if (qid < 1024) {
                src = A + (size_t)(brow + row) * lda + k0 + c * 8;
                dstbase = sb;
            } else {
                src = bp + (size_t)(bcol + row) * ldb + kk + c * 8;
                dstbase = sb + OFF_B;
            }
            cpasync16(dstbase + (uint32_t)row * 128u +
                      (uint32_t)((c ^ (row & 7)) * 16), src);
        }
        asm volatile("cp.async.commit_group;" ::: "memory");
    };

    const int tile = lane >> 3;
    const int rin  = lane & 7;

    const int NC = K / 64;
    for (int s = 0; s < STAGES - 1 && s < NC; s++) load_stage(s);

    for (int c = 0; c < NC; c++) {
        if (c + 2 <= NC - 1) {
            asm volatile("cp.async.wait_group 1;" ::: "memory");
        } else {
            asm volatile("cp.async.wait_group 0;" ::: "memory");
        }
        __syncthreads();
        if (c + 2 < NC) load_stage(c + 2);

        const uint32_t sb = sb0 + (uint32_t)(c % STAGES) * SMEM_STAGE;
#pragma unroll
        for (int ks = 0; ks < 4; ks++) {
            uint32_t ah[4][4], bh_[2][4];
            const int ca = ks * 2 + (tile >> 1);
#pragma unroll
            for (int i = 0; i < 4; i++) {
                const int arow = wm + i * 16 + (tile & 1) * 8 + rin;
                ldsm4(ah[i], sb + (uint32_t)arow * 128u +
                              (uint32_t)((ca ^ (arow & 7)) * 16));
            }
            const int cb = ks * 2 + (tile & 1);
#pragma unroll
            for (int jj = 0; jj < 2; jj++) {
                const int brw = wn + jj * 16 + (tile >> 1) * 8 + rin;
                ldsm4(bh_[jj], sb + OFF_B + (uint32_t)brw * 128u +
                               (uint32_t)((cb ^ (brw & 7)) * 16));
            }
#pragma unroll
            for (int i = 0; i < 4; i++)
#pragma unroll
                for (int j = 0; j < 4; j++)
                    mma16816(acc[i][j], ah[i], &bh_[j >> 1][(j & 1) * 2]);
        }
    }

    const int tq = lane >> 2;
    const int tr = (lane & 3) * 2;
    float bj0[4], bj1[4];
#pragma unroll
    for (int j = 0; j < 4; j++) {
        const int n = bcol + wn + 8 * j + tr;
        float b0 = bias[n], b1 = bias[n + 1];
        if (bias2) { b0 += bias2[n]; b1 += bias2[n + 1]; }
        bj0[j] = b0; bj1[j] = b1;
    }
#pragma unroll
    for (int i = 0; i < 4; i++)
#pragma unroll
        for (int half = 0; half < 2; half++) {
            const int m = brow + wm + 16 * i + tq + half * 8;
#pragma unroll
            for (int j = 0; j < 4; j++) {
                const int n = bcol + wn + 8 * j + tr;
                float v0 = acc[i][j][half * 2 + 0] + bj0[j];
                float v1 = acc[i][j][half * 2 + 1] + bj1[j];
                if (res) {
                    float2 r = *(const float2*)(res + (size_t)m * ldres + n);
                    v0 += r.x; v1 += r.y;
                }
                if (relu) { v0 = fmaxf(v0, 0.f); v1 = fmaxf(v1, 0.f); }
                if (C) *(float2*)(C + (size_t)m * ldc + n) = make_float2(v0, v1);
                if (Ch)
                    *(__half2*)(Ch + (size_t)m * ldc + n) =
                        __halves2half2(__float2half_rn(v0), __float2half_rn(v1));
            }
        }
}

// ================= fp16 GEMM 64x256 + fused LayerNorm (paired over z), 2 CTA/SM =================
#define LSTAGES    4
#define LSTAGE_SZ  20480
#define LOFF_B     4096u
#define GEMMLN_SMEM (LSTAGES*LSTAGE_SZ)

struct GemmLnPair {
    const h16 *A[2];
    const h16 *B0[2], *B1[2];
    const float *bias[2], *bias2[2], *res[2];
    const float *g[2], *bt[2];
    float *O[2];
    h16 *Oh[2];
};

__global__ __launch_bounds__(256, 2) void gemm_ln(
    GemmLnPair gp, int lda, int ldb, int Ksplit, int ldres, int K)
{
    extern __shared__ char smem[];
    const uint32_t sb0 = smem_u32(smem);

    const int z = blockIdx.z;
    const h16* __restrict__ A  = gp.A[z];
    const h16* __restrict__ B0 = gp.B0[z];
    const h16* __restrict__ B1 = gp.B1[z];
    const float* __restrict__ bias  = gp.bias[z];
    const float* __restrict__ bias2 = gp.bias2[z];
    const float* __restrict__ res   = gp.res[z];
    const float* __restrict__ gam   = gp.g[z];
    const float* __restrict__ bet   = gp.bt[z];
    float* __restrict__ O  = gp.O[z];
    h16*   __restrict__ Oh = gp.Oh[z];

    const int tid  = threadIdx.x;
    const int wid  = tid >> 5;
    const int lane = tid & 31;
    const int brow = blockIdx.y * 64;
    const int wm   = (wid >> 2) * 32;
    const int wn   = (wid & 3) * 64;

    float acc[2][8][4];
#pragma unroll
    for (int i = 0; i < 2; i++)
#pragma unroll
        for (int j = 0; j < 8; j++)
#pragma unroll
            for (int r = 0; r < 4; r++) acc[i][j][r] = 0.f;

    auto load_stage = [&](int cIdx) {
        const uint32_t sb = sb0 + (uint32_t)(cIdx % LSTAGES) * LSTAGE_SZ;
        const int k0 = cIdx * 32;
        const h16* bp;
        int kk;
        if (k0 < Ksplit) { bp = B0; kk = k0; }
        else             { bp = B1; kk = k0 - Ksplit; }
#pragma unroll
        for (int s = 0; s < 5; s++) {
            const int qid = tid + s * 256;
            const h16* src;
            uint32_t dstbase;
            int row, c;
            if (qid < 256) {
                row = qid >> 2; c = qid & 3;
                src = A + (size_t)(brow + row) * lda + k0 + c * 8;
                dstbase = sb;
            } else {
                const int q2 = qid - 256;
                row = q2 >> 2; c = q2 & 3;
                src = bp + (size_t)row * ldb + kk + c * 8;
                dstbase = sb + LOFF_B;
            }
            cpasync16(dstbase + (uint32_t)row * 64u +
                      (uint32_t)((c ^ ((row >> 1) & 3)) * 16), src);
        }
        asm volatile("cp.async.commit_group;" ::: "memory");
    };

    const int tile = lane >> 3;
    const int rin  = lane & 7;
    const uint32_t rsw = (uint32_t)(rin >> 1);

    const int NC = K / 32;
    for (int s = 0; s < LSTAGES - 1 && s < NC; s++) load_stage(s);

    for (int c = 0; c < NC; c++) {
        if (c + 3 <= NC) {
            asm volatile("cp.async.wait_group 2;" ::: "memory");
        } else if (c + 2 == NC) {
            asm volatile("cp.async.wait_group 1;" ::: "memory");
        } else {
            asm volatile("cp.async.wait_group 0;" ::: "memory");
        }
        __syncthreads();
        if (c + 3 < NC) load_stage(c + 3);

        const uint32_t sb = sb0 + (uint32_t)(c % LSTAGES) * LSTAGE_SZ;
#pragma unroll
        for (int ks = 0; ks < 2; ks++) {
            uint32_t ah[2][4], bh_[4][4];
            const uint32_t swa = ((uint32_t)(ks * 2 + (tile >> 1)) ^ rsw) * 16u;
#pragma unroll
            for (int i = 0; i < 2; i++)
                ldsm4(ah[i], sb + (uint32_t)(wm + i * 16 + (tile & 1) * 8 + rin) * 64u + swa);
            const uint32_t swb = ((uint32_t)(ks * 2 + (tile & 1)) ^ rsw) * 16u;
#pragma unroll
            for (int jj = 0; jj < 4; jj++)
                ldsm4(bh_[jj], sb + LOFF_B +
                      (uint32_t)(wn + jj * 16 + (tile >> 1) * 8 + rin) * 64u + swb);
#pragma unroll
            for (int i = 0; i < 2; i++)
#pragma unroll
                for (int j = 0; j < 8; j++)
                    mma16816(acc[i][j], ah[i], &bh_[j >> 1][(j & 1) * 2]);
        }
    }

    __syncthreads();
    float* redS = (float*)smem;
    float* redQ = (float*)smem + 256;

    const int tq = lane >> 2;
    const int tr = (lane & 3) * 2;
    const int wslot = wn >> 6;

    float bj0[8], bj1[8];
#pragma unroll
    for (int j = 0; j < 8; j++) {
        const int n = wn + 8 * j + tr;
        float b0 = bias[n], b1 = bias[n + 1];
        if (bias2) { b0 += bias2[n]; b1 += bias2[n + 1]; }
        bj0[j] = b0; bj1[j] = b1;
    }

#pragma unroll
    for (int i = 0; i < 2; i++)
#pragma unroll
        for (int half = 0; half < 2; half++) {
            const int mrow = wm + 16 * i + 8 * half + tq;
            const int m = brow + mrow;
            float s1 = 0.f, s2 = 0.f;
#pragma unroll
            for (int j = 0; j < 8; j++) {
                float v0 = acc[i][j][half * 2 + 0] + bj0[j];
                float v1 = acc[i][j][half * 2 + 1] + bj1[j];
                if (res) {
                    float2 rr = *(const float2*)(res + (size_t)m * ldres + wn + 8 * j + tr);
                    v0 += rr.x; v1 += rr.y;
                }
                acc[i][j][half * 2 + 0] = v0;
                acc[i][j][half * 2 + 1] = v1;
                s1 += v0 + v1;
                s2 += v0 * v0 + v1 * v1;
            }
            s1 += __shfl_xor_sync(0xffffffffu, s1, 1);
            s2 += __shfl_xor_sync(0xffffffffu, s2, 1);
            s1 += __shfl_xor_sync(0xffffffffu, s1, 2);
            s2 += __shfl_xor_sync(0xffffffffu, s2, 2);
            if ((lane & 3) == 0) {
                redS[mrow * 4 + wslot] = s1;
                redQ[mrow * 4 + wslot] = s2;
            }
        }
    __syncthreads();

#pragma unroll
    for (int i = 0; i < 2; i++)
#pragma unroll
        for (int half = 0; half < 2; half++) {
            const int mrow = wm + 16 * i + 8 * half + tq;
            const int m = brow + mrow;
            float tS = redS[mrow * 4 + 0] + redS[mrow * 4 + 1]
                     + redS[mrow * 4 + 2] + redS[mrow * 4 + 3];
            float tQ = redQ[mrow * 4 + 0] + redQ[mrow * 4 + 1]
                     + redQ[mrow * 4 + 2] + redQ[mrow * 4 + 3];
            float mean = tS * (1.0f / F);
            float var  = tQ * (1.0f / F) - mean * mean;
            float rstd = rsqrtf(var + 1e-5f);
#pragma unroll
            for (int j = 0; j < 8; j++) {
                const int n = wn + 8 * j + tr;
                float2 gg = *(const float2*)(gam + n);
                float2 bb = *(const float2*)(bet + n);
                float o0 = gg.x * (acc[i][j][half * 2 + 0] - mean) * rstd + bb.x;
                float o1 = gg.y * (acc[i][j][half * 2 + 1] - mean) * rstd + bb.y;
                if (O) *(float2*)(O + (size_t)m * F + n) = make_float2(o0, o1);
                if (Oh)
                    *(__half2*)(Oh + (size_t)m * F + n) =
                        __halves2half2(__float2half_rn(o0), __float2half_rn(o1));
            }
        }
}

// ================= fused FFN: up(relu) + down + residual + LN2 =================
#define XQ_OFF 0u
#define WU_OFF 32768u
#define WD_OFF 98304u
#define UC_OFF 163840u
#define FFN_SMEM 180224

struct FfnPair {
    const h16 *Xq[2];
    const h16 *Wu[2], *Wd[2];
    const float *bu[2], *bd[2], *res[2];
    const float *g[2], *bt[2];
    float *O[2];
};

__global__ __launch_bounds__(256, 1) void ffn_fused(FfnPair fp)
{
    extern __shared__ char smem[];
    const uint32_t sb = smem_u32(smem);

    const int z = blockIdx.z;
    const h16* __restrict__ Xq = fp.Xq[z];
    const h16* __restrict__ Wu = fp.Wu[z];
    const h16* __restrict__ Wd = fp.Wd[z];
    const float* __restrict__ bu  = fp.bu[z];
    const float* __restrict__ bd  = fp.bd[z];
    const float* __restrict__ res = fp.res[z];
    const float* __restrict__ gam = fp.g[z];
    const float* __restrict__ bet = fp.bt[z];
    float* __restrict__ O = fp.O[z];

    const int tid  = threadIdx.x;
    const int wid  = tid >> 5;
    const int lane = tid & 31;
    const int brow = blockIdx.y * 64;

    const int tile = lane >> 3;
    const int rin  = lane & 7;
    const uint32_t rsw = (uint32_t)(rin >> 1);
    const int tq = lane >> 2;
    const int tr = (lane & 3) * 2;

    const int wm1 = (wid & 1) * 32;
    const int wh  = (wid >> 1) * 32;
    const int wm2 = (wid >> 2) * 32;
    const int wn2 = (wid & 3) * 64;

    float acc[2][8][4];
#pragma unroll
    for (int i = 0; i < 2; i++)
#pragma unroll
        for (int j = 0; j < 8; j++)
#pragma unroll
            for (int r = 0; r < 4; r++) acc[i][j][r] = 0.f;

    auto load_xq = [&]() {
#pragma unroll
        for (int t = 0; t < 8; t++) {
            const int qid = tid + t * 256;
            const int s = qid >> 8, q = qid & 255;
            const int r = q >> 2, c = q & 3;
            cpasync16(sb + XQ_OFF + (uint32_t)s * 4096u + (uint32_t)r * 64u +
                      (uint32_t)((c ^ ((r >> 1) & 3)) * 16),
                      Xq + (size_t)(brow + r) * F + s * 32 + c * 8);
        }
    };
    auto load_wu = [&](int hc) {
#pragma unroll
        for (int t = 0; t < 16; t++) {
            const int qid = tid + t * 256;
            const int s = qid >> 9, q = qid & 511;
            const int r = q >> 2, c = q & 3;
            cpasync16(sb + WU_OFF + (uint32_t)s * 8192u + (uint32_t)r * 64u +
                      (uint32_t)((c ^ ((r >> 1) & 3)) * 16),
                      Wu + (size_t)(hc * 128 + r) * F + s * 32 + c * 8);
        }
        asm volatile("cp.async.commit_group;" ::: "memory");
    };
    auto load_wd = [&](int hc) {
#pragma unroll
        for (int t = 0; t < 16; t++) {
            const int qid = tid + t * 256;
            const int s = qid >> 10, q = qid & 1023;
            const int r = q >> 2, c = q & 3;
            cpasync16(sb + WD_OFF + (uint32_t)s * 16384u + (uint32_t)r * 64u +
                      (uint32_t)((c ^ ((r >> 1) & 3)) * 16),
                      Wd + (size_t)r * HIDN + hc * 128 + s * 32 + c * 8);
        }
        asm volatile("cp.async.commit_group;" ::: "memory");
    };

    load_xq();
    load_wu(0);
    asm volatile("cp.async.wait_group 0;" ::: "memory");
    __syncthreads();

    for (int hc = 0; hc < 8; hc++) {
        load_wd(hc);

        float acc1[2][4][4];
#pragma unroll
        for (int i = 0; i < 2; i++)
#pragma unroll
            for (int j = 0; j < 4; j++)
#pragma unroll
                for (int r = 0; r < 4; r++) acc1[i][j][r] = 0.f;

#pragma unroll
        for (int kc = 0; kc < 8; kc++) {
            const uint32_t sx = sb + XQ_OFF + (uint32_t)kc * 4096u;
            const uint32_t sw = sb + WU_OFF + (uint32_t)kc * 8192u;
#pragma unroll
            for (int ks = 0; ks < 2; ks++) {
                uint32_t ah[2][4], bh_[2][4];
                const uint32_t swa = ((uint32_t)(ks * 2 + (tile >> 1)) ^ rsw) * 16u;
#pragma unroll
                for (int i = 0; i < 2; i++)
                    ldsm4(ah[i], sx + (uint32_t)(wm1 + i * 16 + (tile & 1) * 8 + rin) * 64u + swa);
                const uint32_t swb = ((uint32_t)(ks * 2 + (tile & 1)) ^ rsw) * 16u;
#pragma unroll
                for (int jj = 0; jj < 2; jj++)
                    ldsm4(bh_[jj], sw + (uint32_t)(wh + jj * 16 + (tile >> 1) * 8 + rin) * 64u + swb);
#pragma unroll
                for (int i = 0; i < 2; i++)
#pragma unroll
                    for (int j = 0; j < 4; j++)
                        mma16816(acc1[i][j], ah[i], &bh_[j >> 1][(j & 1) * 2]);
            }
        }

        {
            const int sub = wh >> 5;
            const uint32_t ucb = sb + UC_OFF + (uint32_t)sub * 4096u;
#pragma unroll
            for (int i = 0; i < 2; i++)
#pragma unroll
                for (int j = 0; j < 4; j++) {
                    const int nh = hc * 128 + wh + j * 8 + tr;
                    float b0 = bu[nh], b1 = bu[nh + 1];
                    float v0 = fmaxf(acc1[i][j][0] + b0, 0.f);
                    float v1 = fmaxf(acc1[i][j][1] + b1, 0.f);
                    float v2 = fmaxf(acc1[i][j][2] + b0, 0.f);
                    float v3 = fmaxf(acc1[i][j][3] + b1, 0.f);
                    const int row0 = wm1 + i * 16 + tq;
                    const int row1 = row0 + 8;
                    uint32_t a0 = ucb + (uint32_t)row0 * 64u +
                                  (uint32_t)((j ^ ((row0 >> 1) & 3)) * 16) + (uint32_t)tr * 2u;
                    uint32_t a1 = ucb + (uint32_t)row1 * 64u +
                                  (uint32_t)((j ^ ((row1 >> 1) & 3)) * 16) + (uint32_t)tr * 2u;
                    __half2 h01 = __halves2half2(__float2half_rn(v0), __float2half_rn(v1));
                    __half2 h23 = __halves2half2(__float2half_rn(v2), __float2half_rn(v3));
                    asm volatile("st.shared.b32 [%0], %1;" :: "r"(a0), "r"(*(uint32_t*)&h01) : "memory");
                    asm volatile("st.shared.b32 [%0], %1;" :: "r"(a1), "r"(*(uint32_t*)&h23) : "memory");
                }
        }

        asm volatile("cp.async.wait_group 0;" ::: "memory");
        __syncthreads();

        if (hc < 7) load_wu(hc + 1);

#pragma unroll
        for (int s = 0; s < 4; s++) {
            const uint32_t su = sb + UC_OFF + (uint32_t)s * 4096u;
            const uint32_t sd = sb + WD_OFF + (uint32_t)s * 16384u;
#pragma unroll
            for (int ks = 0; ks < 2; ks++) {
                uint32_t ah[2][4], bh_[4][4];
                const uint32_t swa = ((uint32_t)(ks * 2 + (tile >> 1)) ^ rsw) * 16u;
#pragma unroll
                for (int i = 0; i < 2; i++)
                    ldsm4(ah[i], su + (uint32_t)(wm2 + i * 16 + (tile & 1) * 8 + rin) * 64u + swa);
                const uint32_t swb = ((uint32_t)(ks * 2 + (tile & 1)) ^ rsw) * 16u;
#pragma unroll
                for (int jj = 0; jj < 4; jj++)
                    ldsm4(bh_[jj], sd + (uint32_t)(wn2 + jj * 16 + (tile >> 1) * 8 + rin) * 64u + swb);
#pragma unroll
                for (int i = 0; i < 2; i++)
#pragma unroll
                    for (int j = 0; j < 8; j++)
                        mma16816(acc[i][j], ah[i], &bh_[j >> 1][(j & 1) * 2]);
            }
        }

        asm volatile("cp.async.wait_group 0;" ::: "memory");
        __syncthreads();
    }

    float* redS = (float*)(smem + UC_OFF);
    float* redQ = (float*)(smem + UC_OFF) + 256;
    const int wslot = wn2 >> 6;

    float bj0[8], bj1[8];
#pragma unroll
    for (int j = 0; j < 8; j++) {
        const int n = wn2 + 8 * j + tr;
        bj0[j] = bd[n]; bj1[j] = bd[n + 1];
    }

#pragma unroll
    for (int i = 0; i < 2; i++)
#pragma unroll
        for (int half = 0; half < 2; half++) {
            const int mrow = wm2 + 16 * i + 8 * half + tq;
            const int m = brow + mrow;
            float s1 = 0.f, s2 = 0.f;
#pragma unroll
            for (int j = 0; j < 8; j++) {
                float v0 = acc[i][j][half * 2 + 0] + bj0[j];
                float v1 = acc[i][j][half * 2 + 1] + bj1[j];
                float2 rr = *(const float2*)(res + (size_t)m * F + wn2 + 8 * j + tr);
                v0 += rr.x; v1 += rr.y;
                acc[i][j][half * 2 + 0] = v0;
                acc[i][j][half * 2 + 1] = v1;
                s1 += v0 + v1;
                s2 += v0 * v0 + v1 * v1;
            }
            s1 += __shfl_xor_sync(0xffffffffu, s1, 1);
            s2 += __shfl_xor_sync(0xffffffffu, s2, 1);
            s1 += __shfl_xor_sync(0xffffffffu, s1, 2);
            s2 += __shfl_xor_sync(0xffffffffu, s2, 2);
            if ((lane & 3) == 0) {
                redS[mrow * 4 + wslot] = s1;
                redQ[mrow * 4 + wslot] = s2;
            }
        }
    __syncthreads();

    float gj0[8], gj1[8], tj0[8], tj1[8];
#pragma unroll
    for (int j = 0; j < 8; j++) {
        const int n = wn2 + 8 * j + tr;
        float2 gg = *(const float2*)(gam + n);
        float2 bb = *(const float2*)(bet + n);
        gj0[j] = gg.x; gj1[j] = gg.y;
        tj0[j] = bb.x; tj1[j] = bb.y;
    }

#pragma unroll
    for (int i = 0; i < 2; i++)
#pragma unroll
        for (int half = 0; half < 2; half++) {
            const int mrow = wm2 + 16 * i + 8 * half + tq;
            const int m = brow + mrow;
            float tS = redS[mrow * 4 + 0] + redS[mrow * 4 + 1]
                     + redS[mrow * 4 + 2] + redS[mrow * 4 + 3];
            float tQ = redQ[mrow * 4 + 0] + redQ[mrow * 4 + 1]
                     + redQ[mrow * 4 + 2] + redQ[mrow * 4 + 3];
            float mean = tS * (1.0f / F);
            float var  = tQ * (1.0f / F) - mean * mean;
            float rstd = rsqrtf(var + 1e-5f);
#pragma unroll
            for (int j = 0; j < 8; j++) {
                const int n = wn2 + 8 * j + tr;
                float o0 = gj0[j] * (acc[i][j][half * 2 + 0] - mean) * rstd + tj0[j];
                float o1 = gj1[j] * (acc[i][j][half * 2 + 1] - mean) * rstd + tj1[j];
                *(float2*)(O + (size_t)m * F + n) = make_float2(o0, o1);
            }
        }
}

// ---------------- merged convert fp32 -> fp16 ----------------
#define NSEG 10
struct ConvArgs {
    const float* s[NSEG];
    h16* h[NSEG];
    int end4[NSEG];
};

__global__ __launch_bounds__(256) void conv_all(ConvArgs a, int total4)
{
    int i = blockIdx.x * 256 + threadIdx.x;
    if (i >= total4) return;
    int seg = 0;
#pragma unroll
    for (int s = 0; s < NSEG - 1; s++) seg += (i >= a.end4[s]) ? 1 : 0;
    const int base = seg ? a.end4[seg - 1] : 0;
    const int j = i - base;

    float4 v = ((const float4*)a.s[seg])[j];
    h16* hp = a.h[seg];
    ((__half2*)hp)[2 * j]     = __halves2half2(__float2half_rn(v.x), __float2half_rn(v.y));
    ((__half2*)hp)[2 * j + 1] = __halves2half2(__float2half_rn(v.z), __float2half_rn(v.w));
}

// ---------------- 9-tap attention, smem halo staging (4 slices via y) ----------------
#define APX 16
#define PXSTRIDE 1088u
#define ATT_SMEM (54*1088)

struct AttArgs {
    const h16* Q[4];
    const h16* Kp[4];
    const h16* Vp[4];
    h16* O[4];
};

__global__ __launch_bounds__(256) void attend_kernel(AttArgs a, int ostride)
{
    extern __shared__ char attsm[];
    const uint32_t sb = smem_u32(attsm);

    const int z    = blockIdx.y;
    const int tid  = threadIdx.x;
    const int pix0 = blockIdx.x * APX;
    const int b    = pix0 / (HH * WW);
    const int rr   = pix0 % (HH * WW);
    const int y    = rr / WW;
    const int x0   = rr % WW;

    const h16* __restrict__ Q  = a.Q[z];
    const h16* __restrict__ Kp = a.Kp[z];
    const h16* __restrict__ Vp = a.Vp[z];

#pragma unroll
    for (int t = 0; t < 14; t++) {
        const int qid = tid + t * 256;
        if (qid < 3456) {
            const int e   = qid >> 6;
            const int qq  = qid & 63;
            const int isV = qq >> 5;
            const int q   = qq & 31;
            const int yy  = y + (e / 18) - 1;
            const int xx  = x0 + (e % 18) - 1;
            const bool ok = (yy >= 0 && yy < HH && xx >= 0 && xx < WW);
            const int ys  = ok ? yy : 0;
            const int xs  = ok ? xx : 0;
            const h16* src = (isV ? Vp : Kp) +
                ((size_t)(b * HH + ys) * WW + xs) * PDIM + q * 8;
            cpasync16z(sb + (uint32_t)e * PXSTRIDE + (uint32_t)isV * 512u + (uint32_t)q * 16u,
                       src, ok ? 16 : 0);
        }
    }
    asm volatile("cp.async.commit_group;" ::: "memory");
    asm volatile("cp.async.wait_group 0;" ::: "memory");
    __syncthreads();

    const int px  = tid >> 4;
    const int t16 = tid & 15;
    const int ch  = t16 * 16;
    const int pix = pix0 + px;

    const float scale = 0.17677669529663687f;
    float qf[16];
    {
        const uint4* qp = (const uint4*)(Q + (size_t)pix * PDIM + ch);
        uint4 q0 = qp[0], q1 = qp[1];
        const uint32_t* qu = (const uint32_t*)&q0;
#pragma unroll
        for (int i = 0; i < 4; i++) {
            float2 f = __half22float2(*(__half2*)&qu[i]);
            qf[2 * i] = f.x * scale; qf[2 * i + 1] = f.y * scale;
        }
        const uint32_t* qu2 = (const uint32_t*)&q1;
#pragma unroll
        for (int i = 0; i < 4; i++) {
            float2 f = __half22float2(*(__half2*)&qu2[i]);
            qf[8 + 2 * i] = f.x * scale; qf[8 + 2 * i + 1] = f.y * scale;
        }
    }

    float sc[9];
#pragma unroll
    for (int n = 0; n < 9; n++) {
        const int hal = (n / 3) * 18 + px + (n % 3);
        const char* kb = attsm + hal * PXSTRIDE + ch * 2;
        uint4 k0 = *(const uint4*)kb;
        uint4 k1 = *(const uint4*)(kb + 16);
        float s = 0.f;
        const uint32_t* ku = (const uint32_t*)&k0;
#pragma unroll
        for (int i = 0; i < 4; i++) {
            float2 f = __half22float2(*(__half2*)&ku[i]);
            s = fmaf(qf[2 * i], f.x, s);
            s = fmaf(qf[2 * i + 1], f.y, s);
        }
        const uint32_t* ku2 = (const uint32_t*)&k1;
#pragma unroll
        for (int i = 0; i < 4; i++) {
            float2 f = __half22float2(*(__half2*)&ku2[i]);
            s = fmaf(qf[8 + 2 * i], f.x, s);
            s = fmaf(qf[8 + 2 * i + 1], f.y, s);
        }
        s += __shfl_xor_sync(0xffffffffu, s, 1);
        sc[n] = s;
    }

    float mx = sc[0];
#pragma unroll
    for (int n = 1; n < 9; n++) mx = fmaxf(mx, sc[n]);
    float w[9], den = 0.f;
#pragma unroll
    for (int n = 0; n < 9; n++) { w[n] = __expf(sc[n] - mx); den += w[n]; }

    float o[16];
#pragma unroll
    for (int i = 0; i < 16; i++) o[i] = 0.f;
#pragma unroll
    for (int n = 0; n < 9; n++) {
        const int hal = (n / 3) * 18 + px + (n % 3);
        const char* vb = attsm + hal * PXSTRIDE + 512 + ch * 2;
        uint4 v0 = *(const uint4*)vb;
        uint4 v1 = *(const uint4*)(vb + 16);
        const uint32_t* vu = (const uint32_t*)&v0;
#pragma unroll
        for (int i = 0; i < 4; i++) {
            float2 f = __half22float2(*(__half2*)&vu[i]);
            o[2 * i]     = fmaf(w[n], f.x, o[2 * i]);
            o[2 * i + 1] = fmaf(w[n], f.y, o[2 * i + 1]);
        }
        const uint32_t* vu2 = (const uint32_t*)&v1;
#pragma unroll
        for (int i = 0; i < 4; i++) {
            float2 f = __half22float2(*(__half2*)&vu2[i]);
            o[8 + 2 * i]     = fmaf(w[n], f.x, o[8 + 2 * i]);
            o[8 + 2 * i + 1] = fmaf(w[n], f.y, o[8 + 2 * i + 1]);
        }
    }

    const float inv = 1.f / den;
    uint32_t pk[8];
#pragma unroll
    for (int i = 0; i < 8; i++) {
        __half2 h = __halves2half2(__float2half_rn(o[2 * i] * inv),
                                   __float2half_rn(o[2 * i + 1] * inv));
        pk[i] = *(uint32_t*)&h;
    }
    h16* op = a.O[z] + (size_t)pix * ostride + ch;
    *(uint4*)op        = make_uint4(pk[0], pk[1], pk[2], pk[3]);
    *(uint4*)(op + 8)  = make_uint4(pk[4], pk[5], pk[6], pk[7]);
}

// ---------------- launch ----------------
#define SYM(p, s) cudaGetSymbolAddress((void**)&p, s)

extern "C" void kernel_launch(void* const* d_in, const int* in_sizes, int n_in,
                              void* d_out, int out_size)
{
    const float* feat0       = (const float*)d_in[0];
    const float* feat1       = (const float*)d_in[1];
    const float* in_w0       = (const float*)d_in[2];
    const float* in_b0       = (const float*)d_in[3];
    const float* in_w1       = (const float*)d_in[4];
    const float* in_b1       = (const float*)d_in[5];
    const float* out_w0      = (const float*)d_in[6];
    const float* out_b0      = (const float*)d_in[7];
    const float* out_w1      = (const float*)d_in[8];
    const float* out_b1      = (const float*)d_in[9];
    const float* ln1_g0      = (const float*)d_in[10];
    const float* ln1_b0      = (const float*)d_in[11];
    const float* ln1_g1      = (const float*)d_in[12];
    const float* ln1_b1      = (const float*)d_in[13];
    const float* ffn_up_w0   = (const float*)d_in[14];
    const float* ffn_up_b0   = (const float*)d_in[15];
    const float* ffn_down_w0 = (const float*)d_in[16];
    const float* ffn_down_b0 = (const float*)d_in[17];
    const float* ffn_up_w1   = (const float*)d_in[18];
    const float* ffn_up_b1   = (const float*)d_in[19];
    const float* ffn_down_w1 = (const float*)d_in[20];
    const float* ffn_down_b1 = (const float*)d_in[21];
    const float* ln2_g0      = (const float*)d_in[22];
    const float* ln2_b0      = (const float*)d_in[23];
    const float* ln2_g1      = (const float*)d_in[24];
    const float* ln2_b1      = (const float*)d_in[25];

    float *X0, *X1;
    SYM(X0, g_X0); SYM(X1, g_X1);
    h16 *P0, *P1, *f0, *f1, *wi0, *wi1, *wo0, *wo1, *wu0, *wu1, *wd0, *wd1;
    h16 *QQ0, *QQ1, *Xq0, *Xq1;
    SYM(P0, g_P0); SYM(P1, g_P1);
    SYM(f0, g_f0); SYM(f1, g_f1);
    SYM(wi0, g_wi0); SYM(wi1, g_wi1);
    SYM(wo0, g_wo0); SYM(wo1, g_wo1);
    SYM(wu0, g_wu0); SYM(wu1, g_wu1);
    SYM(wd0, g_wd0); SYM(wd1, g_wd1);
    SYM(QQ0, g_QQ0); SYM(QQ1, g_QQ1); SYM(Xq0, g_Xq0); SYM(Xq1, g_Xq1);

    cudaFuncSetAttribute(gemm_h16, cudaFuncAttributeMaxDynamicSharedMemorySize, GEMM_SMEM);
    cudaFuncSetAttribute(gemm_ln,  cudaFuncAttributeMaxDynamicSharedMemorySize, GEMMLN_SMEM);
    cudaFuncSetAttribute(ffn_fused, cudaFuncAttributeMaxDynamicSharedMemorySize, FFN_SMEM);
    cudaFuncSetAttribute(attend_kernel, cudaFuncAttributeMaxDynamicSharedMemorySize, ATT_SMEM);

    float* out = (float*)d_out;
    dim3 blk(256);
    const int MT = NPIX / 128;   // 100

    // ---- launch 0: all converts ----
    {
        ConvArgs ca;
        const float* srcs[NSEG] = {feat0, feat1, in_w0, in_w1, out_w0, out_w1,
                                   ffn_up_w0, ffn_up_w1, ffn_down_w0, ffn_down_w1};
        h16* hs[NSEG] = {f0, f1, wi0, wi1, wo0, wo1, wu0, wu1, wd0, wd1};
        int sizes4[NSEG] = {NPIX*F/4, NPIX*F/4, PDIM*F/4, PDIM*F/4, F*3*F/4, F*3*F/4,
                            HIDN*F/4, HIDN*F/4, F*HIDN/4, F*HIDN/4};
        int acc4 = 0;
        for (int i = 0; i < NSEG; i++) {
            ca.s[i] = srcs[i]; ca.h[i] = hs[i];
            acc4 += sizes4[i];
            ca.end4[i] = acc4;
        }
        conv_all<<<(acc4 + 255) / 256, blk>>>(ca, acc4);
    }

    // ---- launch 1: in-projection GEMMs -> P fp16 (k-chunk 64) ----
    {
        GemmPair gp = {};
        gp.A[0]=f0; gp.A[1]=f1;
        gp.B0[0]=wi0; gp.B1[0]=wi0;
        gp.B0[1]=wi1; gp.B1[1]=wi1;
        gp.bias[0]=in_b0; gp.bias[1]=in_b1;
        gp.Ch[0]=P0; gp.Ch[1]=P1;
        gemm_h16<<<dim3(PDIM/128, MT, 2), blk, GEMM_SMEM>>>(gp, F, F, F, 0, PDIM, F, 0);
    }

    // ---- launch 2: 4 attentions (smem-tiled) -> QQ fp16 ----
    {
        AttArgs aa;
        aa.Q[0]=P0;     aa.Kp[0]=P0+F;   aa.Vp[0]=P0+2*F; aa.O[0]=QQ0;
        aa.Q[1]=P1;     aa.Kp[1]=P1+F;   aa.Vp[1]=P1+2*F; aa.O[1]=QQ1;
        aa.Q[2]=P0+3*F; aa.Kp[2]=P1+4*F; aa.Vp[2]=P1+5*F; aa.O[2]=QQ0+F;
        aa.Q[3]=P1+3*F; aa.Kp[3]=P0+4*F; aa.Vp[3]=P0+5*F; aa.O[3]=QQ1+F;
        attend_kernel<<<dim3(NPIX/APX, 4), blk, ATT_SMEM>>>(aa, 2*F);
    }

    // ---- launch 3: out-projection (K=512) + residual + LN1 fused ----
    {
        GemmLnPair gp = {};
        gp.A[0]=QQ0; gp.A[1]=QQ1;
        gp.B0[0]=wo0; gp.B1[0]=wo0+F;
        gp.B0[1]=wo1; gp.B1[1]=wo0+F;
        gp.bias[0]=out_b0; gp.bias2[0]=out_b0+F; gp.res[0]=feat0;
        gp.bias[1]=out_b1; gp.bias2[1]=out_b0+F; gp.res[1]=feat1;
        gp.g[0]=ln1_g0; gp.bt[0]=ln1_b0; gp.O[0]=X0; gp.Oh[0]=Xq0;
        gp.g[1]=ln1_g1; gp.bt[1]=ln1_b1; gp.O[1]=X1; gp.Oh[1]=Xq1;
        gemm_ln<<<dim3(1, NPIX/64, 2), blk, GEMMLN_SMEM>>>(gp, 2*F, 3*F, F, F, 2*F);
    }

    // ---- launch 4: fused FFN -> output ----
    {
        FfnPair fp = {};
        fp.Xq[0]=Xq0; fp.Xq[1]=Xq1;
        fp.Wu[0]=wu0; fp.Wu[1]=wu1;
        fp.Wd[0]=wd0; fp.Wd[1]=wd1;
        fp.bu[0]=ffn_up_b0;   fp.bu[1]=ffn_up_b1;
        fp.bd[0]=ffn_down_b0; fp.bd[1]=ffn_down_b1;
        fp.res[0]=X0; fp.res[1]=X1;
        fp.g[0]=ln2_g0; fp.bt[0]=ln2_b0; fp.O[0]=out;
        fp.g[1]=ln2_g1; fp.bt[1]=ln2_b1; fp.O[1]=out + (size_t)NPIX*F;
        ffn_fused<<<dim3(1, NPIX/64, 2), blk, FFN_SMEM>>>(fp);
    }
}

// round 15
// speedup vs baseline: 6.5158x; 1.0086x over previous
#include <cuda_runtime.h>
#include <cuda_fp16.h>
#include <cstdint>
#include <cstddef>

#define F      256
#define NH     8
#define BATCH  2
#define HH     80
#define WW     80
#define NPIX   (BATCH*HH*WW)   // 12800
#define PDIM   1536
#define HIDN   1024

typedef __half h16;

// ---------------- scratch (no allocations allowed) ----------------
__device__ float g_X0[(size_t)NPIX*F];
__device__ float g_X1[(size_t)NPIX*F];

__device__ h16 g_P0[(size_t)NPIX*PDIM];
__device__ h16 g_P1[(size_t)NPIX*PDIM];
__device__ h16 g_f0[(size_t)NPIX*F];
__device__ h16 g_f1[(size_t)NPIX*F];
__device__ h16 g_wi0[(size_t)PDIM*F];
__device__ h16 g_wi1[(size_t)PDIM*F];
__device__ h16 g_wo0[(size_t)F*3*F];
__device__ h16 g_wo1[(size_t)F*3*F];
__device__ h16 g_wu0[(size_t)HIDN*F];
__device__ h16 g_wu1[(size_t)HIDN*F];
__device__ h16 g_wd0[(size_t)F*HIDN];
__device__ h16 g_wd1[(size_t)F*HIDN];
__device__ h16 g_QQ0[(size_t)NPIX*2*F];
__device__ h16 g_QQ1[(size_t)NPIX*2*F];
__device__ h16 g_Xq0[(size_t)NPIX*F];
__device__ h16 g_Xq1[(size_t)NPIX*F];

// ================= helpers =================
__device__ __forceinline__ uint32_t smem_u32(const void* p) {
    uint32_t a;
    asm("{ .reg .u64 t; cvta.to.shared.u64 t, %1; cvt.u32.u64 %0, t; }" : "=r"(a) : "l"(p));
    return a;
}
__device__ __forceinline__ void cpasync16(uint32_t dst, const void* src) {
    asm volatile("cp.async.cg.shared.global [%0], [%1], 16;" :: "r"(dst), "l"(src) : "memory");
}
__device__ __forceinline__ void cpasync16z(uint32_t dst, const void* src, int srcsz) {
    asm volatile("cp.async.cg.shared.global [%0], [%1], 16, %2;"
                 :: "r"(dst), "l"(src), "r"(srcsz) : "memory");
}
__device__ __forceinline__ void ldsm4(uint32_t (&r)[4], uint32_t addr) {
    asm volatile("ldmatrix.sync.aligned.m8n8.x4.shared.b16 {%0,%1,%2,%3}, [%4];"
                 : "=r"(r[0]), "=r"(r[1]), "=r"(r[2]), "=r"(r[3]) : "r"(addr));
}
__device__ __forceinline__ void mma16816(float* d, const uint32_t* a, const uint32_t* b) {
    asm volatile("mma.sync.aligned.m16n8k16.row.col.f32.f16.f16.f32 "
                 "{%0,%1,%2,%3}, {%4,%5,%6,%7}, {%8,%9}, {%0,%1,%2,%3};"
                 : "+f"(d[0]), "+f"(d[1]), "+f"(d[2]), "+f"(d[3])
                 : "r"(a[0]), "r"(a[1]), "r"(a[2]), "r"(a[3]), "r"(b[0]), "r"(b[1]));
}

// ================= fp16 tensor GEMM 128x128, k-chunk 64 (paired over z) =================
#define STAGES     3
#define SMEM_STAGE 32768
#define OFF_B      16384u
#define GEMM_SMEM  (STAGES*SMEM_STAGE)

struct GemmPair {
    const h16 *A[2];
    const h16 *B0[2], *B1[2];
    const float *bias[2], *bias2[2], *res[2];
    float *C[2];
    h16 *Ch[2];
};

__global__ __launch_bounds__(256, 2) void gemm_h16(
    GemmPair gp, int lda, int ldb, int Ksplit,
    int ldres, int ldc, int K, int relu)
{
    extern __shared__ char smem[];
    const uint32_t sb0 = smem_u32(smem);

    const int z = blockIdx.z;
    const h16* __restrict__ A  = gp.A[z];
    const h16* __restrict__ B0 = gp.B0[z];
    const h16* __restrict__ B1 = gp.B1[z];
    const float* __restrict__ bias  = gp.bias[z];
    const float* __restrict__ bias2 = gp.bias2[z];
    const float* __restrict__ res   = gp.res[z];
    float* __restrict__ C  = gp.C[z];
    h16*   __restrict__ Ch = gp.Ch[z];

    const int tid  = threadIdx.x;
    const int wid  = tid >> 5;
    const int lane = tid & 31;
    const int brow = blockIdx.y * 128;
    const int bcol = blockIdx.x * 128;
    const int wm   = (wid >> 2) * 64;
    const int wn   = (wid & 3) * 32;

    float acc[4][4][4];
#pragma unroll
    for (int i = 0; i < 4; i++)
#pragma unroll
        for (int j = 0; j < 4; j++)
#pragma unroll
            for (int r = 0; r < 4; r++) acc[i][j][r] = 0.f;

    auto load_stage = [&](int cIdx) {
        const uint32_t sb = sb0 + (uint32_t)(cIdx % STAGES) * SMEM_STAGE;
        const int k0 = cIdx * 64;
        const h16* bp;
        int kk;
        if (k0 < Ksplit) { bp = B0; kk = k0; }
        else             { bp = B1; kk = k0 - Ksplit; }
#pragma unroll
        for (int s = 0; s < 8; s++) {
            const int qid = tid + s * 256;
            const int q   = qid & 1023;
            const int row = q >> 3;
            const int c   = q & 7;
            const h16* src;
            uint32_t dstbase;
            if (qid < 1024) {
                src = A + (size_t)(brow + row) * lda + k0 + c * 8;
                dstbase = sb;
            } else {
                src = bp + (size_t)(bcol + row) * ldb + kk + c * 8;
                dstbase = sb + OFF_B;
            }
            cpasync16(dstbase + (uint32_t)row * 128u +
                      (uint32_t)((c ^ (row & 7)) * 16), src);
        }
        asm volatile("cp.async.commit_group;" ::: "memory");
    };

    const int tile = lane >> 3;
    const int rin  = lane & 7;

    const int NC = K / 64;
    for (int s = 0; s < STAGES - 1 && s < NC; s++) load_stage(s);

    for (int c = 0; c < NC; c++) {
        if (c + 2 <= NC - 1) {
            asm volatile("cp.async.wait_group 1;" ::: "memory");
        } else {
            asm volatile("cp.async.wait_group 0;" ::: "memory");
        }
        __syncthreads();
        if (c + 2 < NC) load_stage(c + 2);

        const uint32_t sb = sb0 + (uint32_t)(c % STAGES) * SMEM_STAGE;
#pragma unroll
        for (int ks = 0; ks < 4; ks++) {
            uint32_t ah[4][4], bh_[2][4];
            const int ca = ks * 2 + (tile >> 1);
#pragma unroll
            for (int i = 0; i < 4; i++) {
                const int arow = wm + i * 16 + (tile & 1) * 8 + rin;
                ldsm4(ah[i], sb + (uint32_t)arow * 128u +
                              (uint32_t)((ca ^ (arow & 7)) * 16));
            }
            const int cb = ks * 2 + (tile & 1);
#pragma unroll
            for (int jj = 0; jj < 2; jj++) {
                const int brw = wn + jj * 16 + (tile >> 1) * 8 + rin;
                ldsm4(bh_[jj], sb + OFF_B + (uint32_t)brw * 128u +
                               (uint32_t)((cb ^ (brw & 7)) * 16));
            }
#pragma unroll
            for (int i = 0; i < 4; i++)
#pragma unroll
                for (int j = 0; j < 4; j++)
                    mma16816(acc[i][j], ah[i], &bh_[j >> 1][(j & 1) * 2]);
        }
    }

    const int tq = lane >> 2;
    const int tr = (lane & 3) * 2;
    float bj0[4], bj1[4];
#pragma unroll
    for (int j = 0; j < 4; j++) {
        const int n = bcol + wn + 8 * j + tr;
        float b0 = bias[n], b1 = bias[n + 1];
        if (bias2) { b0 += bias2[n]; b1 += bias2[n + 1]; }
        bj0[j] = b0; bj1[j] = b1;
    }
#pragma unroll
    for (int i = 0; i < 4; i++)
#pragma unroll
        for (int half = 0; half < 2; half++) {
            const int m = brow + wm + 16 * i + tq + half * 8;
#pragma unroll
            for (int j = 0; j < 4; j++) {
                const int n = bcol + wn + 8 * j + tr;
                float v0 = acc[i][j][half * 2 + 0] + bj0[j];
                float v1 = acc[i][j][half * 2 + 1] + bj1[j];
                if (res) {
                    float2 r = *(const float2*)(res + (size_t)m * ldres + n);
                    v0 += r.x; v1 += r.y;
                }
                if (relu) { v0 = fmaxf(v0, 0.f); v1 = fmaxf(v1, 0.f); }
                if (C) *(float2*)(C + (size_t)m * ldc + n) = make_float2(v0, v1);
                if (Ch)
                    *(__half2*)(Ch + (size_t)m * ldc + n) =
                        __halves2half2(__float2half_rn(v0), __float2half_rn(v1));
            }
        }
}

// ================= fp16 GEMM 64x256 + fused LayerNorm (paired over z), 2 CTA/SM =================
#define LSTAGES    4
#define LSTAGE_SZ  20480
#define LOFF_B     4096u
#define GEMMLN_SMEM (LSTAGES*LSTAGE_SZ)

struct GemmLnPair {
    const h16 *A[2];
    const h16 *B0[2], *B1[2];
    const float *bias[2], *bias2[2], *res[2];
    const float *g[2], *bt[2];
    float *O[2];
    h16 *Oh[2];
};

__global__ __launch_bounds__(256, 2) void gemm_ln(
    GemmLnPair gp, int lda, int ldb, int Ksplit, int ldres, int K)
{
    extern __shared__ char smem[];
    const uint32_t sb0 = smem_u32(smem);

    const int z = blockIdx.z;
    const h16* __restrict__ A  = gp.A[z];
    const h16* __restrict__ B0 = gp.B0[z];
    const h16* __restrict__ B1 = gp.B1[z];
    const float* __restrict__ bias  = gp.bias[z];
    const float* __restrict__ bias2 = gp.bias2[z];
    const float* __restrict__ res   = gp.res[z];
    const float* __restrict__ gam   = gp.g[z];
    const float* __restrict__ bet   = gp.bt[z];
    float* __restrict__ O  = gp.O[z];
    h16*   __restrict__ Oh = gp.Oh[z];

    const int tid  = threadIdx.x;
    const int wid  = tid >> 5;
    const int lane = tid & 31;
    const int brow = blockIdx.y * 64;
    const int wm   = (wid >> 2) * 32;
    const int wn   = (wid & 3) * 64;

    float acc[2][8][4];
#pragma unroll
    for (int i = 0; i < 2; i++)
#pragma unroll
        for (int j = 0; j < 8; j++)
#pragma unroll
            for (int r = 0; r < 4; r++) acc[i][j][r] = 0.f;

    auto load_stage = [&](int cIdx) {
        const uint32_t sb = sb0 + (uint32_t)(cIdx % LSTAGES) * LSTAGE_SZ;
        const int k0 = cIdx * 32;
        const h16* bp;
        int kk;
        if (k0 < Ksplit) { bp = B0; kk = k0; }
        else             { bp = B1; kk = k0 - Ksplit; }
#pragma unroll
        for (int s = 0; s < 5; s++) {
            const int qid = tid + s * 256;
            const h16* src;
            uint32_t dstbase;
            int row, c;
            if (qid < 256) {
                row = qid >> 2; c = qid & 3;
                src = A + (size_t)(brow + row) * lda + k0 + c * 8;
                dstbase = sb;
            } else {
                const int q2 = qid - 256;
                row = q2 >> 2; c = q2 & 3;
                src = bp + (size_t)row * ldb + kk + c * 8;
                dstbase = sb + LOFF_B;
            }
            cpasync16(dstbase + (uint32_t)row * 64u +
                      (uint32_t)((c ^ ((row >> 1) & 3)) * 16), src);
        }
        asm volatile("cp.async.commit_group;" ::: "memory");
    };

    const int tile = lane >> 3;
    const int rin  = lane & 7;
    const uint32_t rsw = (uint32_t)(rin >> 1);

    const int NC = K / 32;
    for (int s = 0; s < LSTAGES - 1 && s < NC; s++) load_stage(s);

    for (int c = 0; c < NC; c++) {
        if (c + 3 <= NC) {
            asm volatile("cp.async.wait_group 2;" ::: "memory");
        } else if (c + 2 == NC) {
            asm volatile("cp.async.wait_group 1;" ::: "memory");
        } else {
            asm volatile("cp.async.wait_group 0;" ::: "memory");
        }
        __syncthreads();
        if (c + 3 < NC) load_stage(c + 3);

        const uint32_t sb = sb0 + (uint32_t)(c % LSTAGES) * LSTAGE_SZ;
#pragma unroll
        for (int ks = 0; ks < 2; ks++) {
            uint32_t ah[2][4], bh_[4][4];
            const uint32_t swa = ((uint32_t)(ks * 2 + (tile >> 1)) ^ rsw) * 16u;
#pragma unroll
            for (int i = 0; i < 2; i++)
                ldsm4(ah[i], sb + (uint32_t)(wm + i * 16 + (tile & 1) * 8 + rin) * 64u + swa);
            const uint32_t swb = ((uint32_t)(ks * 2 + (tile & 1)) ^ rsw) * 16u;
#pragma unroll
            for (int jj = 0; jj < 4; jj++)
                ldsm4(bh_[jj], sb + LOFF_B +
                      (uint32_t)(wn + jj * 16 + (tile >> 1) * 8 + rin) * 64u + swb);
#pragma unroll
            for (int i = 0; i < 2; i++)
#pragma unroll
                for (int j = 0; j < 8; j++)
                    mma16816(acc[i][j], ah[i], &bh_[j >> 1][(j & 1) * 2]);
        }
    }

    __syncthreads();
    float* redS = (float*)smem;
    float* redQ = (float*)smem + 256;

    const int tq = lane >> 2;
    const int tr = (lane & 3) * 2;
    const int wslot = wn >> 6;

    float bj0[8], bj1[8];
#pragma unroll
    for (int j = 0; j < 8; j++) {
        const int n = wn + 8 * j + tr;
        float b0 = bias[n], b1 = bias[n + 1];
        if (bias2) { b0 += bias2[n]; b1 += bias2[n + 1]; }
        bj0[j] = b0; bj1[j] = b1;
    }

#pragma unroll
    for (int i = 0; i < 2; i++)
#pragma unroll
        for (int half = 0; half < 2; half++) {
            const int mrow = wm + 16 * i + 8 * half + tq;
            const int m = brow + mrow;
            float s1 = 0.f, s2 = 0.f;
#pragma unroll
            for (int j = 0; j < 8; j++) {
                float v0 = acc[i][j][half * 2 + 0] + bj0[j];
                float v1 = acc[i][j][half * 2 + 1] + bj1[j];
                if (res) {
                    float2 rr = *(const float2*)(res + (size_t)m * ldres + wn + 8 * j + tr);
                    v0 += rr.x; v1 += rr.y;
                }
                acc[i][j][half * 2 + 0] = v0;
                acc[i][j][half * 2 + 1] = v1;
                s1 += v0 + v1;
                s2 += v0 * v0 + v1 * v1;
            }
            s1 += __shfl_xor_sync(0xffffffffu, s1, 1);
            s2 += __shfl_xor_sync(0xffffffffu, s2, 1);
            s1 += __shfl_xor_sync(0xffffffffu, s1, 2);
            s2 += __shfl_xor_sync(0xffffffffu, s2, 2);
            if ((lane & 3) == 0) {
                redS[mrow * 4 + wslot] = s1;
                redQ[mrow * 4 + wslot] = s2;
            }
        }
    __syncthreads();

#pragma unroll
    for (int i = 0; i < 2; i++)
#pragma unroll
        for (int half = 0; half < 2; half++) {
            const int mrow = wm + 16 * i + 8 * half + tq;
            const int m = brow + mrow;
            float tS = redS[mrow * 4 + 0] + redS[mrow * 4 + 1]
                     + redS[mrow * 4 + 2] + redS[mrow * 4 + 3];
            float tQ = redQ[mrow * 4 + 0] + redQ[mrow * 4 + 1]
                     + redQ[mrow * 4 + 2] + redQ[mrow * 4 + 3];
            float mean = tS * (1.0f / F);
            float var  = tQ * (1.0f / F) - mean * mean;
            float rstd = rsqrtf(var + 1e-5f);
#pragma unroll
            for (int j = 0; j < 8; j++) {
                const int n = wn + 8 * j + tr;
                float2 gg = *(const float2*)(gam + n);
                float2 bb = *(const float2*)(bet + n);
                float o0 = gg.x * (acc[i][j][half * 2 + 0] - mean) * rstd + bb.x;
                float o1 = gg.y * (acc[i][j][half * 2 + 1] - mean) * rstd + bb.y;
                if (O) *(float2*)(O + (size_t)m * F + n) = make_float2(o0, o1);
                if (Oh)
                    *(__half2*)(Oh + (size_t)m * F + n) =
                        __halves2half2(__float2half_rn(o0), __float2half_rn(o1));
            }
        }
}

// ================= fused FFN (2 CTA/SM): up(relu) + down + residual + LN2 =================
// CTA: 64 rows. 16 hidden chunks of 64.
// smem: XQ 32K | WU 32K | WD 32K | UC 8K = 104KB; launch_bounds(256,2).
#define XQ_OFF 0u
#define WU_OFF 32768u
#define WD_OFF 65536u
#define UC_OFF 98304u
#define FFN_SMEM 106496

struct FfnPair {
    const h16 *Xq[2];
    const h16 *Wu[2], *Wd[2];
    const float *bu[2], *bd[2], *res[2];
    const float *g[2], *bt[2];
    float *O[2];
};

__global__ __launch_bounds__(256, 2) void ffn_fused(FfnPair fp)
{
    extern __shared__ char smem[];
    const uint32_t sb = smem_u32(smem);

    const int z = blockIdx.z;
    const h16* __restrict__ Xq = fp.Xq[z];
    const h16* __restrict__ Wu = fp.Wu[z];
    const h16* __restrict__ Wd = fp.Wd[z];
    const float* __restrict__ bu  = fp.bu[z];
    const float* __restrict__ bd  = fp.bd[z];
    const float* __restrict__ res = fp.res[z];
    const float* __restrict__ gam = fp.g[z];
    const float* __restrict__ bet = fp.bt[z];
    float* __restrict__ O = fp.O[z];

    const int tid  = threadIdx.x;
    const int wid  = tid >> 5;
    const int lane = tid & 31;
    const int brow = blockIdx.y * 64;

    const int tile = lane >> 3;
    const int rin  = lane & 7;
    const uint32_t rsw = (uint32_t)(rin >> 1);
    const int tq = lane >> 2;
    const int tr = (lane & 3) * 2;

    // phase-1: warp tile 32(m) x 16(h): wm1 in {0,32}, wh in {0,16,32,48}
    const int wm1 = (wid & 1) * 32;
    const int wh  = (wid >> 1) * 16;
    // phase-2: warp tile 32(m) x 64(n)
    const int wm2 = (wid >> 2) * 32;
    const int wn2 = (wid & 3) * 64;

    float acc[2][8][4];
#pragma unroll
    for (int i = 0; i < 2; i++)
#pragma unroll
        for (int j = 0; j < 8; j++)
#pragma unroll
            for (int r = 0; r < 4; r++) acc[i][j][r] = 0.f;

    auto load_xq = [&]() {
#pragma unroll
        for (int t = 0; t < 8; t++) {
            const int qid = tid + t * 256;
            const int s = qid >> 8, q = qid & 255;
            const int r = q >> 2, c = q & 3;
            cpasync16(sb + XQ_OFF + (uint32_t)s * 4096u + (uint32_t)r * 64u +
                      (uint32_t)((c ^ ((r >> 1) & 3)) * 16),
                      Xq + (size_t)(brow + r) * F + s * 32 + c * 8);
        }
    };
    // Wu chunk hc: rows hc*64 + r (r<64), layout kc-major: WU_OFF + kc*4096 + r*64
    auto load_wu = [&](int hc) {
#pragma unroll
        for (int t = 0; t < 8; t++) {
            const int qid = tid + t * 256;
            const int kc = qid >> 8, q = qid & 255;
            const int r = q >> 2, c = q & 3;
            cpasync16(sb + WU_OFF + (uint32_t)kc * 4096u + (uint32_t)r * 64u +
                      (uint32_t)((c ^ ((r >> 1) & 3)) * 16),
                      Wu + (size_t)(hc * 64 + r) * F + kc * 32 + c * 8);
        }
        asm volatile("cp.async.commit_group;" ::: "memory");
    };
    // Wd chunk hc: rows r<256, k = hc*64 + s*32; layout WD_OFF + s*16384 + r*64
    auto load_wd = [&](int hc) {
#pragma unroll
        for (int t = 0; t < 8; t++) {
            const int qid = tid + t * 256;
            const int s = qid >> 10, q = qid & 1023;
            const int r = q >> 2, c = q & 3;
            cpasync16(sb + WD_OFF + (uint32_t)s * 16384u + (uint32_t)r * 64u +
                      (uint32_t)((c ^ ((r >> 1) & 3)) * 16),
                      Wd + (size_t)r * HIDN + hc * 64 + s * 32 + c * 8);
        }
        asm volatile("cp.async.commit_group;" ::: "memory");
    };

    load_xq();
    load_wu(0);
    asm volatile("cp.async.wait_group 0;" ::: "memory");
    __syncthreads();

    for (int hc = 0; hc < 16; hc++) {
        load_wd(hc);   // overlaps phase 1

        // ---- phase 1: Uc[64x64] = relu(Xq @ Wu_hc^T + bu) ----
        float acc1[2][2][4];
#pragma unroll
        for (int i = 0; i < 2; i++)
#pragma unroll
            for (int j = 0; j < 2; j++)
#pragma unroll
                for (int r = 0; r < 4; r++) acc1[i][j][r] = 0.f;

#pragma unroll
        for (int kc = 0; kc < 8; kc++) {
            const uint32_t sx = sb + XQ_OFF + (uint32_t)kc * 4096u;
            const uint32_t sw = sb + WU_OFF + (uint32_t)kc * 4096u;
#pragma unroll
            for (int ks = 0; ks < 2; ks++) {
                uint32_t ah[2][4], bh_[4];
                const uint32_t swa = ((uint32_t)(ks * 2 + (tile >> 1)) ^ rsw) * 16u;
#pragma unroll
                for (int i = 0; i < 2; i++)
                    ldsm4(ah[i], sx + (uint32_t)(wm1 + i * 16 + (tile & 1) * 8 + rin) * 64u + swa);
                const uint32_t swb = ((uint32_t)(ks * 2 + (tile & 1)) ^ rsw) * 16u;
                ldsm4(bh_, sw + (uint32_t)(wh + (tile >> 1) * 8 + rin) * 64u + swb);
#pragma unroll
                for (int i = 0; i < 2; i++)
#pragma unroll
                    for (int j = 0; j < 2; j++)
                        mma16816(acc1[i][j], ah[i], &bh_[j * 2]);
            }
        }

        // bias + relu + store Uc (swizzled)
        {
            const int sub   = wh >> 5;          // 0 or 1
            const int cbase = (wh & 31) >> 3;   // quad base 0 or 2
            const uint32_t ucb = sb + UC_OFF + (uint32_t)sub * 4096u;
#pragma unroll
            for (int i = 0; i < 2; i++)
#pragma unroll
                for (int j = 0; j < 2; j++) {
                    const int nh = hc * 64 + wh + j * 8 + tr;
                    float b0 = bu[nh], b1 = bu[nh + 1];
                    float v0 = fmaxf(acc1[i][j][0] + b0, 0.f);
                    float v1 = fmaxf(acc1[i][j][1] + b1, 0.f);
                    float v2 = fmaxf(acc1[i][j][2] + b0, 0.f);
                    float v3 = fmaxf(acc1[i][j][3] + b1, 0.f);
                    const int quad = cbase + j;
                    const int row0 = wm1 + i * 16 + tq;
                    const int row1 = row0 + 8;
                    uint32_t a0 = ucb + (uint32_t)row0 * 64u +
                                  (uint32_t)((quad ^ ((row0 >> 1) & 3)) * 16) + (uint32_t)tr * 2u;
                    uint32_t a1 = ucb + (uint32_t)row1 * 64u +
                                  (uint32_t)((quad ^ ((row1 >> 1) & 3)) * 16) + (uint32_t)tr * 2u;
                    __half2 h01 = __halves2half2(__float2half_rn(v0), __float2half_rn(v1));
                    __half2 h23 = __halves2half2(__float2half_rn(v2), __float2half_rn(v3));
                    asm volatile("st.shared.b32 [%0], %1;" :: "r"(a0), "r"(*(uint32_t*)&h01) : "memory");
                    asm volatile("st.shared.b32 [%0], %1;" :: "r"(a1), "r"(*(uint32_t*)&h23) : "memory");
                }
        }
        __syncthreads();             // WU reads done; Uc visible

        if (hc < 15) load_wu(hc + 1);   // overlaps phase 2 (WU now free)

        // ensure Wd_hc landed (wu(hc+1) may still be pending)
        if (hc < 15) {
            asm volatile("cp.async.wait_group 1;" ::: "memory");
        } else {
            asm volatile("cp.async.wait_group 0;" ::: "memory");
        }

        // ---- phase 2: acc += Uc @ Wd_hc^T ----
#pragma unroll
        for (int s = 0; s < 2; s++) {
            const uint32_t su = sb + UC_OFF + (uint32_t)s * 4096u;
            const uint32_t sd = sb + WD_OFF + (uint32_t)s * 16384u;
#pragma unroll
            for (int ks = 0; ks < 2; ks++) {
                uint32_t ah[2][4], bh_[4][4];
                const uint32_t swa = ((uint32_t)(ks * 2 + (tile >> 1)) ^ rsw) * 16u;
#pragma unroll
                for (int i = 0; i < 2; i++)
                    ldsm4(ah[i], su + (uint32_t)(wm2 + i * 16 + (tile & 1) * 8 + rin) * 64u + swa);
                const uint32_t swb = ((uint32_t)(ks * 2 + (tile & 1)) ^ rsw) * 16u;
#pragma unroll
                for (int jj = 0; jj < 4; jj++)
                    ldsm4(bh_[jj], sd + (uint32_t)(wn2 + jj * 16 + (tile >> 1) * 8 + rin) * 64u + swb);
#pragma unroll
                for (int i = 0; i < 2; i++)
#pragma unroll
                    for (int j = 0; j < 8; j++)
                        mma16816(acc[i][j], ah[i], &bh_[j >> 1][(j & 1) * 2]);
            }
        }

        // own wu(hc+1) copies done + join before next phase1 / Uc reuse
        asm volatile("cp.async.wait_group 0;" ::: "memory");
        __syncthreads();
    }

    // ---- epilogue: bias + residual + LN2 -> O fp32 ----
    float* redS = (float*)(smem + UC_OFF);
    float* redQ = (float*)(smem + UC_OFF) + 256;
    const int wslot = wn2 >> 6;

    float bj0[8], bj1[8];
#pragma unroll
    for (int j = 0; j < 8; j++) {
        const int n = wn2 + 8 * j + tr;
        bj0[j] = bd[n]; bj1[j] = bd[n + 1];
    }

#pragma unroll
    for (int i = 0; i < 2; i++)
#pragma unroll
        for (int half = 0; half < 2; half++) {
            const int mrow = wm2 + 16 * i + 8 * half + tq;
            const int m = brow + mrow;
            float s1 = 0.f, s2 = 0.f;
#pragma unroll
            for (int j = 0; j < 8; j++) {
                float v0 = acc[i][j][half * 2 + 0] + bj0[j];
                float v1 = acc[i][j][half * 2 + 1] + bj1[j];
                float2 rr = *(const float2*)(res + (size_t)m * F + wn2 + 8 * j + tr);
                v0 += rr.x; v1 += rr.y;
                acc[i][j][half * 2 + 0] = v0;
                acc[i][j][half * 2 + 1] = v1;
                s1 += v0 + v1;
                s2 += v0 * v0 + v1 * v1;
            }
            s1 += __shfl_xor_sync(0xffffffffu, s1, 1);
            s2 += __shfl_xor_sync(0xffffffffu, s2, 1);
            s1 += __shfl_xor_sync(0xffffffffu, s1, 2);
            s2 += __shfl_xor_sync(0xffffffffu, s2, 2);
            if ((lane & 3) == 0) {
                redS[mrow * 4 + wslot] = s1;
                redQ[mrow * 4 + wslot] = s2;
            }
        }
    __syncthreads();

#pragma unroll
    for (int i = 0; i < 2; i++)
#pragma unroll
        for (int half = 0; half < 2; half++) {
            const int mrow = wm2 + 16 * i + 8 * half + tq;
            const int m = brow + mrow;
            float tS = redS[mrow * 4 + 0] + redS[mrow * 4 + 1]
                     + redS[mrow * 4 + 2] + redS[mrow * 4 + 3];
            float tQ = redQ[mrow * 4 + 0] + redQ[mrow * 4 + 1]
                     + redQ[mrow * 4 + 2] + redQ[mrow * 4 + 3];
            float mean = tS * (1.0f / F);
            float var  = tQ * (1.0f / F) - mean * mean;
            float rstd = rsqrtf(var + 1e-5f);
#pragma unroll
            for (int j = 0; j < 8; j++) {
                const int n = wn2 + 8 * j + tr;
                float2 gg = *(const float2*)(gam + n);
                float2 bb = *(const float2*)(bet + n);
                float o0 = gg.x * (acc[i][j][half * 2 + 0] - mean) * rstd + bb.x;
                float o1 = gg.y * (acc[i][j][half * 2 + 1] - mean) * rstd + bb.y;
                *(float2*)(O + (size_t)m * F + n) = make_float2(o0, o1);
            }
        }
}

// ---------------- merged convert fp32 -> fp16 ----------------
#define NSEG 10
struct ConvArgs {
    const float* s[NSEG];
    h16* h[NSEG];
    int end4[NSEG];
};

__global__ __launch_bounds__(256) void conv_all(ConvArgs a, int total4)
{
    int i = blockIdx.x * 256 + threadIdx.x;
    if (i >= total4) return;
    int seg = 0;
#pragma unroll
    for (int s = 0; s < NSEG - 1; s++) seg += (i >= a.end4[s]) ? 1 : 0;
    const int base = seg ? a.end4[seg - 1] : 0;
    const int j = i - base;

    float4 v = ((const float4*)a.s[seg])[j];
    h16* hp = a.h[seg];
    ((__half2*)hp)[2 * j]     = __halves2half2(__float2half_rn(v.x), __float2half_rn(v.y));
    ((__half2*)hp)[2 * j + 1] = __halves2half2(__float2half_rn(v.z), __float2half_rn(v.w));
}

// ---------------- 9-tap attention, smem halo staging (4 slices via y) ----------------
#define APX 16
#define PXSTRIDE 1088u
#define ATT_SMEM (54*1088)

struct AttArgs {
    const h16* Q[4];
    const h16* Kp[4];
    const h16* Vp[4];
    h16* O[4];
};

__global__ __launch_bounds__(256) void attend_kernel(AttArgs a, int ostride)
{
    extern __shared__ char attsm[];
    const uint32_t sb = smem_u32(attsm);

    const int z    = blockIdx.y;
    const int tid  = threadIdx.x;
    const int pix0 = blockIdx.x * APX;
    const int b    = pix0 / (HH * WW);
    const int rr   = pix0 % (HH * WW);
    const int y    = rr / WW;
    const int x0   = rr % WW;

    const h16* __restrict__ Q  = a.Q[z];
    const h16* __restrict__ Kp = a.Kp[z];
    const h16* __restrict__ Vp = a.Vp[z];

#pragma unroll
    for (int t = 0; t < 14; t++) {
        const int qid = tid + t * 256;
        if (qid < 3456) {
            const int e   = qid >> 6;
            const int qq  = qid & 63;
            const int isV = qq >> 5;
            const int q   = qq & 31;
            const int yy  = y + (e / 18) - 1;
            const int xx  = x0 + (e % 18) - 1;
            const bool ok = (yy >= 0 && yy < HH && xx >= 0 && xx < WW);
            const int ys  = ok ? yy : 0;
            const int xs  = ok ? xx : 0;
            const h16* src = (isV ? Vp : Kp) +
                ((size_t)(b * HH + ys) * WW + xs) * PDIM + q * 8;
            cpasync16z(sb + (uint32_t)e * PXSTRIDE + (uint32_t)isV * 512u + (uint32_t)q * 16u,
                       src, ok ? 16 : 0);
        }
    }
    asm volatile("cp.async.commit_group;" ::: "memory");
    asm volatile("cp.async.wait_group 0;" ::: "memory");
    __syncthreads();

    const int px  = tid >> 4;
    const int t16 = tid & 15;
    const int ch  = t16 * 16;
    const int pix = pix0 + px;

    const float scale = 0.17677669529663687f;
    float qf[16];
    {
        const uint4* qp = (const uint4*)(Q + (size_t)pix * PDIM + ch);
        uint4 q0 = qp[0], q1 = qp[1];
        const uint32_t* qu = (const uint32_t*)&q0;
#pragma unroll
        for (int i = 0; i < 4; i++) {
            float2 f = __half22float2(*(__half2*)&qu[i]);
            qf[2 * i] = f.x * scale; qf[2 * i + 1] = f.y * scale;
        }
        const uint32_t* qu2 = (const uint32_t*)&q1;
#pragma unroll
        for (int i = 0; i < 4; i++) {
            float2 f = __half22float2(*(__half2*)&qu2[i]);
            qf[8 + 2 * i] = f.x * scale; qf[8 + 2 * i + 1] = f.y * scale;
        }
    }

    float sc[9];
#pragma unroll
    for (int n = 0; n < 9; n++) {
        const int hal = (n / 3) * 18 + px + (n % 3);
        const char* kb = attsm + hal * PXSTRIDE + ch * 2;
        uint4 k0 = *(const uint4*)kb;
        uint4 k1 = *(const uint4*)(kb + 16);
        float s = 0.f;
        const uint32_t* ku = (const uint32_t*)&k0;
#pragma unroll
        for (int i = 0; i < 4; i++) {
            float2 f = __half22float2(*(__half2*)&ku[i]);
            s = fmaf(qf[2 * i], f.x, s);
            s = fmaf(qf[2 * i + 1], f.y, s);
        }
        const uint32_t* ku2 = (const uint32_t*)&k1;
#pragma unroll
        for (int i = 0; i < 4; i++) {
            float2 f = __half22float2(*(__half2*)&ku2[i]);
            s = fmaf(qf[8 + 2 * i], f.x, s);
            s = fmaf(qf[8 + 2 * i + 1], f.y, s);
        }
        s += __shfl_xor_sync(0xffffffffu, s, 1);
        sc[n] = s;
    }

    float mx = sc[0];
#pragma unroll
    for (int n = 1; n < 9; n++) mx = fmaxf(mx, sc[n]);
    float w[9], den = 0.f;
#pragma unroll
    for (int n = 0; n < 9; n++) { w[n] = __expf(sc[n] - mx); den += w[n]; }

    float o[16];
#pragma unroll
    for (int i = 0; i < 16; i++) o[i] = 0.f;
#pragma unroll
    for (int n = 0; n < 9; n++) {
        const int hal = (n / 3) * 18 + px + (n % 3);
        const char* vb = attsm + hal * PXSTRIDE + 512 + ch * 2;
        uint4 v0 = *(const uint4*)vb;
        uint4 v1 = *(const uint4*)(vb + 16);
        const uint32_t* vu = (const uint32_t*)&v0;
#pragma unroll
        for (int i = 0; i < 4; i++) {
            float2 f = __half22float2(*(__half2*)&vu[i]);
            o[2 * i]     = fmaf(w[n], f.x, o[2 * i]);
            o[2 * i + 1] = fmaf(w[n], f.y, o[2 * i + 1]);
        }
        const uint32_t* vu2 = (const uint32_t*)&v1;
#pragma unroll
        for (int i = 0; i < 4; i++) {
            float2 f = __half22float2(*(__half2*)&vu2[i]);
            o[8 + 2 * i]     = fmaf(w[n], f.x, o[8 + 2 * i]);
            o[8 + 2 * i + 1] = fmaf(w[n], f.y, o[8 + 2 * i + 1]);
        }
    }

    const float inv = 1.f / den;
    uint32_t pk[8];
#pragma unroll
    for (int i = 0; i < 8; i++) {
        __half2 h = __halves2half2(__float2half_rn(o[2 * i] * inv),
                                   __float2half_rn(o[2 * i + 1] * inv));
        pk[i] = *(uint32_t*)&h;
    }
    h16* op = a.O[z] + (size_t)pix * ostride + ch;
    *(uint4*)op        = make_uint4(pk[0], pk[1], pk[2], pk[3]);
    *(uint4*)(op + 8)  = make_uint4(pk[4], pk[5], pk[6], pk[7]);
}

// ---------------- launch ----------------
#define SYM(p, s) cudaGetSymbolAddress((void**)&p, s)

extern "C" void kernel_launch(void* const* d_in, const int* in_sizes, int n_in,
                              void* d_out, int out_size)
{
    const float* feat0       = (const float*)d_in[0];
    const float* feat1       = (const float*)d_in[1];
    const float* in_w0       = (const float*)d_in[2];
    const float* in_b0       = (const float*)d_in[3];
    const float* in_w1       = (const float*)d_in[4];
    const float* in_b1       = (const float*)d_in[5];
    const float* out_w0      = (const float*)d_in[6];
    const float* out_b0      = (const float*)d_in[7];
    const float* out_w1      = (const float*)d_in[8];
    const float* out_b1      = (const float*)d_in[9];
    const float* ln1_g0      = (const float*)d_in[10];
    const float* ln1_b0      = (const float*)d_in[11];
    const float* ln1_g1      = (const float*)d_in[12];
    const float* ln1_b1      = (const float*)d_in[13];
    const float* ffn_up_w0   = (const float*)d_in[14];
    const float* ffn_up_b0   = (const float*)d_in[15];
    const float* ffn_down_w0 = (const float*)d_in[16];
    const float* ffn_down_b0 = (const float*)d_in[17];
    const float* ffn_up_w1   = (const float*)d_in[18];
    const float* ffn_up_b1   = (const float*)d_in[19];
    const float* ffn_down_w1 = (const float*)d_in[20];
    const float* ffn_down_b1 = (const float*)d_in[21];
    const float* ln2_g0      = (const float*)d_in[22];
    const float* ln2_b0      = (const float*)d_in[23];
    const float* ln2_g1      = (const float*)d_in[24];
    const float* ln2_b1      = (const float*)d_in[25];

    float *X0, *X1;
    SYM(X0, g_X0); SYM(X1, g_X1);
    h16 *P0, *P1, *f0, *f1, *wi0, *wi1, *wo0, *wo1, *wu0, *wu1, *wd0, *wd1;
    h16 *QQ0, *QQ1, *Xq0, *Xq1;
    SYM(P0, g_P0); SYM(P1, g_P1);
    SYM(f0, g_f0); SYM(f1, g_f1);
    SYM(wi0, g_wi0); SYM(wi1, g_wi1);
    SYM(wo0, g_wo0); SYM(wo1, g_wo1);
    SYM(wu0, g_wu0); SYM(wu1, g_wu1);
    SYM(wd0, g_wd0); SYM(wd1, g_wd1);
    SYM(QQ0, g_QQ0); SYM(QQ1, g_QQ1); SYM(Xq0, g_Xq0); SYM(Xq1, g_Xq1);

    cudaFuncSetAttribute(gemm_h16, cudaFuncAttributeMaxDynamicSharedMemorySize, GEMM_SMEM);
    cudaFuncSetAttribute(gemm_ln,  cudaFuncAttributeMaxDynamicSharedMemorySize, GEMMLN_SMEM);
    cudaFuncSetAttribute(ffn_fused, cudaFuncAttributeMaxDynamicSharedMemorySize, FFN_SMEM);
    cudaFuncSetAttribute(attend_kernel, cudaFuncAttributeMaxDynamicSharedMemorySize, ATT_SMEM);

    float* out = (float*)d_out;
    dim3 blk(256);
    const int MT = NPIX / 128;   // 100

    // ---- launch 0: all converts ----
    {
        ConvArgs ca;
        const float* srcs[NSEG] = {feat0, feat1, in_w0, in_w1, out_w0, out_w1,
                                   ffn_up_w0, ffn_up_w1, ffn_down_w0, ffn_down_w1};
        h16* hs[NSEG] = {f0, f1, wi0, wi1, wo0, wo1, wu0, wu1, wd0, wd1};
        int sizes4[NSEG] = {NPIX*F/4, NPIX*F/4, PDIM*F/4, PDIM*F/4, F*3*F/4, F*3*F/4,
                            HIDN*F/4, HIDN*F/4, F*HIDN/4, F*HIDN/4};
        int acc4 = 0;
        for (int i = 0; i < NSEG; i++) {
            ca.s[i] = srcs[i]; ca.h[i] = hs[i];
            acc4 += sizes4[i];
            ca.end4[i] = acc4;
        }
        conv_all<<<(acc4 + 255) / 256, blk>>>(ca, acc4);
    }

    // ---- launch 1: in-projection GEMMs -> P fp16 (k-chunk 64) ----
    {
        GemmPair gp = {};
        gp.A[0]=f0; gp.A[1]=f1;
        gp.B0[0]=wi0; gp.B1[0]=wi0;
        gp.B0[1]=wi1; gp.B1[1]=wi1;
        gp.bias[0]=in_b0; gp.bias[1]=in_b1;
        gp.Ch[0]=P0; gp.Ch[1]=P1;
        gemm_h16<<<dim3(PDIM/128, MT, 2), blk, GEMM_SMEM>>>(gp, F, F, F, 0, PDIM, F, 0);
    }

    // ---- launch 2: 4 attentions (smem-tiled) -> QQ fp16 ----
    {
        AttArgs aa;
        aa.Q[0]=P0;     aa.Kp[0]=P0+F;   aa.Vp[0]=P0+2*F; aa.O[0]=QQ0;
        aa.Q[1]=P1;     aa.Kp[1]=P1+F;   aa.Vp[1]=P1+2*F; aa.O[1]=QQ1;
        aa.Q[2]=P0+3*F; aa.Kp[2]=P1+4*F; aa.Vp[2]=P1+5*F; aa.O[2]=QQ0+F;
        aa.Q[3]=P1+3*F; aa.Kp[3]=P0+4*F; aa.Vp[3]=P0+5*F; aa.O[3]=QQ1+F;
        attend_kernel<<<dim3(NPIX/APX, 4), blk, ATT_SMEM>>>(aa, 2*F);
    }

    // ---- launch 3: out-projection (K=512) + residual + LN1 fused ----
    {
        GemmLnPair gp = {};
        gp.A[0]=QQ0; gp.A[1]=QQ1;
        gp.B0[0]=wo0; gp.B1[0]=wo0+F;
        gp.B0[1]=wo1; gp.B1[1]=wo0+F;
        gp.bias[0]=out_b0; gp.bias2[0]=out_b0+F; gp.res[0]=feat0;
        gp.bias[1]=out_b1; gp.bias2[1]=out_b0+F; gp.res[1]=feat1;
        gp.g[0]=ln1_g0; gp.bt[0]=ln1_b0; gp.O[0]=X0; gp.Oh[0]=Xq0;
        gp.g[1]=ln1_g1; gp.bt[1]=ln1_b1; gp.O[1]=X1; gp.Oh[1]=Xq1;
        gemm_ln<<<dim3(1, NPIX/64, 2), blk, GEMMLN_SMEM>>>(gp, 2*F, 3*F, F, F, 2*F);
    }

    // ---- launch 4: fused FFN (2 CTA/SM) -> output ----
    {
        FfnPair fp = {};
        fp.Xq[0]=Xq0; fp.Xq[1]=Xq1;
        fp.Wu[0]=wu0; fp.Wu[1]=wu1;
        fp.Wd[0]=wd0; fp.Wd[1]=wd1;
        fp.bu[0]=ffn_up_b0;   fp.bu[1]=ffn_up_b1;
        fp.bd[0]=ffn_down_b0; fp.bd[1]=ffn_down_b1;
        fp.res[0]=X0; fp.res[1]=X1;
        fp.g[0]=ln2_g0; fp.bt[0]=ln2_b0; fp.O[0]=out;
        fp.g[1]=ln2_g1; fp.bt[1]=ln2_b1; fp.O[1]=out + (size_t)NPIX*F;
        ffn_fused<<<dim3(1, NPIX/64, 2), blk, FFN_SMEM>>>(fp);
    }
}

// round 16
// speedup vs baseline: 6.9193x; 1.0619x over previous
#include <cuda_runtime.h>
#include <cuda_fp16.h>
#include <cstdint>
#include <cstddef>

#define F      256
#define NH     8
#define BATCH  2
#define HH     80
#define WW     80
#define NPIX   (BATCH*HH*WW)   // 12800
#define PDIM   1536
#define HIDN   1024

typedef __half h16;

// ---------------- scratch (no allocations allowed) ----------------
__device__ h16 g_P0[(size_t)NPIX*PDIM];
__device__ h16 g_P1[(size_t)NPIX*PDIM];
__device__ h16 g_f0[(size_t)NPIX*F];
__device__ h16 g_f1[(size_t)NPIX*F];
__device__ h16 g_wi0[(size_t)PDIM*F];
__device__ h16 g_wi1[(size_t)PDIM*F];
__device__ h16 g_wo0[(size_t)F*3*F];
__device__ h16 g_wo1[(size_t)F*3*F];
__device__ h16 g_wu0[(size_t)HIDN*F];
__device__ h16 g_wu1[(size_t)HIDN*F];
__device__ h16 g_wd0[(size_t)F*HIDN];
__device__ h16 g_wd1[(size_t)F*HIDN];
__device__ h16 g_QQ0[(size_t)NPIX*2*F];
__device__ h16 g_QQ1[(size_t)NPIX*2*F];

// ================= helpers =================
__device__ __forceinline__ uint32_t smem_u32(const void* p) {
    uint32_t a;
    asm("{ .reg .u64 t; cvta.to.shared.u64 t, %1; cvt.u32.u64 %0, t; }" : "=r"(a) : "l"(p));
    return a;
}
__device__ __forceinline__ void cpasync16(uint32_t dst, const void* src) {
    asm volatile("cp.async.cg.shared.global [%0], [%1], 16;" :: "r"(dst), "l"(src) : "memory");
}
__device__ __forceinline__ void cpasync16z(uint32_t dst, const void* src, int srcsz) {
    asm volatile("cp.async.cg.shared.global [%0], [%1], 16, %2;"
                 :: "r"(dst), "l"(src), "r"(srcsz) : "memory");
}
__device__ __forceinline__ void ldsm4(uint32_t (&r)[4], uint32_t addr) {
    asm volatile("ldmatrix.sync.aligned.m8n8.x4.shared.b16 {%0,%1,%2,%3}, [%4];"
                 : "=r"(r[0]), "=r"(r[1]), "=r"(r[2]), "=r"(r[3]) : "r"(addr));
}
__device__ __forceinline__ void mma16816(float* d, const uint32_t* a, const uint32_t* b) {
    asm volatile("mma.sync.aligned.m16n8k16.row.col.f32.f16.f16.f32 "
                 "{%0,%1,%2,%3}, {%4,%5,%6,%7}, {%8,%9}, {%0,%1,%2,%3};"
                 : "+f"(d[0]), "+f"(d[1]), "+f"(d[2]), "+f"(d[3])
                 : "r"(a[0]), "r"(a[1]), "r"(a[2]), "r"(a[3]), "r"(b[0]), "r"(b[1]));
}

// ================= fp16 tensor GEMM 128x128, k-chunk 64 (paired over z) =================
#define STAGES     3
#define SMEM_STAGE 32768
#define OFF_B      16384u
#define GEMM_SMEM  (STAGES*SMEM_STAGE)

struct GemmPair {
    const h16 *A[2];
    const h16 *B0[2], *B1[2];
    const float *bias[2];
    h16 *Ch[2];
};

__global__ __launch_bounds__(256, 2) void gemm_h16(
    GemmPair gp, int lda, int ldb, int Ksplit, int ldc, int K)
{
    extern __shared__ char smem[];
    const uint32_t sb0 = smem_u32(smem);

    const int z = blockIdx.z;
    const h16* __restrict__ A  = gp.A[z];
    const h16* __restrict__ B0 = gp.B0[z];
    const h16* __restrict__ B1 = gp.B1[z];
    const float* __restrict__ bias = gp.bias[z];
    h16* __restrict__ Ch = gp.Ch[z];

    const int tid  = threadIdx.x;
    const int wid  = tid >> 5;
    const int lane = tid & 31;
    const int brow = blockIdx.y * 128;
    const int bcol = blockIdx.x * 128;
    const int wm   = (wid >> 2) * 64;
    const int wn   = (wid & 3) * 32;

    float acc[4][4][4];
#pragma unroll
    for (int i = 0; i < 4; i++)
#pragma unroll
        for (int j = 0; j < 4; j++)
#pragma unroll
            for (int r = 0; r < 4; r++) acc[i][j][r] = 0.f;

    auto load_stage = [&](int cIdx) {
        const uint32_t sb = sb0 + (uint32_t)(cIdx % STAGES) * SMEM_STAGE;
        const int k0 = cIdx * 64;
        const h16* bp;
        int kk;
        if (k0 < Ksplit) { bp = B0; kk = k0; }
        else             { bp = B1; kk = k0 - Ksplit; }
#pragma unroll
        for (int s = 0; s < 8; s++) {
            const int qid = tid + s * 256;
            const int q   = qid & 1023;
            const int row = q >> 3;
            const int c   = q & 7;
            const h16* src;
            uint32_t dstbase;
            if (qid < 1024) {
                src = A + (size_t)(brow + row) * lda + k0 + c * 8;
                dstbase = sb;
            } else {
                src = bp + (size_t)(bcol + row) * ldb + kk + c * 8;
                dstbase = sb + OFF_B;
            }
            cpasync16(dstbase + (uint32_t)row * 128u +
                      (uint32_t)((c ^ (row & 7)) * 16), src);
        }
        asm volatile("cp.async.commit_group;" ::: "memory");
    };

    const int tile = lane >> 3;
    const int rin  = lane & 7;

    const int NC = K / 64;
    for (int s = 0; s < STAGES - 1 && s < NC; s++) load_stage(s);

    for (int c = 0; c < NC; c++) {
        if (c + 2 <= NC - 1) {
            asm volatile("cp.async.wait_group 1;" ::: "memory");
        } else {
            asm volatile("cp.async.wait_group 0;" ::: "memory");
        }
        __syncthreads();
        if (c + 2 < NC) load_stage(c + 2);

        const uint32_t sb = sb0 + (uint32_t)(c % STAGES) * SMEM_STAGE;
#pragma unroll
        for (int ks = 0; ks < 4; ks++) {
            uint32_t ah[4][4], bh_[2][4];
            const int ca = ks * 2 + (tile >> 1);
#pragma unroll
            for (int i = 0; i < 4; i++) {
                const int arow = wm + i * 16 + (tile & 1) * 8 + rin;
                ldsm4(ah[i], sb + (uint32_t)arow * 128u +
                              (uint32_t)((ca ^ (arow & 7)) * 16));
            }
            const int cb = ks * 2 + (tile & 1);
#pragma unroll
            for (int jj = 0; jj < 2; jj++) {
                const int brw = wn + jj * 16 + (tile >> 1) * 8 + rin;
                ldsm4(bh_[jj], sb + OFF_B + (uint32_t)brw * 128u +
                               (uint32_t)((cb ^ (brw & 7)) * 16));
            }
#pragma unroll
            for (int i = 0; i < 4; i++)
#pragma unroll
                for (int j = 0; j < 4; j++)
                    mma16816(acc[i][j], ah[i], &bh_[j >> 1][(j & 1) * 2]);
        }
    }

    const int tq = lane >> 2;
    const int tr = (lane & 3) * 2;
    float bj0[4], bj1[4];
#pragma unroll
    for (int j = 0; j < 4; j++) {
        const int n = bcol + wn + 8 * j + tr;
        bj0[j] = bias[n]; bj1[j] = bias[n + 1];
    }
#pragma unroll
    for (int i = 0; i < 4; i++)
#pragma unroll
        for (int half = 0; half < 2; half++) {
            const int m = brow + wm + 16 * i + tq + half * 8;
#pragma unroll
            for (int j = 0; j < 4; j++) {
                const int n = bcol + wn + 8 * j + tr;
                float v0 = acc[i][j][half * 2 + 0] + bj0[j];
                float v1 = acc[i][j][half * 2 + 1] + bj1[j];
                *(__half2*)(Ch + (size_t)m * ldc + n) =
                    __halves2half2(__float2half_rn(v0), __float2half_rn(v1));
            }
        }
}

// ================= mega: out-proj + LN1 + FFN + LN2 (paired over z) =================
// CTA: 64 rows, complete chain, out written to gmem.
// smem map: phase A: stages 2x40KB at 0..81920 (A 8K + B 32K per stage)
//           XQ 32KB at 81920..114688 (persists into FFN)
//           FFN: WU 0..32K, WD 32K..64K, UC 64K..72K; LN scratch at 64K.
#define MG_ST_SZ   40960u
#define MG_STB     8192u
#define MG_XQ      81920u
#define MG_WU      0u
#define MG_WD      32768u
#define MG_UC      65536u
#define MEGA_SMEM  114688

struct MegaPair {
    const h16 *QQ[2];
    const h16 *Wo0[2], *Wo1[2];
    const float *ob[2], *ob2[2], *feat[2];
    const float *g1[2], *b1[2];
    const h16 *Wu[2], *Wd[2];
    const float *bu[2], *bd[2];
    const float *g2[2], *b2[2];
    float *O[2];
};

__global__ __launch_bounds__(256, 2) void mega_kernel(MegaPair mp)
{
    extern __shared__ char smem[];
    const uint32_t sb = smem_u32(smem);

    const int z = blockIdx.z;
    const h16* __restrict__ QQ  = mp.QQ[z];
    const h16* __restrict__ Wo0 = mp.Wo0[z];
    const h16* __restrict__ Wo1 = mp.Wo1[z];
    const float* __restrict__ ob   = mp.ob[z];
    const float* __restrict__ ob2  = mp.ob2[z];
    const float* __restrict__ feat = mp.feat[z];
    const float* __restrict__ g1   = mp.g1[z];
    const float* __restrict__ b1   = mp.b1[z];
    const h16* __restrict__ Wu = mp.Wu[z];
    const h16* __restrict__ Wd = mp.Wd[z];
    const float* __restrict__ bu = mp.bu[z];
    const float* __restrict__ bd = mp.bd[z];
    const float* __restrict__ g2 = mp.g2[z];
    const float* __restrict__ b2 = mp.b2[z];
    float* __restrict__ O = mp.O[z];

    const int tid  = threadIdx.x;
    const int wid  = tid >> 5;
    const int lane = tid & 31;
    const int brow = blockIdx.y * 64;

    const int tile = lane >> 3;
    const int rin  = lane & 7;
    const uint32_t rsw = (uint32_t)(rin >> 1);
    const int tq = lane >> 2;
    const int tr = (lane & 3) * 2;

    // 32x64 warp tile used in phase A and FFN phase 2
    const int wm = (wid >> 2) * 32;
    const int wn = (wid & 3) * 64;
    // FFN phase-1 tile
    const int wm1 = (wid & 1) * 32;
    const int wh  = (wid >> 1) * 16;

    float acc[2][8][4];
#pragma unroll
    for (int i = 0; i < 2; i++)
#pragma unroll
        for (int j = 0; j < 8; j++)
#pragma unroll
            for (int r = 0; r < 4; r++) acc[i][j][r] = 0.f;

    // ---------- PHASE A: out-proj, K=512 in 8 chunks of 64, 2 stages ----------
    auto loadA = [&](int cIdx) {
        const uint32_t st = sb + (uint32_t)(cIdx & 1) * MG_ST_SZ;
        const int k0 = cIdx * 64;
        const h16* bp;
        int kk;
        if (k0 < 256) { bp = Wo0; kk = k0; }
        else          { bp = Wo1; kk = k0 - 256; }
#pragma unroll
        for (int s = 0; s < 10; s++) {
            const int qid = tid + s * 256;
            if (qid < 512) {                 // A: QQ rows (64 x 64k)
                const int row = qid >> 3, c = qid & 7;
                cpasync16(st + (uint32_t)row * 128u + (uint32_t)((c ^ (row & 7)) * 16),
                          QQ + (size_t)(brow + row) * (2 * F) + k0 + c * 8);
            } else {                          // B: 256 rows x 64k
                const int q = qid - 512;
                const int row = q >> 3, c = q & 7;
                cpasync16(st + MG_STB + (uint32_t)row * 128u +
                          (uint32_t)((c ^ (row & 7)) * 16),
                          bp + (size_t)row * (3 * F) + kk + c * 8);
            }
        }
        asm volatile("cp.async.commit_group;" ::: "memory");
    };

    loadA(0);
    for (int c = 0; c < 8; c++) {
        asm volatile("cp.async.wait_group 0;" ::: "memory");
        __syncthreads();
        if (c + 1 < 8) loadA(c + 1);

        const uint32_t st = sb + (uint32_t)(c & 1) * MG_ST_SZ;
#pragma unroll
        for (int ks = 0; ks < 4; ks++) {
            uint32_t ah[2][4], bh_[4][4];
            const int ca = ks * 2 + (tile >> 1);
#pragma unroll
            for (int i = 0; i < 2; i++) {
                const int arow = wm + i * 16 + (tile & 1) * 8 + rin;
                ldsm4(ah[i], st + (uint32_t)arow * 128u +
                              (uint32_t)((ca ^ (arow & 7)) * 16));
            }
            const int cb = ks * 2 + (tile & 1);
#pragma unroll
            for (int jj = 0; jj < 4; jj++) {
                const int brw = wn + jj * 16 + (tile >> 1) * 8 + rin;
                ldsm4(bh_[jj], st + MG_STB + (uint32_t)brw * 128u +
                               (uint32_t)((cb ^ (brw & 7)) * 16));
            }
#pragma unroll
            for (int i = 0; i < 2; i++)
#pragma unroll
                for (int j = 0; j < 8; j++)
                    mma16816(acc[i][j], ah[i], &bh_[j >> 1][(j & 1) * 2]);
        }
    }
    __syncthreads();   // staging dead

    // ---------- LN1 epilogue -> Xq in smem ----------
    {
        float* redS = (float*)(smem + MG_UC);
        float* redQ = (float*)(smem + MG_UC) + 256;
        const int wslot = wn >> 6;

        float bj0[8], bj1[8];
#pragma unroll
        for (int j = 0; j < 8; j++) {
            const int n = wn + 8 * j + tr;
            bj0[j] = ob[n] + ob2[n];
            bj1[j] = ob[n + 1] + ob2[n + 1];
        }
#pragma unroll
        for (int i = 0; i < 2; i++)
#pragma unroll
            for (int half = 0; half < 2; half++) {
                const int mrow = wm + 16 * i + 8 * half + tq;
                const int m = brow + mrow;
                float s1 = 0.f, s2 = 0.f;
#pragma unroll
                for (int j = 0; j < 8; j++) {
                    float v0 = acc[i][j][half * 2 + 0] + bj0[j];
                    float v1 = acc[i][j][half * 2 + 1] + bj1[j];
                    float2 rr = *(const float2*)(feat + (size_t)m * F + wn + 8 * j + tr);
                    v0 += rr.x; v1 += rr.y;
                    acc[i][j][half * 2 + 0] = v0;
                    acc[i][j][half * 2 + 1] = v1;
                    s1 += v0 + v1;
                    s2 += v0 * v0 + v1 * v1;
                }
                s1 += __shfl_xor_sync(0xffffffffu, s1, 1);
                s2 += __shfl_xor_sync(0xffffffffu, s2, 1);
                s1 += __shfl_xor_sync(0xffffffffu, s1, 2);
                s2 += __shfl_xor_sync(0xffffffffu, s2, 2);
                if ((lane & 3) == 0) {
                    redS[mrow * 4 + wslot] = s1;
                    redQ[mrow * 4 + wslot] = s2;
                }
            }
        __syncthreads();

#pragma unroll
        for (int i = 0; i < 2; i++)
#pragma unroll
            for (int half = 0; half < 2; half++) {
                const int mrow = wm + 16 * i + 8 * half + tq;
                float tS = redS[mrow * 4 + 0] + redS[mrow * 4 + 1]
                         + redS[mrow * 4 + 2] + redS[mrow * 4 + 3];
                float tQ = redQ[mrow * 4 + 0] + redQ[mrow * 4 + 1]
                         + redQ[mrow * 4 + 2] + redQ[mrow * 4 + 3];
                float mean = tS * (1.0f / F);
                float var  = tQ * (1.0f / F) - mean * mean;
                float rstd = rsqrtf(var + 1e-5f);
#pragma unroll
                for (int j = 0; j < 8; j++) {
                    const int n = wn + 8 * j + tr;
                    float2 gg = *(const float2*)(g1 + n);
                    float2 bb = *(const float2*)(b1 + n);
                    float o0 = gg.x * (acc[i][j][half * 2 + 0] - mean) * rstd + bb.x;
                    float o1 = gg.y * (acc[i][j][half * 2 + 1] - mean) * rstd + bb.y;
                    // write Xq to smem (load_xq layout)
                    const int s = n >> 5;
                    const int quad = (n >> 3) & 3;
                    uint32_t ad = sb + MG_XQ + (uint32_t)s * 4096u + (uint32_t)mrow * 64u +
                                  (uint32_t)((quad ^ ((mrow >> 1) & 3)) * 16) + (uint32_t)tr * 2u;
                    __half2 hh = __halves2half2(__float2half_rn(o0), __float2half_rn(o1));
                    asm volatile("st.shared.b32 [%0], %1;" :: "r"(ad), "r"(*(uint32_t*)&hh) : "memory");
                }
            }
    }
    __syncthreads();

    // ---------- FFN: 16 hidden chunks of 64 ----------
#pragma unroll
    for (int i = 0; i < 2; i++)
#pragma unroll
        for (int j = 0; j < 8; j++)
#pragma unroll
            for (int r = 0; r < 4; r++) acc[i][j][r] = 0.f;

    auto load_wu = [&](int hc) {
#pragma unroll
        for (int t = 0; t < 8; t++) {
            const int qid = tid + t * 256;
            const int kc = qid >> 8, q = qid & 255;
            const int r = q >> 2, c = q & 3;
            cpasync16(sb + MG_WU + (uint32_t)kc * 4096u + (uint32_t)r * 64u +
                      (uint32_t)((c ^ ((r >> 1) & 3)) * 16),
                      Wu + (size_t)(hc * 64 + r) * F + kc * 32 + c * 8);
        }
        asm volatile("cp.async.commit_group;" ::: "memory");
    };
    auto load_wd = [&](int hc) {
#pragma unroll
        for (int t = 0; t < 8; t++) {
            const int qid = tid + t * 256;
            const int s = qid >> 10, q = qid & 1023;
            const int r = q >> 2, c = q & 3;
            cpasync16(sb + MG_WD + (uint32_t)s * 16384u + (uint32_t)r * 64u +
                      (uint32_t)((c ^ ((r >> 1) & 3)) * 16),
                      Wd + (size_t)r * HIDN + hc * 64 + s * 32 + c * 8);
        }
        asm volatile("cp.async.commit_group;" ::: "memory");
    };

    load_wu(0);
    asm volatile("cp.async.wait_group 0;" ::: "memory");
    __syncthreads();

    for (int hc = 0; hc < 16; hc++) {
        load_wd(hc);

        float acc1[2][2][4];
#pragma unroll
        for (int i = 0; i < 2; i++)
#pragma unroll
            for (int j = 0; j < 2; j++)
#pragma unroll
                for (int r = 0; r < 4; r++) acc1[i][j][r] = 0.f;

#pragma unroll
        for (int kc = 0; kc < 8; kc++) {
            const uint32_t sx = sb + MG_XQ + (uint32_t)kc * 4096u;
            const uint32_t sw = sb + MG_WU + (uint32_t)kc * 4096u;
#pragma unroll
            for (int ks = 0; ks < 2; ks++) {
                uint32_t ah[2][4], bh_[4];
                const uint32_t swa = ((uint32_t)(ks * 2 + (tile >> 1)) ^ rsw) * 16u;
#pragma unroll
                for (int i = 0; i < 2; i++)
                    ldsm4(ah[i], sx + (uint32_t)(wm1 + i * 16 + (tile & 1) * 8 + rin) * 64u + swa);
                const uint32_t swb = ((uint32_t)(ks * 2 + (tile & 1)) ^ rsw) * 16u;
                ldsm4(bh_, sw + (uint32_t)(wh + (tile >> 1) * 8 + rin) * 64u + swb);
#pragma unroll
                for (int i = 0; i < 2; i++)
#pragma unroll
                    for (int j = 0; j < 2; j++)
                        mma16816(acc1[i][j], ah[i], &bh_[j * 2]);
            }
        }

        {
            const int sub   = wh >> 5;
            const int cbase = (wh & 31) >> 3;
            const uint32_t ucb = sb + MG_UC + (uint32_t)sub * 4096u;
#pragma unroll
            for (int i = 0; i < 2; i++)
#pragma unroll
                for (int j = 0; j < 2; j++) {
                    const int nh = hc * 64 + wh + j * 8 + tr;
                    float bb0 = bu[nh], bb1 = bu[nh + 1];
                    float v0 = fmaxf(acc1[i][j][0] + bb0, 0.f);
                    float v1 = fmaxf(acc1[i][j][1] + bb1, 0.f);
                    float v2 = fmaxf(acc1[i][j][2] + bb0, 0.f);
                    float v3 = fmaxf(acc1[i][j][3] + bb1, 0.f);
                    const int quad = cbase + j;
                    const int row0 = wm1 + i * 16 + tq;
                    const int row1 = row0 + 8;
                    uint32_t a0 = ucb + (uint32_t)row0 * 64u +
                                  (uint32_t)((quad ^ ((row0 >> 1) & 3)) * 16) + (uint32_t)tr * 2u;
                    uint32_t a1 = ucb + (uint32_t)row1 * 64u +
                                  (uint32_t)((quad ^ ((row1 >> 1) & 3)) * 16) + (uint32_t)tr * 2u;
                    __half2 h01 = __halves2half2(__float2half_rn(v0), __float2half_rn(v1));
                    __half2 h23 = __halves2half2(__float2half_rn(v2), __float2half_rn(v3));
                    asm volatile("st.shared.b32 [%0], %1;" :: "r"(a0), "r"(*(uint32_t*)&h01) : "memory");
                    asm volatile("st.shared.b32 [%0], %1;" :: "r"(a1), "r"(*(uint32_t*)&h23) : "memory");
                }
        }
        __syncthreads();

        if (hc < 15) load_wu(hc + 1);

        if (hc < 15) {
            asm volatile("cp.async.wait_group 1;" ::: "memory");
        } else {
            asm volatile("cp.async.wait_group 0;" ::: "memory");
        }

#pragma unroll
        for (int s = 0; s < 2; s++) {
            const uint32_t su = sb + MG_UC + (uint32_t)s * 4096u;
            const uint32_t sd = sb + MG_WD + (uint32_t)s * 16384u;
#pragma unroll
            for (int ks = 0; ks < 2; ks++) {
                uint32_t ah[2][4], bh_[4][4];
                const uint32_t swa = ((uint32_t)(ks * 2 + (tile >> 1)) ^ rsw) * 16u;
#pragma unroll
                for (int i = 0; i < 2; i++)
                    ldsm4(ah[i], su + (uint32_t)(wm + i * 16 + (tile & 1) * 8 + rin) * 64u + swa);
                const uint32_t swb = ((uint32_t)(ks * 2 + (tile & 1)) ^ rsw) * 16u;
#pragma unroll
                for (int jj = 0; jj < 4; jj++)
                    ldsm4(bh_[jj], sd + (uint32_t)(wn + jj * 16 + (tile >> 1) * 8 + rin) * 64u + swb);
#pragma unroll
                for (int i = 0; i < 2; i++)
#pragma unroll
                    for (int j = 0; j < 8; j++)
                        mma16816(acc[i][j], ah[i], &bh_[j >> 1][(j & 1) * 2]);
            }
        }

        asm volatile("cp.async.wait_group 0;" ::: "memory");
        __syncthreads();
    }

    // ---------- LN2 epilogue -> out (residual = Xq from smem) ----------
    {
        float* redS = (float*)(smem + MG_UC);
        float* redQ = (float*)(smem + MG_UC) + 256;
        const int wslot = wn >> 6;

        float bj0[8], bj1[8];
#pragma unroll
        for (int j = 0; j < 8; j++) {
            const int n = wn + 8 * j + tr;
            bj0[j] = bd[n]; bj1[j] = bd[n + 1];
        }

#pragma unroll
        for (int i = 0; i < 2; i++)
#pragma unroll
            for (int half = 0; half < 2; half++) {
                const int mrow = wm + 16 * i + 8 * half + tq;
                float s1 = 0.f, s2 = 0.f;
#pragma unroll
                for (int j = 0; j < 8; j++) {
                    const int n = wn + 8 * j + tr;
                    float v0 = acc[i][j][half * 2 + 0] + bj0[j];
                    float v1 = acc[i][j][half * 2 + 1] + bj1[j];
                    // residual from Xq smem
                    const int s = n >> 5;
                    const int quad = (n >> 3) & 3;
                    uint32_t ad = sb + MG_XQ + (uint32_t)s * 4096u + (uint32_t)mrow * 64u +
                                  (uint32_t)((quad ^ ((mrow >> 1) & 3)) * 16) + (uint32_t)tr * 2u;
                    uint32_t xv;
                    asm volatile("ld.shared.b32 %0, [%1];" : "=r"(xv) : "r"(ad));
                    float2 xf = __half22float2(*(__half2*)&xv);
                    v0 += xf.x; v1 += xf.y;
                    acc[i][j][half * 2 + 0] = v0;
                    acc[i][j][half * 2 + 1] = v1;
                    s1 += v0 + v1;
                    s2 += v0 * v0 + v1 * v1;
                }
                s1 += __shfl_xor_sync(0xffffffffu, s1, 1);
                s2 += __shfl_xor_sync(0xffffffffu, s2, 1);
                s1 += __shfl_xor_sync(0xffffffffu, s1, 2);
                s2 += __shfl_xor_sync(0xffffffffu, s2, 2);
                if ((lane & 3) == 0) {
                    redS[mrow * 4 + wslot] = s1;
                    redQ[mrow * 4 + wslot] = s2;
                }
            }
        __syncthreads();

#pragma unroll
        for (int i = 0; i < 2; i++)
#pragma unroll
            for (int half = 0; half < 2; half++) {
                const int mrow = wm + 16 * i + 8 * half + tq;
                const int m = brow + mrow;
                float tS = redS[mrow * 4 + 0] + redS[mrow * 4 + 1]
                         + redS[mrow * 4 + 2] + redS[mrow * 4 + 3];
                float tQ = redQ[mrow * 4 + 0] + redQ[mrow * 4 + 1]
                         + redQ[mrow * 4 + 2] + redQ[mrow * 4 + 3];
                float mean = tS * (1.0f / F);
                float var  = tQ * (1.0f / F) - mean * mean;
                float rstd = rsqrtf(var + 1e-5f);
#pragma unroll
                for (int j = 0; j < 8; j++) {
                    const int n = wn + 8 * j + tr;
                    float2 gg = *(const float2*)(g2 + n);
                    float2 bb = *(const float2*)(b2 + n);
                    float o0 = gg.x * (acc[i][j][half * 2 + 0] - mean) * rstd + bb.x;
                    float o1 = gg.y * (acc[i][j][half * 2 + 1] - mean) * rstd + bb.y;
                    *(float2*)(O + (size_t)m * F + n) = make_float2(o0, o1);
                }
            }
    }
}

// ---------------- merged convert fp32 -> fp16 ----------------
#define NSEG 10
struct ConvArgs {
    const float* s[NSEG];
    h16* h[NSEG];
    int end4[NSEG];
};

__global__ __launch_bounds__(256) void conv_all(ConvArgs a, int total4)
{
    int i = blockIdx.x * 256 + threadIdx.x;
    if (i >= total4) return;
    int seg = 0;
#pragma unroll
    for (int s = 0; s < NSEG - 1; s++) seg += (i >= a.end4[s]) ? 1 : 0;
    const int base = seg ? a.end4[seg - 1] : 0;
    const int j = i - base;

    float4 v = ((const float4*)a.s[seg])[j];
    h16* hp = a.h[seg];
    ((__half2*)hp)[2 * j]     = __halves2half2(__float2half_rn(v.x), __float2half_rn(v.y));
    ((__half2*)hp)[2 * j + 1] = __halves2half2(__float2half_rn(v.z), __float2half_rn(v.w));
}

// ---------------- 9-tap attention, smem halo staging (4 slices via y) ----------------
#define APX 16
#define PXSTRIDE 1088u
#define ATT_SMEM (54*1088)

struct AttArgs {
    const h16* Q[4];
    const h16* Kp[4];
    const h16* Vp[4];
    h16* O[4];
};

__global__ __launch_bounds__(256) void attend_kernel(AttArgs a, int ostride)
{
    extern __shared__ char attsm[];
    const uint32_t sb = smem_u32(attsm);

    const int z    = blockIdx.y;
    const int tid  = threadIdx.x;
    const int pix0 = blockIdx.x * APX;
    const int b    = pix0 / (HH * WW);
    const int rr   = pix0 % (HH * WW);
    const int y    = rr / WW;
    const int x0   = rr % WW;

    const h16* __restrict__ Q  = a.Q[z];
    const h16* __restrict__ Kp = a.Kp[z];
    const h16* __restrict__ Vp = a.Vp[z];

#pragma unroll
    for (int t = 0; t < 14; t++) {
        const int qid = tid + t * 256;
        if (qid < 3456) {
            const int e   = qid >> 6;
            const int qq  = qid & 63;
            const int isV = qq >> 5;
            const int q   = qq & 31;
            const int yy  = y + (e / 18) - 1;
            const int xx  = x0 + (e % 18) - 1;
            const bool ok = (yy >= 0 && yy < HH && xx >= 0 && xx < WW);
            const int ys  = ok ? yy : 0;
            const int xs  = ok ? xx : 0;
            const h16* src = (isV ? Vp : Kp) +
                ((size_t)(b * HH + ys) * WW + xs) * PDIM + q * 8;
            cpasync16z(sb + (uint32_t)e * PXSTRIDE + (uint32_t)isV * 512u + (uint32_t)q * 16u,
                       src, ok ? 16 : 0);
        }
    }
    asm volatile("cp.async.commit_group;" ::: "memory");
    asm volatile("cp.async.wait_group 0;" ::: "memory");
    __syncthreads();

    const int px  = tid >> 4;
    const int t16 = tid & 15;
    const int ch  = t16 * 16;
    const int pix = pix0 + px;

    const float scale = 0.17677669529663687f;
    float qf[16];
    {
        const uint4* qp = (const uint4*)(Q + (size_t)pix * PDIM + ch);
        uint4 q0 = qp[0], q1 = qp[1];
        const uint32_t* qu = (const uint32_t*)&q0;
#pragma unroll
        for (int i = 0; i < 4; i++) {
            float2 f = __half22float2(*(__half2*)&qu[i]);
            qf[2 * i] = f.x * scale; qf[2 * i + 1] = f.y * scale;
        }
        const uint32_t* qu2 = (const uint32_t*)&q1;
#pragma unroll
        for (int i = 0; i < 4; i++) {
            float2 f = __half22float2(*(__half2*)&qu2[i]);
            qf[8 + 2 * i] = f.x * scale; qf[8 + 2 * i + 1] = f.y * scale;
        }
    }

    float sc[9];
#pragma unroll
    for (int n = 0; n < 9; n++) {
        const int hal = (n / 3) * 18 + px + (n % 3);
        const char* kb = attsm + hal * PXSTRIDE + ch * 2;
        uint4 k0 = *(const uint4*)kb;
        uint4 k1 = *(const uint4*)(kb + 16);
        float s = 0.f;
        const uint32_t* ku = (const uint32_t*)&k0;
#pragma unroll
        for (int i = 0; i < 4; i++) {
            float2 f = __half22float2(*(__half2*)&ku[i]);
            s = fmaf(qf[2 * i], f.x, s);
            s = fmaf(qf[2 * i + 1], f.y, s);
        }
        const uint32_t* ku2 = (const uint32_t*)&k1;
#pragma unroll
        for (int i = 0; i < 4; i++) {
            float2 f = __half22float2(*(__half2*)&ku2[i]);
            s = fmaf(qf[8 + 2 * i], f.x, s);
            s = fmaf(qf[8 + 2 * i + 1], f.y, s);
        }
        s += __shfl_xor_sync(0xffffffffu, s, 1);
        sc[n] = s;
    }

    float mx = sc[0];
#pragma unroll
    for (int n = 1; n < 9; n++) mx = fmaxf(mx, sc[n]);
    float w[9], den = 0.f;
#pragma unroll
    for (int n = 0; n < 9; n++) { w[n] = __expf(sc[n] - mx); den += w[n]; }

    float o[16];
#pragma unroll
    for (int i = 0; i < 16; i++) o[i] = 0.f;
#pragma unroll
    for (int n = 0; n < 9; n++) {
        const int hal = (n / 3) * 18 + px + (n % 3);
        const char* vb = attsm + hal * PXSTRIDE + 512 + ch * 2;
        uint4 v0 = *(const uint4*)vb;
        uint4 v1 = *(const uint4*)(vb + 16);
        const uint32_t* vu = (const uint32_t*)&v0;
#pragma unroll
        for (int i = 0; i < 4; i++) {
            float2 f = __half22float2(*(__half2*)&vu[i]);
            o[2 * i]     = fmaf(w[n], f.x, o[2 * i]);
            o[2 * i + 1] = fmaf(w[n], f.y, o[2 * i + 1]);
        }
        const uint32_t* vu2 = (const uint32_t*)&v1;
#pragma unroll
        for (int i = 0; i < 4; i++) {
            float2 f = __half22float2(*(__half2*)&vu2[i]);
            o[8 + 2 * i]     = fmaf(w[n], f.x, o[8 + 2 * i]);
            o[8 + 2 * i + 1] = fmaf(w[n], f.y, o[8 + 2 * i + 1]);
        }
    }

    const float inv = 1.f / den;
    uint32_t pk[8];
#pragma unroll
    for (int i = 0; i < 8; i++) {
        __half2 h = __halves2half2(__float2half_rn(o[2 * i] * inv),
                                   __float2half_rn(o[2 * i + 1] * inv));
        pk[i] = *(uint32_t*)&h;
    }
    h16* op = a.O[z] + (size_t)pix * ostride + ch;
    *(uint4*)op        = make_uint4(pk[0], pk[1], pk[2], pk[3]);
    *(uint4*)(op + 8)  = make_uint4(pk[4], pk[5], pk[6], pk[7]);
}

// ---------------- launch ----------------
#define SYM(p, s) cudaGetSymbolAddress((void**)&p, s)

extern "C" void kernel_launch(void* const* d_in, const int* in_sizes, int n_in,
                              void* d_out, int out_size)
{
    const float* feat0       = (const float*)d_in[0];
    const float* feat1       = (const float*)d_in[1];
    const float* in_w0       = (const float*)d_in[2];
    const float* in_b0       = (const float*)d_in[3];
    const float* in_w1       = (const float*)d_in[4];
    const float* in_b1       = (const float*)d_in[5];
    const float* out_w0      = (const float*)d_in[6];
    const float* out_b0      = (const float*)d_in[7];
    const float* out_w1      = (const float*)d_in[8];
    const float* out_b1      = (const float*)d_in[9];
    const float* ln1_g0      = (const float*)d_in[10];
    const float* ln1_b0      = (const float*)d_in[11];
    const float* ln1_g1      = (const float*)d_in[12];
    const float* ln1_b1      = (const float*)d_in[13];
    const float* ffn_up_w0   = (const float*)d_in[14];
    const float* ffn_up_b0   = (const float*)d_in[15];
    const float* ffn_down_w0 = (const float*)d_in[16];
    const float* ffn_down_b0 = (const float*)d_in[17];
    const float* ffn_up_w1   = (const float*)d_in[18];
    const float* ffn_up_b1   = (const float*)d_in[19];
    const float* ffn_down_w1 = (const float*)d_in[20];
    const float* ffn_down_b1 = (const float*)d_in[21];
    const float* ln2_g0      = (const float*)d_in[22];
    const float* ln2_b0      = (const float*)d_in[23];
    const float* ln2_g1      = (const float*)d_in[24];
    const float* ln2_b1      = (const float*)d_in[25];

    h16 *P0, *P1, *f0, *f1, *wi0, *wi1, *wo0, *wo1, *wu0, *wu1, *wd0, *wd1;
    h16 *QQ0, *QQ1;
    SYM(P0, g_P0); SYM(P1, g_P1);
    SYM(f0, g_f0); SYM(f1, g_f1);
    SYM(wi0, g_wi0); SYM(wi1, g_wi1);
    SYM(wo0, g_wo0); SYM(wo1, g_wo1);
    SYM(wu0, g_wu0); SYM(wu1, g_wu1);
    SYM(wd0, g_wd0); SYM(wd1, g_wd1);
    SYM(QQ0, g_QQ0); SYM(QQ1, g_QQ1);

    cudaFuncSetAttribute(gemm_h16, cudaFuncAttributeMaxDynamicSharedMemorySize, GEMM_SMEM);
    cudaFuncSetAttribute(mega_kernel, cudaFuncAttributeMaxDynamicSharedMemorySize, MEGA_SMEM);
    cudaFuncSetAttribute(attend_kernel, cudaFuncAttributeMaxDynamicSharedMemorySize, ATT_SMEM);

    float* out = (float*)d_out;
    dim3 blk(256);
    const int MT = NPIX / 128;   // 100

    // ---- launch 0: all converts ----
    {
        ConvArgs ca;
        const float* srcs[NSEG] = {feat0, feat1, in_w0, in_w1, out_w0, out_w1,
                                   ffn_up_w0, ffn_up_w1, ffn_down_w0, ffn_down_w1};
        h16* hs[NSEG] = {f0, f1, wi0, wi1, wo0, wo1, wu0, wu1, wd0, wd1};
        int sizes4[NSEG] = {NPIX*F/4, NPIX*F/4, PDIM*F/4, PDIM*F/4, F*3*F/4, F*3*F/4,
                            HIDN*F/4, HIDN*F/4, F*HIDN/4, F*HIDN/4};
        int acc4 = 0;
        for (int i = 0; i < NSEG; i++) {
            ca.s[i] = srcs[i]; ca.h[i] = hs[i];
            acc4 += sizes4[i];
            ca.end4[i] = acc4;
        }
        conv_all<<<(acc4 + 255) / 256, blk>>>(ca, acc4);
    }

    // ---- launch 1: in-projection GEMMs -> P fp16 ----
    {
        GemmPair gp = {};
        gp.A[0]=f0; gp.A[1]=f1;
        gp.B0[0]=wi0; gp.B1[0]=wi0;
        gp.B0[1]=wi1; gp.B1[1]=wi1;
        gp.bias[0]=in_b0; gp.bias[1]=in_b1;
        gp.Ch[0]=P0; gp.Ch[1]=P1;
        gemm_h16<<<dim3(PDIM/128, MT, 2), blk, GEMM_SMEM>>>(gp, F, F, F, PDIM, F);
    }

    // ---- launch 2: 4 attentions (smem-tiled) -> QQ fp16 ----
    {
        AttArgs aa;
        aa.Q[0]=P0;     aa.Kp[0]=P0+F;   aa.Vp[0]=P0+2*F; aa.O[0]=QQ0;
        aa.Q[1]=P1;     aa.Kp[1]=P1+F;   aa.Vp[1]=P1+2*F; aa.O[1]=QQ1;
        aa.Q[2]=P0+3*F; aa.Kp[2]=P1+4*F; aa.Vp[2]=P1+5*F; aa.O[2]=QQ0+F;
        aa.Q[3]=P1+3*F; aa.Kp[3]=P0+4*F; aa.Vp[3]=P0+5*F; aa.O[3]=QQ1+F;
        attend_kernel<<<dim3(NPIX/APX, 4), blk, ATT_SMEM>>>(aa, 2*F);
    }

    // ---- launch 3: mega (out-proj + LN1 + FFN + LN2) -> output ----
    {
        MegaPair mp = {};
        mp.QQ[0]=QQ0; mp.QQ[1]=QQ1;
        mp.Wo0[0]=wo0; mp.Wo1[0]=wo0+F;
        mp.Wo0[1]=wo1; mp.Wo1[1]=wo0+F;
        mp.ob[0]=out_b0; mp.ob2[0]=out_b0+F; mp.feat[0]=feat0;
        mp.ob[1]=out_b1; mp.ob2[1]=out_b0+F; mp.feat[1]=feat1;
        mp.g1[0]=ln1_g0; mp.b1[0]=ln1_b0;
        mp.g1[1]=ln1_g1; mp.b1[1]=ln1_b1;
        mp.Wu[0]=wu0; mp.Wu[1]=wu1;
        mp.Wd[0]=wd0; mp.Wd[1]=wd1;
        mp.bu[0]=ffn_up_b0;   mp.bu[1]=ffn_up_b1;
        mp.bd[0]=ffn_down_b0; mp.bd[1]=ffn_down_b1;
        mp.g2[0]=ln2_g0; mp.b2[0]=ln2_b0; mp.O[0]=out;
        mp.g2[1]=ln2_g1; mp.b2[1]=ln2_b1; mp.O[1]=out + (size_t)NPIX*F;
        mega_kernel<<<dim3(1, NPIX/64, 2), blk, MEGA_SMEM>>>(mp);
    }
}

// round 17
// speedup vs baseline: 7.0184x; 1.0143x over previous
#include <cuda_runtime.h>
#include <cuda_fp16.h>
#include <cstdint>
#include <cstddef>

#define F      256
#define NH     8
#define BATCH  2
#define HH     80
#define WW     80
#define NPIX   (BATCH*HH*WW)   // 12800
#define PDIM   1536
#define HIDN   1024

typedef __half h16;

// ---------------- scratch (no allocations allowed) ----------------
__device__ h16 g_P0[(size_t)NPIX*PDIM];
__device__ h16 g_P1[(size_t)NPIX*PDIM];
__device__ h16 g_f0[(size_t)NPIX*F];
__device__ h16 g_f1[(size_t)NPIX*F];
__device__ h16 g_wi0[(size_t)PDIM*F];
__device__ h16 g_wi1[(size_t)PDIM*F];
__device__ h16 g_wo0[(size_t)F*3*F];
__device__ h16 g_wo1[(size_t)F*3*F];
__device__ h16 g_wu0[(size_t)HIDN*F];
__device__ h16 g_wu1[(size_t)HIDN*F];
__device__ h16 g_wd0[(size_t)F*HIDN];
__device__ h16 g_wd1[(size_t)F*HIDN];
__device__ h16 g_QQ0[(size_t)NPIX*2*F];
__device__ h16 g_QQ1[(size_t)NPIX*2*F];

// ================= helpers =================
__device__ __forceinline__ uint32_t smem_u32(const void* p) {
    uint32_t a;
    asm("{ .reg .u64 t; cvta.to.shared.u64 t, %1; cvt.u32.u64 %0, t; }" : "=r"(a) : "l"(p));
    return a;
}
__device__ __forceinline__ void cpasync16(uint32_t dst, const void* src) {
    asm volatile("cp.async.cg.shared.global [%0], [%1], 16;" :: "r"(dst), "l"(src) : "memory");
}
__device__ __forceinline__ void cpasync16z(uint32_t dst, const void* src, int srcsz) {
    asm volatile("cp.async.cg.shared.global [%0], [%1], 16, %2;"
                 :: "r"(dst), "l"(src), "r"(srcsz) : "memory");
}
__device__ __forceinline__ void ldsm4(uint32_t (&r)[4], uint32_t addr) {
    asm volatile("ldmatrix.sync.aligned.m8n8.x4.shared.b16 {%0,%1,%2,%3}, [%4];"
                 : "=r"(r[0]), "=r"(r[1]), "=r"(r[2]), "=r"(r[3]) : "r"(addr));
}
__device__ __forceinline__ void mma16816(float* d, const uint32_t* a, const uint32_t* b) {
    asm volatile("mma.sync.aligned.m16n8k16.row.col.f32.f16.f16.f32 "
                 "{%0,%1,%2,%3}, {%4,%5,%6,%7}, {%8,%9}, {%0,%1,%2,%3};"
                 : "+f"(d[0]), "+f"(d[1]), "+f"(d[2]), "+f"(d[3])
                 : "r"(a[0]), "r"(a[1]), "r"(a[2]), "r"(a[3]), "r"(b[0]), "r"(b[1]));
}

// ================= fp16 GEMM 64x256, k-chunk 64 (mega phase-A geometry, paired over z) =================
// Stage: [A 8K][B 32K] = 40KB; 2 stages = 80KB; 2 CTAs/SM.
#define G2_ST_SZ  40960u
#define G2_STB    8192u
#define GEMM_SMEM (2*40960)

struct GemmPair {
    const h16 *A[2];
    const h16 *B[2];
    const float *bias[2];
    h16 *Ch[2];
};

__global__ __launch_bounds__(256, 2) void gemm_h16(
    GemmPair gp, int lda, int ldb, int ldc, int K)
{
    extern __shared__ char smem[];
    const uint32_t sb = smem_u32(smem);

    const int z = blockIdx.z;
    const h16* __restrict__ A = gp.A[z];
    const h16* __restrict__ B = gp.B[z];
    const float* __restrict__ bias = gp.bias[z];
    h16* __restrict__ Ch = gp.Ch[z];

    const int tid  = threadIdx.x;
    const int wid  = tid >> 5;
    const int lane = tid & 31;
    const int brow = blockIdx.y * 64;
    const int bcol = blockIdx.x * 256;
    const int wm   = (wid >> 2) * 32;
    const int wn   = (wid & 3) * 64;

    const int tile = lane >> 3;
    const int rin  = lane & 7;

    float acc[2][8][4];
#pragma unroll
    for (int i = 0; i < 2; i++)
#pragma unroll
        for (int j = 0; j < 8; j++)
#pragma unroll
            for (int r = 0; r < 4; r++) acc[i][j][r] = 0.f;

    auto loadS = [&](int cIdx) {
        const uint32_t st = sb + (uint32_t)(cIdx & 1) * G2_ST_SZ;
        const int k0 = cIdx * 64;
#pragma unroll
        for (int s = 0; s < 10; s++) {
            const int qid = tid + s * 256;
            if (qid < 512) {
                const int row = qid >> 3, c = qid & 7;
                cpasync16(st + (uint32_t)row * 128u + (uint32_t)((c ^ (row & 7)) * 16),
                          A + (size_t)(brow + row) * lda + k0 + c * 8);
            } else {
                const int q = qid - 512;
                const int row = q >> 3, c = q & 7;
                cpasync16(st + G2_STB + (uint32_t)row * 128u +
                          (uint32_t)((c ^ (row & 7)) * 16),
                          B + (size_t)(bcol + row) * ldb + k0 + c * 8);
            }
        }
        asm volatile("cp.async.commit_group;" ::: "memory");
    };

    loadS(0);
    const int NC = K / 64;
    for (int c = 0; c < NC; c++) {
        asm volatile("cp.async.wait_group 0;" ::: "memory");
        __syncthreads();
        if (c + 1 < NC) loadS(c + 1);

        const uint32_t st = sb + (uint32_t)(c & 1) * G2_ST_SZ;
#pragma unroll
        for (int ks = 0; ks < 4; ks++) {
            uint32_t ah[2][4], bh_[4][4];
            const int ca = ks * 2 + (tile >> 1);
#pragma unroll
            for (int i = 0; i < 2; i++) {
                const int arow = wm + i * 16 + (tile & 1) * 8 + rin;
                ldsm4(ah[i], st + (uint32_t)arow * 128u +
                              (uint32_t)((ca ^ (arow & 7)) * 16));
            }
            const int cb = ks * 2 + (tile & 1);
#pragma unroll
            for (int jj = 0; jj < 4; jj++) {
                const int brw = wn + jj * 16 + (tile >> 1) * 8 + rin;
                ldsm4(bh_[jj], st + G2_STB + (uint32_t)brw * 128u +
                               (uint32_t)((cb ^ (brw & 7)) * 16));
            }
#pragma unroll
            for (int i = 0; i < 2; i++)
#pragma unroll
                for (int j = 0; j < 8; j++)
                    mma16816(acc[i][j], ah[i], &bh_[j >> 1][(j & 1) * 2]);
        }
    }

    const int tq = lane >> 2;
    const int tr = (lane & 3) * 2;
    float bj0[8], bj1[8];
#pragma unroll
    for (int j = 0; j < 8; j++) {
        const int n = bcol + wn + 8 * j + tr;
        bj0[j] = bias[n]; bj1[j] = bias[n + 1];
    }
#pragma unroll
    for (int i = 0; i < 2; i++)
#pragma unroll
        for (int half = 0; half < 2; half++) {
            const int m = brow + wm + 16 * i + 8 * half + tq;
#pragma unroll
            for (int j = 0; j < 8; j++) {
                const int n = bcol + wn + 8 * j + tr;
                float v0 = acc[i][j][half * 2 + 0] + bj0[j];
                float v1 = acc[i][j][half * 2 + 1] + bj1[j];
                *(__half2*)(Ch + (size_t)m * ldc + n) =
                    __halves2half2(__float2half_rn(v0), __float2half_rn(v1));
            }
        }
}

// ================= mega: out-proj + LN1 + FFN + LN2 (paired over z) =================
#define MG_ST_SZ   40960u
#define MG_STB     8192u
#define MG_XQ      81920u
#define MG_WU      0u
#define MG_WD      32768u
#define MG_UC      65536u
#define MEGA_SMEM  114688

struct MegaPair {
    const h16 *QQ[2];
    const h16 *Wo0[2], *Wo1[2];
    const float *ob[2], *ob2[2], *feat[2];
    const float *g1[2], *b1[2];
    const h16 *Wu[2], *Wd[2];
    const float *bu[2], *bd[2];
    const float *g2[2], *b2[2];
    float *O[2];
};

__global__ __launch_bounds__(256, 2) void mega_kernel(MegaPair mp)
{
    extern __shared__ char smem[];
    const uint32_t sb = smem_u32(smem);

    const int z = blockIdx.z;
    const h16* __restrict__ QQ  = mp.QQ[z];
    const h16* __restrict__ Wo0 = mp.Wo0[z];
    const h16* __restrict__ Wo1 = mp.Wo1[z];
    const float* __restrict__ ob   = mp.ob[z];
    const float* __restrict__ ob2  = mp.ob2[z];
    const float* __restrict__ feat = mp.feat[z];
    const float* __restrict__ g1   = mp.g1[z];
    const float* __restrict__ b1   = mp.b1[z];
    const h16* __restrict__ Wu = mp.Wu[z];
    const h16* __restrict__ Wd = mp.Wd[z];
    const float* __restrict__ bu = mp.bu[z];
    const float* __restrict__ bd = mp.bd[z];
    const float* __restrict__ g2 = mp.g2[z];
    const float* __restrict__ b2 = mp.b2[z];
    float* __restrict__ O = mp.O[z];

    const int tid  = threadIdx.x;
    const int wid  = tid >> 5;
    const int lane = tid & 31;
    const int brow = blockIdx.y * 64;

    const int tile = lane >> 3;
    const int rin  = lane & 7;
    const uint32_t rsw = (uint32_t)(rin >> 1);
    const int tq = lane >> 2;
    const int tr = (lane & 3) * 2;

    const int wm = (wid >> 2) * 32;
    const int wn = (wid & 3) * 64;
    const int wm1 = (wid & 1) * 32;
    const int wh  = (wid >> 1) * 16;

    float acc[2][8][4];
#pragma unroll
    for (int i = 0; i < 2; i++)
#pragma unroll
        for (int j = 0; j < 8; j++)
#pragma unroll
            for (int r = 0; r < 4; r++) acc[i][j][r] = 0.f;

    // ---------- PHASE A: out-proj, K=512 in 8 chunks of 64, 2 stages ----------
    auto loadA = [&](int cIdx) {
        const uint32_t st = sb + (uint32_t)(cIdx & 1) * MG_ST_SZ;
        const int k0 = cIdx * 64;
        const h16* bp;
        int kk;
        if (k0 < 256) { bp = Wo0; kk = k0; }
        else          { bp = Wo1; kk = k0 - 256; }
#pragma unroll
        for (int s = 0; s < 10; s++) {
            const int qid = tid + s * 256;
            if (qid < 512) {
                const int row = qid >> 3, c = qid & 7;
                cpasync16(st + (uint32_t)row * 128u + (uint32_t)((c ^ (row & 7)) * 16),
                          QQ + (size_t)(brow + row) * (2 * F) + k0 + c * 8);
            } else {
                const int q = qid - 512;
                const int row = q >> 3, c = q & 7;
                cpasync16(st + MG_STB + (uint32_t)row * 128u +
                          (uint32_t)((c ^ (row & 7)) * 16),
                          bp + (size_t)row * (3 * F) + kk + c * 8);
            }
        }
        asm volatile("cp.async.commit_group;" ::: "memory");
    };

    loadA(0);
    for (int c = 0; c < 8; c++) {
        asm volatile("cp.async.wait_group 0;" ::: "memory");
        __syncthreads();
        if (c + 1 < 8) loadA(c + 1);

        const uint32_t st = sb + (uint32_t)(c & 1) * MG_ST_SZ;
#pragma unroll
        for (int ks = 0; ks < 4; ks++) {
            uint32_t ah[2][4], bh_[4][4];
            const int ca = ks * 2 + (tile >> 1);
#pragma unroll
            for (int i = 0; i < 2; i++) {
                const int arow = wm + i * 16 + (tile & 1) * 8 + rin;
                ldsm4(ah[i], st + (uint32_t)arow * 128u +
                              (uint32_t)((ca ^ (arow & 7)) * 16));
            }
            const int cb = ks * 2 + (tile & 1);
#pragma unroll
            for (int jj = 0; jj < 4; jj++) {
                const int brw = wn + jj * 16 + (tile >> 1) * 8 + rin;
                ldsm4(bh_[jj], st + MG_STB + (uint32_t)brw * 128u +
                               (uint32_t)((cb ^ (brw & 7)) * 16));
            }
#pragma unroll
            for (int i = 0; i < 2; i++)
#pragma unroll
                for (int j = 0; j < 8; j++)
                    mma16816(acc[i][j], ah[i], &bh_[j >> 1][(j & 1) * 2]);
        }
    }
    __syncthreads();

    // ---------- LN1 epilogue -> Xq in smem ----------
    {
        float* redS = (float*)(smem + MG_UC);
        float* redQ = (float*)(smem + MG_UC) + 256;
        const int wslot = wn >> 6;

        float bj0[8], bj1[8];
#pragma unroll
        for (int j = 0; j < 8; j++) {
            const int n = wn + 8 * j + tr;
            bj0[j] = ob[n] + ob2[n];
            bj1[j] = ob[n + 1] + ob2[n + 1];
        }
#pragma unroll
        for (int i = 0; i < 2; i++)
#pragma unroll
            for (int half = 0; half < 2; half++) {
                const int mrow = wm + 16 * i + 8 * half + tq;
                const int m = brow + mrow;
                float s1 = 0.f, s2 = 0.f;
#pragma unroll
                for (int j = 0; j < 8; j++) {
                    float v0 = acc[i][j][half * 2 + 0] + bj0[j];
                    float v1 = acc[i][j][half * 2 + 1] + bj1[j];
                    float2 rr = *(const float2*)(feat + (size_t)m * F + wn + 8 * j + tr);
                    v0 += rr.x; v1 += rr.y;
                    acc[i][j][half * 2 + 0] = v0;
                    acc[i][j][half * 2 + 1] = v1;
                    s1 += v0 + v1;
                    s2 += v0 * v0 + v1 * v1;
                }
                s1 += __shfl_xor_sync(0xffffffffu, s1, 1);
                s2 += __shfl_xor_sync(0xffffffffu, s2, 1);
                s1 += __shfl_xor_sync(0xffffffffu, s1, 2);
                s2 += __shfl_xor_sync(0xffffffffu, s2, 2);
                if ((lane & 3) == 0) {
                    redS[mrow * 4 + wslot] = s1;
                    redQ[mrow * 4 + wslot] = s2;
                }
            }
        __syncthreads();

#pragma unroll
        for (int i = 0; i < 2; i++)
#pragma unroll
            for (int half = 0; half < 2; half++) {
                const int mrow = wm + 16 * i + 8 * half + tq;
                float tS = redS[mrow * 4 + 0] + redS[mrow * 4 + 1]
                         + redS[mrow * 4 + 2] + redS[mrow * 4 + 3];
                float tQ = redQ[mrow * 4 + 0] + redQ[mrow * 4 + 1]
                         + redQ[mrow * 4 + 2] + redQ[mrow * 4 + 3];
                float mean = tS * (1.0f / F);
                float var  = tQ * (1.0f / F) - mean * mean;
                float rstd = rsqrtf(var + 1e-5f);
#pragma unroll
                for (int j = 0; j < 8; j++) {
                    const int n = wn + 8 * j + tr;
                    float2 gg = *(const float2*)(g1 + n);
                    float2 bb = *(const float2*)(b1 + n);
                    float o0 = gg.x * (acc[i][j][half * 2 + 0] - mean) * rstd + bb.x;
                    float o1 = gg.y * (acc[i][j][half * 2 + 1] - mean) * rstd + bb.y;
                    const int s = n >> 5;
                    const int quad = (n >> 3) & 3;
                    uint32_t ad = sb + MG_XQ + (uint32_t)s * 4096u + (uint32_t)mrow * 64u +
                                  (uint32_t)((quad ^ ((mrow >> 1) & 3)) * 16) + (uint32_t)tr * 2u;
                    __half2 hh = __halves2half2(__float2half_rn(o0), __float2half_rn(o1));
                    asm volatile("st.shared.b32 [%0], %1;" :: "r"(ad), "r"(*(uint32_t*)&hh) : "memory");
                }
            }
    }
    __syncthreads();

    // ---------- FFN: 16 hidden chunks of 64 ----------
#pragma unroll
    for (int i = 0; i < 2; i++)
#pragma unroll
        for (int j = 0; j < 8; j++)
#pragma unroll
            for (int r = 0; r < 4; r++) acc[i][j][r] = 0.f;

    auto load_wu = [&](int hc) {
#pragma unroll
        for (int t = 0; t < 8; t++) {
            const int qid = tid + t * 256;
            const int kc = qid >> 8, q = qid & 255;
            const int r = q >> 2, c = q & 3;
            cpasync16(sb + MG_WU + (uint32_t)kc * 4096u + (uint32_t)r * 64u +
                      (uint32_t)((c ^ ((r >> 1) & 3)) * 16),
                      Wu + (size_t)(hc * 64 + r) * F + kc * 32 + c * 8);
        }
        asm volatile("cp.async.commit_group;" ::: "memory");
    };
    auto load_wd = [&](int hc) {
#pragma unroll
        for (int t = 0; t < 8; t++) {
            const int qid = tid + t * 256;
            const int s = qid >> 10, q = qid & 1023;
            const int r = q >> 2, c = q & 3;
            cpasync16(sb + MG_WD + (uint32_t)s * 16384u + (uint32_t)r * 64u +
                      (uint32_t)((c ^ ((r >> 1) & 3)) * 16),
                      Wd + (size_t)r * HIDN + hc * 64 + s * 32 + c * 8);
        }
        asm volatile("cp.async.commit_group;" ::: "memory");
    };

    load_wu(0);
    asm volatile("cp.async.wait_group 0;" ::: "memory");
    __syncthreads();

    for (int hc = 0; hc < 16; hc++) {
        load_wd(hc);

        float acc1[2][2][4];
#pragma unroll
        for (int i = 0; i < 2; i++)
#pragma unroll
            for (int j = 0; j < 2; j++)
#pragma unroll
                for (int r = 0; r < 4; r++) acc1[i][j][r] = 0.f;

#pragma unroll
        for (int kc = 0; kc < 8; kc++) {
            const uint32_t sx = sb + MG_XQ + (uint32_t)kc * 4096u;
            const uint32_t sw = sb + MG_WU + (uint32_t)kc * 4096u;
#pragma unroll
            for (int ks = 0; ks < 2; ks++) {
                uint32_t ah[2][4], bh_[4];
                const uint32_t swa = ((uint32_t)(ks * 2 + (tile >> 1)) ^ rsw) * 16u;
#pragma unroll
                for (int i = 0; i < 2; i++)
                    ldsm4(ah[i], sx + (uint32_t)(wm1 + i * 16 + (tile & 1) * 8 + rin) * 64u + swa);
                const uint32_t swb = ((uint32_t)(ks * 2 + (tile & 1)) ^ rsw) * 16u;
                ldsm4(bh_, sw + (uint32_t)(wh + (tile >> 1) * 8 + rin) * 64u + swb);
#pragma unroll
                for (int i = 0; i < 2; i++)
#pragma unroll
                    for (int j = 0; j < 2; j++)
                        mma16816(acc1[i][j], ah[i], &bh_[j * 2]);
            }
        }

        {
            const int sub   = wh >> 5;
            const int cbase = (wh & 31) >> 3;
            const uint32_t ucb = sb + MG_UC + (uint32_t)sub * 4096u;
#pragma unroll
            for (int i = 0; i < 2; i++)
#pragma unroll
                for (int j = 0; j < 2; j++) {
                    const int nh = hc * 64 + wh + j * 8 + tr;
                    float bb0 = bu[nh], bb1 = bu[nh + 1];
                    float v0 = fmaxf(acc1[i][j][0] + bb0, 0.f);
                    float v1 = fmaxf(acc1[i][j][1] + bb1, 0.f);
                    float v2 = fmaxf(acc1[i][j][2] + bb0, 0.f);
                    float v3 = fmaxf(acc1[i][j][3] + bb1, 0.f);
                    const int quad = cbase + j;
                    const int row0 = wm1 + i * 16 + tq;
                    const int row1 = row0 + 8;
                    uint32_t a0 = ucb + (uint32_t)row0 * 64u +
                                  (uint32_t)((quad ^ ((row0 >> 1) & 3)) * 16) + (uint32_t)tr * 2u;
                    uint32_t a1 = ucb + (uint32_t)row1 * 64u +
                                  (uint32_t)((quad ^ ((row1 >> 1) & 3)) * 16) + (uint32_t)tr * 2u;
                    __half2 h01 = __halves2half2(__float2half_rn(v0), __float2half_rn(v1));
                    __half2 h23 = __halves2half2(__float2half_rn(v2), __float2half_rn(v3));
                    asm volatile("st.shared.b32 [%0], %1;" :: "r"(a0), "r"(*(uint32_t*)&h01) : "memory");
                    asm volatile("st.shared.b32 [%0], %1;" :: "r"(a1), "r"(*(uint32_t*)&h23) : "memory");
                }
        }
        __syncthreads();

        if (hc < 15) load_wu(hc + 1);

        if (hc < 15) {
            asm volatile("cp.async.wait_group 1;" ::: "memory");
        } else {
            asm volatile("cp.async.wait_group 0;" ::: "memory");
        }

#pragma unroll
        for (int s = 0; s < 2; s++) {
            const uint32_t su = sb + MG_UC + (uint32_t)s * 4096u;
            const uint32_t sd = sb + MG_WD + (uint32_t)s * 16384u;
#pragma unroll
            for (int ks = 0; ks < 2; ks++) {
                uint32_t ah[2][4], bh_[4][4];
                const uint32_t swa = ((uint32_t)(ks * 2 + (tile >> 1)) ^ rsw) * 16u;
#pragma unroll
                for (int i = 0; i < 2; i++)
                    ldsm4(ah[i], su + (uint32_t)(wm + i * 16 + (tile & 1) * 8 + rin) * 64u + swa);
                const uint32_t swb = ((uint32_t)(ks * 2 + (tile & 1)) ^ rsw) * 16u;
#pragma unroll
                for (int jj = 0; jj < 4; jj++)
                    ldsm4(bh_[jj], sd + (uint32_t)(wn + jj * 16 + (tile >> 1) * 8 + rin) * 64u + swb);
#pragma unroll
                for (int i = 0; i < 2; i++)
#pragma unroll
                    for (int j = 0; j < 8; j++)
                        mma16816(acc[i][j], ah[i], &bh_[j >> 1][(j & 1) * 2]);
            }
        }

        asm volatile("cp.async.wait_group 0;" ::: "memory");
        __syncthreads();
    }

    // ---------- LN2 epilogue -> out (residual = Xq from smem) ----------
    {
        float* redS = (float*)(smem + MG_UC);
        float* redQ = (float*)(smem + MG_UC) + 256;
        const int wslot = wn >> 6;

        float bj0[8], bj1[8];
#pragma unroll
        for (int j = 0; j < 8; j++) {
            const int n = wn + 8 * j + tr;
            bj0[j] = bd[n]; bj1[j] = bd[n + 1];
        }

#pragma unroll
        for (int i = 0; i < 2; i++)
#pragma unroll
            for (int half = 0; half < 2; half++) {
                const int mrow = wm + 16 * i + 8 * half + tq;
                float s1 = 0.f, s2 = 0.f;
#pragma unroll
                for (int j = 0; j < 8; j++) {
                    const int n = wn + 8 * j + tr;
                    float v0 = acc[i][j][half * 2 + 0] + bj0[j];
                    float v1 = acc[i][j][half * 2 + 1] + bj1[j];
                    const int s = n >> 5;
                    const int quad = (n >> 3) & 3;
                    uint32_t ad = sb + MG_XQ + (uint32_t)s * 4096u + (uint32_t)mrow * 64u +
                                  (uint32_t)((quad ^ ((mrow >> 1) & 3)) * 16) + (uint32_t)tr * 2u;
                    uint32_t xv;
                    asm volatile("ld.shared.b32 %0, [%1];" : "=r"(xv) : "r"(ad));
                    float2 xf = __half22float2(*(__half2*)&xv);
                    v0 += xf.x; v1 += xf.y;
                    acc[i][j][half * 2 + 0] = v0;
                    acc[i][j][half * 2 + 1] = v1;
                    s1 += v0 + v1;
                    s2 += v0 * v0 + v1 * v1;
                }
                s1 += __shfl_xor_sync(0xffffffffu, s1, 1);
                s2 += __shfl_xor_sync(0xffffffffu, s2, 1);
                s1 += __shfl_xor_sync(0xffffffffu, s1, 2);
                s2 += __shfl_xor_sync(0xffffffffu, s2, 2);
                if ((lane & 3) == 0) {
                    redS[mrow * 4 + wslot] = s1;
                    redQ[mrow * 4 + wslot] = s2;
                }
            }
        __syncthreads();

#pragma unroll
        for (int i = 0; i < 2; i++)
#pragma unroll
            for (int half = 0; half < 2; half++) {
                const int mrow = wm + 16 * i + 8 * half + tq;
                const int m = brow + mrow;
                float tS = redS[mrow * 4 + 0] + redS[mrow * 4 + 1]
                         + redS[mrow * 4 + 2] + redS[mrow * 4 + 3];
                float tQ = redQ[mrow * 4 + 0] + redQ[mrow * 4 + 1]
                         + redQ[mrow * 4 + 2] + redQ[mrow * 4 + 3];
                float mean = tS * (1.0f / F);
                float var  = tQ * (1.0f / F) - mean * mean;
                float rstd = rsqrtf(var + 1e-5f);
#pragma unroll
                for (int j = 0; j < 8; j++) {
                    const int n = wn + 8 * j + tr;
                    float2 gg = *(const float2*)(g2 + n);
                    float2 bb = *(const float2*)(b2 + n);
                    float o0 = gg.x * (acc[i][j][half * 2 + 0] - mean) * rstd + bb.x;
                    float o1 = gg.y * (acc[i][j][half * 2 + 1] - mean) * rstd + bb.y;
                    *(float2*)(O + (size_t)m * F + n) = make_float2(o0, o1);
                }
            }
    }
}

// ---------------- merged convert fp32 -> fp16 ----------------
#define NSEG 10
struct ConvArgs {
    const float* s[NSEG];
    h16* h[NSEG];
    int end4[NSEG];
};

__global__ __launch_bounds__(256) void conv_all(ConvArgs a, int total4)
{
    int i = blockIdx.x * 256 + threadIdx.x;
    if (i >= total4) return;
    int seg = 0;
#pragma unroll
    for (int s = 0; s < NSEG - 1; s++) seg += (i >= a.end4[s]) ? 1 : 0;
    const int base = seg ? a.end4[seg - 1] : 0;
    const int j = i - base;

    float4 v = ((const float4*)a.s[seg])[j];
    h16* hp = a.h[seg];
    ((__half2*)hp)[2 * j]     = __halves2half2(__float2half_rn(v.x), __float2half_rn(v.y));
    ((__half2*)hp)[2 * j + 1] = __halves2half2(__float2half_rn(v.z), __float2half_rn(v.w));
}

// ---------------- 9-tap attention, smem halo staging (4 slices via y) ----------------
#define APX 16
#define PXSTRIDE 1088u
#define ATT_SMEM (54*1088)

struct AttArgs {
    const h16* Q[4];
    const h16* Kp[4];
    const h16* Vp[4];
    h16* O[4];
};

__global__ __launch_bounds__(256) void attend_kernel(AttArgs a, int ostride)
{
    extern __shared__ char attsm[];
    const uint32_t sb = smem_u32(attsm);

    const int z    = blockIdx.y;
    const int tid  = threadIdx.x;
    const int pix0 = blockIdx.x * APX;
    const int b    = pix0 / (HH * WW);
    const int rr   = pix0 % (HH * WW);
    const int y    = rr / WW;
    const int x0   = rr % WW;

    const h16* __restrict__ Q  = a.Q[z];
    const h16* __restrict__ Kp = a.Kp[z];
    const h16* __restrict__ Vp = a.Vp[z];

#pragma unroll
    for (int t = 0; t < 14; t++) {
        const int qid = tid + t * 256;
        if (qid < 3456) {
            const int e   = qid >> 6;
            const int qq  = qid & 63;
            const int isV = qq >> 5;
            const int q   = qq & 31;
            const int yy  = y + (e / 18) - 1;
            const int xx  = x0 + (e % 18) - 1;
            const bool ok = (yy >= 0 && yy < HH && xx >= 0 && xx < WW);
            const int ys  = ok ? yy : 0;
            const int xs  = ok ? xx : 0;
            const h16* src = (isV ? Vp : Kp) +
                ((size_t)(b * HH + ys) * WW + xs) * PDIM + q * 8;
            cpasync16z(sb + (uint32_t)e * PXSTRIDE + (uint32_t)isV * 512u + (uint32_t)q * 16u,
                       src, ok ? 16 : 0);
        }
    }
    asm volatile("cp.async.commit_group;" ::: "memory");
    asm volatile("cp.async.wait_group 0;" ::: "memory");
    __syncthreads();

    const int px  = tid >> 4;
    const int t16 = tid & 15;
    const int ch  = t16 * 16;
    const int pix = pix0 + px;

    const float scale = 0.17677669529663687f;
    float qf[16];
    {
        const uint4* qp = (const uint4*)(Q + (size_t)pix * PDIM + ch);
        uint4 q0 = qp[0], q1 = qp[1];
        const uint32_t* qu = (const uint32_t*)&q0;
#pragma unroll
        for (int i = 0; i < 4; i++) {
            float2 f = __half22float2(*(__half2*)&qu[i]);
            qf[2 * i] = f.x * scale; qf[2 * i + 1] = f.y * scale;
        }
        const uint32_t* qu2 = (const uint32_t*)&q1;
#pragma unroll
        for (int i = 0; i < 4; i++) {
            float2 f = __half22float2(*(__half2*)&qu2[i]);
            qf[8 + 2 * i] = f.x * scale; qf[8 + 2 * i + 1] = f.y * scale;
        }
    }

    float sc[9];
#pragma unroll
    for (int n = 0; n < 9; n++) {
        const int hal = (n / 3) * 18 + px + (n % 3);
        const char* kb = attsm + hal * PXSTRIDE + ch * 2;
        uint4 k0 = *(const uint4*)kb;
        uint4 k1 = *(const uint4*)(kb + 16);
        float s = 0.f;
        const uint32_t* ku = (const uint32_t*)&k0;
#pragma unroll
        for (int i = 0; i < 4; i++) {
            float2 f = __half22float2(*(__half2*)&ku[i]);
            s = fmaf(qf[2 * i], f.x, s);
            s = fmaf(qf[2 * i + 1], f.y, s);
        }
        const uint32_t* ku2 = (const uint32_t*)&k1;
#pragma unroll
        for (int i = 0; i < 4; i++) {
            float2 f = __half22float2(*(__half2*)&ku2[i]);
            s = fmaf(qf[8 + 2 * i], f.x, s);
            s = fmaf(qf[8 + 2 * i + 1], f.y, s);
        }
        s += __shfl_xor_sync(0xffffffffu, s, 1);
        sc[n] = s;
    }

    float mx = sc[0];
#pragma unroll
    for (int n = 1; n < 9; n++) mx = fmaxf(mx, sc[n]);
    float w[9], den = 0.f;
#pragma unroll
    for (int n = 0; n < 9; n++) { w[n] = __expf(sc[n] - mx); den += w[n]; }

    float o[16];
#pragma unroll
    for (int i = 0; i < 16; i++) o[i] = 0.f;
#pragma unroll
    for (int n = 0; n < 9; n++) {
        const int hal = (n / 3) * 18 + px + (n % 3);
        const char* vb = attsm + hal * PXSTRIDE + 512 + ch * 2;
        uint4 v0 = *(const uint4*)vb;
        uint4 v1 = *(const uint4*)(vb + 16);
        const uint32_t* vu = (const uint32_t*)&v0;
#pragma unroll
        for (int i = 0; i < 4; i++) {
            float2 f = __half22float2(*(__half2*)&vu[i]);
            o[2 * i]     = fmaf(w[n], f.x, o[2 * i]);
            o[2 * i + 1] = fmaf(w[n], f.y, o[2 * i + 1]);
        }
        const uint32_t* vu2 = (const uint32_t*)&v1;
#pragma unroll
        for (int i = 0; i < 4; i++) {
            float2 f = __half22float2(*(__half2*)&vu2[i]);
            o[8 + 2 * i]     = fmaf(w[n], f.x, o[8 + 2 * i]);
            o[8 + 2 * i + 1] = fmaf(w[n], f.y, o[8 + 2 * i + 1]);
        }
    }

    const float inv = 1.f / den;
    uint32_t pk[8];
#pragma unroll
    for (int i = 0; i < 8; i++) {
        __half2 h = __halves2half2(__float2half_rn(o[2 * i] * inv),
                                   __float2half_rn(o[2 * i + 1] * inv));
        pk[i] = *(uint32_t*)&h;
    }
    h16* op = a.O[z] + (size_t)pix * ostride + ch;
    *(uint4*)op        = make_uint4(pk[0], pk[1], pk[2], pk[3]);
    *(uint4*)(op + 8)  = make_uint4(pk[4], pk[5], pk[6], pk[7]);
}

// ---------------- launch ----------------
#define SYM(p, s) cudaGetSymbolAddress((void**)&p, s)

extern "C" void kernel_launch(void* const* d_in, const int* in_sizes, int n_in,
                              void* d_out, int out_size)
{
    const float* feat0       = (const float*)d_in[0];
    const float* feat1       = (const float*)d_in[1];
    const float* in_w0       = (const float*)d_in[2];
    const float* in_b0       = (const float*)d_in[3];
    const float* in_w1       = (const float*)d_in[4];
    const float* in_b1       = (const float*)d_in[5];
    const float* out_w0      = (const float*)d_in[6];
    const float* out_b0      = (const float*)d_in[7];
    const float* out_w1      = (const float*)d_in[8];
    const float* out_b1      = (const float*)d_in[9];
    const float* ln1_g0      = (const float*)d_in[10];
    const float* ln1_b0      = (const float*)d_in[11];
    const float* ln1_g1      = (const float*)d_in[12];
    const float* ln1_b1      = (const float*)d_in[13];
    const float* ffn_up_w0   = (const float*)d_in[14];
    const float* ffn_up_b0   = (const float*)d_in[15];
    const float* ffn_down_w0 = (const float*)d_in[16];
    const float* ffn_down_b0 = (const float*)d_in[17];
    const float* ffn_up_w1   = (const float*)d_in[18];
    const float* ffn_up_b1   = (const float*)d_in[19];
    const float* ffn_down_w1 = (const float*)d_in[20];
    const float* ffn_down_b1 = (const float*)d_in[21];
    const float* ln2_g0      = (const float*)d_in[22];
    const float* ln2_b0      = (const float*)d_in[23];
    const float* ln2_g1      = (const float*)d_in[24];
    const float* ln2_b1      = (const float*)d_in[25];

    h16 *P0, *P1, *f0, *f1, *wi0, *wi1, *wo0, *wo1, *wu0, *wu1, *wd0, *wd1;
    h16 *QQ0, *QQ1;
    SYM(P0, g_P0); SYM(P1, g_P1);
    SYM(f0, g_f0); SYM(f1, g_f1);
    SYM(wi0, g_wi0); SYM(wi1, g_wi1);
    SYM(wo0, g_wo0); SYM(wo1, g_wo1);
    SYM(wu0, g_wu0); SYM(wu1, g_wu1);
    SYM(wd0, g_wd0); SYM(wd1, g_wd1);
    SYM(QQ0, g_QQ0); SYM(QQ1, g_QQ1);

    cudaFuncSetAttribute(gemm_h16, cudaFuncAttributeMaxDynamicSharedMemorySize, GEMM_SMEM);
    cudaFuncSetAttribute(mega_kernel, cudaFuncAttributeMaxDynamicSharedMemorySize, MEGA_SMEM);
    cudaFuncSetAttribute(attend_kernel, cudaFuncAttributeMaxDynamicSharedMemorySize, ATT_SMEM);

    float* out = (float*)d_out;
    dim3 blk(256);

    // ---- launch 0: all converts ----
    {
        ConvArgs ca;
        const float* srcs[NSEG] = {feat0, feat1, in_w0, in_w1, out_w0, out_w1,
                                   ffn_up_w0, ffn_up_w1, ffn_down_w0, ffn_down_w1};
        h16* hs[NSEG] = {f0, f1, wi0, wi1, wo0, wo1, wu0, wu1, wd0, wd1};
        int sizes4[NSEG] = {NPIX*F/4, NPIX*F/4, PDIM*F/4, PDIM*F/4, F*3*F/4, F*3*F/4,
                            HIDN*F/4, HIDN*F/4, F*HIDN/4, F*HIDN/4};
        int acc4 = 0;
        for (int i = 0; i < NSEG; i++) {
            ca.s[i] = srcs[i]; ca.h[i] = hs[i];
            acc4 += sizes4[i];
            ca.end4[i] = acc4;
        }
        conv_all<<<(acc4 + 255) / 256, blk>>>(ca, acc4);
    }

    // ---- launch 1: in-projection GEMMs -> P fp16 (64x256 mega-geometry) ----
    {
        GemmPair gp = {};
        gp.A[0]=f0; gp.A[1]=f1;
        gp.B[0]=wi0; gp.B[1]=wi1;
        gp.bias[0]=in_b0; gp.bias[1]=in_b1;
        gp.Ch[0]=P0; gp.Ch[1]=P1;
        gemm_h16<<<dim3(PDIM/256, NPIX/64, 2), blk, GEMM_SMEM>>>(gp, F, F, PDIM, F);
    }

    // ---- launch 2: 4 attentions (smem-tiled) -> QQ fp16 ----
    {
        AttArgs aa;
        aa.Q[0]=P0;     aa.Kp[0]=P0+F;   aa.Vp[0]=P0+2*F; aa.O[0]=QQ0;
        aa.Q[1]=P1;     aa.Kp[1]=P1+F;   aa.Vp[1]=P1+2*F; aa.O[1]=QQ1;
        aa.Q[2]=P0+3*F; aa.Kp[2]=P1+4*F; aa.Vp[2]=P1+5*F; aa.O[2]=QQ0+F;
        aa.Q[3]=P1+3*F; aa.Kp[3]=P0+4*F; aa.Vp[3]=P0+5*F; aa.O[3]=QQ1+F;
        attend_kernel<<<dim3(NPIX/APX, 4), blk, ATT_SMEM>>>(aa, 2*F);
    }

    // ---- launch 3: mega (out-proj + LN1 + FFN + LN2) -> output ----
    {
        MegaPair mp = {};
        mp.QQ[0]=QQ0; mp.QQ[1]=QQ1;
        mp.Wo0[0]=wo0; mp.Wo1[0]=wo0+F;
        mp.Wo0[1]=wo1; mp.Wo1[1]=wo0+F;
        mp.ob[0]=out_b0; mp.ob2[0]=out_b0+F; mp.feat[0]=feat0;
        mp.ob[1]=out_b1; mp.ob2[1]=out_b0+F; mp.feat[1]=feat1;
        mp.g1[0]=ln1_g0; mp.b1[0]=ln1_b0;
        mp.g1[1]=ln1_g1; mp.b1[1]=ln1_b1;
        mp.Wu[0]=wu0; mp.Wu[1]=wu1;
        mp.Wd[0]=wd0; mp.Wd[1]=wd1;
        mp.bu[0]=ffn_up_b0;   mp.bu[1]=ffn_up_b1;
        mp.bd[0]=ffn_down_b0; mp.bd[1]=ffn_down_b1;
        mp.g2[0]=ln2_g0; mp.b2[0]=ln2_b0; mp.O[0]=out;
        mp.g2[1]=ln2_g1; mp.b2[1]=ln2_b1; mp.O[1]=out + (size_t)NPIX*F;
        mega_kernel<<<dim3(1, NPIX/64, 2), blk, MEGA_SMEM>>>(mp);
    }
}